// round 1
// baseline (speedup 1.0000x reference)
#include <cuda_runtime.h>
#include <math.h>

#define NL 3
#define D_MODEL 128
#define N_HEADS 4
#define DHEAD 32
#define DFF 512
#define DIN 64
#define BATCH 2
#define LSEQ 2048
#define S_LEN 2049
#define MROWS (BATCH * S_LEN)   // 4098

// ---------------- scratch (device globals; no allocation) ----------------
__device__ float g_h[MROWS * D_MODEL];
__device__ float g_hn[MROWS * D_MODEL];
__device__ float g_qkv[MROWS * 3 * D_MODEL];
__device__ float g_attn[MROWS * D_MODEL];
__device__ float g_ff[MROWS * DFF];

// ---------------- embedding ----------------
// h[b,0,:] = cls + pos[0]; h[b,s,:] = x[b,s-1] @ embed_w^T + embed_b + pos[s]
__global__ __launch_bounds__(128) void embed_kernel(
    const float* __restrict__ x, const float* __restrict__ ew,
    const float* __restrict__ eb, const float* __restrict__ pos,
    const float* __restrict__ cls, float* __restrict__ h)
{
    __shared__ float xs[DIN];
    int s = blockIdx.x, b = blockIdx.y;
    int d = threadIdx.x;
    float val;
    if (s == 0) {
        val = cls[d] + pos[d];
    } else {
        if (d < DIN) xs[d] = x[((size_t)b * LSEQ + (s - 1)) * DIN + d];
        __syncthreads();
        float acc = 0.f;
        const float* wr = ew + (size_t)d * DIN;
        #pragma unroll
        for (int j = 0; j < DIN; j++) acc = fmaf(xs[j], wr[j], acc);
        val = acc + eb[d] + pos[(size_t)s * D_MODEL + d];
    }
    h[((size_t)b * S_LEN + s) * D_MODEL + d] = val;
}

// ---------------- layernorm (warp per 128-wide row) ----------------
__global__ __launch_bounds__(256) void ln_kernel(
    const float* __restrict__ x, const float* __restrict__ sc,
    const float* __restrict__ bi, float* __restrict__ y, int nrows)
{
    int row = blockIdx.x * 8 + (threadIdx.x >> 5);
    if (row >= nrows) return;
    int lane = threadIdx.x & 31;
    const float* xr = x + (size_t)row * D_MODEL;
    float4 v = *reinterpret_cast<const float4*>(xr + lane * 4);
    float sum = v.x + v.y + v.z + v.w;
    #pragma unroll
    for (int o = 16; o; o >>= 1) sum += __shfl_xor_sync(0xffffffffu, sum, o);
    float mean = sum * (1.f / 128.f);
    float dx = v.x - mean, dy = v.y - mean, dz = v.z - mean, dw = v.w - mean;
    float vs = dx * dx + dy * dy + dz * dz + dw * dw;
    #pragma unroll
    for (int o = 16; o; o >>= 1) vs += __shfl_xor_sync(0xffffffffu, vs, o);
    float rstd = rsqrtf(vs * (1.f / 128.f) + 1e-5f);
    float4 s4 = *reinterpret_cast<const float4*>(sc + lane * 4);
    float4 b4 = *reinterpret_cast<const float4*>(bi + lane * 4);
    float4 o4;
    o4.x = dx * rstd * s4.x + b4.x;
    o4.y = dy * rstd * s4.y + b4.y;
    o4.z = dz * rstd * s4.z + b4.z;
    o4.w = dw * rstd * s4.w + b4.w;
    *reinterpret_cast<float4*>(y + (size_t)row * D_MODEL + lane * 4) = o4;
}

// ---------------- GEMM: C[m,n] = A[m,:] . W[n,:] + bias[n] (+resid) (ReLU?) ----
// A: [M,K] row-major, W: [N,K] row-major. 64x64x16 tiles, 256 threads, 4x4/thread.
template <bool RELU, bool RESID>
__global__ __launch_bounds__(256) void gemm_kernel(
    const float* __restrict__ A, const float* __restrict__ W,
    const float* __restrict__ bias, const float* __restrict__ resid,
    float* __restrict__ C, int M, int N, int K)
{
    __shared__ float As[16][64];
    __shared__ float Ws[16][64];
    int tid = threadIdx.x;
    int tx = tid & 15, ty = tid >> 4;
    int m0 = blockIdx.y * 64, n0 = blockIdx.x * 64;
    int lrow = tid >> 2;          // 0..63
    int lq = (tid & 3) * 4;       // 0,4,8,12
    float acc[4][4] = {};
    for (int k0 = 0; k0 < K; k0 += 16) {
        int m = m0 + lrow;
        float4 av = (m < M)
            ? *reinterpret_cast<const float4*>(A + (size_t)m * K + k0 + lq)
            : make_float4(0.f, 0.f, 0.f, 0.f);
        float4 wv = *reinterpret_cast<const float4*>(W + (size_t)(n0 + lrow) * K + k0 + lq);
        As[lq + 0][lrow] = av.x; As[lq + 1][lrow] = av.y;
        As[lq + 2][lrow] = av.z; As[lq + 3][lrow] = av.w;
        Ws[lq + 0][lrow] = wv.x; Ws[lq + 1][lrow] = wv.y;
        Ws[lq + 2][lrow] = wv.z; Ws[lq + 3][lrow] = wv.w;
        __syncthreads();
        #pragma unroll
        for (int k = 0; k < 16; k++) {
            float4 a = *reinterpret_cast<const float4*>(&As[k][ty * 4]);
            float4 b = *reinterpret_cast<const float4*>(&Ws[k][tx * 4]);
            float av2[4] = {a.x, a.y, a.z, a.w};
            float bv2[4] = {b.x, b.y, b.z, b.w};
            #pragma unroll
            for (int i = 0; i < 4; i++)
                #pragma unroll
                for (int j = 0; j < 4; j++)
                    acc[i][j] = fmaf(av2[i], bv2[j], acc[i][j]);
        }
        __syncthreads();
    }
    #pragma unroll
    for (int i = 0; i < 4; i++) {
        int m = m0 + ty * 4 + i;
        if (m >= M) continue;
        #pragma unroll
        for (int j = 0; j < 4; j++) {
            int n = n0 + tx * 4 + j;
            float v = acc[i][j] + bias[n];
            if (RESID) v += resid[(size_t)m * N + n];
            if (RELU) v = fmaxf(v, 0.f);
            C[(size_t)m * N + n] = v;
        }
    }
}

// ---------------- attention (flash-lite, thread = 1 query, 32-key tiles) ----
__global__ __launch_bounds__(128) void attn_kernel(
    const float* __restrict__ qkv, float* __restrict__ out)
{
    const int b = blockIdx.z, h = blockIdx.y;
    const int q = blockIdx.x * 128 + threadIdx.x;
    const bool qvalid = (q < S_LEN);
    __shared__ float Ks[32][32];
    __shared__ float Vs[32][32];
    const float scale = 0.17677669529663687f; // 1/sqrt(32)
    float qv[32];
    const float* qptr = qkv + ((size_t)(b * S_LEN + (qvalid ? q : 0))) * 384 + h * 32;
    #pragma unroll
    for (int d = 0; d < 32; d += 4) {
        float4 v = *reinterpret_cast<const float4*>(qptr + d);
        qv[d] = v.x * scale; qv[d + 1] = v.y * scale;
        qv[d + 2] = v.z * scale; qv[d + 3] = v.w * scale;
    }
    float m = -1e30f, l = 0.f;
    float acc[32] = {};
    for (int kb = 0; kb < S_LEN; kb += 32) {
        int kcnt = min(32, S_LEN - kb);
        __syncthreads();
        for (int idx = threadIdx.x; idx < 32 * 32; idx += 128) {
            int kk = idx >> 5, d = idx & 31;
            if (kk < kcnt) {
                size_t base = ((size_t)(b * S_LEN + kb + kk)) * 384 + h * 32 + d;
                Ks[kk][d] = qkv[base + 128];
                Vs[kk][d] = qkv[base + 256];
            } else { Ks[kk][d] = 0.f; Vs[kk][d] = 0.f; }
        }
        __syncthreads();
        float sc[32];
        float tmax = -1e30f;
        #pragma unroll
        for (int kk = 0; kk < 32; kk++) {
            float s = 0.f;
            #pragma unroll
            for (int d = 0; d < 32; d++) s = fmaf(qv[d], Ks[kk][d], s);
            s = (kb + kk < S_LEN) ? s : -1e30f;
            sc[kk] = s;
            tmax = fmaxf(tmax, s);
        }
        float mnew = fmaxf(m, tmax);
        float corr = __expf(m - mnew);
        l *= corr;
        #pragma unroll
        for (int d = 0; d < 32; d++) acc[d] *= corr;
        #pragma unroll
        for (int kk = 0; kk < 32; kk++) {
            float p = __expf(sc[kk] - mnew);
            l += p;
            #pragma unroll
            for (int d = 0; d < 32; d++) acc[d] = fmaf(p, Vs[kk][d], acc[d]);
        }
        m = mnew;
    }
    if (qvalid) {
        float inv = 1.f / l;
        float* optr = out + ((size_t)(b * S_LEN + q)) * 128 + h * 32;
        #pragma unroll
        for (int d = 0; d < 32; d++) optr[d] = acc[d] * inv;
    }
}

// ---------------- head: LN(h[:,0]) . head_w + head_b -> out[B] ----------------
__global__ __launch_bounds__(64) void head_kernel(
    const float* __restrict__ h, const float* __restrict__ ls,
    const float* __restrict__ lb, const float* __restrict__ hw,
    const float* __restrict__ hb, float* __restrict__ out)
{
    int bidx = threadIdx.x >> 5;
    if (bidx >= BATCH) return;
    int lane = threadIdx.x & 31;
    const float* xr = h + (size_t)bidx * S_LEN * D_MODEL;
    float4 v = *reinterpret_cast<const float4*>(xr + lane * 4);
    float sum = v.x + v.y + v.z + v.w;
    #pragma unroll
    for (int o = 16; o; o >>= 1) sum += __shfl_xor_sync(0xffffffffu, sum, o);
    float mean = sum * (1.f / 128.f);
    float dx = v.x - mean, dy = v.y - mean, dz = v.z - mean, dw = v.w - mean;
    float vs = dx * dx + dy * dy + dz * dz + dw * dw;
    #pragma unroll
    for (int o = 16; o; o >>= 1) vs += __shfl_xor_sync(0xffffffffu, vs, o);
    float rstd = rsqrtf(vs * (1.f / 128.f) + 1e-5f);
    float4 s4 = *reinterpret_cast<const float4*>(ls + lane * 4);
    float4 b4 = *reinterpret_cast<const float4*>(lb + lane * 4);
    float4 w4 = *reinterpret_cast<const float4*>(hw + lane * 4);
    float dot = (dx * rstd * s4.x + b4.x) * w4.x
              + (dy * rstd * s4.y + b4.y) * w4.y
              + (dz * rstd * s4.z + b4.z) * w4.z
              + (dw * rstd * s4.w + b4.w) * w4.w;
    #pragma unroll
    for (int o = 16; o; o >>= 1) dot += __shfl_xor_sync(0xffffffffu, dot, o);
    if (lane == 0) out[bidx] = dot + hb[0];
}

// ---------------- launch ----------------
extern "C" void kernel_launch(void* const* d_in, const int* in_sizes, int n_in,
                              void* d_out, int out_size)
{
    const float* x        = (const float*)d_in[0];
    const float* embed_w  = (const float*)d_in[1];
    const float* embed_b  = (const float*)d_in[2];
    const float* pos_emb  = (const float*)d_in[3];
    const float* cls      = (const float*)d_in[4];
    const float* in_w     = (const float*)d_in[5];
    const float* in_b     = (const float*)d_in[6];
    const float* out_w    = (const float*)d_in[7];
    const float* out_b    = (const float*)d_in[8];
    const float* ln1_s    = (const float*)d_in[9];
    const float* ln1_b    = (const float*)d_in[10];
    const float* ln2_s    = (const float*)d_in[11];
    const float* ln2_b    = (const float*)d_in[12];
    const float* ff1_w    = (const float*)d_in[13];
    const float* ff1_b    = (const float*)d_in[14];
    const float* ff2_w    = (const float*)d_in[15];
    const float* ff2_b    = (const float*)d_in[16];
    const float* hln_s    = (const float*)d_in[17];
    const float* hln_b    = (const float*)d_in[18];
    const float* head_w   = (const float*)d_in[19];
    const float* head_b   = (const float*)d_in[20];
    float* outp = (float*)d_out;

    float *h, *hn, *qkv, *attn, *ff;
    cudaGetSymbolAddress((void**)&h,    g_h);
    cudaGetSymbolAddress((void**)&hn,   g_hn);
    cudaGetSymbolAddress((void**)&qkv,  g_qkv);
    cudaGetSymbolAddress((void**)&attn, g_attn);
    cudaGetSymbolAddress((void**)&ff,   g_ff);

    // embedding + CLS + positions
    embed_kernel<<<dim3(S_LEN, BATCH), 128>>>(x, embed_w, embed_b, pos_emb, cls, h);

    const int M = MROWS;
    dim3 lnGrid((M + 7) / 8);
    dim3 gemmBlk(256);

    for (int i = 0; i < NL; i++) {
        // LN1
        ln_kernel<<<lnGrid, 256>>>(h, ln1_s + i * D_MODEL, ln1_b + i * D_MODEL, hn, M);
        // QKV projection: [M,128] x [384,128]^T
        gemm_kernel<false, false><<<dim3(384 / 64, (M + 63) / 64), gemmBlk>>>(
            hn, in_w + (size_t)i * 384 * 128, in_b + (size_t)i * 384,
            nullptr, qkv, M, 384, 128);
        // attention
        attn_kernel<<<dim3((S_LEN + 127) / 128, N_HEADS, BATCH), 128>>>(qkv, attn);
        // out projection + residual into h
        gemm_kernel<false, true><<<dim3(128 / 64, (M + 63) / 64), gemmBlk>>>(
            attn, out_w + (size_t)i * 128 * 128, out_b + (size_t)i * 128,
            h, h, M, 128, 128);
        // LN2
        ln_kernel<<<lnGrid, 256>>>(h, ln2_s + i * D_MODEL, ln2_b + i * D_MODEL, hn, M);
        // FF1 + ReLU
        gemm_kernel<true, false><<<dim3(512 / 64, (M + 63) / 64), gemmBlk>>>(
            hn, ff1_w + (size_t)i * 512 * 128, ff1_b + (size_t)i * 512,
            nullptr, ff, M, 512, 128);
        // FF2 + residual into h
        gemm_kernel<false, true><<<dim3(128 / 64, (M + 63) / 64), gemmBlk>>>(
            ff, ff2_w + (size_t)i * 128 * 512, ff2_b + (size_t)i * 128,
            h, h, M, 128, 512);
    }

    head_kernel<<<1, 64>>>(h, hln_s, hln_b, head_w, head_b, outp);
}

// round 2
// speedup vs baseline: 1.2934x; 1.2934x over previous
#include <cuda_runtime.h>
#include <math.h>

#define NL 3
#define D_MODEL 128
#define N_HEADS 4
#define DHEAD 32
#define DFF 512
#define DIN 64
#define BATCH 2
#define LSEQ 2048
#define S_LEN 2049
#define MROWS (BATCH * S_LEN)   // 4098

// ---------------- scratch (device globals; no allocation) ----------------
__device__ float g_h[MROWS * D_MODEL];
__device__ float g_hn[MROWS * D_MODEL];
__device__ float g_qkv[MROWS * 3 * D_MODEL];
__device__ float g_attn[MROWS * D_MODEL];
__device__ float g_ff[MROWS * DFF];

// ---------------- embedding ----------------
__global__ __launch_bounds__(128) void embed_kernel(
    const float* __restrict__ x, const float* __restrict__ ew,
    const float* __restrict__ eb, const float* __restrict__ pos,
    const float* __restrict__ cls, float* __restrict__ h)
{
    __shared__ float xs[DIN];
    int s = blockIdx.x, b = blockIdx.y;
    int d = threadIdx.x;
    float val;
    if (s == 0) {
        val = cls[d] + pos[d];
    } else {
        if (d < DIN) xs[d] = x[((size_t)b * LSEQ + (s - 1)) * DIN + d];
        __syncthreads();
        float acc = 0.f;
        const float* wr = ew + (size_t)d * DIN;
        #pragma unroll
        for (int j = 0; j < DIN; j++) acc = fmaf(xs[j], wr[j], acc);
        val = acc + eb[d] + pos[(size_t)s * D_MODEL + d];
    }
    h[((size_t)b * S_LEN + s) * D_MODEL + d] = val;
}

// ---------------- layernorm (warp per 128-wide row) ----------------
__global__ __launch_bounds__(256) void ln_kernel(
    const float* __restrict__ x, const float* __restrict__ sc,
    const float* __restrict__ bi, float* __restrict__ y, int nrows)
{
    int row = blockIdx.x * 8 + (threadIdx.x >> 5);
    if (row >= nrows) return;
    int lane = threadIdx.x & 31;
    const float* xr = x + (size_t)row * D_MODEL;
    float4 v = *reinterpret_cast<const float4*>(xr + lane * 4);
    float sum = v.x + v.y + v.z + v.w;
    #pragma unroll
    for (int o = 16; o; o >>= 1) sum += __shfl_xor_sync(0xffffffffu, sum, o);
    float mean = sum * (1.f / 128.f);
    float dx = v.x - mean, dy = v.y - mean, dz = v.z - mean, dw = v.w - mean;
    float vs = dx * dx + dy * dy + dz * dz + dw * dw;
    #pragma unroll
    for (int o = 16; o; o >>= 1) vs += __shfl_xor_sync(0xffffffffu, vs, o);
    float rstd = rsqrtf(vs * (1.f / 128.f) + 1e-5f);
    float4 s4 = *reinterpret_cast<const float4*>(sc + lane * 4);
    float4 b4 = *reinterpret_cast<const float4*>(bi + lane * 4);
    float4 o4;
    o4.x = dx * rstd * s4.x + b4.x;
    o4.y = dy * rstd * s4.y + b4.y;
    o4.z = dz * rstd * s4.z + b4.z;
    o4.w = dw * rstd * s4.w + b4.w;
    *reinterpret_cast<float4*>(y + (size_t)row * D_MODEL + lane * 4) = o4;
}

// ---------------- GEMM: C = A . W^T + bias (+resid) (ReLU?) ----------------
template <bool RELU, bool RESID>
__global__ __launch_bounds__(256) void gemm_kernel(
    const float* __restrict__ A, const float* __restrict__ W,
    const float* __restrict__ bias, const float* __restrict__ resid,
    float* __restrict__ C, int M, int N, int K)
{
    __shared__ float As[16][64];
    __shared__ float Ws[16][64];
    int tid = threadIdx.x;
    int tx = tid & 15, ty = tid >> 4;
    int m0 = blockIdx.y * 64, n0 = blockIdx.x * 64;
    int lrow = tid >> 2;
    int lq = (tid & 3) * 4;
    float acc[4][4] = {};
    for (int k0 = 0; k0 < K; k0 += 16) {
        int m = m0 + lrow;
        float4 av = (m < M)
            ? *reinterpret_cast<const float4*>(A + (size_t)m * K + k0 + lq)
            : make_float4(0.f, 0.f, 0.f, 0.f);
        float4 wv = *reinterpret_cast<const float4*>(W + (size_t)(n0 + lrow) * K + k0 + lq);
        As[lq + 0][lrow] = av.x; As[lq + 1][lrow] = av.y;
        As[lq + 2][lrow] = av.z; As[lq + 3][lrow] = av.w;
        Ws[lq + 0][lrow] = wv.x; Ws[lq + 1][lrow] = wv.y;
        Ws[lq + 2][lrow] = wv.z; Ws[lq + 3][lrow] = wv.w;
        __syncthreads();
        #pragma unroll
        for (int k = 0; k < 16; k++) {
            float4 a = *reinterpret_cast<const float4*>(&As[k][ty * 4]);
            float4 b = *reinterpret_cast<const float4*>(&Ws[k][tx * 4]);
            float av2[4] = {a.x, a.y, a.z, a.w};
            float bv2[4] = {b.x, b.y, b.z, b.w};
            #pragma unroll
            for (int i = 0; i < 4; i++)
                #pragma unroll
                for (int j = 0; j < 4; j++)
                    acc[i][j] = fmaf(av2[i], bv2[j], acc[i][j]);
        }
        __syncthreads();
    }
    #pragma unroll
    for (int i = 0; i < 4; i++) {
        int m = m0 + ty * 4 + i;
        if (m >= M) continue;
        #pragma unroll
        for (int j = 0; j < 4; j++) {
            int n = n0 + tx * 4 + j;
            float v = acc[i][j] + bias[n];
            if (RESID) v += resid[(size_t)m * N + n];
            if (RELU) v = fmaxf(v, 0.f);
            C[(size_t)m * N + n] = v;
        }
    }
}

// ---------------- attention: block-tiled flash (BQ=64, BK=32, 256 thr) ----
#define BQ 64
#define BK 32

__global__ __launch_bounds__(256) void attn_kernel(
    const float* __restrict__ qkv, float* __restrict__ out)
{
    __shared__ float Qs[BQ][33];
    __shared__ float Ks[BK][33];
    __shared__ float Vs[BK][33];
    __shared__ float Ps[BQ][33];
    const int tid = threadIdx.x;
    const int tx = tid & 7;     // 4 key/dim cols each  -> 32
    const int ty = tid >> 3;    // 2 query rows each    -> 64
    const int b = blockIdx.z, h = blockIdx.y;
    const int q0 = blockIdx.x * BQ;
    const float scale = 0.17677669529663687f; // 1/sqrt(32)

    // Q tile: 64 rows x 32 d, pre-scaled
    #pragma unroll
    for (int idx = tid; idx < BQ * 8; idx += 256) {
        int r = idx >> 3, c4 = (idx & 7) << 2;
        int q = q0 + r;
        float4 v = make_float4(0.f, 0.f, 0.f, 0.f);
        if (q < S_LEN)
            v = *reinterpret_cast<const float4*>(
                qkv + ((size_t)(b * S_LEN + q)) * 384 + h * 32 + c4);
        Qs[r][c4 + 0] = v.x * scale; Qs[r][c4 + 1] = v.y * scale;
        Qs[r][c4 + 2] = v.z * scale; Qs[r][c4 + 3] = v.w * scale;
    }
    float m0 = -1e30f, m1 = -1e30f, l0 = 0.f, l1 = 0.f;
    float acc[2][4] = {};
    __syncthreads();

    for (int kb = 0; kb < S_LEN; kb += BK) {
        // K/V tile load: 32 rows x 8 float4 -> one slot per thread
        {
            int kk = tid >> 3, c4 = (tid & 7) << 2;
            int kg = kb + kk;
            float4 k4 = make_float4(0.f, 0.f, 0.f, 0.f);
            float4 v4 = make_float4(0.f, 0.f, 0.f, 0.f);
            if (kg < S_LEN) {
                const float* base = qkv + ((size_t)(b * S_LEN + kg)) * 384 + h * 32 + c4;
                k4 = *reinterpret_cast<const float4*>(base + 128);
                v4 = *reinterpret_cast<const float4*>(base + 256);
            }
            Ks[kk][c4 + 0] = k4.x; Ks[kk][c4 + 1] = k4.y;
            Ks[kk][c4 + 2] = k4.z; Ks[kk][c4 + 3] = k4.w;
            Vs[kk][c4 + 0] = v4.x; Vs[kk][c4 + 1] = v4.y;
            Vs[kk][c4 + 2] = v4.z; Vs[kk][c4 + 3] = v4.w;
        }
        __syncthreads();

        // scores: 2x4 fragment of Q.K^T
        float s[2][4] = {};
        #pragma unroll
        for (int d = 0; d < 32; d++) {
            float a0 = Qs[ty * 2 + 0][d];
            float a1 = Qs[ty * 2 + 1][d];
            float b0 = Ks[tx * 4 + 0][d];
            float b1 = Ks[tx * 4 + 1][d];
            float b2 = Ks[tx * 4 + 2][d];
            float b3 = Ks[tx * 4 + 3][d];
            s[0][0] = fmaf(a0, b0, s[0][0]); s[0][1] = fmaf(a0, b1, s[0][1]);
            s[0][2] = fmaf(a0, b2, s[0][2]); s[0][3] = fmaf(a0, b3, s[0][3]);
            s[1][0] = fmaf(a1, b0, s[1][0]); s[1][1] = fmaf(a1, b1, s[1][1]);
            s[1][2] = fmaf(a1, b2, s[1][2]); s[1][3] = fmaf(a1, b3, s[1][3]);
        }
        // mask invalid keys
        #pragma unroll
        for (int c = 0; c < 4; c++) {
            if (kb + tx * 4 + c >= S_LEN) { s[0][c] = -1e30f; s[1][c] = -1e30f; }
        }
        // row max (4 local + 8-lane shuffle group over tx)
        float t0 = fmaxf(fmaxf(s[0][0], s[0][1]), fmaxf(s[0][2], s[0][3]));
        float t1 = fmaxf(fmaxf(s[1][0], s[1][1]), fmaxf(s[1][2], s[1][3]));
        #pragma unroll
        for (int o = 1; o < 8; o <<= 1) {
            t0 = fmaxf(t0, __shfl_xor_sync(0xffffffffu, t0, o));
            t1 = fmaxf(t1, __shfl_xor_sync(0xffffffffu, t1, o));
        }
        float mn0 = fmaxf(m0, t0), mn1 = fmaxf(m1, t1);
        float c0 = __expf(m0 - mn0), c1 = __expf(m1 - mn1);
        float p[2][4];
        float ps0 = 0.f, ps1 = 0.f;
        #pragma unroll
        for (int c = 0; c < 4; c++) {
            p[0][c] = __expf(s[0][c] - mn0); ps0 += p[0][c];
            p[1][c] = __expf(s[1][c] - mn1); ps1 += p[1][c];
        }
        #pragma unroll
        for (int o = 1; o < 8; o <<= 1) {
            ps0 += __shfl_xor_sync(0xffffffffu, ps0, o);
            ps1 += __shfl_xor_sync(0xffffffffu, ps1, o);
        }
        l0 = l0 * c0 + ps0; l1 = l1 * c1 + ps1;
        m0 = mn0; m1 = mn1;
        #pragma unroll
        for (int c = 0; c < 4; c++) { acc[0][c] *= c0; acc[1][c] *= c1; }
        // stage P
        #pragma unroll
        for (int c = 0; c < 4; c++) {
            Ps[ty * 2 + 0][tx * 4 + c] = p[0][c];
            Ps[ty * 2 + 1][tx * 4 + c] = p[1][c];
        }
        __syncthreads();
        // PV: 2x4 fragment of P.V
        #pragma unroll
        for (int kk = 0; kk < BK; kk++) {
            float pa = Ps[ty * 2 + 0][kk];
            float pb = Ps[ty * 2 + 1][kk];
            float v0 = Vs[kk][tx * 4 + 0];
            float v1 = Vs[kk][tx * 4 + 1];
            float v2 = Vs[kk][tx * 4 + 2];
            float v3 = Vs[kk][tx * 4 + 3];
            acc[0][0] = fmaf(pa, v0, acc[0][0]); acc[0][1] = fmaf(pa, v1, acc[0][1]);
            acc[0][2] = fmaf(pa, v2, acc[0][2]); acc[0][3] = fmaf(pa, v3, acc[0][3]);
            acc[1][0] = fmaf(pb, v0, acc[1][0]); acc[1][1] = fmaf(pb, v1, acc[1][1]);
            acc[1][2] = fmaf(pb, v2, acc[1][2]); acc[1][3] = fmaf(pb, v3, acc[1][3]);
        }
        __syncthreads();
    }
    // write out
    #pragma unroll
    for (int r = 0; r < 2; r++) {
        int q = q0 + ty * 2 + r;
        if (q >= S_LEN) continue;
        float inv = 1.f / (r ? l1 : l0);
        float4 o4 = make_float4(acc[r][0] * inv, acc[r][1] * inv,
                                acc[r][2] * inv, acc[r][3] * inv);
        *reinterpret_cast<float4*>(
            out + ((size_t)(b * S_LEN + q)) * 128 + h * 32 + tx * 4) = o4;
    }
}

// ---------------- head ----------------
__global__ __launch_bounds__(64) void head_kernel(
    const float* __restrict__ h, const float* __restrict__ ls,
    const float* __restrict__ lb, const float* __restrict__ hw,
    const float* __restrict__ hb, float* __restrict__ out)
{
    int bidx = threadIdx.x >> 5;
    if (bidx >= BATCH) return;
    int lane = threadIdx.x & 31;
    const float* xr = h + (size_t)bidx * S_LEN * D_MODEL;
    float4 v = *reinterpret_cast<const float4*>(xr + lane * 4);
    float sum = v.x + v.y + v.z + v.w;
    #pragma unroll
    for (int o = 16; o; o >>= 1) sum += __shfl_xor_sync(0xffffffffu, sum, o);
    float mean = sum * (1.f / 128.f);
    float dx = v.x - mean, dy = v.y - mean, dz = v.z - mean, dw = v.w - mean;
    float vs = dx * dx + dy * dy + dz * dz + dw * dw;
    #pragma unroll
    for (int o = 16; o; o >>= 1) vs += __shfl_xor_sync(0xffffffffu, vs, o);
    float rstd = rsqrtf(vs * (1.f / 128.f) + 1e-5f);
    float4 s4 = *reinterpret_cast<const float4*>(ls + lane * 4);
    float4 b4 = *reinterpret_cast<const float4*>(lb + lane * 4);
    float4 w4 = *reinterpret_cast<const float4*>(hw + lane * 4);
    float dot = (dx * rstd * s4.x + b4.x) * w4.x
              + (dy * rstd * s4.y + b4.y) * w4.y
              + (dz * rstd * s4.z + b4.z) * w4.z
              + (dw * rstd * s4.w + b4.w) * w4.w;
    #pragma unroll
    for (int o = 16; o; o >>= 1) dot += __shfl_xor_sync(0xffffffffu, dot, o);
    if (lane == 0) out[bidx] = dot + hb[0];
}

// ---------------- launch ----------------
extern "C" void kernel_launch(void* const* d_in, const int* in_sizes, int n_in,
                              void* d_out, int out_size)
{
    const float* x        = (const float*)d_in[0];
    const float* embed_w  = (const float*)d_in[1];
    const float* embed_b  = (const float*)d_in[2];
    const float* pos_emb  = (const float*)d_in[3];
    const float* cls      = (const float*)d_in[4];
    const float* in_w     = (const float*)d_in[5];
    const float* in_b     = (const float*)d_in[6];
    const float* out_w    = (const float*)d_in[7];
    const float* out_b    = (const float*)d_in[8];
    const float* ln1_s    = (const float*)d_in[9];
    const float* ln1_b    = (const float*)d_in[10];
    const float* ln2_s    = (const float*)d_in[11];
    const float* ln2_b    = (const float*)d_in[12];
    const float* ff1_w    = (const float*)d_in[13];
    const float* ff1_b    = (const float*)d_in[14];
    const float* ff2_w    = (const float*)d_in[15];
    const float* ff2_b    = (const float*)d_in[16];
    const float* hln_s    = (const float*)d_in[17];
    const float* hln_b    = (const float*)d_in[18];
    const float* head_w   = (const float*)d_in[19];
    const float* head_b   = (const float*)d_in[20];
    float* outp = (float*)d_out;

    float *h, *hn, *qkv, *attn, *ff;
    cudaGetSymbolAddress((void**)&h,    g_h);
    cudaGetSymbolAddress((void**)&hn,   g_hn);
    cudaGetSymbolAddress((void**)&qkv,  g_qkv);
    cudaGetSymbolAddress((void**)&attn, g_attn);
    cudaGetSymbolAddress((void**)&ff,   g_ff);

    embed_kernel<<<dim3(S_LEN, BATCH), 128>>>(x, embed_w, embed_b, pos_emb, cls, h);

    const int M = MROWS;
    dim3 lnGrid((M + 7) / 8);
    dim3 gemmBlk(256);

    for (int i = 0; i < NL; i++) {
        ln_kernel<<<lnGrid, 256>>>(h, ln1_s + i * D_MODEL, ln1_b + i * D_MODEL, hn, M);
        gemm_kernel<false, false><<<dim3(384 / 64, (M + 63) / 64), gemmBlk>>>(
            hn, in_w + (size_t)i * 384 * 128, in_b + (size_t)i * 384,
            nullptr, qkv, M, 384, 128);
        attn_kernel<<<dim3((S_LEN + BQ - 1) / BQ, N_HEADS, BATCH), 256>>>(qkv, attn);
        gemm_kernel<false, true><<<dim3(128 / 64, (M + 63) / 64), gemmBlk>>>(
            attn, out_w + (size_t)i * 128 * 128, out_b + (size_t)i * 128,
            h, h, M, 128, 128);
        ln_kernel<<<lnGrid, 256>>>(h, ln2_s + i * D_MODEL, ln2_b + i * D_MODEL, hn, M);
        gemm_kernel<true, false><<<dim3(512 / 64, (M + 63) / 64), gemmBlk>>>(
            hn, ff1_w + (size_t)i * 512 * 128, ff1_b + (size_t)i * 512,
            nullptr, ff, M, 512, 128);
        gemm_kernel<false, true><<<dim3(128 / 64, (M + 63) / 64), gemmBlk>>>(
            ff, ff2_w + (size_t)i * 128 * 512, ff2_b + (size_t)i * 128,
            h, h, M, 128, 512);
    }

    head_kernel<<<1, 64>>>(h, hln_s, hln_b, head_w, head_b, outp);
}

// round 3
// speedup vs baseline: 1.4703x; 1.1368x over previous
#include <cuda_runtime.h>
#include <math.h>

#define NL 3
#define D_MODEL 128
#define N_HEADS 4
#define DHEAD 32
#define DFF 512
#define DIN 64
#define BATCH 2
#define LSEQ 2048
#define S_LEN 2049
#define MROWS (BATCH * S_LEN)   // 4098

// ---------------- scratch (device globals; no allocation) ----------------
__device__ float g_h[MROWS * D_MODEL];
__device__ float g_hn[MROWS * D_MODEL];
__device__ float g_qkv[MROWS * 3 * D_MODEL];
__device__ float g_attn[MROWS * D_MODEL];
__device__ float g_ff[MROWS * DFF];

// ---------------- embedding ----------------
__global__ __launch_bounds__(128) void embed_kernel(
    const float* __restrict__ x, const float* __restrict__ ew,
    const float* __restrict__ eb, const float* __restrict__ pos,
    const float* __restrict__ cls, float* __restrict__ h)
{
    __shared__ float xs[DIN];
    int s = blockIdx.x, b = blockIdx.y;
    int d = threadIdx.x;
    float val;
    if (s == 0) {
        val = cls[d] + pos[d];
    } else {
        if (d < DIN) xs[d] = x[((size_t)b * LSEQ + (s - 1)) * DIN + d];
        __syncthreads();
        float acc = 0.f;
        const float* wr = ew + (size_t)d * DIN;
        #pragma unroll
        for (int j = 0; j < DIN; j++) acc = fmaf(xs[j], wr[j], acc);
        val = acc + eb[d] + pos[(size_t)s * D_MODEL + d];
    }
    h[((size_t)b * S_LEN + s) * D_MODEL + d] = val;
}

// ---------------- layernorm (warp per 128-wide row) ----------------
__global__ __launch_bounds__(256) void ln_kernel(
    const float* __restrict__ x, const float* __restrict__ sc,
    const float* __restrict__ bi, float* __restrict__ y, int nrows)
{
    int row = blockIdx.x * 8 + (threadIdx.x >> 5);
    if (row >= nrows) return;
    int lane = threadIdx.x & 31;
    const float* xr = x + (size_t)row * D_MODEL;
    float4 v = *reinterpret_cast<const float4*>(xr + lane * 4);
    float sum = v.x + v.y + v.z + v.w;
    #pragma unroll
    for (int o = 16; o; o >>= 1) sum += __shfl_xor_sync(0xffffffffu, sum, o);
    float mean = sum * (1.f / 128.f);
    float dx = v.x - mean, dy = v.y - mean, dz = v.z - mean, dw = v.w - mean;
    float vs = dx * dx + dy * dy + dz * dz + dw * dw;
    #pragma unroll
    for (int o = 16; o; o >>= 1) vs += __shfl_xor_sync(0xffffffffu, vs, o);
    float rstd = rsqrtf(vs * (1.f / 128.f) + 1e-5f);
    float4 s4 = *reinterpret_cast<const float4*>(sc + lane * 4);
    float4 b4 = *reinterpret_cast<const float4*>(bi + lane * 4);
    float4 o4;
    o4.x = dx * rstd * s4.x + b4.x;
    o4.y = dy * rstd * s4.y + b4.y;
    o4.z = dz * rstd * s4.z + b4.z;
    o4.w = dw * rstd * s4.w + b4.w;
    *reinterpret_cast<float4*>(y + (size_t)row * D_MODEL + lane * 4) = o4;
}

// ---------------- GEMM: C = A . W^T + bias (+resid) (ReLU?) ----------------
template <bool RELU, bool RESID>
__global__ __launch_bounds__(256) void gemm_kernel(
    const float* __restrict__ A, const float* __restrict__ W,
    const float* __restrict__ bias, const float* __restrict__ resid,
    float* __restrict__ C, int M, int N, int K)
{
    __shared__ float As[16][64];
    __shared__ float Ws[16][64];
    int tid = threadIdx.x;
    int tx = tid & 15, ty = tid >> 4;
    int m0 = blockIdx.y * 64, n0 = blockIdx.x * 64;
    int lrow = tid >> 2;
    int lq = (tid & 3) * 4;
    float acc[4][4] = {};
    for (int k0 = 0; k0 < K; k0 += 16) {
        int m = m0 + lrow;
        float4 av = (m < M)
            ? *reinterpret_cast<const float4*>(A + (size_t)m * K + k0 + lq)
            : make_float4(0.f, 0.f, 0.f, 0.f);
        float4 wv = *reinterpret_cast<const float4*>(W + (size_t)(n0 + lrow) * K + k0 + lq);
        As[lq + 0][lrow] = av.x; As[lq + 1][lrow] = av.y;
        As[lq + 2][lrow] = av.z; As[lq + 3][lrow] = av.w;
        Ws[lq + 0][lrow] = wv.x; Ws[lq + 1][lrow] = wv.y;
        Ws[lq + 2][lrow] = wv.z; Ws[lq + 3][lrow] = wv.w;
        __syncthreads();
        #pragma unroll
        for (int k = 0; k < 16; k++) {
            float4 a = *reinterpret_cast<const float4*>(&As[k][ty * 4]);
            float4 b = *reinterpret_cast<const float4*>(&Ws[k][tx * 4]);
            float av2[4] = {a.x, a.y, a.z, a.w};
            float bv2[4] = {b.x, b.y, b.z, b.w};
            #pragma unroll
            for (int i = 0; i < 4; i++)
                #pragma unroll
                for (int j = 0; j < 4; j++)
                    acc[i][j] = fmaf(av2[i], bv2[j], acc[i][j]);
        }
        __syncthreads();
    }
    #pragma unroll
    for (int i = 0; i < 4; i++) {
        int m = m0 + ty * 4 + i;
        if (m >= M) continue;
        #pragma unroll
        for (int j = 0; j < 4; j++) {
            int n = n0 + tx * 4 + j;
            float v = acc[i][j] + bias[n];
            if (RESID) v += resid[(size_t)m * N + n];
            if (RELU) v = fmaxf(v, 0.f);
            C[(size_t)m * N + n] = v;
        }
    }
}

// ---------------- attention: flash, BQ=128, BK=32, 256 thr, 4x4 frags ----
#define BQ 128
#define BK 32
#define APITCH 36   // 144B row pitch: 16B-aligned, 4-bank rotation per row

__global__ __launch_bounds__(256) void attn_kernel(
    const float* __restrict__ qkv, float* __restrict__ out)
{
    __shared__ float Qs[BQ][APITCH];
    __shared__ float Ks[BK][APITCH];
    __shared__ float Vs[BK][APITCH];
    __shared__ float Ps[BQ][APITCH];
    const int tid = threadIdx.x;
    const int tx = tid & 7;     // key group / dim group
    const int ty = tid >> 3;    // 0..31, query row base
    const int b = blockIdx.z, h = blockIdx.y;
    const int q0 = blockIdx.x * BQ;
    const float scale = 0.17677669529663687f; // 1/sqrt(32)

    // ---- load Q tile (scaled): 128 rows x 32 dims ----
    #pragma unroll
    for (int idx = tid; idx < BQ * 8; idx += 256) {
        int r = idx >> 3, c4 = (idx & 7) << 2;
        int q = q0 + r;
        float4 v = make_float4(0.f, 0.f, 0.f, 0.f);
        if (q < S_LEN)
            v = *reinterpret_cast<const float4*>(
                qkv + ((size_t)(b * S_LEN + q)) * 384 + h * 32 + c4);
        Qs[r][c4 + 0] = v.x * scale; Qs[r][c4 + 1] = v.y * scale;
        Qs[r][c4 + 2] = v.z * scale; Qs[r][c4 + 3] = v.w * scale;
    }

    float m[4] = {-1e30f, -1e30f, -1e30f, -1e30f};
    float l[4] = {};
    float acc[4][4] = {};
    __syncthreads();

    for (int kb = 0; kb < S_LEN; kb += BK) {
        // ---- load K/V tile: 32 rows x 8 float4, exactly one slot/thread ----
        {
            int kk = tid >> 3, c4 = (tid & 7) << 2;
            int kg = kb + kk;
            float4 k4 = make_float4(0.f, 0.f, 0.f, 0.f);
            float4 v4 = make_float4(0.f, 0.f, 0.f, 0.f);
            if (kg < S_LEN) {
                const float* base = qkv + ((size_t)(b * S_LEN + kg)) * 384 + h * 32 + c4;
                k4 = *reinterpret_cast<const float4*>(base + 128);
                v4 = *reinterpret_cast<const float4*>(base + 256);
            }
            Ks[kk][c4 + 0] = k4.x; Ks[kk][c4 + 1] = k4.y;
            Ks[kk][c4 + 2] = k4.z; Ks[kk][c4 + 3] = k4.w;
            Vs[kk][c4 + 0] = v4.x; Vs[kk][c4 + 1] = v4.y;
            Vs[kk][c4 + 2] = v4.z; Vs[kk][c4 + 3] = v4.w;
        }
        __syncthreads();

        // ---- QK^T: 4x4 fragment. rows ty+32i, cols tx+8j ----
        float s[4][4] = {};
        #pragma unroll
        for (int d = 0; d < 32; d += 4) {
            float4 qv[4], kv[4];
            #pragma unroll
            for (int i = 0; i < 4; i++)
                qv[i] = *reinterpret_cast<const float4*>(&Qs[ty + 32 * i][d]);
            #pragma unroll
            for (int j = 0; j < 4; j++)
                kv[j] = *reinterpret_cast<const float4*>(&Ks[tx + 8 * j][d]);
            #pragma unroll
            for (int i = 0; i < 4; i++)
                #pragma unroll
                for (int j = 0; j < 4; j++) {
                    s[i][j] = fmaf(qv[i].x, kv[j].x, s[i][j]);
                    s[i][j] = fmaf(qv[i].y, kv[j].y, s[i][j]);
                    s[i][j] = fmaf(qv[i].z, kv[j].z, s[i][j]);
                    s[i][j] = fmaf(qv[i].w, kv[j].w, s[i][j]);
                }
        }
        // mask invalid keys
        #pragma unroll
        for (int j = 0; j < 4; j++) {
            if (kb + tx + 8 * j >= S_LEN) {
                #pragma unroll
                for (int i = 0; i < 4; i++) s[i][j] = -1e30f;
            }
        }

        // ---- online softmax per row (reduce across 8 tx lanes) ----
        float p[4][4];
        #pragma unroll
        for (int i = 0; i < 4; i++) {
            float t = fmaxf(fmaxf(s[i][0], s[i][1]), fmaxf(s[i][2], s[i][3]));
            #pragma unroll
            for (int o = 1; o < 8; o <<= 1)
                t = fmaxf(t, __shfl_xor_sync(0xffffffffu, t, o));
            float mn = fmaxf(m[i], t);
            float corr = __expf(m[i] - mn);
            float ps = 0.f;
            #pragma unroll
            for (int j = 0; j < 4; j++) {
                p[i][j] = __expf(s[i][j] - mn);
                ps += p[i][j];
            }
            #pragma unroll
            for (int o = 1; o < 8; o <<= 1)
                ps += __shfl_xor_sync(0xffffffffu, ps, o);
            l[i] = l[i] * corr + ps;
            m[i] = mn;
            #pragma unroll
            for (int j = 0; j < 4; j++) acc[i][j] *= corr;
        }
        // stage P
        #pragma unroll
        for (int i = 0; i < 4; i++)
            #pragma unroll
            for (int j = 0; j < 4; j++)
                Ps[ty + 32 * i][tx + 8 * j] = p[i][j];
        __syncthreads();

        // ---- PV: rows ty+32i, dims tx*4..+3, k vectorized by 4 ----
        #pragma unroll
        for (int kk = 0; kk < BK; kk += 4) {
            float4 pv[4], vv[4];
            #pragma unroll
            for (int i = 0; i < 4; i++)
                pv[i] = *reinterpret_cast<const float4*>(&Ps[ty + 32 * i][kk]);
            #pragma unroll
            for (int t = 0; t < 4; t++)
                vv[t] = *reinterpret_cast<const float4*>(&Vs[kk + t][tx * 4]);
            #pragma unroll
            for (int i = 0; i < 4; i++) {
                acc[i][0] = fmaf(pv[i].x, vv[0].x, acc[i][0]);
                acc[i][1] = fmaf(pv[i].x, vv[0].y, acc[i][1]);
                acc[i][2] = fmaf(pv[i].x, vv[0].z, acc[i][2]);
                acc[i][3] = fmaf(pv[i].x, vv[0].w, acc[i][3]);
                acc[i][0] = fmaf(pv[i].y, vv[1].x, acc[i][0]);
                acc[i][1] = fmaf(pv[i].y, vv[1].y, acc[i][1]);
                acc[i][2] = fmaf(pv[i].y, vv[1].z, acc[i][2]);
                acc[i][3] = fmaf(pv[i].y, vv[1].w, acc[i][3]);
                acc[i][0] = fmaf(pv[i].z, vv[2].x, acc[i][0]);
                acc[i][1] = fmaf(pv[i].z, vv[2].y, acc[i][1]);
                acc[i][2] = fmaf(pv[i].z, vv[2].z, acc[i][2]);
                acc[i][3] = fmaf(pv[i].z, vv[2].w, acc[i][3]);
                acc[i][0] = fmaf(pv[i].w, vv[3].x, acc[i][0]);
                acc[i][1] = fmaf(pv[i].w, vv[3].y, acc[i][1]);
                acc[i][2] = fmaf(pv[i].w, vv[3].z, acc[i][2]);
                acc[i][3] = fmaf(pv[i].w, vv[3].w, acc[i][3]);
            }
        }
        __syncthreads();
    }

    // ---- write output: rows ty+32i, dims tx*4..+3 ----
    #pragma unroll
    for (int i = 0; i < 4; i++) {
        int q = q0 + ty + 32 * i;
        if (q >= S_LEN) continue;
        float inv = 1.f / l[i];
        float4 o4 = make_float4(acc[i][0] * inv, acc[i][1] * inv,
                                acc[i][2] * inv, acc[i][3] * inv);
        *reinterpret_cast<float4*>(
            out + ((size_t)(b * S_LEN + q)) * 128 + h * 32 + tx * 4) = o4;
    }
}

// ---------------- head ----------------
__global__ __launch_bounds__(64) void head_kernel(
    const float* __restrict__ h, const float* __restrict__ ls,
    const float* __restrict__ lb, const float* __restrict__ hw,
    const float* __restrict__ hb, float* __restrict__ out)
{
    int bidx = threadIdx.x >> 5;
    if (bidx >= BATCH) return;
    int lane = threadIdx.x & 31;
    const float* xr = h + (size_t)bidx * S_LEN * D_MODEL;
    float4 v = *reinterpret_cast<const float4*>(xr + lane * 4);
    float sum = v.x + v.y + v.z + v.w;
    #pragma unroll
    for (int o = 16; o; o >>= 1) sum += __shfl_xor_sync(0xffffffffu, sum, o);
    float mean = sum * (1.f / 128.f);
    float dx = v.x - mean, dy = v.y - mean, dz = v.z - mean, dw = v.w - mean;
    float vs = dx * dx + dy * dy + dz * dz + dw * dw;
    #pragma unroll
    for (int o = 16; o; o >>= 1) vs += __shfl_xor_sync(0xffffffffu, vs, o);
    float rstd = rsqrtf(vs * (1.f / 128.f) + 1e-5f);
    float4 s4 = *reinterpret_cast<const float4*>(ls + lane * 4);
    float4 b4 = *reinterpret_cast<const float4*>(lb + lane * 4);
    float4 w4 = *reinterpret_cast<const float4*>(hw + lane * 4);
    float dot = (dx * rstd * s4.x + b4.x) * w4.x
              + (dy * rstd * s4.y + b4.y) * w4.y
              + (dz * rstd * s4.z + b4.z) * w4.z
              + (dw * rstd * s4.w + b4.w) * w4.w;
    #pragma unroll
    for (int o = 16; o; o >>= 1) dot += __shfl_xor_sync(0xffffffffu, dot, o);
    if (lane == 0) out[bidx] = dot + hb[0];
}

// ---------------- launch ----------------
extern "C" void kernel_launch(void* const* d_in, const int* in_sizes, int n_in,
                              void* d_out, int out_size)
{
    const float* x        = (const float*)d_in[0];
    const float* embed_w  = (const float*)d_in[1];
    const float* embed_b  = (const float*)d_in[2];
    const float* pos_emb  = (const float*)d_in[3];
    const float* cls      = (const float*)d_in[4];
    const float* in_w     = (const float*)d_in[5];
    const float* in_b     = (const float*)d_in[6];
    const float* out_w    = (const float*)d_in[7];
    const float* out_b    = (const float*)d_in[8];
    const float* ln1_s    = (const float*)d_in[9];
    const float* ln1_b    = (const float*)d_in[10];
    const float* ln2_s    = (const float*)d_in[11];
    const float* ln2_b    = (const float*)d_in[12];
    const float* ff1_w    = (const float*)d_in[13];
    const float* ff1_b    = (const float*)d_in[14];
    const float* ff2_w    = (const float*)d_in[15];
    const float* ff2_b    = (const float*)d_in[16];
    const float* hln_s    = (const float*)d_in[17];
    const float* hln_b    = (const float*)d_in[18];
    const float* head_w   = (const float*)d_in[19];
    const float* head_b   = (const float*)d_in[20];
    float* outp = (float*)d_out;

    float *h, *hn, *qkv, *attn, *ff;
    cudaGetSymbolAddress((void**)&h,    g_h);
    cudaGetSymbolAddress((void**)&hn,   g_hn);
    cudaGetSymbolAddress((void**)&qkv,  g_qkv);
    cudaGetSymbolAddress((void**)&attn, g_attn);
    cudaGetSymbolAddress((void**)&ff,   g_ff);

    embed_kernel<<<dim3(S_LEN, BATCH), 128>>>(x, embed_w, embed_b, pos_emb, cls, h);

    const int M = MROWS;
    dim3 lnGrid((M + 7) / 8);
    dim3 gemmBlk(256);

    for (int i = 0; i < NL; i++) {
        ln_kernel<<<lnGrid, 256>>>(h, ln1_s + i * D_MODEL, ln1_b + i * D_MODEL, hn, M);
        gemm_kernel<false, false><<<dim3(384 / 64, (M + 63) / 64), gemmBlk>>>(
            hn, in_w + (size_t)i * 384 * 128, in_b + (size_t)i * 384,
            nullptr, qkv, M, 384, 128);
        attn_kernel<<<dim3((S_LEN + BQ - 1) / BQ, N_HEADS, BATCH), 256>>>(qkv, attn);
        gemm_kernel<false, true><<<dim3(128 / 64, (M + 63) / 64), gemmBlk>>>(
            attn, out_w + (size_t)i * 128 * 128, out_b + (size_t)i * 128,
            h, h, M, 128, 128);
        ln_kernel<<<lnGrid, 256>>>(h, ln2_s + i * D_MODEL, ln2_b + i * D_MODEL, hn, M);
        gemm_kernel<true, false><<<dim3(512 / 64, (M + 63) / 64), gemmBlk>>>(
            hn, ff1_w + (size_t)i * 512 * 128, ff1_b + (size_t)i * 512,
            nullptr, ff, M, 512, 128);
        gemm_kernel<false, true><<<dim3(128 / 64, (M + 63) / 64), gemmBlk>>>(
            ff, ff2_w + (size_t)i * 128 * 512, ff2_b + (size_t)i * 128,
            h, h, M, 128, 512);
    }

    head_kernel<<<1, 64>>>(h, hln_s, hln_b, head_w, head_b, outp);
}

// round 4
// speedup vs baseline: 2.6020x; 1.7697x over previous
#include <cuda_runtime.h>
#include <cuda_fp16.h>
#include <math.h>

#define NL 3
#define D_MODEL 128
#define N_HEADS 4
#define DHEAD 32
#define DFF 512
#define DIN 64
#define BATCH 2
#define LSEQ 2048
#define S_LEN 2049
#define MROWS (BATCH * S_LEN)   // 4098
#define QK_SCALE 0.17677669529663687f

// ---------------- scratch (device globals; no allocation) ----------------
__device__ float  g_h[MROWS * D_MODEL];
__device__ float  g_hn[MROWS * D_MODEL];
__device__ __half g_qkvh[MROWS * 3 * D_MODEL];
__device__ float  g_attn[MROWS * D_MODEL];
__device__ float  g_ff[MROWS * DFF];

// ---------------- embedding ----------------
__global__ __launch_bounds__(128) void embed_kernel(
    const float* __restrict__ x, const float* __restrict__ ew,
    const float* __restrict__ eb, const float* __restrict__ pos,
    const float* __restrict__ cls, float* __restrict__ h)
{
    __shared__ float xs[DIN];
    int s = blockIdx.x, b = blockIdx.y;
    int d = threadIdx.x;
    float val;
    if (s == 0) {
        val = cls[d] + pos[d];
    } else {
        if (d < DIN) xs[d] = x[((size_t)b * LSEQ + (s - 1)) * DIN + d];
        __syncthreads();
        float acc = 0.f;
        const float* wr = ew + (size_t)d * DIN;
        #pragma unroll
        for (int j = 0; j < DIN; j++) acc = fmaf(xs[j], wr[j], acc);
        val = acc + eb[d] + pos[(size_t)s * D_MODEL + d];
    }
    h[((size_t)b * S_LEN + s) * D_MODEL + d] = val;
}

// ---------------- layernorm (warp per 128-wide row) ----------------
__global__ __launch_bounds__(256) void ln_kernel(
    const float* __restrict__ x, const float* __restrict__ sc,
    const float* __restrict__ bi, float* __restrict__ y, int nrows)
{
    int row = blockIdx.x * 8 + (threadIdx.x >> 5);
    if (row >= nrows) return;
    int lane = threadIdx.x & 31;
    const float* xr = x + (size_t)row * D_MODEL;
    float4 v = *reinterpret_cast<const float4*>(xr + lane * 4);
    float sum = v.x + v.y + v.z + v.w;
    #pragma unroll
    for (int o = 16; o; o >>= 1) sum += __shfl_xor_sync(0xffffffffu, sum, o);
    float mean = sum * (1.f / 128.f);
    float dx = v.x - mean, dy = v.y - mean, dz = v.z - mean, dw = v.w - mean;
    float vs = dx * dx + dy * dy + dz * dz + dw * dw;
    #pragma unroll
    for (int o = 16; o; o >>= 1) vs += __shfl_xor_sync(0xffffffffu, vs, o);
    float rstd = rsqrtf(vs * (1.f / 128.f) + 1e-5f);
    float4 s4 = *reinterpret_cast<const float4*>(sc + lane * 4);
    float4 b4 = *reinterpret_cast<const float4*>(bi + lane * 4);
    float4 o4;
    o4.x = dx * rstd * s4.x + b4.x;
    o4.y = dy * rstd * s4.y + b4.y;
    o4.z = dz * rstd * s4.z + b4.z;
    o4.w = dw * rstd * s4.w + b4.w;
    *reinterpret_cast<float4*>(y + (size_t)row * D_MODEL + lane * 4) = o4;
}

// ---------------- GEMM: C = A . W^T + bias (+resid) (ReLU?) ----------------
// HALFQ: write __half output; columns n<128 (Q) scaled by QK_SCALE.
template <bool RELU, bool RESID, bool HALFQ>
__global__ __launch_bounds__(256) void gemm_kernel(
    const float* __restrict__ A, const float* __restrict__ W,
    const float* __restrict__ bias, const float* __restrict__ resid,
    void* __restrict__ Cv, int M, int N, int K)
{
    __shared__ float As[16][64];
    __shared__ float Ws[16][64];
    int tid = threadIdx.x;
    int tx = tid & 15, ty = tid >> 4;
    int m0 = blockIdx.y * 64, n0 = blockIdx.x * 64;
    int lrow = tid >> 2;
    int lq = (tid & 3) * 4;
    float acc[4][4] = {};
    for (int k0 = 0; k0 < K; k0 += 16) {
        int m = m0 + lrow;
        float4 av = (m < M)
            ? *reinterpret_cast<const float4*>(A + (size_t)m * K + k0 + lq)
            : make_float4(0.f, 0.f, 0.f, 0.f);
        float4 wv = *reinterpret_cast<const float4*>(W + (size_t)(n0 + lrow) * K + k0 + lq);
        As[lq + 0][lrow] = av.x; As[lq + 1][lrow] = av.y;
        As[lq + 2][lrow] = av.z; As[lq + 3][lrow] = av.w;
        Ws[lq + 0][lrow] = wv.x; Ws[lq + 1][lrow] = wv.y;
        Ws[lq + 2][lrow] = wv.z; Ws[lq + 3][lrow] = wv.w;
        __syncthreads();
        #pragma unroll
        for (int k = 0; k < 16; k++) {
            float4 a = *reinterpret_cast<const float4*>(&As[k][ty * 4]);
            float4 b = *reinterpret_cast<const float4*>(&Ws[k][tx * 4]);
            float av2[4] = {a.x, a.y, a.z, a.w};
            float bv2[4] = {b.x, b.y, b.z, b.w};
            #pragma unroll
            for (int i = 0; i < 4; i++)
                #pragma unroll
                for (int j = 0; j < 4; j++)
                    acc[i][j] = fmaf(av2[i], bv2[j], acc[i][j]);
        }
        __syncthreads();
    }
    #pragma unroll
    for (int i = 0; i < 4; i++) {
        int m = m0 + ty * 4 + i;
        if (m >= M) continue;
        #pragma unroll
        for (int j = 0; j < 4; j++) {
            int n = n0 + tx * 4 + j;
            float v = acc[i][j] + bias[n];
            if (RESID) v += ((const float*)resid)[(size_t)m * N + n];
            if (RELU) v = fmaxf(v, 0.f);
            if (HALFQ) {
                if (n < 128) v *= QK_SCALE;
                ((__half*)Cv)[(size_t)m * N + n] = __float2half_rn(v);
            } else {
                ((float*)Cv)[(size_t)m * N + n] = v;
            }
        }
    }
}

// ---------------- tensor-core flash attention ----------------
// BQ=128 (warp owns 16 q rows), BK=64, mma.sync.m16n8k16 f16 / f32 acc.
#define BQ 128
#define BK 64
#define QPITCH 40   // halfs
#define VPITCH 72   // halfs; (VPITCH/2) % 32 == 4 -> conflict-free B reads

__device__ __forceinline__ void mma16816(
    float c[4], const unsigned a[4], const unsigned b[2])
{
    asm volatile(
        "mma.sync.aligned.m16n8k16.row.col.f32.f16.f16.f32 "
        "{%0,%1,%2,%3}, {%4,%5,%6,%7}, {%8,%9}, {%0,%1,%2,%3};\n"
        : "+f"(c[0]), "+f"(c[1]), "+f"(c[2]), "+f"(c[3])
        : "r"(a[0]), "r"(a[1]), "r"(a[2]), "r"(a[3]),
          "r"(b[0]), "r"(b[1]));
}

__global__ __launch_bounds__(256) void attn_kernel(
    const __half* __restrict__ qkv, float* __restrict__ out)
{
    __shared__ __half Qs[BQ][QPITCH];
    __shared__ __half Kt[BK][QPITCH];
    __shared__ __half Vt[DHEAD][VPITCH];
    const int tid = threadIdx.x;
    const int warp = tid >> 5;
    const int lane = tid & 31;
    const int g = lane >> 2;      // group id: row within fragment
    const int tig = lane & 3;     // thread in group
    const int b = blockIdx.z, h = blockIdx.y;
    const int q0 = blockIdx.x * BQ;
    const int qbase = warp * 16;

    // ---- load Q tile (already scaled, fp16): 128 rows x 32 halfs ----
    #pragma unroll
    for (int idx = tid; idx < BQ * 4; idx += 256) {
        int r = idx >> 2, quad = idx & 3;
        int q = q0 + r;
        uint4 v = make_uint4(0u, 0u, 0u, 0u);
        if (q < S_LEN)
            v = *reinterpret_cast<const uint4*>(
                qkv + ((size_t)(b * S_LEN + q)) * 384 + h * 32 + quad * 8);
        *reinterpret_cast<uint4*>(&Qs[r][quad * 8]) = v;
    }

    float m0 = -1e30f, m1 = -1e30f, l0 = 0.f, l1 = 0.f;
    float o[4][4] = {};
    __syncthreads();

    for (int kb = 0; kb < S_LEN; kb += BK) {
        // ---- K tile: 64 rows x 32 halfs ----
        {
            int r = tid >> 2, quad = tid & 3;
            int kg = kb + r;
            uint4 v = make_uint4(0u, 0u, 0u, 0u);
            if (kg < S_LEN)
                v = *reinterpret_cast<const uint4*>(
                    qkv + ((size_t)(b * S_LEN + kg)) * 384 + 128 + h * 32 + quad * 8);
            *reinterpret_cast<uint4*>(&Kt[r][quad * 8]) = v;
        }
        // ---- V tile transposed: Vt[dim][key] ----
        #pragma unroll
        for (int idx = tid; idx < BK * 16; idx += 256) {
            int kl = idx >> 4, dp = idx & 15;
            int kg = kb + kl;
            __half2 hv = __float2half2_rn(0.f);
            if (kg < S_LEN)
                hv = *reinterpret_cast<const __half2*>(
                    qkv + ((size_t)(b * S_LEN + kg)) * 384 + 256 + h * 32 + dp * 2);
            Vt[dp * 2 + 0][kl] = __low2half(hv);
            Vt[dp * 2 + 1][kl] = __high2half(hv);
        }
        __syncthreads();

        // ---- QK^T: warp computes 16 x 64 scores (8 n-tiles, 2 k-steps) ----
        unsigned A[2][4];
        #pragma unroll
        for (int ks = 0; ks < 2; ks++) {
            A[ks][0] = *reinterpret_cast<const unsigned*>(&Qs[qbase + g    ][ks * 16 + tig * 2]);
            A[ks][1] = *reinterpret_cast<const unsigned*>(&Qs[qbase + g + 8][ks * 16 + tig * 2]);
            A[ks][2] = *reinterpret_cast<const unsigned*>(&Qs[qbase + g    ][ks * 16 + tig * 2 + 8]);
            A[ks][3] = *reinterpret_cast<const unsigned*>(&Qs[qbase + g + 8][ks * 16 + tig * 2 + 8]);
        }
        float s[8][4];
        #pragma unroll
        for (int j = 0; j < 8; j++) {
            s[j][0] = s[j][1] = s[j][2] = s[j][3] = 0.f;
            #pragma unroll
            for (int ks = 0; ks < 2; ks++) {
                unsigned bfr[2];
                bfr[0] = *reinterpret_cast<const unsigned*>(&Kt[j * 8 + g][ks * 16 + tig * 2]);
                bfr[1] = *reinterpret_cast<const unsigned*>(&Kt[j * 8 + g][ks * 16 + tig * 2 + 8]);
                mma16816(s[j], A[ks], bfr);
            }
        }
        // mask invalid keys (only final tile)
        if (kb + BK > S_LEN) {
            #pragma unroll
            for (int j = 0; j < 8; j++) {
                int key = kb + j * 8 + tig * 2;
                if (key >= S_LEN)     { s[j][0] = -1e30f; s[j][2] = -1e30f; }
                if (key + 1 >= S_LEN) { s[j][1] = -1e30f; s[j][3] = -1e30f; }
            }
        }

        // ---- online softmax (rows g and g+8; 4 lanes per row) ----
        float t0 = -1e30f, t1 = -1e30f;
        #pragma unroll
        for (int j = 0; j < 8; j++) {
            t0 = fmaxf(t0, fmaxf(s[j][0], s[j][1]));
            t1 = fmaxf(t1, fmaxf(s[j][2], s[j][3]));
        }
        t0 = fmaxf(t0, __shfl_xor_sync(0xffffffffu, t0, 1));
        t0 = fmaxf(t0, __shfl_xor_sync(0xffffffffu, t0, 2));
        t1 = fmaxf(t1, __shfl_xor_sync(0xffffffffu, t1, 1));
        t1 = fmaxf(t1, __shfl_xor_sync(0xffffffffu, t1, 2));
        float mn0 = fmaxf(m0, t0), mn1 = fmaxf(m1, t1);
        float c0 = __expf(m0 - mn0), c1 = __expf(m1 - mn1);
        unsigned ph[8][2];
        float ps0 = 0.f, ps1 = 0.f;
        #pragma unroll
        for (int j = 0; j < 8; j++) {
            __half2 h2a = __floats2half2_rn(__expf(s[j][0] - mn0), __expf(s[j][1] - mn0));
            __half2 h2b = __floats2half2_rn(__expf(s[j][2] - mn1), __expf(s[j][3] - mn1));
            ph[j][0] = *reinterpret_cast<unsigned*>(&h2a);
            ph[j][1] = *reinterpret_cast<unsigned*>(&h2b);
            float2 fa = __half22float2(h2a);
            float2 fb = __half22float2(h2b);
            ps0 += fa.x + fa.y;
            ps1 += fb.x + fb.y;
        }
        ps0 += __shfl_xor_sync(0xffffffffu, ps0, 1);
        ps0 += __shfl_xor_sync(0xffffffffu, ps0, 2);
        ps1 += __shfl_xor_sync(0xffffffffu, ps1, 1);
        ps1 += __shfl_xor_sync(0xffffffffu, ps1, 2);
        l0 = l0 * c0 + ps0;
        l1 = l1 * c1 + ps1;
        m0 = mn0; m1 = mn1;
        #pragma unroll
        for (int nt = 0; nt < 4; nt++) {
            o[nt][0] *= c0; o[nt][1] *= c0;
            o[nt][2] *= c1; o[nt][3] *= c1;
        }

        // ---- PV: A from P registers, B from Vt ----
        #pragma unroll
        for (int kt = 0; kt < 4; kt++) {
            unsigned pa[4] = { ph[2 * kt][0], ph[2 * kt][1],
                               ph[2 * kt + 1][0], ph[2 * kt + 1][1] };
            #pragma unroll
            for (int nt = 0; nt < 4; nt++) {
                unsigned bfr[2];
                bfr[0] = *reinterpret_cast<const unsigned*>(&Vt[nt * 8 + g][kt * 16 + tig * 2]);
                bfr[1] = *reinterpret_cast<const unsigned*>(&Vt[nt * 8 + g][kt * 16 + tig * 2 + 8]);
                mma16816(o[nt], pa, bfr);
            }
        }
        __syncthreads();
    }

    // ---- write output (fp32) ----
    float inv0 = 1.f / l0, inv1 = 1.f / l1;
    int qa = q0 + qbase + g;
    int qb2 = qa + 8;
    #pragma unroll
    for (int nt = 0; nt < 4; nt++) {
        if (qa < S_LEN) {
            float2 v = make_float2(o[nt][0] * inv0, o[nt][1] * inv0);
            *reinterpret_cast<float2*>(
                out + ((size_t)(b * S_LEN + qa)) * 128 + h * 32 + nt * 8 + tig * 2) = v;
        }
        if (qb2 < S_LEN) {
            float2 v = make_float2(o[nt][2] * inv1, o[nt][3] * inv1);
            *reinterpret_cast<float2*>(
                out + ((size_t)(b * S_LEN + qb2)) * 128 + h * 32 + nt * 8 + tig * 2) = v;
        }
    }
}

// ---------------- head ----------------
__global__ __launch_bounds__(64) void head_kernel(
    const float* __restrict__ h, const float* __restrict__ ls,
    const float* __restrict__ lb, const float* __restrict__ hw,
    const float* __restrict__ hb, float* __restrict__ out)
{
    int bidx = threadIdx.x >> 5;
    if (bidx >= BATCH) return;
    int lane = threadIdx.x & 31;
    const float* xr = h + (size_t)bidx * S_LEN * D_MODEL;
    float4 v = *reinterpret_cast<const float4*>(xr + lane * 4);
    float sum = v.x + v.y + v.z + v.w;
    #pragma unroll
    for (int o = 16; o; o >>= 1) sum += __shfl_xor_sync(0xffffffffu, sum, o);
    float mean = sum * (1.f / 128.f);
    float dx = v.x - mean, dy = v.y - mean, dz = v.z - mean, dw = v.w - mean;
    float vs = dx * dx + dy * dy + dz * dz + dw * dw;
    #pragma unroll
    for (int o = 16; o; o >>= 1) vs += __shfl_xor_sync(0xffffffffu, vs, o);
    float rstd = rsqrtf(vs * (1.f / 128.f) + 1e-5f);
    float4 s4 = *reinterpret_cast<const float4*>(ls + lane * 4);
    float4 b4 = *reinterpret_cast<const float4*>(lb + lane * 4);
    float4 w4 = *reinterpret_cast<const float4*>(hw + lane * 4);
    float dot = (dx * rstd * s4.x + b4.x) * w4.x
              + (dy * rstd * s4.y + b4.y) * w4.y
              + (dz * rstd * s4.z + b4.z) * w4.z
              + (dw * rstd * s4.w + b4.w) * w4.w;
    #pragma unroll
    for (int o = 16; o; o >>= 1) dot += __shfl_xor_sync(0xffffffffu, dot, o);
    if (lane == 0) out[bidx] = dot + hb[0];
}

// ---------------- launch ----------------
extern "C" void kernel_launch(void* const* d_in, const int* in_sizes, int n_in,
                              void* d_out, int out_size)
{
    const float* x        = (const float*)d_in[0];
    const float* embed_w  = (const float*)d_in[1];
    const float* embed_b  = (const float*)d_in[2];
    const float* pos_emb  = (const float*)d_in[3];
    const float* cls      = (const float*)d_in[4];
    const float* in_w     = (const float*)d_in[5];
    const float* in_b     = (const float*)d_in[6];
    const float* out_w    = (const float*)d_in[7];
    const float* out_b    = (const float*)d_in[8];
    const float* ln1_s    = (const float*)d_in[9];
    const float* ln1_b    = (const float*)d_in[10];
    const float* ln2_s    = (const float*)d_in[11];
    const float* ln2_b    = (const float*)d_in[12];
    const float* ff1_w    = (const float*)d_in[13];
    const float* ff1_b    = (const float*)d_in[14];
    const float* ff2_w    = (const float*)d_in[15];
    const float* ff2_b    = (const float*)d_in[16];
    const float* hln_s    = (const float*)d_in[17];
    const float* hln_b    = (const float*)d_in[18];
    const float* head_w   = (const float*)d_in[19];
    const float* head_b   = (const float*)d_in[20];
    float* outp = (float*)d_out;

    float *h, *hn, *attn, *ff;
    __half *qkvh;
    cudaGetSymbolAddress((void**)&h,     g_h);
    cudaGetSymbolAddress((void**)&hn,    g_hn);
    cudaGetSymbolAddress((void**)&qkvh,  g_qkvh);
    cudaGetSymbolAddress((void**)&attn,  g_attn);
    cudaGetSymbolAddress((void**)&ff,    g_ff);

    embed_kernel<<<dim3(S_LEN, BATCH), 128>>>(x, embed_w, embed_b, pos_emb, cls, h);

    const int M = MROWS;
    dim3 lnGrid((M + 7) / 8);
    dim3 gemmBlk(256);

    for (int i = 0; i < NL; i++) {
        ln_kernel<<<lnGrid, 256>>>(h, ln1_s + i * D_MODEL, ln1_b + i * D_MODEL, hn, M);
        // QKV projection -> fp16, Q pre-scaled
        gemm_kernel<false, false, true><<<dim3(384 / 64, (M + 63) / 64), gemmBlk>>>(
            hn, in_w + (size_t)i * 384 * 128, in_b + (size_t)i * 384,
            nullptr, qkvh, M, 384, 128);
        attn_kernel<<<dim3((S_LEN + BQ - 1) / BQ, N_HEADS, BATCH), 256>>>(qkvh, attn);
        gemm_kernel<false, true, false><<<dim3(128 / 64, (M + 63) / 64), gemmBlk>>>(
            attn, out_w + (size_t)i * 128 * 128, out_b + (size_t)i * 128,
            h, h, M, 128, 128);
        ln_kernel<<<lnGrid, 256>>>(h, ln2_s + i * D_MODEL, ln2_b + i * D_MODEL, hn, M);
        gemm_kernel<true, false, false><<<dim3(512 / 64, (M + 63) / 64), gemmBlk>>>(
            hn, ff1_w + (size_t)i * 512 * 128, ff1_b + (size_t)i * 512,
            nullptr, ff, M, 512, 128);
        gemm_kernel<false, true, false><<<dim3(128 / 64, (M + 63) / 64), gemmBlk>>>(
            ff, ff2_w + (size_t)i * 128 * 512, ff2_b + (size_t)i * 128,
            h, h, M, 128, 512);
    }

    head_kernel<<<1, 64>>>(h, hln_s, hln_b, head_w, head_b, outp);
}

// round 5
// speedup vs baseline: 3.4326x; 1.3192x over previous
#include <cuda_runtime.h>
#include <cuda_fp16.h>
#include <math.h>

#define NL 3
#define D_MODEL 128
#define N_HEADS 4
#define DHEAD 32
#define DFF 512
#define DIN 64
#define BATCH 2
#define LSEQ 2048
#define S_LEN 2049
#define MROWS (BATCH * S_LEN)   // 4098
#define QK_SCALE 0.17677669529663687f

// ---------------- scratch (device globals; no allocation) ----------------
__device__ float  g_h[MROWS * D_MODEL];
__device__ __half g_hnh[MROWS * D_MODEL];
__device__ __half g_qkvh[MROWS * 3 * D_MODEL];
__device__ __half g_attnh[MROWS * D_MODEL];
__device__ __half g_ffh[MROWS * DFF];

// ---------------- mma helper ----------------
__device__ __forceinline__ void mma16816(
    float c[4], const unsigned a[4], const unsigned b[2])
{
    asm volatile(
        "mma.sync.aligned.m16n8k16.row.col.f32.f16.f16.f32 "
        "{%0,%1,%2,%3}, {%4,%5,%6,%7}, {%8,%9}, {%0,%1,%2,%3};\n"
        : "+f"(c[0]), "+f"(c[1]), "+f"(c[2]), "+f"(c[3])
        : "r"(a[0]), "r"(a[1]), "r"(a[2]), "r"(a[3]),
          "r"(b[0]), "r"(b[1]));
}

// ---------------- embedding ----------------
__global__ __launch_bounds__(128) void embed_kernel(
    const float* __restrict__ x, const float* __restrict__ ew,
    const float* __restrict__ eb, const float* __restrict__ pos,
    const float* __restrict__ cls, float* __restrict__ h)
{
    __shared__ float xs[DIN];
    int s = blockIdx.x, b = blockIdx.y;
    int d = threadIdx.x;
    float val;
    if (s == 0) {
        val = cls[d] + pos[d];
    } else {
        if (d < DIN) xs[d] = x[((size_t)b * LSEQ + (s - 1)) * DIN + d];
        __syncthreads();
        float acc = 0.f;
        const float* wr = ew + (size_t)d * DIN;
        #pragma unroll
        for (int j = 0; j < DIN; j++) acc = fmaf(xs[j], wr[j], acc);
        val = acc + eb[d] + pos[(size_t)s * D_MODEL + d];
    }
    h[((size_t)b * S_LEN + s) * D_MODEL + d] = val;
}

// ---------------- layernorm: fp32 in -> fp16 out ----------------
__global__ __launch_bounds__(256) void ln_kernel(
    const float* __restrict__ x, const float* __restrict__ sc,
    const float* __restrict__ bi, __half* __restrict__ y, int nrows)
{
    int row = blockIdx.x * 8 + (threadIdx.x >> 5);
    if (row >= nrows) return;
    int lane = threadIdx.x & 31;
    const float* xr = x + (size_t)row * D_MODEL;
    float4 v = *reinterpret_cast<const float4*>(xr + lane * 4);
    float sum = v.x + v.y + v.z + v.w;
    #pragma unroll
    for (int o = 16; o; o >>= 1) sum += __shfl_xor_sync(0xffffffffu, sum, o);
    float mean = sum * (1.f / 128.f);
    float dx = v.x - mean, dy = v.y - mean, dz = v.z - mean, dw = v.w - mean;
    float vs = dx * dx + dy * dy + dz * dz + dw * dw;
    #pragma unroll
    for (int o = 16; o; o >>= 1) vs += __shfl_xor_sync(0xffffffffu, vs, o);
    float rstd = rsqrtf(vs * (1.f / 128.f) + 1e-5f);
    float4 s4 = *reinterpret_cast<const float4*>(sc + lane * 4);
    float4 b4 = *reinterpret_cast<const float4*>(bi + lane * 4);
    __half2 h2a = __floats2half2_rn(dx * rstd * s4.x + b4.x, dy * rstd * s4.y + b4.y);
    __half2 h2b = __floats2half2_rn(dz * rstd * s4.z + b4.z, dw * rstd * s4.w + b4.w);
    uint2 pk;
    pk.x = *reinterpret_cast<unsigned*>(&h2a);
    pk.y = *reinterpret_cast<unsigned*>(&h2b);
    *reinterpret_cast<uint2*>(y + (size_t)row * D_MODEL + lane * 4) = pk;
}

// ---------------- tensor-core GEMM ----------------
// C[M,N] = A[M,K](fp16) . W[N,K](fp32->fp16)^T + bias (+resid fp32) (ReLU?)
// Block tile 128x64, BK=32, 256 threads = 8 warps (4m x 2n), warp tile 32x32.
#define GPITCH 40
template <bool RELU, bool RESID, bool HALF_OUT, bool QSCALE>
__global__ __launch_bounds__(256) void hgemm_kernel(
    const __half* __restrict__ A, const float* __restrict__ W,
    const float* __restrict__ bias, const float* __restrict__ resid,
    void* __restrict__ Cv, int M, int N, int K)
{
    __shared__ __half As[128][GPITCH];
    __shared__ __half Ws[64][GPITCH];
    const int tid = threadIdx.x;
    const int warp = tid >> 5;
    const int lane = tid & 31;
    const int g = lane >> 2;
    const int tig = lane & 3;
    const int warp_m = warp >> 1;   // 0..3
    const int warp_n = warp & 1;    // 0..1
    const int m0 = blockIdx.y * 128;
    const int n0 = blockIdx.x * 64;

    float c[2][4][4] = {};

    for (int k0 = 0; k0 < K; k0 += 32) {
        // stage A: 128 rows x 32 halfs (uint4 = 8 halfs)
        #pragma unroll
        for (int it = 0; it < 2; it++) {
            int idx = tid + it * 256;
            int r = idx >> 2, quad = idx & 3;
            int m = m0 + r;
            uint4 v = make_uint4(0u, 0u, 0u, 0u);
            if (m < M)
                v = *reinterpret_cast<const uint4*>(A + (size_t)m * K + k0 + quad * 8);
            *reinterpret_cast<uint4*>(&As[r][quad * 8]) = v;
        }
        // stage W: 64 rows x 32 fp32 -> fp16
        #pragma unroll
        for (int it = 0; it < 2; it++) {
            int idx = tid + it * 256;
            int r = idx >> 3, q = idx & 7;
            float4 wv = *reinterpret_cast<const float4*>(
                W + (size_t)(n0 + r) * K + k0 + q * 4);
            __half2 h2a = __floats2half2_rn(wv.x, wv.y);
            __half2 h2b = __floats2half2_rn(wv.z, wv.w);
            uint2 pk;
            pk.x = *reinterpret_cast<unsigned*>(&h2a);
            pk.y = *reinterpret_cast<unsigned*>(&h2b);
            *reinterpret_cast<uint2*>(&Ws[r][q * 4]) = pk;
        }
        __syncthreads();

        #pragma unroll
        for (int ks = 0; ks < 2; ks++) {
            unsigned a[2][4];
            #pragma unroll
            for (int mt = 0; mt < 2; mt++) {
                int rbase = warp_m * 32 + mt * 16;
                a[mt][0] = *reinterpret_cast<const unsigned*>(&As[rbase + g    ][ks * 16 + tig * 2]);
                a[mt][1] = *reinterpret_cast<const unsigned*>(&As[rbase + g + 8][ks * 16 + tig * 2]);
                a[mt][2] = *reinterpret_cast<const unsigned*>(&As[rbase + g    ][ks * 16 + tig * 2 + 8]);
                a[mt][3] = *reinterpret_cast<const unsigned*>(&As[rbase + g + 8][ks * 16 + tig * 2 + 8]);
            }
            #pragma unroll
            for (int nt = 0; nt < 4; nt++) {
                unsigned bfr[2];
                int nrow = warp_n * 32 + nt * 8 + g;
                bfr[0] = *reinterpret_cast<const unsigned*>(&Ws[nrow][ks * 16 + tig * 2]);
                bfr[1] = *reinterpret_cast<const unsigned*>(&Ws[nrow][ks * 16 + tig * 2 + 8]);
                mma16816(c[0][nt], a[0], bfr);
                mma16816(c[1][nt], a[1], bfr);
            }
        }
        __syncthreads();
    }

    // epilogue
    #pragma unroll
    for (int mt = 0; mt < 2; mt++) {
        #pragma unroll
        for (int half_row = 0; half_row < 2; half_row++) {
            int m = m0 + warp_m * 32 + mt * 16 + g + half_row * 8;
            if (m >= M) continue;
            #pragma unroll
            for (int nt = 0; nt < 4; nt++) {
                int n = n0 + warp_n * 32 + nt * 8 + tig * 2;
                float v0 = c[mt][nt][half_row * 2 + 0] + bias[n];
                float v1 = c[mt][nt][half_row * 2 + 1] + bias[n + 1];
                if (RESID) {
                    v0 += resid[(size_t)m * N + n];
                    v1 += resid[(size_t)m * N + n + 1];
                }
                if (RELU) { v0 = fmaxf(v0, 0.f); v1 = fmaxf(v1, 0.f); }
                if (HALF_OUT) {
                    if (QSCALE && n < 128) { v0 *= QK_SCALE; v1 *= QK_SCALE; }
                    __half2 hv = __floats2half2_rn(v0, v1);
                    *reinterpret_cast<unsigned*>(
                        (__half*)Cv + (size_t)m * N + n) = *reinterpret_cast<unsigned*>(&hv);
                } else {
                    float2 fv = make_float2(v0, v1);
                    *reinterpret_cast<float2*>((float*)Cv + (size_t)m * N + n) = fv;
                }
            }
        }
    }
}

// ---------------- tensor-core flash attention (fp16 out) ----------------
#define BQ 128
#define BK 64
#define QPITCH 40
#define VPITCH 72

__global__ __launch_bounds__(256) void attn_kernel(
    const __half* __restrict__ qkv, __half* __restrict__ out)
{
    __shared__ __half Qs[BQ][QPITCH];
    __shared__ __half Kt[BK][QPITCH];
    __shared__ __half Vt[DHEAD][VPITCH];
    const int tid = threadIdx.x;
    const int warp = tid >> 5;
    const int lane = tid & 31;
    const int g = lane >> 2;
    const int tig = lane & 3;
    const int b = blockIdx.z, h = blockIdx.y;
    const int q0 = blockIdx.x * BQ;
    const int qbase = warp * 16;

    #pragma unroll
    for (int idx = tid; idx < BQ * 4; idx += 256) {
        int r = idx >> 2, quad = idx & 3;
        int q = q0 + r;
        uint4 v = make_uint4(0u, 0u, 0u, 0u);
        if (q < S_LEN)
            v = *reinterpret_cast<const uint4*>(
                qkv + ((size_t)(b * S_LEN + q)) * 384 + h * 32 + quad * 8);
        *reinterpret_cast<uint4*>(&Qs[r][quad * 8]) = v;
    }

    float m0 = -1e30f, m1 = -1e30f, l0 = 0.f, l1 = 0.f;
    float o[4][4] = {};
    __syncthreads();

    for (int kb = 0; kb < S_LEN; kb += BK) {
        {
            int r = tid >> 2, quad = tid & 3;
            int kg = kb + r;
            uint4 v = make_uint4(0u, 0u, 0u, 0u);
            if (kg < S_LEN)
                v = *reinterpret_cast<const uint4*>(
                    qkv + ((size_t)(b * S_LEN + kg)) * 384 + 128 + h * 32 + quad * 8);
            *reinterpret_cast<uint4*>(&Kt[r][quad * 8]) = v;
        }
        #pragma unroll
        for (int idx = tid; idx < BK * 16; idx += 256) {
            int kl = idx >> 4, dp = idx & 15;
            int kg = kb + kl;
            __half2 hv = __float2half2_rn(0.f);
            if (kg < S_LEN)
                hv = *reinterpret_cast<const __half2*>(
                    qkv + ((size_t)(b * S_LEN + kg)) * 384 + 256 + h * 32 + dp * 2);
            Vt[dp * 2 + 0][kl] = __low2half(hv);
            Vt[dp * 2 + 1][kl] = __high2half(hv);
        }
        __syncthreads();

        unsigned A[2][4];
        #pragma unroll
        for (int ks = 0; ks < 2; ks++) {
            A[ks][0] = *reinterpret_cast<const unsigned*>(&Qs[qbase + g    ][ks * 16 + tig * 2]);
            A[ks][1] = *reinterpret_cast<const unsigned*>(&Qs[qbase + g + 8][ks * 16 + tig * 2]);
            A[ks][2] = *reinterpret_cast<const unsigned*>(&Qs[qbase + g    ][ks * 16 + tig * 2 + 8]);
            A[ks][3] = *reinterpret_cast<const unsigned*>(&Qs[qbase + g + 8][ks * 16 + tig * 2 + 8]);
        }
        float s[8][4];
        #pragma unroll
        for (int j = 0; j < 8; j++) {
            s[j][0] = s[j][1] = s[j][2] = s[j][3] = 0.f;
            #pragma unroll
            for (int ks = 0; ks < 2; ks++) {
                unsigned bfr[2];
                bfr[0] = *reinterpret_cast<const unsigned*>(&Kt[j * 8 + g][ks * 16 + tig * 2]);
                bfr[1] = *reinterpret_cast<const unsigned*>(&Kt[j * 8 + g][ks * 16 + tig * 2 + 8]);
                mma16816(s[j], A[ks], bfr);
            }
        }
        if (kb + BK > S_LEN) {
            #pragma unroll
            for (int j = 0; j < 8; j++) {
                int key = kb + j * 8 + tig * 2;
                if (key >= S_LEN)     { s[j][0] = -1e30f; s[j][2] = -1e30f; }
                if (key + 1 >= S_LEN) { s[j][1] = -1e30f; s[j][3] = -1e30f; }
            }
        }

        float t0 = -1e30f, t1 = -1e30f;
        #pragma unroll
        for (int j = 0; j < 8; j++) {
            t0 = fmaxf(t0, fmaxf(s[j][0], s[j][1]));
            t1 = fmaxf(t1, fmaxf(s[j][2], s[j][3]));
        }
        t0 = fmaxf(t0, __shfl_xor_sync(0xffffffffu, t0, 1));
        t0 = fmaxf(t0, __shfl_xor_sync(0xffffffffu, t0, 2));
        t1 = fmaxf(t1, __shfl_xor_sync(0xffffffffu, t1, 1));
        t1 = fmaxf(t1, __shfl_xor_sync(0xffffffffu, t1, 2));
        float mn0 = fmaxf(m0, t0), mn1 = fmaxf(m1, t1);
        float c0 = __expf(m0 - mn0), c1 = __expf(m1 - mn1);
        unsigned ph[8][2];
        float ps0 = 0.f, ps1 = 0.f;
        #pragma unroll
        for (int j = 0; j < 8; j++) {
            __half2 h2a = __floats2half2_rn(__expf(s[j][0] - mn0), __expf(s[j][1] - mn0));
            __half2 h2b = __floats2half2_rn(__expf(s[j][2] - mn1), __expf(s[j][3] - mn1));
            ph[j][0] = *reinterpret_cast<unsigned*>(&h2a);
            ph[j][1] = *reinterpret_cast<unsigned*>(&h2b);
            float2 fa = __half22float2(h2a);
            float2 fb = __half22float2(h2b);
            ps0 += fa.x + fa.y;
            ps1 += fb.x + fb.y;
        }
        ps0 += __shfl_xor_sync(0xffffffffu, ps0, 1);
        ps0 += __shfl_xor_sync(0xffffffffu, ps0, 2);
        ps1 += __shfl_xor_sync(0xffffffffu, ps1, 1);
        ps1 += __shfl_xor_sync(0xffffffffu, ps1, 2);
        l0 = l0 * c0 + ps0;
        l1 = l1 * c1 + ps1;
        m0 = mn0; m1 = mn1;
        #pragma unroll
        for (int nt = 0; nt < 4; nt++) {
            o[nt][0] *= c0; o[nt][1] *= c0;
            o[nt][2] *= c1; o[nt][3] *= c1;
        }

        #pragma unroll
        for (int kt = 0; kt < 4; kt++) {
            unsigned pa[4] = { ph[2 * kt][0], ph[2 * kt][1],
                               ph[2 * kt + 1][0], ph[2 * kt + 1][1] };
            #pragma unroll
            for (int nt = 0; nt < 4; nt++) {
                unsigned bfr[2];
                bfr[0] = *reinterpret_cast<const unsigned*>(&Vt[nt * 8 + g][kt * 16 + tig * 2]);
                bfr[1] = *reinterpret_cast<const unsigned*>(&Vt[nt * 8 + g][kt * 16 + tig * 2 + 8]);
                mma16816(o[nt], pa, bfr);
            }
        }
        __syncthreads();
    }

    float inv0 = 1.f / l0, inv1 = 1.f / l1;
    int qa = q0 + qbase + g;
    int qb2 = qa + 8;
    #pragma unroll
    for (int nt = 0; nt < 4; nt++) {
        if (qa < S_LEN) {
            __half2 hv = __floats2half2_rn(o[nt][0] * inv0, o[nt][1] * inv0);
            *reinterpret_cast<unsigned*>(
                out + ((size_t)(b * S_LEN + qa)) * 128 + h * 32 + nt * 8 + tig * 2)
                = *reinterpret_cast<unsigned*>(&hv);
        }
        if (qb2 < S_LEN) {
            __half2 hv = __floats2half2_rn(o[nt][2] * inv1, o[nt][3] * inv1);
            *reinterpret_cast<unsigned*>(
                out + ((size_t)(b * S_LEN + qb2)) * 128 + h * 32 + nt * 8 + tig * 2)
                = *reinterpret_cast<unsigned*>(&hv);
        }
    }
}

// ---------------- head ----------------
__global__ __launch_bounds__(64) void head_kernel(
    const float* __restrict__ h, const float* __restrict__ ls,
    const float* __restrict__ lb, const float* __restrict__ hw,
    const float* __restrict__ hb, float* __restrict__ out)
{
    int bidx = threadIdx.x >> 5;
    if (bidx >= BATCH) return;
    int lane = threadIdx.x & 31;
    const float* xr = h + (size_t)bidx * S_LEN * D_MODEL;
    float4 v = *reinterpret_cast<const float4*>(xr + lane * 4);
    float sum = v.x + v.y + v.z + v.w;
    #pragma unroll
    for (int o = 16; o; o >>= 1) sum += __shfl_xor_sync(0xffffffffu, sum, o);
    float mean = sum * (1.f / 128.f);
    float dx = v.x - mean, dy = v.y - mean, dz = v.z - mean, dw = v.w - mean;
    float vs = dx * dx + dy * dy + dz * dz + dw * dw;
    #pragma unroll
    for (int o = 16; o; o >>= 1) vs += __shfl_xor_sync(0xffffffffu, vs, o);
    float rstd = rsqrtf(vs * (1.f / 128.f) + 1e-5f);
    float4 s4 = *reinterpret_cast<const float4*>(ls + lane * 4);
    float4 b4 = *reinterpret_cast<const float4*>(lb + lane * 4);
    float4 w4 = *reinterpret_cast<const float4*>(hw + lane * 4);
    float dot = (dx * rstd * s4.x + b4.x) * w4.x
              + (dy * rstd * s4.y + b4.y) * w4.y
              + (dz * rstd * s4.z + b4.z) * w4.z
              + (dw * rstd * s4.w + b4.w) * w4.w;
    #pragma unroll
    for (int o = 16; o; o >>= 1) dot += __shfl_xor_sync(0xffffffffu, dot, o);
    if (lane == 0) out[bidx] = dot + hb[0];
}

// ---------------- launch ----------------
extern "C" void kernel_launch(void* const* d_in, const int* in_sizes, int n_in,
                              void* d_out, int out_size)
{
    const float* x        = (const float*)d_in[0];
    const float* embed_w  = (const float*)d_in[1];
    const float* embed_b  = (const float*)d_in[2];
    const float* pos_emb  = (const float*)d_in[3];
    const float* cls      = (const float*)d_in[4];
    const float* in_w     = (const float*)d_in[5];
    const float* in_b     = (const float*)d_in[6];
    const float* out_w    = (const float*)d_in[7];
    const float* out_b    = (const float*)d_in[8];
    const float* ln1_s    = (const float*)d_in[9];
    const float* ln1_b    = (const float*)d_in[10];
    const float* ln2_s    = (const float*)d_in[11];
    const float* ln2_b    = (const float*)d_in[12];
    const float* ff1_w    = (const float*)d_in[13];
    const float* ff1_b    = (const float*)d_in[14];
    const float* ff2_w    = (const float*)d_in[15];
    const float* ff2_b    = (const float*)d_in[16];
    const float* hln_s    = (const float*)d_in[17];
    const float* hln_b    = (const float*)d_in[18];
    const float* head_w   = (const float*)d_in[19];
    const float* head_b   = (const float*)d_in[20];
    float* outp = (float*)d_out;

    float *h;
    __half *hnh, *qkvh, *attnh, *ffh;
    cudaGetSymbolAddress((void**)&h,     g_h);
    cudaGetSymbolAddress((void**)&hnh,   g_hnh);
    cudaGetSymbolAddress((void**)&qkvh,  g_qkvh);
    cudaGetSymbolAddress((void**)&attnh, g_attnh);
    cudaGetSymbolAddress((void**)&ffh,   g_ffh);

    embed_kernel<<<dim3(S_LEN, BATCH), 128>>>(x, embed_w, embed_b, pos_emb, cls, h);

    const int M = MROWS;
    const int MB = (M + 127) / 128;
    dim3 lnGrid((M + 7) / 8);

    for (int i = 0; i < NL; i++) {
        ln_kernel<<<lnGrid, 256>>>(h, ln1_s + i * D_MODEL, ln1_b + i * D_MODEL, hnh, M);
        // QKV projection -> fp16 (Q pre-scaled)
        hgemm_kernel<false, false, true, true><<<dim3(384 / 64, MB), 256>>>(
            hnh, in_w + (size_t)i * 384 * 128, in_b + (size_t)i * 384,
            nullptr, qkvh, M, 384, 128);
        attn_kernel<<<dim3((S_LEN + BQ - 1) / BQ, N_HEADS, BATCH), 256>>>(qkvh, attnh);
        // out projection + residual -> fp32 h
        hgemm_kernel<false, true, false, false><<<dim3(128 / 64, MB), 256>>>(
            attnh, out_w + (size_t)i * 128 * 128, out_b + (size_t)i * 128,
            h, h, M, 128, 128);
        ln_kernel<<<lnGrid, 256>>>(h, ln2_s + i * D_MODEL, ln2_b + i * D_MODEL, hnh, M);
        // FF1 + ReLU -> fp16
        hgemm_kernel<true, false, true, false><<<dim3(512 / 64, MB), 256>>>(
            hnh, ff1_w + (size_t)i * 512 * 128, ff1_b + (size_t)i * 512,
            nullptr, ffh, M, 512, 128);
        // FF2 + residual -> fp32 h
        hgemm_kernel<false, true, false, false><<<dim3(128 / 64, MB), 256>>>(
            ffh, ff2_w + (size_t)i * 128 * 512, ff2_b + (size_t)i * 128,
            h, h, M, 128, 512);
    }

    head_kernel<<<1, 64>>>(h, hln_s, hln_b, head_w, head_b, outp);
}

// round 6
// speedup vs baseline: 3.8559x; 1.1233x over previous
#include <cuda_runtime.h>
#include <cuda_fp16.h>
#include <math.h>

#define NL 3
#define D_MODEL 128
#define N_HEADS 4
#define DHEAD 32
#define DFF 512
#define DIN 64
#define BATCH 2
#define LSEQ 2048
#define S_LEN 2049
#define MROWS (BATCH * S_LEN)   // 4098
#define QK_SCALE 0.17677669529663687f

#define SPLITS 4
#define KCHUNK 576   // 9 tiles of 64; 4*576 >= 2049

// ---------------- scratch (device globals; no allocation) ----------------
__device__ float  g_h[MROWS * D_MODEL];
__device__ __half g_hnh[MROWS * D_MODEL];
__device__ __half g_qkvh[MROWS * 3 * D_MODEL];
__device__ __half g_attnh[MROWS * D_MODEL];
__device__ __half g_ffh[MROWS * DFF];
__device__ float  g_po[SPLITS * BATCH * N_HEADS * S_LEN * DHEAD];
__device__ float  g_pm[SPLITS * BATCH * N_HEADS * S_LEN];
__device__ float  g_pl[SPLITS * BATCH * N_HEADS * S_LEN];

// ---------------- mma helper ----------------
__device__ __forceinline__ void mma16816(
    float c[4], const unsigned a[4], const unsigned b[2])
{
    asm volatile(
        "mma.sync.aligned.m16n8k16.row.col.f32.f16.f16.f32 "
        "{%0,%1,%2,%3}, {%4,%5,%6,%7}, {%8,%9}, {%0,%1,%2,%3};\n"
        : "+f"(c[0]), "+f"(c[1]), "+f"(c[2]), "+f"(c[3])
        : "r"(a[0]), "r"(a[1]), "r"(a[2]), "r"(a[3]),
          "r"(b[0]), "r"(b[1]));
}

// ---------------- embedding ----------------
__global__ __launch_bounds__(128) void embed_kernel(
    const float* __restrict__ x, const float* __restrict__ ew,
    const float* __restrict__ eb, const float* __restrict__ pos,
    const float* __restrict__ cls, float* __restrict__ h)
{
    __shared__ float xs[DIN];
    int s = blockIdx.x, b = blockIdx.y;
    int d = threadIdx.x;
    float val;
    if (s == 0) {
        val = cls[d] + pos[d];
    } else {
        if (d < DIN) xs[d] = x[((size_t)b * LSEQ + (s - 1)) * DIN + d];
        __syncthreads();
        float acc = 0.f;
        const float* wr = ew + (size_t)d * DIN;
        #pragma unroll
        for (int j = 0; j < DIN; j++) acc = fmaf(xs[j], wr[j], acc);
        val = acc + eb[d] + pos[(size_t)s * D_MODEL + d];
    }
    h[((size_t)b * S_LEN + s) * D_MODEL + d] = val;
}

// ---------------- layernorm: fp32 in -> fp16 out ----------------
__global__ __launch_bounds__(256) void ln_kernel(
    const float* __restrict__ x, const float* __restrict__ sc,
    const float* __restrict__ bi, __half* __restrict__ y, int nrows)
{
    int row = blockIdx.x * 8 + (threadIdx.x >> 5);
    if (row >= nrows) return;
    int lane = threadIdx.x & 31;
    const float* xr = x + (size_t)row * D_MODEL;
    float4 v = *reinterpret_cast<const float4*>(xr + lane * 4);
    float sum = v.x + v.y + v.z + v.w;
    #pragma unroll
    for (int o = 16; o; o >>= 1) sum += __shfl_xor_sync(0xffffffffu, sum, o);
    float mean = sum * (1.f / 128.f);
    float dx = v.x - mean, dy = v.y - mean, dz = v.z - mean, dw = v.w - mean;
    float vs = dx * dx + dy * dy + dz * dz + dw * dw;
    #pragma unroll
    for (int o = 16; o; o >>= 1) vs += __shfl_xor_sync(0xffffffffu, vs, o);
    float rstd = rsqrtf(vs * (1.f / 128.f) + 1e-5f);
    float4 s4 = *reinterpret_cast<const float4*>(sc + lane * 4);
    float4 b4 = *reinterpret_cast<const float4*>(bi + lane * 4);
    __half2 h2a = __floats2half2_rn(dx * rstd * s4.x + b4.x, dy * rstd * s4.y + b4.y);
    __half2 h2b = __floats2half2_rn(dz * rstd * s4.z + b4.z, dw * rstd * s4.w + b4.w);
    uint2 pk;
    pk.x = *reinterpret_cast<unsigned*>(&h2a);
    pk.y = *reinterpret_cast<unsigned*>(&h2b);
    *reinterpret_cast<uint2*>(y + (size_t)row * D_MODEL + lane * 4) = pk;
}

// ---------------- tensor-core GEMM ----------------
// C[M,N] = A[M,K](fp16) . W[N,K](fp32->fp16)^T + bias (+resid fp32) (ReLU?)
// Block tile MTILE x 64, BK=32, 256 threads (8 warps).
// MTILE=128: warps 4m x 2n (32x32).  MTILE=64: warps 2m x 4n (32x16).
#define GPITCH 40
template <int MTILE, bool RELU, bool RESID, bool HALF_OUT, bool QSCALE>
__global__ __launch_bounds__(256) void hgemm_kernel(
    const __half* __restrict__ A, const float* __restrict__ W,
    const float* __restrict__ bias, const float* __restrict__ resid,
    void* __restrict__ Cv, int M, int N, int K)
{
    constexpr int NW = (MTILE == 128) ? 2 : 4;
    constexpr int NT = 64 / (NW * 8);          // n fragments per warp (4 or 2)
    constexpr int AITERS = (MTILE * 4) / 256;  // A stage iterations (2 or 1)
    __shared__ __half As[MTILE][GPITCH];
    __shared__ __half Ws[64][GPITCH];
    const int tid = threadIdx.x;
    const int warp = tid >> 5;
    const int lane = tid & 31;
    const int g = lane >> 2;
    const int tig = lane & 3;
    const int warp_m = warp / NW;
    const int warp_n = warp % NW;
    const int m0 = blockIdx.y * MTILE;
    const int n0 = blockIdx.x * 64;

    float c[2][NT][4] = {};

    for (int k0 = 0; k0 < K; k0 += 32) {
        #pragma unroll
        for (int it = 0; it < AITERS; it++) {
            int idx = tid + it * 256;
            int r = idx >> 2, quad = idx & 3;
            int m = m0 + r;
            uint4 v = make_uint4(0u, 0u, 0u, 0u);
            if (m < M)
                v = *reinterpret_cast<const uint4*>(A + (size_t)m * K + k0 + quad * 8);
            *reinterpret_cast<uint4*>(&As[r][quad * 8]) = v;
        }
        #pragma unroll
        for (int it = 0; it < 2; it++) {
            int idx = tid + it * 256;
            int r = idx >> 3, q = idx & 7;
            float4 wv = *reinterpret_cast<const float4*>(
                W + (size_t)(n0 + r) * K + k0 + q * 4);
            __half2 h2a = __floats2half2_rn(wv.x, wv.y);
            __half2 h2b = __floats2half2_rn(wv.z, wv.w);
            uint2 pk;
            pk.x = *reinterpret_cast<unsigned*>(&h2a);
            pk.y = *reinterpret_cast<unsigned*>(&h2b);
            *reinterpret_cast<uint2*>(&Ws[r][q * 4]) = pk;
        }
        __syncthreads();

        #pragma unroll
        for (int ks = 0; ks < 2; ks++) {
            unsigned a[2][4];
            #pragma unroll
            for (int mt = 0; mt < 2; mt++) {
                int rbase = warp_m * 32 + mt * 16;
                a[mt][0] = *reinterpret_cast<const unsigned*>(&As[rbase + g    ][ks * 16 + tig * 2]);
                a[mt][1] = *reinterpret_cast<const unsigned*>(&As[rbase + g + 8][ks * 16 + tig * 2]);
                a[mt][2] = *reinterpret_cast<const unsigned*>(&As[rbase + g    ][ks * 16 + tig * 2 + 8]);
                a[mt][3] = *reinterpret_cast<const unsigned*>(&As[rbase + g + 8][ks * 16 + tig * 2 + 8]);
            }
            #pragma unroll
            for (int nt = 0; nt < NT; nt++) {
                unsigned bfr[2];
                int nrow = warp_n * (NT * 8) + nt * 8 + g;
                bfr[0] = *reinterpret_cast<const unsigned*>(&Ws[nrow][ks * 16 + tig * 2]);
                bfr[1] = *reinterpret_cast<const unsigned*>(&Ws[nrow][ks * 16 + tig * 2 + 8]);
                mma16816(c[0][nt], a[0], bfr);
                mma16816(c[1][nt], a[1], bfr);
            }
        }
        __syncthreads();
    }

    #pragma unroll
    for (int mt = 0; mt < 2; mt++) {
        #pragma unroll
        for (int half_row = 0; half_row < 2; half_row++) {
            int m = m0 + warp_m * 32 + mt * 16 + g + half_row * 8;
            if (m >= M) continue;
            #pragma unroll
            for (int nt = 0; nt < NT; nt++) {
                int n = n0 + warp_n * (NT * 8) + nt * 8 + tig * 2;
                float v0 = c[mt][nt][half_row * 2 + 0] + bias[n];
                float v1 = c[mt][nt][half_row * 2 + 1] + bias[n + 1];
                if (RESID) {
                    v0 += resid[(size_t)m * N + n];
                    v1 += resid[(size_t)m * N + n + 1];
                }
                if (RELU) { v0 = fmaxf(v0, 0.f); v1 = fmaxf(v1, 0.f); }
                if (HALF_OUT) {
                    if (QSCALE && n < 128) { v0 *= QK_SCALE; v1 *= QK_SCALE; }
                    __half2 hv = __floats2half2_rn(v0, v1);
                    *reinterpret_cast<unsigned*>(
                        (__half*)Cv + (size_t)m * N + n) = *reinterpret_cast<unsigned*>(&hv);
                } else {
                    float2 fv = make_float2(v0, v1);
                    *reinterpret_cast<float2*>((float*)Cv + (size_t)m * N + n) = fv;
                }
            }
        }
    }
}

// ---------------- split-S tensor-core flash attention ----------------
#define BQ 128
#define BK 64
#define QPITCH 40
#define VPITCH 72

__global__ __launch_bounds__(256) void attn_kernel(
    const __half* __restrict__ qkv,
    float* __restrict__ po, float* __restrict__ pm, float* __restrict__ pl)
{
    __shared__ __half Qs[BQ][QPITCH];
    __shared__ __half Kt[BK][QPITCH];
    __shared__ __half Vt[DHEAD][VPITCH];
    const int tid = threadIdx.x;
    const int warp = tid >> 5;
    const int lane = tid & 31;
    const int g = lane >> 2;
    const int tig = lane & 3;
    const int b = blockIdx.z, h = blockIdx.y;
    const int tile = blockIdx.x / SPLITS;
    const int split = blockIdx.x % SPLITS;
    const int q0 = tile * BQ;
    const int qbase = warp * 16;
    const int kstart = split * KCHUNK;
    const int kend = min(kstart + KCHUNK, S_LEN);

    #pragma unroll
    for (int idx = tid; idx < BQ * 4; idx += 256) {
        int r = idx >> 2, quad = idx & 3;
        int q = q0 + r;
        uint4 v = make_uint4(0u, 0u, 0u, 0u);
        if (q < S_LEN)
            v = *reinterpret_cast<const uint4*>(
                qkv + ((size_t)(b * S_LEN + q)) * 384 + h * 32 + quad * 8);
        *reinterpret_cast<uint4*>(&Qs[r][quad * 8]) = v;
    }

    float m0 = -1e30f, m1 = -1e30f, l0 = 0.f, l1 = 0.f;
    float o[4][4] = {};
    __syncthreads();

    for (int kb = kstart; kb < kend; kb += BK) {
        {
            int r = tid >> 2, quad = tid & 3;
            int kg = kb + r;
            uint4 v = make_uint4(0u, 0u, 0u, 0u);
            if (kg < S_LEN)
                v = *reinterpret_cast<const uint4*>(
                    qkv + ((size_t)(b * S_LEN + kg)) * 384 + 128 + h * 32 + quad * 8);
            *reinterpret_cast<uint4*>(&Kt[r][quad * 8]) = v;
        }
        #pragma unroll
        for (int idx = tid; idx < BK * 16; idx += 256) {
            int kl = idx >> 4, dp = idx & 15;
            int kg = kb + kl;
            __half2 hv = __float2half2_rn(0.f);
            if (kg < S_LEN)
                hv = *reinterpret_cast<const __half2*>(
                    qkv + ((size_t)(b * S_LEN + kg)) * 384 + 256 + h * 32 + dp * 2);
            Vt[dp * 2 + 0][kl] = __low2half(hv);
            Vt[dp * 2 + 1][kl] = __high2half(hv);
        }
        __syncthreads();

        unsigned A[2][4];
        #pragma unroll
        for (int ks = 0; ks < 2; ks++) {
            A[ks][0] = *reinterpret_cast<const unsigned*>(&Qs[qbase + g    ][ks * 16 + tig * 2]);
            A[ks][1] = *reinterpret_cast<const unsigned*>(&Qs[qbase + g + 8][ks * 16 + tig * 2]);
            A[ks][2] = *reinterpret_cast<const unsigned*>(&Qs[qbase + g    ][ks * 16 + tig * 2 + 8]);
            A[ks][3] = *reinterpret_cast<const unsigned*>(&Qs[qbase + g + 8][ks * 16 + tig * 2 + 8]);
        }
        float s[8][4];
        #pragma unroll
        for (int j = 0; j < 8; j++) {
            s[j][0] = s[j][1] = s[j][2] = s[j][3] = 0.f;
            #pragma unroll
            for (int ks = 0; ks < 2; ks++) {
                unsigned bfr[2];
                bfr[0] = *reinterpret_cast<const unsigned*>(&Kt[j * 8 + g][ks * 16 + tig * 2]);
                bfr[1] = *reinterpret_cast<const unsigned*>(&Kt[j * 8 + g][ks * 16 + tig * 2 + 8]);
                mma16816(s[j], A[ks], bfr);
            }
        }
        if (kb + BK > S_LEN) {
            #pragma unroll
            for (int j = 0; j < 8; j++) {
                int key = kb + j * 8 + tig * 2;
                if (key >= S_LEN)     { s[j][0] = -1e30f; s[j][2] = -1e30f; }
                if (key + 1 >= S_LEN) { s[j][1] = -1e30f; s[j][3] = -1e30f; }
            }
        }

        float t0 = -1e30f, t1 = -1e30f;
        #pragma unroll
        for (int j = 0; j < 8; j++) {
            t0 = fmaxf(t0, fmaxf(s[j][0], s[j][1]));
            t1 = fmaxf(t1, fmaxf(s[j][2], s[j][3]));
        }
        t0 = fmaxf(t0, __shfl_xor_sync(0xffffffffu, t0, 1));
        t0 = fmaxf(t0, __shfl_xor_sync(0xffffffffu, t0, 2));
        t1 = fmaxf(t1, __shfl_xor_sync(0xffffffffu, t1, 1));
        t1 = fmaxf(t1, __shfl_xor_sync(0xffffffffu, t1, 2));
        float mn0 = fmaxf(m0, t0), mn1 = fmaxf(m1, t1);
        float c0 = __expf(m0 - mn0), c1 = __expf(m1 - mn1);
        unsigned ph[8][2];
        float ps0 = 0.f, ps1 = 0.f;
        #pragma unroll
        for (int j = 0; j < 8; j++) {
            __half2 h2a = __floats2half2_rn(__expf(s[j][0] - mn0), __expf(s[j][1] - mn0));
            __half2 h2b = __floats2half2_rn(__expf(s[j][2] - mn1), __expf(s[j][3] - mn1));
            ph[j][0] = *reinterpret_cast<unsigned*>(&h2a);
            ph[j][1] = *reinterpret_cast<unsigned*>(&h2b);
            float2 fa = __half22float2(h2a);
            float2 fb = __half22float2(h2b);
            ps0 += fa.x + fa.y;
            ps1 += fb.x + fb.y;
        }
        ps0 += __shfl_xor_sync(0xffffffffu, ps0, 1);
        ps0 += __shfl_xor_sync(0xffffffffu, ps0, 2);
        ps1 += __shfl_xor_sync(0xffffffffu, ps1, 1);
        ps1 += __shfl_xor_sync(0xffffffffu, ps1, 2);
        l0 = l0 * c0 + ps0;
        l1 = l1 * c1 + ps1;
        m0 = mn0; m1 = mn1;
        #pragma unroll
        for (int nt = 0; nt < 4; nt++) {
            o[nt][0] *= c0; o[nt][1] *= c0;
            o[nt][2] *= c1; o[nt][3] *= c1;
        }

        #pragma unroll
        for (int kt = 0; kt < 4; kt++) {
            unsigned pa[4] = { ph[2 * kt][0], ph[2 * kt][1],
                               ph[2 * kt + 1][0], ph[2 * kt + 1][1] };
            #pragma unroll
            for (int nt = 0; nt < 4; nt++) {
                unsigned bfr[2];
                bfr[0] = *reinterpret_cast<const unsigned*>(&Vt[nt * 8 + g][kt * 16 + tig * 2]);
                bfr[1] = *reinterpret_cast<const unsigned*>(&Vt[nt * 8 + g][kt * 16 + tig * 2 + 8]);
                mma16816(o[nt], pa, bfr);
            }
        }
        __syncthreads();
    }

    // ---- write partials (unnormalized acc, m, l) ----
    const size_t pbase = (((size_t)split * BATCH + b) * N_HEADS + h) * S_LEN;
    int qa = q0 + qbase + g;
    int qb2 = qa + 8;
    if (qa < S_LEN) {
        #pragma unroll
        for (int nt = 0; nt < 4; nt++) {
            float2 v = make_float2(o[nt][0], o[nt][1]);
            *reinterpret_cast<float2*>(po + (pbase + qa) * DHEAD + nt * 8 + tig * 2) = v;
        }
        if (tig == 0) { pm[pbase + qa] = m0; pl[pbase + qa] = l0; }
    }
    if (qb2 < S_LEN) {
        #pragma unroll
        for (int nt = 0; nt < 4; nt++) {
            float2 v = make_float2(o[nt][2], o[nt][3]);
            *reinterpret_cast<float2*>(po + (pbase + qb2) * DHEAD + nt * 8 + tig * 2) = v;
        }
        if (tig == 0) { pm[pbase + qb2] = m1; pl[pbase + qb2] = l1; }
    }
}

// ---------------- merge split-S partials -> fp16 ----------------
__global__ __launch_bounds__(128) void attn_merge_kernel(
    const float* __restrict__ po, const float* __restrict__ pm,
    const float* __restrict__ pl, __half* __restrict__ out)
{
    const int q = blockIdx.x, b = blockIdx.y;
    const int d = threadIdx.x;
    const int h = d >> 5, dd = d & 31;
    const size_t row = ((size_t)b * N_HEADS + h) * S_LEN + q;
    const size_t stride = (size_t)BATCH * N_HEADS * S_LEN;
    float ms[SPLITS], ls[SPLITS];
    float M = -1e30f;
    #pragma unroll
    for (int s = 0; s < SPLITS; s++) {
        ms[s] = pm[row + s * stride];
        ls[s] = pl[row + s * stride];
        M = fmaxf(M, ms[s]);
    }
    float L = 0.f, O = 0.f;
    #pragma unroll
    for (int s = 0; s < SPLITS; s++) {
        float w = __expf(ms[s] - M);
        L += w * ls[s];
        O += w * po[(row + s * stride) * DHEAD + dd];
    }
    out[((size_t)b * S_LEN + q) * D_MODEL + d] = __float2half_rn(O / L);
}

// ---------------- head ----------------
__global__ __launch_bounds__(64) void head_kernel(
    const float* __restrict__ h, const float* __restrict__ ls,
    const float* __restrict__ lb, const float* __restrict__ hw,
    const float* __restrict__ hb, float* __restrict__ out)
{
    int bidx = threadIdx.x >> 5;
    if (bidx >= BATCH) return;
    int lane = threadIdx.x & 31;
    const float* xr = h + (size_t)bidx * S_LEN * D_MODEL;
    float4 v = *reinterpret_cast<const float4*>(xr + lane * 4);
    float sum = v.x + v.y + v.z + v.w;
    #pragma unroll
    for (int o = 16; o; o >>= 1) sum += __shfl_xor_sync(0xffffffffu, sum, o);
    float mean = sum * (1.f / 128.f);
    float dx = v.x - mean, dy = v.y - mean, dz = v.z - mean, dw = v.w - mean;
    float vs = dx * dx + dy * dy + dz * dz + dw * dw;
    #pragma unroll
    for (int o = 16; o; o >>= 1) vs += __shfl_xor_sync(0xffffffffu, vs, o);
    float rstd = rsqrtf(vs * (1.f / 128.f) + 1e-5f);
    float4 s4 = *reinterpret_cast<const float4*>(ls + lane * 4);
    float4 b4 = *reinterpret_cast<const float4*>(lb + lane * 4);
    float4 w4 = *reinterpret_cast<const float4*>(hw + lane * 4);
    float dot = (dx * rstd * s4.x + b4.x) * w4.x
              + (dy * rstd * s4.y + b4.y) * w4.y
              + (dz * rstd * s4.z + b4.z) * w4.z
              + (dw * rstd * s4.w + b4.w) * w4.w;
    #pragma unroll
    for (int o = 16; o; o >>= 1) dot += __shfl_xor_sync(0xffffffffu, dot, o);
    if (lane == 0) out[bidx] = dot + hb[0];
}

// ---------------- launch ----------------
extern "C" void kernel_launch(void* const* d_in, const int* in_sizes, int n_in,
                              void* d_out, int out_size)
{
    const float* x        = (const float*)d_in[0];
    const float* embed_w  = (const float*)d_in[1];
    const float* embed_b  = (const float*)d_in[2];
    const float* pos_emb  = (const float*)d_in[3];
    const float* cls      = (const float*)d_in[4];
    const float* in_w     = (const float*)d_in[5];
    const float* in_b     = (const float*)d_in[6];
    const float* out_w    = (const float*)d_in[7];
    const float* out_b    = (const float*)d_in[8];
    const float* ln1_s    = (const float*)d_in[9];
    const float* ln1_b    = (const float*)d_in[10];
    const float* ln2_s    = (const float*)d_in[11];
    const float* ln2_b    = (const float*)d_in[12];
    const float* ff1_w    = (const float*)d_in[13];
    const float* ff1_b    = (const float*)d_in[14];
    const float* ff2_w    = (const float*)d_in[15];
    const float* ff2_b    = (const float*)d_in[16];
    const float* hln_s    = (const float*)d_in[17];
    const float* hln_b    = (const float*)d_in[18];
    const float* head_w   = (const float*)d_in[19];
    const float* head_b   = (const float*)d_in[20];
    float* outp = (float*)d_out;

    float *h, *po, *pm, *pl;
    __half *hnh, *qkvh, *attnh, *ffh;
    cudaGetSymbolAddress((void**)&h,     g_h);
    cudaGetSymbolAddress((void**)&hnh,   g_hnh);
    cudaGetSymbolAddress((void**)&qkvh,  g_qkvh);
    cudaGetSymbolAddress((void**)&attnh, g_attnh);
    cudaGetSymbolAddress((void**)&ffh,   g_ffh);
    cudaGetSymbolAddress((void**)&po,    g_po);
    cudaGetSymbolAddress((void**)&pm,    g_pm);
    cudaGetSymbolAddress((void**)&pl,    g_pl);

    embed_kernel<<<dim3(S_LEN, BATCH), 128>>>(x, embed_w, embed_b, pos_emb, cls, h);

    const int M = MROWS;
    const int MB128 = (M + 127) / 128;
    const int MB64  = (M + 63) / 64;
    const int QTILES = (S_LEN + BQ - 1) / BQ;
    dim3 lnGrid((M + 7) / 8);

    for (int i = 0; i < NL; i++) {
        ln_kernel<<<lnGrid, 256>>>(h, ln1_s + i * D_MODEL, ln1_b + i * D_MODEL, hnh, M);
        // QKV projection -> fp16 (Q pre-scaled)
        hgemm_kernel<128, false, false, true, true><<<dim3(384 / 64, MB128), 256>>>(
            hnh, in_w + (size_t)i * 384 * 128, in_b + (size_t)i * 384,
            nullptr, qkvh, M, 384, 128);
        // split-S attention + merge
        attn_kernel<<<dim3(QTILES * SPLITS, N_HEADS, BATCH), 256>>>(qkvh, po, pm, pl);
        attn_merge_kernel<<<dim3(S_LEN, BATCH), 128>>>(po, pm, pl, attnh);
        // out projection + residual -> fp32 h   (64-row tiles: grid 2x65)
        hgemm_kernel<64, false, true, false, false><<<dim3(128 / 64, MB64), 256>>>(
            attnh, out_w + (size_t)i * 128 * 128, out_b + (size_t)i * 128,
            h, h, M, 128, 128);
        ln_kernel<<<lnGrid, 256>>>(h, ln2_s + i * D_MODEL, ln2_b + i * D_MODEL, hnh, M);
        // FF1 + ReLU -> fp16
        hgemm_kernel<128, true, false, true, false><<<dim3(512 / 64, MB128), 256>>>(
            hnh, ff1_w + (size_t)i * 512 * 128, ff1_b + (size_t)i * 512,
            nullptr, ffh, M, 512, 128);
        // FF2 + residual -> fp32 h   (64-row tiles)
        hgemm_kernel<64, false, true, false, false><<<dim3(128 / 64, MB64), 256>>>(
            ffh, ff2_w + (size_t)i * 128 * 512, ff2_b + (size_t)i * 128,
            h, h, M, 128, 512);
    }

    head_kernel<<<1, 64>>>(h, hln_s, hln_b, head_w, head_b, outp);
}

// round 7
// speedup vs baseline: 3.9976x; 1.0368x over previous
#include <cuda_runtime.h>
#include <cuda_fp16.h>
#include <math.h>

#define NL 3
#define D_MODEL 128
#define N_HEADS 4
#define DHEAD 32
#define DFF 512
#define DIN 64
#define BATCH 2
#define LSEQ 2048
#define S_LEN 2049
#define MROWS (BATCH * S_LEN)   // 4098
#define QK_SCALE 0.17677669529663687f

#define SPLITS 4
#define KCHUNK 576

// ---------------- scratch (device globals; no allocation) ----------------
__device__ float  g_h[MROWS * D_MODEL];
__device__ __half g_hnh[MROWS * D_MODEL];
__device__ __half g_qkvh[MROWS * 3 * D_MODEL];
__device__ __half g_attnh[MROWS * D_MODEL];
__device__ __half g_ffh[MROWS * DFF];
__device__ float  g_po[SPLITS * BATCH * N_HEADS * S_LEN * DHEAD];
__device__ float  g_pm[SPLITS * BATCH * N_HEADS * S_LEN];
__device__ float  g_pl[SPLITS * BATCH * N_HEADS * S_LEN];

// ---------------- mma helper ----------------
__device__ __forceinline__ void mma16816(
    float c[4], const unsigned a[4], const unsigned b[2])
{
    asm volatile(
        "mma.sync.aligned.m16n8k16.row.col.f32.f16.f16.f32 "
        "{%0,%1,%2,%3}, {%4,%5,%6,%7}, {%8,%9}, {%0,%1,%2,%3};\n"
        : "+f"(c[0]), "+f"(c[1]), "+f"(c[2]), "+f"(c[3])
        : "r"(a[0]), "r"(a[1]), "r"(a[2]), "r"(a[3]),
          "r"(b[0]), "r"(b[1]));
}

// ---------------- embedding + fused LN1(layer0) ----------------
__global__ __launch_bounds__(128) void embed_ln_kernel(
    const float* __restrict__ x, const float* __restrict__ ew,
    const float* __restrict__ eb, const float* __restrict__ pos,
    const float* __restrict__ cls, const float* __restrict__ lns,
    const float* __restrict__ lnb, float* __restrict__ h,
    __half* __restrict__ hn)
{
    __shared__ float xs[DIN];
    __shared__ float red[8];
    int s = blockIdx.x, b = blockIdx.y;
    int d = threadIdx.x;
    if (s > 0 && d < DIN) xs[d] = x[((size_t)b * LSEQ + (s - 1)) * DIN + d];
    __syncthreads();
    float val;
    if (s == 0) {
        val = cls[d] + pos[d];
    } else {
        float acc = 0.f;
        const float* wr = ew + (size_t)d * DIN;
        #pragma unroll
        for (int j = 0; j < DIN; j++) acc = fmaf(xs[j], wr[j], acc);
        val = acc + eb[d] + pos[(size_t)s * D_MODEL + d];
    }
    size_t row = (size_t)b * S_LEN + s;
    h[row * D_MODEL + d] = val;
    // LN across the 128 threads
    int w = d >> 5, lane = d & 31;
    float sv = val, qv = val * val;
    #pragma unroll
    for (int o = 16; o; o >>= 1) {
        sv += __shfl_xor_sync(0xffffffffu, sv, o);
        qv += __shfl_xor_sync(0xffffffffu, qv, o);
    }
    if (lane == 0) { red[w] = sv; red[4 + w] = qv; }
    __syncthreads();
    float sum = red[0] + red[1] + red[2] + red[3];
    float sq  = red[4] + red[5] + red[6] + red[7];
    float mean = sum * (1.f / 128.f);
    float rstd = rsqrtf(sq * (1.f / 128.f) - mean * mean + 1e-5f);
    hn[row * D_MODEL + d] = __float2half_rn((val - mean) * rstd * lns[d] + lnb[d]);
}

// ---------------- tensor-core GEMM (128x64 tile, reg-prefetch) ----------
// C[M,N](fp16) = A[M,K](fp16) . W[N,K](fp32->fp16)^T + bias (ReLU?/QSCALE?)
#define GPITCH 40
template <bool RELU, bool QSCALE>
__global__ __launch_bounds__(256) void hgemm_kernel(
    const __half* __restrict__ A, const float* __restrict__ W,
    const float* __restrict__ bias, __half* __restrict__ C,
    int M, int N, int K)
{
    __shared__ __half As[128][GPITCH];
    __shared__ __half Ws[64][GPITCH];
    const int tid = threadIdx.x;
    const int warp = tid >> 5;
    const int lane = tid & 31;
    const int g = lane >> 2;
    const int tig = lane & 3;
    const int warp_m = warp >> 1;
    const int warp_n = warp & 1;
    const int m0 = blockIdx.y * 128;
    const int n0 = blockIdx.x * 64;
    const int NK = K / 32;

    float c[2][4][4] = {};

    // prefetch k-tile 0
    uint4 aReg[2];
    float4 wReg[2];
    #pragma unroll
    for (int it = 0; it < 2; it++) {
        int idx = tid + it * 256;
        int r = idx >> 2, quad = idx & 3;
        int m = m0 + r;
        aReg[it] = (m < M)
            ? *reinterpret_cast<const uint4*>(A + (size_t)m * K + quad * 8)
            : make_uint4(0u, 0u, 0u, 0u);
    }
    #pragma unroll
    for (int it = 0; it < 2; it++) {
        int idx = tid + it * 256;
        int r = idx >> 3, q = idx & 7;
        wReg[it] = *reinterpret_cast<const float4*>(W + (size_t)(n0 + r) * K + q * 4);
    }

    for (int kt = 0; kt < NK; kt++) {
        // store staged tile
        #pragma unroll
        for (int it = 0; it < 2; it++) {
            int idx = tid + it * 256;
            int r = idx >> 2, quad = idx & 3;
            *reinterpret_cast<uint4*>(&As[r][quad * 8]) = aReg[it];
        }
        #pragma unroll
        for (int it = 0; it < 2; it++) {
            int idx = tid + it * 256;
            int r = idx >> 3, q = idx & 7;
            __half2 h2a = __floats2half2_rn(wReg[it].x, wReg[it].y);
            __half2 h2b = __floats2half2_rn(wReg[it].z, wReg[it].w);
            uint2 pk;
            pk.x = *reinterpret_cast<unsigned*>(&h2a);
            pk.y = *reinterpret_cast<unsigned*>(&h2b);
            *reinterpret_cast<uint2*>(&Ws[r][q * 4]) = pk;
        }
        __syncthreads();
        // prefetch next k-tile
        if (kt + 1 < NK) {
            int k0 = (kt + 1) * 32;
            #pragma unroll
            for (int it = 0; it < 2; it++) {
                int idx = tid + it * 256;
                int r = idx >> 2, quad = idx & 3;
                int m = m0 + r;
                aReg[it] = (m < M)
                    ? *reinterpret_cast<const uint4*>(A + (size_t)m * K + k0 + quad * 8)
                    : make_uint4(0u, 0u, 0u, 0u);
            }
            #pragma unroll
            for (int it = 0; it < 2; it++) {
                int idx = tid + it * 256;
                int r = idx >> 3, q = idx & 7;
                wReg[it] = *reinterpret_cast<const float4*>(
                    W + (size_t)(n0 + r) * K + k0 + q * 4);
            }
        }
        #pragma unroll
        for (int ks = 0; ks < 2; ks++) {
            unsigned a[2][4];
            #pragma unroll
            for (int mt = 0; mt < 2; mt++) {
                int rbase = warp_m * 32 + mt * 16;
                a[mt][0] = *reinterpret_cast<const unsigned*>(&As[rbase + g    ][ks * 16 + tig * 2]);
                a[mt][1] = *reinterpret_cast<const unsigned*>(&As[rbase + g + 8][ks * 16 + tig * 2]);
                a[mt][2] = *reinterpret_cast<const unsigned*>(&As[rbase + g    ][ks * 16 + tig * 2 + 8]);
                a[mt][3] = *reinterpret_cast<const unsigned*>(&As[rbase + g + 8][ks * 16 + tig * 2 + 8]);
            }
            #pragma unroll
            for (int nt = 0; nt < 4; nt++) {
                unsigned bfr[2];
                int nrow = warp_n * 32 + nt * 8 + g;
                bfr[0] = *reinterpret_cast<const unsigned*>(&Ws[nrow][ks * 16 + tig * 2]);
                bfr[1] = *reinterpret_cast<const unsigned*>(&Ws[nrow][ks * 16 + tig * 2 + 8]);
                mma16816(c[0][nt], a[0], bfr);
                mma16816(c[1][nt], a[1], bfr);
            }
        }
        __syncthreads();
    }

    #pragma unroll
    for (int mt = 0; mt < 2; mt++) {
        #pragma unroll
        for (int half_row = 0; half_row < 2; half_row++) {
            int m = m0 + warp_m * 32 + mt * 16 + g + half_row * 8;
            if (m >= M) continue;
            #pragma unroll
            for (int nt = 0; nt < 4; nt++) {
                int n = n0 + warp_n * 32 + nt * 8 + tig * 2;
                float v0 = c[mt][nt][half_row * 2 + 0] + bias[n];
                float v1 = c[mt][nt][half_row * 2 + 1] + bias[n + 1];
                if (RELU) { v0 = fmaxf(v0, 0.f); v1 = fmaxf(v1, 0.f); }
                if (QSCALE && n < 128) { v0 *= QK_SCALE; v1 *= QK_SCALE; }
                __half2 hv = __floats2half2_rn(v0, v1);
                *reinterpret_cast<unsigned*>(
                    C + (size_t)m * N + n) = *reinterpret_cast<unsigned*>(&hv);
            }
        }
    }
}

// ---------------- GEMM + residual + fused row-LN (N=128 fixed) ----------
// h[M,128] += A(fp16).W^T + bias ; hn = LN(h) (fp16).  Tile 32x128, grid=M/32.
template <bool DO_LN>
__global__ __launch_bounds__(256) void hgemm_ln_kernel(
    const __half* __restrict__ A, const float* __restrict__ W,
    const float* __restrict__ bias,
    const float* __restrict__ lns, const float* __restrict__ lnb,
    float* __restrict__ h, __half* __restrict__ hn, int M, int K)
{
    __shared__ __half As[32][GPITCH];
    __shared__ __half Ws[128][GPITCH];
    __shared__ float psum[32][4], psq[32][4];
    const int tid = threadIdx.x;
    const int warp = tid >> 5;
    const int lane = tid & 31;
    const int g = lane >> 2;
    const int tig = lane & 3;
    const int warp_m = warp >> 2;   // 0..1
    const int warp_n = warp & 3;    // 0..3
    const int m0 = blockIdx.x * 32;
    const int NK = K / 32;

    float c[4][4] = {};   // [nt][row0 c0,c1, row1 c0,c1]

    // prefetch k-tile 0
    const bool aAct = tid < 128;
    const int ar = tid >> 2, aq = tid & 3;
    uint4 aReg = make_uint4(0u, 0u, 0u, 0u);
    if (aAct) {
        int m = m0 + ar;
        if (m < M) aReg = *reinterpret_cast<const uint4*>(A + (size_t)m * K + aq * 8);
    }
    float4 wReg[4];
    #pragma unroll
    for (int it = 0; it < 4; it++) {
        int idx = tid + it * 256;
        int r = idx >> 3, q = idx & 7;
        wReg[it] = *reinterpret_cast<const float4*>(W + (size_t)r * K + q * 4);
    }

    for (int kt = 0; kt < NK; kt++) {
        if (aAct) *reinterpret_cast<uint4*>(&As[ar][aq * 8]) = aReg;
        #pragma unroll
        for (int it = 0; it < 4; it++) {
            int idx = tid + it * 256;
            int r = idx >> 3, q = idx & 7;
            __half2 h2a = __floats2half2_rn(wReg[it].x, wReg[it].y);
            __half2 h2b = __floats2half2_rn(wReg[it].z, wReg[it].w);
            uint2 pk;
            pk.x = *reinterpret_cast<unsigned*>(&h2a);
            pk.y = *reinterpret_cast<unsigned*>(&h2b);
            *reinterpret_cast<uint2*>(&Ws[r][q * 4]) = pk;
        }
        __syncthreads();
        if (kt + 1 < NK) {
            int k0 = (kt + 1) * 32;
            if (aAct) {
                int m = m0 + ar;
                aReg = (m < M)
                    ? *reinterpret_cast<const uint4*>(A + (size_t)m * K + k0 + aq * 8)
                    : make_uint4(0u, 0u, 0u, 0u);
            }
            #pragma unroll
            for (int it = 0; it < 4; it++) {
                int idx = tid + it * 256;
                int r = idx >> 3, q = idx & 7;
                wReg[it] = *reinterpret_cast<const float4*>(W + (size_t)r * K + k0 + q * 4);
            }
        }
        #pragma unroll
        for (int ks = 0; ks < 2; ks++) {
            unsigned a[4];
            int rbase = warp_m * 16;
            a[0] = *reinterpret_cast<const unsigned*>(&As[rbase + g    ][ks * 16 + tig * 2]);
            a[1] = *reinterpret_cast<const unsigned*>(&As[rbase + g + 8][ks * 16 + tig * 2]);
            a[2] = *reinterpret_cast<const unsigned*>(&As[rbase + g    ][ks * 16 + tig * 2 + 8]);
            a[3] = *reinterpret_cast<const unsigned*>(&As[rbase + g + 8][ks * 16 + tig * 2 + 8]);
            #pragma unroll
            for (int nt = 0; nt < 4; nt++) {
                unsigned bfr[2];
                int nrow = warp_n * 32 + nt * 8 + g;
                bfr[0] = *reinterpret_cast<const unsigned*>(&Ws[nrow][ks * 16 + tig * 2]);
                bfr[1] = *reinterpret_cast<const unsigned*>(&Ws[nrow][ks * 16 + tig * 2 + 8]);
                mma16816(c[nt], a, bfr);
            }
        }
        __syncthreads();
    }

    // epilogue: bias + residual, write h
    const int lr0 = warp_m * 16 + g, lr1 = lr0 + 8;
    const int mrow0 = m0 + lr0, mrow1 = m0 + lr1;
    #pragma unroll
    for (int nt = 0; nt < 4; nt++) {
        int n = warp_n * 32 + nt * 8 + tig * 2;
        float b0 = bias[n], b1 = bias[n + 1];
        if (mrow0 < M) {
            float2 r2 = *reinterpret_cast<const float2*>(h + (size_t)mrow0 * 128 + n);
            c[nt][0] += b0 + r2.x;
            c[nt][1] += b1 + r2.y;
            *reinterpret_cast<float2*>(h + (size_t)mrow0 * 128 + n) =
                make_float2(c[nt][0], c[nt][1]);
        }
        if (mrow1 < M) {
            float2 r2 = *reinterpret_cast<const float2*>(h + (size_t)mrow1 * 128 + n);
            c[nt][2] += b0 + r2.x;
            c[nt][3] += b1 + r2.y;
            *reinterpret_cast<float2*>(h + (size_t)mrow1 * 128 + n) =
                make_float2(c[nt][2], c[nt][3]);
        }
    }
    if (DO_LN) {
        float s0 = 0.f, q0 = 0.f, s1 = 0.f, q1 = 0.f;
        #pragma unroll
        for (int nt = 0; nt < 4; nt++) {
            s0 += c[nt][0] + c[nt][1];
            q0 += c[nt][0] * c[nt][0] + c[nt][1] * c[nt][1];
            s1 += c[nt][2] + c[nt][3];
            q1 += c[nt][2] * c[nt][2] + c[nt][3] * c[nt][3];
        }
        #pragma unroll
        for (int o = 1; o < 4; o <<= 1) {
            s0 += __shfl_xor_sync(0xffffffffu, s0, o);
            q0 += __shfl_xor_sync(0xffffffffu, q0, o);
            s1 += __shfl_xor_sync(0xffffffffu, s1, o);
            q1 += __shfl_xor_sync(0xffffffffu, q1, o);
        }
        if (tig == 0) {
            psum[lr0][warp_n] = s0; psq[lr0][warp_n] = q0;
            psum[lr1][warp_n] = s1; psq[lr1][warp_n] = q1;
        }
        __syncthreads();
        float sum0 = psum[lr0][0] + psum[lr0][1] + psum[lr0][2] + psum[lr0][3];
        float sq0  = psq[lr0][0] + psq[lr0][1] + psq[lr0][2] + psq[lr0][3];
        float sum1 = psum[lr1][0] + psum[lr1][1] + psum[lr1][2] + psum[lr1][3];
        float sq1  = psq[lr1][0] + psq[lr1][1] + psq[lr1][2] + psq[lr1][3];
        float mean0 = sum0 * (1.f / 128.f);
        float rstd0 = rsqrtf(sq0 * (1.f / 128.f) - mean0 * mean0 + 1e-5f);
        float mean1 = sum1 * (1.f / 128.f);
        float rstd1 = rsqrtf(sq1 * (1.f / 128.f) - mean1 * mean1 + 1e-5f);
        #pragma unroll
        for (int nt = 0; nt < 4; nt++) {
            int n = warp_n * 32 + nt * 8 + tig * 2;
            float g0 = lns[n], g1 = lns[n + 1];
            float bb0 = lnb[n], bb1 = lnb[n + 1];
            if (mrow0 < M) {
                __half2 hv = __floats2half2_rn(
                    (c[nt][0] - mean0) * rstd0 * g0 + bb0,
                    (c[nt][1] - mean0) * rstd0 * g1 + bb1);
                *reinterpret_cast<unsigned*>(hn + (size_t)mrow0 * 128 + n)
                    = *reinterpret_cast<unsigned*>(&hv);
            }
            if (mrow1 < M) {
                __half2 hv = __floats2half2_rn(
                    (c[nt][2] - mean1) * rstd1 * g0 + bb0,
                    (c[nt][3] - mean1) * rstd1 * g1 + bb1);
                *reinterpret_cast<unsigned*>(hn + (size_t)mrow1 * 128 + n)
                    = *reinterpret_cast<unsigned*>(&hv);
            }
        }
    }
}

// ---------------- split-S tensor-core flash attention ----------------
#define BQ 128
#define BK 64
#define QPITCH 40
#define VPITCH 72

__global__ __launch_bounds__(256) void attn_kernel(
    const __half* __restrict__ qkv,
    float* __restrict__ po, float* __restrict__ pm, float* __restrict__ pl)
{
    __shared__ __half Qs[BQ][QPITCH];
    __shared__ __half Kt[BK][QPITCH];
    __shared__ __half Vt[DHEAD][VPITCH];
    const int tid = threadIdx.x;
    const int warp = tid >> 5;
    const int lane = tid & 31;
    const int g = lane >> 2;
    const int tig = lane & 3;
    const int b = blockIdx.z, h = blockIdx.y;
    const int tile = blockIdx.x / SPLITS;
    const int split = blockIdx.x % SPLITS;
    const int q0 = tile * BQ;
    const int qbase = warp * 16;
    const int kstart = split * KCHUNK;
    const int kend = min(kstart + KCHUNK, S_LEN);

    #pragma unroll
    for (int idx = tid; idx < BQ * 4; idx += 256) {
        int r = idx >> 2, quad = idx & 3;
        int q = q0 + r;
        uint4 v = make_uint4(0u, 0u, 0u, 0u);
        if (q < S_LEN)
            v = *reinterpret_cast<const uint4*>(
                qkv + ((size_t)(b * S_LEN + q)) * 384 + h * 32 + quad * 8);
        *reinterpret_cast<uint4*>(&Qs[r][quad * 8]) = v;
    }

    float m0 = -1e30f, m1 = -1e30f, l0 = 0.f, l1 = 0.f;
    float o[4][4] = {};
    __syncthreads();

    for (int kb = kstart; kb < kend; kb += BK) {
        {
            int r = tid >> 2, quad = tid & 3;
            int kg = kb + r;
            uint4 v = make_uint4(0u, 0u, 0u, 0u);
            if (kg < S_LEN)
                v = *reinterpret_cast<const uint4*>(
                    qkv + ((size_t)(b * S_LEN + kg)) * 384 + 128 + h * 32 + quad * 8);
            *reinterpret_cast<uint4*>(&Kt[r][quad * 8]) = v;
        }
        #pragma unroll
        for (int idx = tid; idx < BK * 16; idx += 256) {
            int kl = idx >> 4, dp = idx & 15;
            int kg = kb + kl;
            __half2 hv = __float2half2_rn(0.f);
            if (kg < S_LEN)
                hv = *reinterpret_cast<const __half2*>(
                    qkv + ((size_t)(b * S_LEN + kg)) * 384 + 256 + h * 32 + dp * 2);
            Vt[dp * 2 + 0][kl] = __low2half(hv);
            Vt[dp * 2 + 1][kl] = __high2half(hv);
        }
        __syncthreads();

        unsigned A[2][4];
        #pragma unroll
        for (int ks = 0; ks < 2; ks++) {
            A[ks][0] = *reinterpret_cast<const unsigned*>(&Qs[qbase + g    ][ks * 16 + tig * 2]);
            A[ks][1] = *reinterpret_cast<const unsigned*>(&Qs[qbase + g + 8][ks * 16 + tig * 2]);
            A[ks][2] = *reinterpret_cast<const unsigned*>(&Qs[qbase + g    ][ks * 16 + tig * 2 + 8]);
            A[ks][3] = *reinterpret_cast<const unsigned*>(&Qs[qbase + g + 8][ks * 16 + tig * 2 + 8]);
        }
        float s[8][4];
        #pragma unroll
        for (int j = 0; j < 8; j++) {
            s[j][0] = s[j][1] = s[j][2] = s[j][3] = 0.f;
            #pragma unroll
            for (int ks = 0; ks < 2; ks++) {
                unsigned bfr[2];
                bfr[0] = *reinterpret_cast<const unsigned*>(&Kt[j * 8 + g][ks * 16 + tig * 2]);
                bfr[1] = *reinterpret_cast<const unsigned*>(&Kt[j * 8 + g][ks * 16 + tig * 2 + 8]);
                mma16816(s[j], A[ks], bfr);
            }
        }
        if (kb + BK > S_LEN) {
            #pragma unroll
            for (int j = 0; j < 8; j++) {
                int key = kb + j * 8 + tig * 2;
                if (key >= S_LEN)     { s[j][0] = -1e30f; s[j][2] = -1e30f; }
                if (key + 1 >= S_LEN) { s[j][1] = -1e30f; s[j][3] = -1e30f; }
            }
        }

        float t0 = -1e30f, t1 = -1e30f;
        #pragma unroll
        for (int j = 0; j < 8; j++) {
            t0 = fmaxf(t0, fmaxf(s[j][0], s[j][1]));
            t1 = fmaxf(t1, fmaxf(s[j][2], s[j][3]));
        }
        t0 = fmaxf(t0, __shfl_xor_sync(0xffffffffu, t0, 1));
        t0 = fmaxf(t0, __shfl_xor_sync(0xffffffffu, t0, 2));
        t1 = fmaxf(t1, __shfl_xor_sync(0xffffffffu, t1, 1));
        t1 = fmaxf(t1, __shfl_xor_sync(0xffffffffu, t1, 2));
        float mn0 = fmaxf(m0, t0), mn1 = fmaxf(m1, t1);
        float c0 = __expf(m0 - mn0), c1 = __expf(m1 - mn1);
        unsigned ph[8][2];
        float ps0 = 0.f, ps1 = 0.f;
        #pragma unroll
        for (int j = 0; j < 8; j++) {
            __half2 h2a = __floats2half2_rn(__expf(s[j][0] - mn0), __expf(s[j][1] - mn0));
            __half2 h2b = __floats2half2_rn(__expf(s[j][2] - mn1), __expf(s[j][3] - mn1));
            ph[j][0] = *reinterpret_cast<unsigned*>(&h2a);
            ph[j][1] = *reinterpret_cast<unsigned*>(&h2b);
            float2 fa = __half22float2(h2a);
            float2 fb = __half22float2(h2b);
            ps0 += fa.x + fa.y;
            ps1 += fb.x + fb.y;
        }
        ps0 += __shfl_xor_sync(0xffffffffu, ps0, 1);
        ps0 += __shfl_xor_sync(0xffffffffu, ps0, 2);
        ps1 += __shfl_xor_sync(0xffffffffu, ps1, 1);
        ps1 += __shfl_xor_sync(0xffffffffu, ps1, 2);
        l0 = l0 * c0 + ps0;
        l1 = l1 * c1 + ps1;
        m0 = mn0; m1 = mn1;
        #pragma unroll
        for (int nt = 0; nt < 4; nt++) {
            o[nt][0] *= c0; o[nt][1] *= c0;
            o[nt][2] *= c1; o[nt][3] *= c1;
        }

        #pragma unroll
        for (int kt = 0; kt < 4; kt++) {
            unsigned pa[4] = { ph[2 * kt][0], ph[2 * kt][1],
                               ph[2 * kt + 1][0], ph[2 * kt + 1][1] };
            #pragma unroll
            for (int nt = 0; nt < 4; nt++) {
                unsigned bfr[2];
                bfr[0] = *reinterpret_cast<const unsigned*>(&Vt[nt * 8 + g][kt * 16 + tig * 2]);
                bfr[1] = *reinterpret_cast<const unsigned*>(&Vt[nt * 8 + g][kt * 16 + tig * 2 + 8]);
                mma16816(o[nt], pa, bfr);
            }
        }
        __syncthreads();
    }

    const size_t pbase = (((size_t)split * BATCH + b) * N_HEADS + h) * S_LEN;
    int qa = q0 + qbase + g;
    int qb2 = qa + 8;
    if (qa < S_LEN) {
        #pragma unroll
        for (int nt = 0; nt < 4; nt++) {
            float2 v = make_float2(o[nt][0], o[nt][1]);
            *reinterpret_cast<float2*>(po + (pbase + qa) * DHEAD + nt * 8 + tig * 2) = v;
        }
        if (tig == 0) { pm[pbase + qa] = m0; pl[pbase + qa] = l0; }
    }
    if (qb2 < S_LEN) {
        #pragma unroll
        for (int nt = 0; nt < 4; nt++) {
            float2 v = make_float2(o[nt][2], o[nt][3]);
            *reinterpret_cast<float2*>(po + (pbase + qb2) * DHEAD + nt * 8 + tig * 2) = v;
        }
        if (tig == 0) { pm[pbase + qb2] = m1; pl[pbase + qb2] = l1; }
    }
}

// ---------------- merge split-S partials -> fp16 ----------------
__global__ __launch_bounds__(128) void attn_merge_kernel(
    const float* __restrict__ po, const float* __restrict__ pm,
    const float* __restrict__ pl, __half* __restrict__ out)
{
    const int q = blockIdx.x, b = blockIdx.y;
    const int d = threadIdx.x;
    const int h = d >> 5, dd = d & 31;
    const size_t row = ((size_t)b * N_HEADS + h) * S_LEN + q;
    const size_t stride = (size_t)BATCH * N_HEADS * S_LEN;
    float ms[SPLITS], ls[SPLITS];
    float M = -1e30f;
    #pragma unroll
    for (int s = 0; s < SPLITS; s++) {
        ms[s] = pm[row + s * stride];
        ls[s] = pl[row + s * stride];
        M = fmaxf(M, ms[s]);
    }
    float L = 0.f, O = 0.f;
    #pragma unroll
    for (int s = 0; s < SPLITS; s++) {
        float w = __expf(ms[s] - M);
        L += w * ls[s];
        O += w * po[(row + s * stride) * DHEAD + dd];
    }
    out[((size_t)b * S_LEN + q) * D_MODEL + d] = __float2half_rn(O / L);
}

// ---------------- head ----------------
__global__ __launch_bounds__(64) void head_kernel(
    const float* __restrict__ h, const float* __restrict__ ls,
    const float* __restrict__ lb, const float* __restrict__ hw,
    const float* __restrict__ hb, float* __restrict__ out)
{
    int bidx = threadIdx.x >> 5;
    if (bidx >= BATCH) return;
    int lane = threadIdx.x & 31;
    const float* xr = h + (size_t)bidx * S_LEN * D_MODEL;
    float4 v = *reinterpret_cast<const float4*>(xr + lane * 4);
    float sum = v.x + v.y + v.z + v.w;
    #pragma unroll
    for (int o = 16; o; o >>= 1) sum += __shfl_xor_sync(0xffffffffu, sum, o);
    float mean = sum * (1.f / 128.f);
    float dx = v.x - mean, dy = v.y - mean, dz = v.z - mean, dw = v.w - mean;
    float vs = dx * dx + dy * dy + dz * dz + dw * dw;
    #pragma unroll
    for (int o = 16; o; o >>= 1) vs += __shfl_xor_sync(0xffffffffu, vs, o);
    float rstd = rsqrtf(vs * (1.f / 128.f) + 1e-5f);
    float4 s4 = *reinterpret_cast<const float4*>(ls + lane * 4);
    float4 b4 = *reinterpret_cast<const float4*>(lb + lane * 4);
    float4 w4 = *reinterpret_cast<const float4*>(hw + lane * 4);
    float dot = (dx * rstd * s4.x + b4.x) * w4.x
              + (dy * rstd * s4.y + b4.y) * w4.y
              + (dz * rstd * s4.z + b4.z) * w4.z
              + (dw * rstd * s4.w + b4.w) * w4.w;
    #pragma unroll
    for (int o = 16; o; o >>= 1) dot += __shfl_xor_sync(0xffffffffu, dot, o);
    if (lane == 0) out[bidx] = dot + hb[0];
}

// ---------------- launch ----------------
extern "C" void kernel_launch(void* const* d_in, const int* in_sizes, int n_in,
                              void* d_out, int out_size)
{
    const float* x        = (const float*)d_in[0];
    const float* embed_w  = (const float*)d_in[1];
    const float* embed_b  = (const float*)d_in[2];
    const float* pos_emb  = (const float*)d_in[3];
    const float* cls      = (const float*)d_in[4];
    const float* in_w     = (const float*)d_in[5];
    const float* in_b     = (const float*)d_in[6];
    const float* out_w    = (const float*)d_in[7];
    const float* out_b    = (const float*)d_in[8];
    const float* ln1_s    = (const float*)d_in[9];
    const float* ln1_b    = (const float*)d_in[10];
    const float* ln2_s    = (const float*)d_in[11];
    const float* ln2_b    = (const float*)d_in[12];
    const float* ff1_w    = (const float*)d_in[13];
    const float* ff1_b    = (const float*)d_in[14];
    const float* ff2_w    = (const float*)d_in[15];
    const float* ff2_b    = (const float*)d_in[16];
    const float* hln_s    = (const float*)d_in[17];
    const float* hln_b    = (const float*)d_in[18];
    const float* head_w   = (const float*)d_in[19];
    const float* head_b   = (const float*)d_in[20];
    float* outp = (float*)d_out;

    float *h, *po, *pm, *pl;
    __half *hnh, *qkvh, *attnh, *ffh;
    cudaGetSymbolAddress((void**)&h,     g_h);
    cudaGetSymbolAddress((void**)&hnh,   g_hnh);
    cudaGetSymbolAddress((void**)&qkvh,  g_qkvh);
    cudaGetSymbolAddress((void**)&attnh, g_attnh);
    cudaGetSymbolAddress((void**)&ffh,   g_ffh);
    cudaGetSymbolAddress((void**)&po,    g_po);
    cudaGetSymbolAddress((void**)&pm,    g_pm);
    cudaGetSymbolAddress((void**)&pl,    g_pl);

    const int M = MROWS;
    const int MB128 = (M + 127) / 128;  // 33
    const int MB32  = (M + 31) / 32;    // 129
    const int QTILES = (S_LEN + BQ - 1) / BQ;

    // embedding + fused LN1(layer 0)
    embed_ln_kernel<<<dim3(S_LEN, BATCH), 128>>>(
        x, embed_w, embed_b, pos_emb, cls, ln1_s, ln1_b, h, hnh);

    for (int i = 0; i < NL; i++) {
        // QKV projection -> fp16 (Q pre-scaled)
        hgemm_kernel<false, true><<<dim3(384 / 64, MB128), 256>>>(
            hnh, in_w + (size_t)i * 384 * 128, in_b + (size_t)i * 384,
            qkvh, M, 384, 128);
        // split-S attention + merge
        attn_kernel<<<dim3(QTILES * SPLITS, N_HEADS, BATCH), 256>>>(qkvh, po, pm, pl);
        attn_merge_kernel<<<dim3(S_LEN, BATCH), 128>>>(po, pm, pl, attnh);
        // out projection + residual + fused LN2 -> h, hnh
        hgemm_ln_kernel<true><<<MB32, 256>>>(
            attnh, out_w + (size_t)i * 128 * 128, out_b + (size_t)i * 128,
            ln2_s + i * D_MODEL, ln2_b + i * D_MODEL, h, hnh, M, 128);
        // FF1 + ReLU -> fp16
        hgemm_kernel<true, false><<<dim3(512 / 64, MB128), 256>>>(
            hnh, ff1_w + (size_t)i * 512 * 128, ff1_b + (size_t)i * 512,
            ffh, M, 512, 128);
        // FF2 + residual (+ fused LN1 of next layer) -> h, hnh
        if (i + 1 < NL) {
            hgemm_ln_kernel<true><<<MB32, 256>>>(
                ffh, ff2_w + (size_t)i * 128 * 512, ff2_b + (size_t)i * 128,
                ln1_s + (i + 1) * D_MODEL, ln1_b + (i + 1) * D_MODEL,
                h, hnh, M, 512);
        } else {
            hgemm_ln_kernel<false><<<MB32, 256>>>(
                ffh, ff2_w + (size_t)i * 128 * 512, ff2_b + (size_t)i * 128,
                nullptr, nullptr, h, nullptr, M, 512);
        }
    }

    head_kernel<<<1, 64>>>(h, hln_s, hln_b, head_w, head_b, outp);
}

// round 8
// speedup vs baseline: 4.1675x; 1.0425x over previous
#include <cuda_runtime.h>
#include <cuda_fp16.h>
#include <math.h>

#define NL 3
#define D_MODEL 128
#define N_HEADS 4
#define DHEAD 32
#define DFF 512
#define DIN 64
#define BATCH 2
#define LSEQ 2048
#define S_LEN 2049
#define MROWS (BATCH * S_LEN)   // 4098
#define QK_SCALE 0.17677669529663687f

#define SPLITS 4
#define KCHUNK 576
#define VT_PITCH 2112   // padded keys pitch (>= 2049 + 63, mult of 8)

// ---------------- scratch (device globals; no allocation) ----------------
__device__ float  g_h[MROWS * D_MODEL];
__device__ __half g_hnh[MROWS * D_MODEL];
__device__ __half g_qkvh[MROWS * 3 * D_MODEL];
__device__ __half g_vt[BATCH * N_HEADS * DHEAD * VT_PITCH];
__device__ __half g_attnh[MROWS * D_MODEL];
__device__ __half g_ffh[MROWS * DFF];
__device__ float  g_po[SPLITS * BATCH * N_HEADS * S_LEN * DHEAD];
__device__ float  g_pm[SPLITS * BATCH * N_HEADS * S_LEN];
__device__ float  g_pl[SPLITS * BATCH * N_HEADS * S_LEN];
// fp16 weights: in_w | out_w | ff1_w | ff2_w
#define WOFF_IN  0
#define WOFF_OUT (NL * 384 * 128)
#define WOFF_FF1 (WOFF_OUT + NL * 128 * 128)
#define WOFF_FF2 (WOFF_FF1 + NL * 512 * 128)
#define WTOTAL   (WOFF_FF2 + NL * 128 * 512)
__device__ __half g_wh[WTOTAL];

// ---------------- mma helper ----------------
__device__ __forceinline__ void mma16816(
    float c[4], const unsigned a[4], const unsigned b[2])
{
    asm volatile(
        "mma.sync.aligned.m16n8k16.row.col.f32.f16.f16.f32 "
        "{%0,%1,%2,%3}, {%4,%5,%6,%7}, {%8,%9}, {%0,%1,%2,%3};\n"
        : "+f"(c[0]), "+f"(c[1]), "+f"(c[2]), "+f"(c[3])
        : "r"(a[0]), "r"(a[1]), "r"(a[2]), "r"(a[3]),
          "r"(b[0]), "r"(b[1]));
}

// ---------------- weight fp32 -> fp16 conversion ----------------
__global__ __launch_bounds__(256) void convw_kernel(
    const float* __restrict__ src, __half* __restrict__ dst, int n4)
{
    int i = blockIdx.x * 256 + threadIdx.x;
    if (i >= n4) return;
    float4 v = *reinterpret_cast<const float4*>(src + (size_t)i * 4);
    __half2 a = __floats2half2_rn(v.x, v.y);
    __half2 b = __floats2half2_rn(v.z, v.w);
    uint2 pk;
    pk.x = *reinterpret_cast<unsigned*>(&a);
    pk.y = *reinterpret_cast<unsigned*>(&b);
    *reinterpret_cast<uint2*>(dst + (size_t)i * 4) = pk;
}

// ---------------- embedding + fused LN1(layer0) ----------------
__global__ __launch_bounds__(128) void embed_ln_kernel(
    const float* __restrict__ x, const float* __restrict__ ew,
    const float* __restrict__ eb, const float* __restrict__ pos,
    const float* __restrict__ cls, const float* __restrict__ lns,
    const float* __restrict__ lnb, float* __restrict__ h,
    __half* __restrict__ hn)
{
    __shared__ float xs[DIN];
    __shared__ float red[8];
    int s = blockIdx.x, b = blockIdx.y;
    int d = threadIdx.x;
    if (s > 0 && d < DIN) xs[d] = x[((size_t)b * LSEQ + (s - 1)) * DIN + d];
    __syncthreads();
    float val;
    if (s == 0) {
        val = cls[d] + pos[d];
    } else {
        float acc = 0.f;
        const float* wr = ew + (size_t)d * DIN;
        #pragma unroll
        for (int j = 0; j < DIN; j++) acc = fmaf(xs[j], wr[j], acc);
        val = acc + eb[d] + pos[(size_t)s * D_MODEL + d];
    }
    size_t row = (size_t)b * S_LEN + s;
    h[row * D_MODEL + d] = val;
    int w = d >> 5, lane = d & 31;
    float sv = val, qv = val * val;
    #pragma unroll
    for (int o = 16; o; o >>= 1) {
        sv += __shfl_xor_sync(0xffffffffu, sv, o);
        qv += __shfl_xor_sync(0xffffffffu, qv, o);
    }
    if (lane == 0) { red[w] = sv; red[4 + w] = qv; }
    __syncthreads();
    float sum = red[0] + red[1] + red[2] + red[3];
    float sq  = red[4] + red[5] + red[6] + red[7];
    float mean = sum * (1.f / 128.f);
    float rstd = rsqrtf(sq * (1.f / 128.f) - mean * mean + 1e-5f);
    hn[row * D_MODEL + d] = __float2half_rn((val - mean) * rstd * lns[d] + lnb[d]);
}

// ---------------- tensor-core GEMM (128x64 tile, fp16 W, reg-prefetch) ----
// C(fp16) = A(fp16).W^T + bias.  VSTORE: columns n>=256 go transposed to vT.
#define GPITCH 40
template <bool RELU, bool QSCALE, bool VSTORE>
__global__ __launch_bounds__(256) void hgemm_kernel(
    const __half* __restrict__ A, const __half* __restrict__ W,
    const float* __restrict__ bias, __half* __restrict__ C,
    __half* __restrict__ vT, int M, int N, int K)
{
    __shared__ __half As[128][GPITCH];
    __shared__ __half Ws[64][GPITCH];
    const int tid = threadIdx.x;
    const int warp = tid >> 5;
    const int lane = tid & 31;
    const int g = lane >> 2;
    const int tig = lane & 3;
    const int warp_m = warp >> 1;
    const int warp_n = warp & 1;
    const int m0 = blockIdx.y * 128;
    const int n0 = blockIdx.x * 64;
    const int NK = K / 32;
    const int wr = tid >> 2, wq = tid & 3;   // W stage coords

    float c[2][4][4] = {};

    uint4 aReg[2], wReg;
    #pragma unroll
    for (int it = 0; it < 2; it++) {
        int idx = tid + it * 256;
        int r = idx >> 2, quad = idx & 3;
        int m = m0 + r;
        aReg[it] = (m < M)
            ? *reinterpret_cast<const uint4*>(A + (size_t)m * K + quad * 8)
            : make_uint4(0u, 0u, 0u, 0u);
    }
    wReg = *reinterpret_cast<const uint4*>(W + (size_t)(n0 + wr) * K + wq * 8);

    for (int kt = 0; kt < NK; kt++) {
        #pragma unroll
        for (int it = 0; it < 2; it++) {
            int idx = tid + it * 256;
            int r = idx >> 2, quad = idx & 3;
            *reinterpret_cast<uint4*>(&As[r][quad * 8]) = aReg[it];
        }
        *reinterpret_cast<uint4*>(&Ws[wr][wq * 8]) = wReg;
        __syncthreads();
        if (kt + 1 < NK) {
            int k0 = (kt + 1) * 32;
            #pragma unroll
            for (int it = 0; it < 2; it++) {
                int idx = tid + it * 256;
                int r = idx >> 2, quad = idx & 3;
                int m = m0 + r;
                aReg[it] = (m < M)
                    ? *reinterpret_cast<const uint4*>(A + (size_t)m * K + k0 + quad * 8)
                    : make_uint4(0u, 0u, 0u, 0u);
            }
            wReg = *reinterpret_cast<const uint4*>(W + (size_t)(n0 + wr) * K + k0 + wq * 8);
        }
        #pragma unroll
        for (int ks = 0; ks < 2; ks++) {
            unsigned a[2][4];
            #pragma unroll
            for (int mt = 0; mt < 2; mt++) {
                int rbase = warp_m * 32 + mt * 16;
                a[mt][0] = *reinterpret_cast<const unsigned*>(&As[rbase + g    ][ks * 16 + tig * 2]);
                a[mt][1] = *reinterpret_cast<const unsigned*>(&As[rbase + g + 8][ks * 16 + tig * 2]);
                a[mt][2] = *reinterpret_cast<const unsigned*>(&As[rbase + g    ][ks * 16 + tig * 2 + 8]);
                a[mt][3] = *reinterpret_cast<const unsigned*>(&As[rbase + g + 8][ks * 16 + tig * 2 + 8]);
            }
            #pragma unroll
            for (int nt = 0; nt < 4; nt++) {
                unsigned bfr[2];
                int nrow = warp_n * 32 + nt * 8 + g;
                bfr[0] = *reinterpret_cast<const unsigned*>(&Ws[nrow][ks * 16 + tig * 2]);
                bfr[1] = *reinterpret_cast<const unsigned*>(&Ws[nrow][ks * 16 + tig * 2 + 8]);
                mma16816(c[0][nt], a[0], bfr);
                mma16816(c[1][nt], a[1], bfr);
            }
        }
        __syncthreads();
    }

    #pragma unroll
    for (int mt = 0; mt < 2; mt++) {
        #pragma unroll
        for (int half_row = 0; half_row < 2; half_row++) {
            int m = m0 + warp_m * 32 + mt * 16 + g + half_row * 8;
            if (m >= M) continue;
            int bb = m / S_LEN, ss = m % S_LEN;   // only used for VSTORE
            #pragma unroll
            for (int nt = 0; nt < 4; nt++) {
                int n = n0 + warp_n * 32 + nt * 8 + tig * 2;
                float v0 = c[mt][nt][half_row * 2 + 0] + bias[n];
                float v1 = c[mt][nt][half_row * 2 + 1] + bias[n + 1];
                if (RELU) { v0 = fmaxf(v0, 0.f); v1 = fmaxf(v1, 0.f); }
                if (VSTORE && n >= 256) {
                    int hh = (n - 256) >> 5, dd = (n - 256) & 31;
                    __half* vbase = vT + ((size_t)(bb * N_HEADS + hh) * DHEAD + dd) * VT_PITCH + ss;
                    vbase[0] = __float2half_rn(v0);
                    vbase[VT_PITCH] = __float2half_rn(v1);
                } else {
                    if (QSCALE && n < 128) { v0 *= QK_SCALE; v1 *= QK_SCALE; }
                    __half2 hv = __floats2half2_rn(v0, v1);
                    *reinterpret_cast<unsigned*>(
                        C + (size_t)m * N + n) = *reinterpret_cast<unsigned*>(&hv);
                }
            }
        }
    }
}

// ---------------- GEMM + residual + fused row-LN (N=128, fp16 W) ---------
template <bool DO_LN>
__global__ __launch_bounds__(256) void hgemm_ln_kernel(
    const __half* __restrict__ A, const __half* __restrict__ W,
    const float* __restrict__ bias,
    const float* __restrict__ lns, const float* __restrict__ lnb,
    float* __restrict__ h, __half* __restrict__ hn, int M, int K)
{
    __shared__ __half As[32][GPITCH];
    __shared__ __half Ws[128][GPITCH];
    __shared__ float psum[32][4], psq[32][4];
    const int tid = threadIdx.x;
    const int warp = tid >> 5;
    const int lane = tid & 31;
    const int g = lane >> 2;
    const int tig = lane & 3;
    const int warp_m = warp >> 2;
    const int warp_n = warp & 3;
    const int m0 = blockIdx.x * 32;
    const int NK = K / 32;

    float c[4][4] = {};

    const bool aAct = tid < 128;
    const int ar = tid >> 2, aq = tid & 3;
    uint4 aReg = make_uint4(0u, 0u, 0u, 0u);
    if (aAct) {
        int m = m0 + ar;
        if (m < M) aReg = *reinterpret_cast<const uint4*>(A + (size_t)m * K + aq * 8);
    }
    uint4 wReg[2];
    #pragma unroll
    for (int it = 0; it < 2; it++) {
        int idx = tid + it * 256;
        int r = idx >> 2, q = idx & 3;
        wReg[it] = *reinterpret_cast<const uint4*>(W + (size_t)r * K + q * 8);
    }

    for (int kt = 0; kt < NK; kt++) {
        if (aAct) *reinterpret_cast<uint4*>(&As[ar][aq * 8]) = aReg;
        #pragma unroll
        for (int it = 0; it < 2; it++) {
            int idx = tid + it * 256;
            int r = idx >> 2, q = idx & 3;
            *reinterpret_cast<uint4*>(&Ws[r][q * 8]) = wReg[it];
        }
        __syncthreads();
        if (kt + 1 < NK) {
            int k0 = (kt + 1) * 32;
            if (aAct) {
                int m = m0 + ar;
                aReg = (m < M)
                    ? *reinterpret_cast<const uint4*>(A + (size_t)m * K + k0 + aq * 8)
                    : make_uint4(0u, 0u, 0u, 0u);
            }
            #pragma unroll
            for (int it = 0; it < 2; it++) {
                int idx = tid + it * 256;
                int r = idx >> 2, q = idx & 3;
                wReg[it] = *reinterpret_cast<const uint4*>(W + (size_t)r * K + k0 + q * 8);
            }
        }
        #pragma unroll
        for (int ks = 0; ks < 2; ks++) {
            unsigned a[4];
            int rbase = warp_m * 16;
            a[0] = *reinterpret_cast<const unsigned*>(&As[rbase + g    ][ks * 16 + tig * 2]);
            a[1] = *reinterpret_cast<const unsigned*>(&As[rbase + g + 8][ks * 16 + tig * 2]);
            a[2] = *reinterpret_cast<const unsigned*>(&As[rbase + g    ][ks * 16 + tig * 2 + 8]);
            a[3] = *reinterpret_cast<const unsigned*>(&As[rbase + g + 8][ks * 16 + tig * 2 + 8]);
            #pragma unroll
            for (int nt = 0; nt < 4; nt++) {
                unsigned bfr[2];
                int nrow = warp_n * 32 + nt * 8 + g;
                bfr[0] = *reinterpret_cast<const unsigned*>(&Ws[nrow][ks * 16 + tig * 2]);
                bfr[1] = *reinterpret_cast<const unsigned*>(&Ws[nrow][ks * 16 + tig * 2 + 8]);
                mma16816(c[nt], a, bfr);
            }
        }
        __syncthreads();
    }

    const int lr0 = warp_m * 16 + g, lr1 = lr0 + 8;
    const int mrow0 = m0 + lr0, mrow1 = m0 + lr1;
    #pragma unroll
    for (int nt = 0; nt < 4; nt++) {
        int n = warp_n * 32 + nt * 8 + tig * 2;
        float b0 = bias[n], b1 = bias[n + 1];
        if (mrow0 < M) {
            float2 r2 = *reinterpret_cast<const float2*>(h + (size_t)mrow0 * 128 + n);
            c[nt][0] += b0 + r2.x;
            c[nt][1] += b1 + r2.y;
            *reinterpret_cast<float2*>(h + (size_t)mrow0 * 128 + n) =
                make_float2(c[nt][0], c[nt][1]);
        }
        if (mrow1 < M) {
            float2 r2 = *reinterpret_cast<const float2*>(h + (size_t)mrow1 * 128 + n);
            c[nt][2] += b0 + r2.x;
            c[nt][3] += b1 + r2.y;
            *reinterpret_cast<float2*>(h + (size_t)mrow1 * 128 + n) =
                make_float2(c[nt][2], c[nt][3]);
        }
    }
    if (DO_LN) {
        float s0 = 0.f, q0 = 0.f, s1 = 0.f, q1 = 0.f;
        #pragma unroll
        for (int nt = 0; nt < 4; nt++) {
            s0 += c[nt][0] + c[nt][1];
            q0 += c[nt][0] * c[nt][0] + c[nt][1] * c[nt][1];
            s1 += c[nt][2] + c[nt][3];
            q1 += c[nt][2] * c[nt][2] + c[nt][3] * c[nt][3];
        }
        #pragma unroll
        for (int o = 1; o < 4; o <<= 1) {
            s0 += __shfl_xor_sync(0xffffffffu, s0, o);
            q0 += __shfl_xor_sync(0xffffffffu, q0, o);
            s1 += __shfl_xor_sync(0xffffffffu, s1, o);
            q1 += __shfl_xor_sync(0xffffffffu, q1, o);
        }
        if (tig == 0) {
            psum[lr0][warp_n] = s0; psq[lr0][warp_n] = q0;
            psum[lr1][warp_n] = s1; psq[lr1][warp_n] = q1;
        }
        __syncthreads();
        float sum0 = psum[lr0][0] + psum[lr0][1] + psum[lr0][2] + psum[lr0][3];
        float sq0  = psq[lr0][0] + psq[lr0][1] + psq[lr0][2] + psq[lr0][3];
        float sum1 = psum[lr1][0] + psum[lr1][1] + psum[lr1][2] + psum[lr1][3];
        float sq1  = psq[lr1][0] + psq[lr1][1] + psq[lr1][2] + psq[lr1][3];
        float mean0 = sum0 * (1.f / 128.f);
        float rstd0 = rsqrtf(sq0 * (1.f / 128.f) - mean0 * mean0 + 1e-5f);
        float mean1 = sum1 * (1.f / 128.f);
        float rstd1 = rsqrtf(sq1 * (1.f / 128.f) - mean1 * mean1 + 1e-5f);
        #pragma unroll
        for (int nt = 0; nt < 4; nt++) {
            int n = warp_n * 32 + nt * 8 + tig * 2;
            float g0 = lns[n], g1 = lns[n + 1];
            float bb0 = lnb[n], bb1 = lnb[n + 1];
            if (mrow0 < M) {
                __half2 hv = __floats2half2_rn(
                    (c[nt][0] - mean0) * rstd0 * g0 + bb0,
                    (c[nt][1] - mean0) * rstd0 * g1 + bb1);
                *reinterpret_cast<unsigned*>(hn + (size_t)mrow0 * 128 + n)
                    = *reinterpret_cast<unsigned*>(&hv);
            }
            if (mrow1 < M) {
                __half2 hv = __floats2half2_rn(
                    (c[nt][2] - mean1) * rstd1 * g0 + bb0,
                    (c[nt][3] - mean1) * rstd1 * g1 + bb1);
                *reinterpret_cast<unsigned*>(hn + (size_t)mrow1 * 128 + n)
                    = *reinterpret_cast<unsigned*>(&hv);
            }
        }
    }
}

// ---------------- split-S flash attention (double-buffered K/V) ----------
#define BQ 128
#define BK 64
#define QPITCH 40
#define VPITCH 72

__global__ __launch_bounds__(256, 3) void attn_kernel(
    const __half* __restrict__ qkv, const __half* __restrict__ vT,
    float* __restrict__ po, float* __restrict__ pm, float* __restrict__ pl)
{
    __shared__ __half Qs[BQ][QPITCH];
    __shared__ __half Kt[2][BK][QPITCH];
    __shared__ __half Vt[2][DHEAD][VPITCH];
    const int tid = threadIdx.x;
    const int warp = tid >> 5;
    const int lane = tid & 31;
    const int g = lane >> 2;
    const int tig = lane & 3;
    const int b = blockIdx.z, h = blockIdx.y;
    const int tile = blockIdx.x / SPLITS;
    const int split = blockIdx.x % SPLITS;
    const int q0 = tile * BQ;
    const int qbase = warp * 16;
    const int kstart = split * KCHUNK;
    const int kend = min(kstart + KCHUNK, S_LEN);
    const int ntile = (kend - kstart + BK - 1) / BK;

    // ---- load Q tile ----
    #pragma unroll
    for (int idx = tid; idx < BQ * 4; idx += 256) {
        int r = idx >> 2, quad = idx & 3;
        int q = q0 + r;
        uint4 v = make_uint4(0u, 0u, 0u, 0u);
        if (q < S_LEN)
            v = *reinterpret_cast<const uint4*>(
                qkv + ((size_t)(b * S_LEN + q)) * 384 + h * 32 + quad * 8);
        *reinterpret_cast<uint4*>(&Qs[r][quad * 8]) = v;
    }

    const __half* Kbase = qkv + (size_t)b * S_LEN * 384 + 128 + h * 32;
    const __half* Vbase = vT + (size_t)(b * N_HEADS + h) * DHEAD * VT_PITCH;
    const int kr = tid >> 2, kq = tid & 3;
    const int vr = tid >> 3, vq = tid & 7;

    // ---- prefetch tile 0 ----
    uint4 kreg, vreg;
    {
        int kg = kstart + kr;
        kreg = (kg < S_LEN)
            ? *reinterpret_cast<const uint4*>(Kbase + (size_t)kg * 384 + kq * 8)
            : make_uint4(0u, 0u, 0u, 0u);
        vreg = *reinterpret_cast<const uint4*>(Vbase + (size_t)vr * VT_PITCH + kstart + vq * 8);
    }
    *reinterpret_cast<uint4*>(&Kt[0][kr][kq * 8]) = kreg;
    *reinterpret_cast<uint4*>(&Vt[0][vr][vq * 8]) = vreg;
    __syncthreads();

    // ---- hoisted Q fragments ----
    unsigned A[2][4];
    #pragma unroll
    for (int ks = 0; ks < 2; ks++) {
        A[ks][0] = *reinterpret_cast<const unsigned*>(&Qs[qbase + g    ][ks * 16 + tig * 2]);
        A[ks][1] = *reinterpret_cast<const unsigned*>(&Qs[qbase + g + 8][ks * 16 + tig * 2]);
        A[ks][2] = *reinterpret_cast<const unsigned*>(&Qs[qbase + g    ][ks * 16 + tig * 2 + 8]);
        A[ks][3] = *reinterpret_cast<const unsigned*>(&Qs[qbase + g + 8][ks * 16 + tig * 2 + 8]);
    }

    float m0 = -1e30f, m1 = -1e30f, l0 = 0.f, l1 = 0.f;
    float o[4][4] = {};

    for (int t = 0; t < ntile; t++) {
        const int kb = kstart + t * BK;
        const int buf = t & 1;
        // prefetch next tile into regs
        if (t + 1 < ntile) {
            int kb2 = kb + BK;
            int kg = kb2 + kr;
            kreg = (kg < S_LEN)
                ? *reinterpret_cast<const uint4*>(Kbase + (size_t)kg * 384 + kq * 8)
                : make_uint4(0u, 0u, 0u, 0u);
            vreg = *reinterpret_cast<const uint4*>(Vbase + (size_t)vr * VT_PITCH + kb2 + vq * 8);
        }

        // ---- QK^T ----
        float s[8][4];
        #pragma unroll
        for (int j = 0; j < 8; j++) {
            s[j][0] = s[j][1] = s[j][2] = s[j][3] = 0.f;
            #pragma unroll
            for (int ks = 0; ks < 2; ks++) {
                unsigned bfr[2];
                bfr[0] = *reinterpret_cast<const unsigned*>(&Kt[buf][j * 8 + g][ks * 16 + tig * 2]);
                bfr[1] = *reinterpret_cast<const unsigned*>(&Kt[buf][j * 8 + g][ks * 16 + tig * 2 + 8]);
                mma16816(s[j], A[ks], bfr);
            }
        }
        if (kb + BK > S_LEN) {
            #pragma unroll
            for (int j = 0; j < 8; j++) {
                int key = kb + j * 8 + tig * 2;
                if (key >= S_LEN)     { s[j][0] = -1e30f; s[j][2] = -1e30f; }
                if (key + 1 >= S_LEN) { s[j][1] = -1e30f; s[j][3] = -1e30f; }
            }
        }

        // ---- online softmax ----
        float t0 = -1e30f, t1 = -1e30f;
        #pragma unroll
        for (int j = 0; j < 8; j++) {
            t0 = fmaxf(t0, fmaxf(s[j][0], s[j][1]));
            t1 = fmaxf(t1, fmaxf(s[j][2], s[j][3]));
        }
        t0 = fmaxf(t0, __shfl_xor_sync(0xffffffffu, t0, 1));
        t0 = fmaxf(t0, __shfl_xor_sync(0xffffffffu, t0, 2));
        t1 = fmaxf(t1, __shfl_xor_sync(0xffffffffu, t1, 1));
        t1 = fmaxf(t1, __shfl_xor_sync(0xffffffffu, t1, 2));
        float mn0 = fmaxf(m0, t0), mn1 = fmaxf(m1, t1);
        float c0 = __expf(m0 - mn0), c1 = __expf(m1 - mn1);
        unsigned ph[8][2];
        float ps0 = 0.f, ps1 = 0.f;
        #pragma unroll
        for (int j = 0; j < 8; j++) {
            __half2 h2a = __floats2half2_rn(__expf(s[j][0] - mn0), __expf(s[j][1] - mn0));
            __half2 h2b = __floats2half2_rn(__expf(s[j][2] - mn1), __expf(s[j][3] - mn1));
            ph[j][0] = *reinterpret_cast<unsigned*>(&h2a);
            ph[j][1] = *reinterpret_cast<unsigned*>(&h2b);
            float2 fa = __half22float2(h2a);
            float2 fb = __half22float2(h2b);
            ps0 += fa.x + fa.y;
            ps1 += fb.x + fb.y;
        }
        ps0 += __shfl_xor_sync(0xffffffffu, ps0, 1);
        ps0 += __shfl_xor_sync(0xffffffffu, ps0, 2);
        ps1 += __shfl_xor_sync(0xffffffffu, ps1, 1);
        ps1 += __shfl_xor_sync(0xffffffffu, ps1, 2);
        l0 = l0 * c0 + ps0;
        l1 = l1 * c1 + ps1;
        m0 = mn0; m1 = mn1;
        #pragma unroll
        for (int nt = 0; nt < 4; nt++) {
            o[nt][0] *= c0; o[nt][1] *= c0;
            o[nt][2] *= c1; o[nt][3] *= c1;
        }

        // ---- PV ----
        #pragma unroll
        for (int kt = 0; kt < 4; kt++) {
            unsigned pa[4] = { ph[2 * kt][0], ph[2 * kt][1],
                               ph[2 * kt + 1][0], ph[2 * kt + 1][1] };
            #pragma unroll
            for (int nt = 0; nt < 4; nt++) {
                unsigned bfr[2];
                bfr[0] = *reinterpret_cast<const unsigned*>(&Vt[buf][nt * 8 + g][kt * 16 + tig * 2]);
                bfr[1] = *reinterpret_cast<const unsigned*>(&Vt[buf][nt * 8 + g][kt * 16 + tig * 2 + 8]);
                mma16816(o[nt], pa, bfr);
            }
        }
        // stage next tile
        if (t + 1 < ntile) {
            *reinterpret_cast<uint4*>(&Kt[buf ^ 1][kr][kq * 8]) = kreg;
            *reinterpret_cast<uint4*>(&Vt[buf ^ 1][vr][vq * 8]) = vreg;
        }
        __syncthreads();
    }

    const size_t pbase = (((size_t)split * BATCH + b) * N_HEADS + h) * S_LEN;
    int qa = q0 + qbase + g;
    int qb2 = qa + 8;
    if (qa < S_LEN) {
        #pragma unroll
        for (int nt = 0; nt < 4; nt++) {
            float2 v = make_float2(o[nt][0], o[nt][1]);
            *reinterpret_cast<float2*>(po + (pbase + qa) * DHEAD + nt * 8 + tig * 2) = v;
        }
        if (tig == 0) { pm[pbase + qa] = m0; pl[pbase + qa] = l0; }
    }
    if (qb2 < S_LEN) {
        #pragma unroll
        for (int nt = 0; nt < 4; nt++) {
            float2 v = make_float2(o[nt][2], o[nt][3]);
            *reinterpret_cast<float2*>(po + (pbase + qb2) * DHEAD + nt * 8 + tig * 2) = v;
        }
        if (tig == 0) { pm[pbase + qb2] = m1; pl[pbase + qb2] = l1; }
    }
}

// ---------------- merge split-S partials -> fp16 ----------------
__global__ __launch_bounds__(128) void attn_merge_kernel(
    const float* __restrict__ po, const float* __restrict__ pm,
    const float* __restrict__ pl, __half* __restrict__ out)
{
    const int q = blockIdx.x, b = blockIdx.y;
    const int d = threadIdx.x;
    const int h = d >> 5, dd = d & 31;
    const size_t row = ((size_t)b * N_HEADS + h) * S_LEN + q;
    const size_t stride = (size_t)BATCH * N_HEADS * S_LEN;
    float ms[SPLITS], ls[SPLITS];
    float M = -1e30f;
    #pragma unroll
    for (int s = 0; s < SPLITS; s++) {
        ms[s] = pm[row + s * stride];
        ls[s] = pl[row + s * stride];
        M = fmaxf(M, ms[s]);
    }
    float L = 0.f, O = 0.f;
    #pragma unroll
    for (int s = 0; s < SPLITS; s++) {
        float w = __expf(ms[s] - M);
        L += w * ls[s];
        O += w * po[(row + s * stride) * DHEAD + dd];
    }
    out[((size_t)b * S_LEN + q) * D_MODEL + d] = __float2half_rn(O / L);
}

// ---------------- head ----------------
__global__ __launch_bounds__(64) void head_kernel(
    const float* __restrict__ h, const float* __restrict__ ls,
    const float* __restrict__ lb, const float* __restrict__ hw,
    const float* __restrict__ hb, float* __restrict__ out)
{
    int bidx = threadIdx.x >> 5;
    if (bidx >= BATCH) return;
    int lane = threadIdx.x & 31;
    const float* xr = h + (size_t)bidx * S_LEN * D_MODEL;
    float4 v = *reinterpret_cast<const float4*>(xr + lane * 4);
    float sum = v.x + v.y + v.z + v.w;
    #pragma unroll
    for (int o = 16; o; o >>= 1) sum += __shfl_xor_sync(0xffffffffu, sum, o);
    float mean = sum * (1.f / 128.f);
    float dx = v.x - mean, dy = v.y - mean, dz = v.z - mean, dw = v.w - mean;
    float vs = dx * dx + dy * dy + dz * dz + dw * dw;
    #pragma unroll
    for (int o = 16; o; o >>= 1) vs += __shfl_xor_sync(0xffffffffu, vs, o);
    float rstd = rsqrtf(vs * (1.f / 128.f) + 1e-5f);
    float4 s4 = *reinterpret_cast<const float4*>(ls + lane * 4);
    float4 b4 = *reinterpret_cast<const float4*>(lb + lane * 4);
    float4 w4 = *reinterpret_cast<const float4*>(hw + lane * 4);
    float dot = (dx * rstd * s4.x + b4.x) * w4.x
              + (dy * rstd * s4.y + b4.y) * w4.y
              + (dz * rstd * s4.z + b4.z) * w4.z
              + (dw * rstd * s4.w + b4.w) * w4.w;
    #pragma unroll
    for (int o = 16; o; o >>= 1) dot += __shfl_xor_sync(0xffffffffu, dot, o);
    if (lane == 0) out[bidx] = dot + hb[0];
}

// ---------------- launch ----------------
extern "C" void kernel_launch(void* const* d_in, const int* in_sizes, int n_in,
                              void* d_out, int out_size)
{
    const float* x        = (const float*)d_in[0];
    const float* embed_w  = (const float*)d_in[1];
    const float* embed_b  = (const float*)d_in[2];
    const float* pos_emb  = (const float*)d_in[3];
    const float* cls      = (const float*)d_in[4];
    const float* in_w     = (const float*)d_in[5];
    const float* in_b     = (const float*)d_in[6];
    const float* out_w    = (const float*)d_in[7];
    const float* out_b    = (const float*)d_in[8];
    const float* ln1_s    = (const float*)d_in[9];
    const float* ln1_b    = (const float*)d_in[10];
    const float* ln2_s    = (const float*)d_in[11];
    const float* ln2_b    = (const float*)d_in[12];
    const float* ff1_w    = (const float*)d_in[13];
    const float* ff1_b    = (const float*)d_in[14];
    const float* ff2_w    = (const float*)d_in[15];
    const float* ff2_b    = (const float*)d_in[16];
    const float* hln_s    = (const float*)d_in[17];
    const float* hln_b    = (const float*)d_in[18];
    const float* head_w   = (const float*)d_in[19];
    const float* head_b   = (const float*)d_in[20];
    float* outp = (float*)d_out;

    float *h, *po, *pm, *pl;
    __half *hnh, *qkvh, *vt, *attnh, *ffh, *wh;
    cudaGetSymbolAddress((void**)&h,     g_h);
    cudaGetSymbolAddress((void**)&hnh,   g_hnh);
    cudaGetSymbolAddress((void**)&qkvh,  g_qkvh);
    cudaGetSymbolAddress((void**)&vt,    g_vt);
    cudaGetSymbolAddress((void**)&attnh, g_attnh);
    cudaGetSymbolAddress((void**)&ffh,   g_ffh);
    cudaGetSymbolAddress((void**)&po,    g_po);
    cudaGetSymbolAddress((void**)&pm,    g_pm);
    cudaGetSymbolAddress((void**)&pl,    g_pl);
    cudaGetSymbolAddress((void**)&wh,    g_wh);

    const int M = MROWS;
    const int MB128 = (M + 127) / 128;  // 33
    const int MB32  = (M + 31) / 32;    // 129
    const int QTILES = (S_LEN + BQ - 1) / BQ;

    // one-time-per-launch weight conversion fp32 -> fp16
    {
        int n4;
        n4 = NL * 384 * 128 / 4;
        convw_kernel<<<(n4 + 255) / 256, 256>>>(in_w,  wh + WOFF_IN,  n4);
        n4 = NL * 128 * 128 / 4;
        convw_kernel<<<(n4 + 255) / 256, 256>>>(out_w, wh + WOFF_OUT, n4);
        n4 = NL * 512 * 128 / 4;
        convw_kernel<<<(n4 + 255) / 256, 256>>>(ff1_w, wh + WOFF_FF1, n4);
        n4 = NL * 128 * 512 / 4;
        convw_kernel<<<(n4 + 255) / 256, 256>>>(ff2_w, wh + WOFF_FF2, n4);
    }

    // embedding + fused LN1(layer 0)
    embed_ln_kernel<<<dim3(S_LEN, BATCH), 128>>>(
        x, embed_w, embed_b, pos_emb, cls, ln1_s, ln1_b, h, hnh);

    for (int i = 0; i < NL; i++) {
        // QKV projection -> fp16 (Q pre-scaled, V transposed into vt)
        hgemm_kernel<false, true, true><<<dim3(384 / 64, MB128), 256>>>(
            hnh, wh + WOFF_IN + (size_t)i * 384 * 128, in_b + (size_t)i * 384,
            qkvh, vt, M, 384, 128);
        // split-S attention + merge
        attn_kernel<<<dim3(QTILES * SPLITS, N_HEADS, BATCH), 256>>>(qkvh, vt, po, pm, pl);
        attn_merge_kernel<<<dim3(S_LEN, BATCH), 128>>>(po, pm, pl, attnh);
        // out projection + residual + fused LN2
        hgemm_ln_kernel<true><<<MB32, 256>>>(
            attnh, wh + WOFF_OUT + (size_t)i * 128 * 128, out_b + (size_t)i * 128,
            ln2_s + i * D_MODEL, ln2_b + i * D_MODEL, h, hnh, M, 128);
        // FF1 + ReLU -> fp16
        hgemm_kernel<true, false, false><<<dim3(512 / 64, MB128), 256>>>(
            hnh, wh + WOFF_FF1 + (size_t)i * 512 * 128, ff1_b + (size_t)i * 512,
            ffh, nullptr, M, 512, 128);
        // FF2 + residual (+ fused LN1 of next layer)
        if (i + 1 < NL) {
            hgemm_ln_kernel<true><<<MB32, 256>>>(
                ffh, wh + WOFF_FF2 + (size_t)i * 128 * 512, ff2_b + (size_t)i * 128,
                ln1_s + (i + 1) * D_MODEL, ln1_b + (i + 1) * D_MODEL,
                h, hnh, M, 512);
        } else {
            hgemm_ln_kernel<false><<<MB32, 256>>>(
                ffh, wh + WOFF_FF2 + (size_t)i * 128 * 512, ff2_b + (size_t)i * 128,
                nullptr, nullptr, h, nullptr, M, 512);
        }
    }

    head_kernel<<<1, 64>>>(h, hln_s, hln_b, head_w, head_b, outp);
}

// round 9
// speedup vs baseline: 4.4009x; 1.0560x over previous
#include <cuda_runtime.h>
#include <cuda_fp16.h>
#include <math.h>

#define NL 3
#define D_MODEL 128
#define N_HEADS 4
#define DHEAD 32
#define DFF 512
#define DIN 64
#define BATCH 2
#define LSEQ 2048
#define S_LEN 2049
#define MROWS (BATCH * S_LEN)   // 4098
#define QK_SCALE 0.17677669529663687f

#define SPLITS 3
#define KCHUNK 704    // multiple of 64; 3*704 = 2112 >= 2049
#define VT_PITCH 2112

// ---------------- scratch (device globals; no allocation) ----------------
__device__ float  g_h[MROWS * D_MODEL];
__device__ __half g_hnh[MROWS * D_MODEL];
__device__ __half g_qkvh[MROWS * 3 * D_MODEL];
__device__ __half g_vt[BATCH * N_HEADS * DHEAD * VT_PITCH];
__device__ __half g_attnh[MROWS * D_MODEL];
__device__ __half g_ffh[MROWS * DFF];
__device__ float  g_po[SPLITS * BATCH * N_HEADS * S_LEN * DHEAD];
__device__ float  g_pm[SPLITS * BATCH * N_HEADS * S_LEN];
__device__ float  g_pl[SPLITS * BATCH * N_HEADS * S_LEN];
// fp16 weights: in_w | out_w | ff1_w | ff2_w
#define WOFF_IN  0
#define WOFF_OUT (NL * 384 * 128)
#define WOFF_FF1 (WOFF_OUT + NL * 128 * 128)
#define WOFF_FF2 (WOFF_FF1 + NL * 512 * 128)
#define WTOTAL   (WOFF_FF2 + NL * 128 * 512)
__device__ __half g_wh[WTOTAL];

// segment sizes in float4 units
#define CW_N0 (NL * 384 * 128 / 4)
#define CW_N1 (NL * 128 * 128 / 4)
#define CW_N2 (NL * 512 * 128 / 4)
#define CW_N3 (NL * 128 * 512 / 4)
#define CW_TOTAL (CW_N0 + CW_N1 + CW_N2 + CW_N3)

// ---------------- mma helper ----------------
__device__ __forceinline__ void mma16816(
    float c[4], const unsigned a[4], const unsigned b[2])
{
    asm volatile(
        "mma.sync.aligned.m16n8k16.row.col.f32.f16.f16.f32 "
        "{%0,%1,%2,%3}, {%4,%5,%6,%7}, {%8,%9}, {%0,%1,%2,%3};\n"
        : "+f"(c[0]), "+f"(c[1]), "+f"(c[2]), "+f"(c[3])
        : "r"(a[0]), "r"(a[1]), "r"(a[2]), "r"(a[3]),
          "r"(b[0]), "r"(b[1]));
}

// ---------------- fused weight fp32 -> fp16 conversion (one launch) ------
__global__ __launch_bounds__(256) void convw_all_kernel(
    const float* __restrict__ s0, const float* __restrict__ s1,
    const float* __restrict__ s2, const float* __restrict__ s3,
    __half* __restrict__ dst)
{
    int i = blockIdx.x * 256 + threadIdx.x;
    if (i >= CW_TOTAL) return;
    const float* src;
    int off, local = i;
    if (local < CW_N0)                { src = s0; off = WOFF_IN; }
    else if ((local -= CW_N0) < CW_N1){ src = s1; off = WOFF_OUT; }
    else if ((local -= CW_N1) < CW_N2){ src = s2; off = WOFF_FF1; }
    else { local -= CW_N2;              src = s3; off = WOFF_FF2; }
    float4 v = *reinterpret_cast<const float4*>(src + (size_t)local * 4);
    __half2 a = __floats2half2_rn(v.x, v.y);
    __half2 b = __floats2half2_rn(v.z, v.w);
    uint2 pk;
    pk.x = *reinterpret_cast<unsigned*>(&a);
    pk.y = *reinterpret_cast<unsigned*>(&b);
    *reinterpret_cast<uint2*>(dst + (size_t)off + (size_t)local * 4) = pk;
}

// ---------------- embedding + fused LN1(layer0) ----------------
__global__ __launch_bounds__(128) void embed_ln_kernel(
    const float* __restrict__ x, const float* __restrict__ ew,
    const float* __restrict__ eb, const float* __restrict__ pos,
    const float* __restrict__ cls, const float* __restrict__ lns,
    const float* __restrict__ lnb, float* __restrict__ h,
    __half* __restrict__ hn)
{
    __shared__ float xs[DIN];
    __shared__ float red[8];
    int s = blockIdx.x, b = blockIdx.y;
    int d = threadIdx.x;
    if (s > 0 && d < DIN) xs[d] = x[((size_t)b * LSEQ + (s - 1)) * DIN + d];
    __syncthreads();
    float val;
    if (s == 0) {
        val = cls[d] + pos[d];
    } else {
        float acc = 0.f;
        const float* wr = ew + (size_t)d * DIN;
        #pragma unroll
        for (int j = 0; j < DIN; j++) acc = fmaf(xs[j], wr[j], acc);
        val = acc + eb[d] + pos[(size_t)s * D_MODEL + d];
    }
    size_t row = (size_t)b * S_LEN + s;
    h[row * D_MODEL + d] = val;
    int w = d >> 5, lane = d & 31;
    float sv = val, qv = val * val;
    #pragma unroll
    for (int o = 16; o; o >>= 1) {
        sv += __shfl_xor_sync(0xffffffffu, sv, o);
        qv += __shfl_xor_sync(0xffffffffu, qv, o);
    }
    if (lane == 0) { red[w] = sv; red[4 + w] = qv; }
    __syncthreads();
    float sum = red[0] + red[1] + red[2] + red[3];
    float sq  = red[4] + red[5] + red[6] + red[7];
    float mean = sum * (1.f / 128.f);
    float rstd = rsqrtf(sq * (1.f / 128.f) - mean * mean + 1e-5f);
    hn[row * D_MODEL + d] = __float2half_rn((val - mean) * rstd * lns[d] + lnb[d]);
}

// ---------------- tensor-core GEMM (128x64 tile, fp16 W, reg-prefetch) ----
#define GPITCH 40
template <bool RELU, bool QSCALE, bool VSTORE>
__global__ __launch_bounds__(256) void hgemm_kernel(
    const __half* __restrict__ A, const __half* __restrict__ W,
    const float* __restrict__ bias, __half* __restrict__ C,
    __half* __restrict__ vT, int M, int N, int K)
{
    __shared__ __half As[128][GPITCH];
    __shared__ __half Ws[64][GPITCH];
    const int tid = threadIdx.x;
    const int warp = tid >> 5;
    const int lane = tid & 31;
    const int g = lane >> 2;
    const int tig = lane & 3;
    const int warp_m = warp >> 1;
    const int warp_n = warp & 1;
    const int m0 = blockIdx.y * 128;
    const int n0 = blockIdx.x * 64;
    const int NK = K / 32;
    const int wr = tid >> 2, wq = tid & 3;

    float c[2][4][4] = {};

    uint4 aReg[2], wReg;
    #pragma unroll
    for (int it = 0; it < 2; it++) {
        int idx = tid + it * 256;
        int r = idx >> 2, quad = idx & 3;
        int m = m0 + r;
        aReg[it] = (m < M)
            ? *reinterpret_cast<const uint4*>(A + (size_t)m * K + quad * 8)
            : make_uint4(0u, 0u, 0u, 0u);
    }
    wReg = *reinterpret_cast<const uint4*>(W + (size_t)(n0 + wr) * K + wq * 8);

    for (int kt = 0; kt < NK; kt++) {
        #pragma unroll
        for (int it = 0; it < 2; it++) {
            int idx = tid + it * 256;
            int r = idx >> 2, quad = idx & 3;
            *reinterpret_cast<uint4*>(&As[r][quad * 8]) = aReg[it];
        }
        *reinterpret_cast<uint4*>(&Ws[wr][wq * 8]) = wReg;
        __syncthreads();
        if (kt + 1 < NK) {
            int k0 = (kt + 1) * 32;
            #pragma unroll
            for (int it = 0; it < 2; it++) {
                int idx = tid + it * 256;
                int r = idx >> 2, quad = idx & 3;
                int m = m0 + r;
                aReg[it] = (m < M)
                    ? *reinterpret_cast<const uint4*>(A + (size_t)m * K + k0 + quad * 8)
                    : make_uint4(0u, 0u, 0u, 0u);
            }
            wReg = *reinterpret_cast<const uint4*>(W + (size_t)(n0 + wr) * K + k0 + wq * 8);
        }
        #pragma unroll
        for (int ks = 0; ks < 2; ks++) {
            unsigned a[2][4];
            #pragma unroll
            for (int mt = 0; mt < 2; mt++) {
                int rbase = warp_m * 32 + mt * 16;
                a[mt][0] = *reinterpret_cast<const unsigned*>(&As[rbase + g    ][ks * 16 + tig * 2]);
                a[mt][1] = *reinterpret_cast<const unsigned*>(&As[rbase + g + 8][ks * 16 + tig * 2]);
                a[mt][2] = *reinterpret_cast<const unsigned*>(&As[rbase + g    ][ks * 16 + tig * 2 + 8]);
                a[mt][3] = *reinterpret_cast<const unsigned*>(&As[rbase + g + 8][ks * 16 + tig * 2 + 8]);
            }
            #pragma unroll
            for (int nt = 0; nt < 4; nt++) {
                unsigned bfr[2];
                int nrow = warp_n * 32 + nt * 8 + g;
                bfr[0] = *reinterpret_cast<const unsigned*>(&Ws[nrow][ks * 16 + tig * 2]);
                bfr[1] = *reinterpret_cast<const unsigned*>(&Ws[nrow][ks * 16 + tig * 2 + 8]);
                mma16816(c[0][nt], a[0], bfr);
                mma16816(c[1][nt], a[1], bfr);
            }
        }
        __syncthreads();
    }

    #pragma unroll
    for (int mt = 0; mt < 2; mt++) {
        #pragma unroll
        for (int half_row = 0; half_row < 2; half_row++) {
            int m = m0 + warp_m * 32 + mt * 16 + g + half_row * 8;
            if (m >= M) continue;
            int bb = m / S_LEN, ss = m % S_LEN;
            #pragma unroll
            for (int nt = 0; nt < 4; nt++) {
                int n = n0 + warp_n * 32 + nt * 8 + tig * 2;
                float v0 = c[mt][nt][half_row * 2 + 0] + bias[n];
                float v1 = c[mt][nt][half_row * 2 + 1] + bias[n + 1];
                if (RELU) { v0 = fmaxf(v0, 0.f); v1 = fmaxf(v1, 0.f); }
                if (VSTORE && n >= 256) {
                    int hh = (n - 256) >> 5, dd = (n - 256) & 31;
                    __half* vbase = vT + ((size_t)(bb * N_HEADS + hh) * DHEAD + dd) * VT_PITCH + ss;
                    vbase[0] = __float2half_rn(v0);
                    vbase[VT_PITCH] = __float2half_rn(v1);
                } else {
                    if (QSCALE && n < 128) { v0 *= QK_SCALE; v1 *= QK_SCALE; }
                    __half2 hv = __floats2half2_rn(v0, v1);
                    *reinterpret_cast<unsigned*>(
                        C + (size_t)m * N + n) = *reinterpret_cast<unsigned*>(&hv);
                }
            }
        }
    }
}

// ---------------- GEMM + residual + fused row-LN (N=128, fp16 W) ---------
template <bool DO_LN>
__global__ __launch_bounds__(256) void hgemm_ln_kernel(
    const __half* __restrict__ A, const __half* __restrict__ W,
    const float* __restrict__ bias,
    const float* __restrict__ lns, const float* __restrict__ lnb,
    float* __restrict__ h, __half* __restrict__ hn, int M, int K)
{
    __shared__ __half As[32][GPITCH];
    __shared__ __half Ws[128][GPITCH];
    __shared__ float psum[32][4], psq[32][4];
    const int tid = threadIdx.x;
    const int warp = tid >> 5;
    const int lane = tid & 31;
    const int g = lane >> 2;
    const int tig = lane & 3;
    const int warp_m = warp >> 2;
    const int warp_n = warp & 3;
    const int m0 = blockIdx.x * 32;
    const int NK = K / 32;

    float c[4][4] = {};

    const bool aAct = tid < 128;
    const int ar = tid >> 2, aq = tid & 3;
    uint4 aReg = make_uint4(0u, 0u, 0u, 0u);
    if (aAct) {
        int m = m0 + ar;
        if (m < M) aReg = *reinterpret_cast<const uint4*>(A + (size_t)m * K + aq * 8);
    }
    uint4 wReg[2];
    #pragma unroll
    for (int it = 0; it < 2; it++) {
        int idx = tid + it * 256;
        int r = idx >> 2, q = idx & 3;
        wReg[it] = *reinterpret_cast<const uint4*>(W + (size_t)r * K + q * 8);
    }

    for (int kt = 0; kt < NK; kt++) {
        if (aAct) *reinterpret_cast<uint4*>(&As[ar][aq * 8]) = aReg;
        #pragma unroll
        for (int it = 0; it < 2; it++) {
            int idx = tid + it * 256;
            int r = idx >> 2, q = idx & 3;
            *reinterpret_cast<uint4*>(&Ws[r][q * 8]) = wReg[it];
        }
        __syncthreads();
        if (kt + 1 < NK) {
            int k0 = (kt + 1) * 32;
            if (aAct) {
                int m = m0 + ar;
                aReg = (m < M)
                    ? *reinterpret_cast<const uint4*>(A + (size_t)m * K + k0 + aq * 8)
                    : make_uint4(0u, 0u, 0u, 0u);
            }
            #pragma unroll
            for (int it = 0; it < 2; it++) {
                int idx = tid + it * 256;
                int r = idx >> 2, q = idx & 3;
                wReg[it] = *reinterpret_cast<const uint4*>(W + (size_t)r * K + k0 + q * 8);
            }
        }
        #pragma unroll
        for (int ks = 0; ks < 2; ks++) {
            unsigned a[4];
            int rbase = warp_m * 16;
            a[0] = *reinterpret_cast<const unsigned*>(&As[rbase + g    ][ks * 16 + tig * 2]);
            a[1] = *reinterpret_cast<const unsigned*>(&As[rbase + g + 8][ks * 16 + tig * 2]);
            a[2] = *reinterpret_cast<const unsigned*>(&As[rbase + g    ][ks * 16 + tig * 2 + 8]);
            a[3] = *reinterpret_cast<const unsigned*>(&As[rbase + g + 8][ks * 16 + tig * 2 + 8]);
            #pragma unroll
            for (int nt = 0; nt < 4; nt++) {
                unsigned bfr[2];
                int nrow = warp_n * 32 + nt * 8 + g;
                bfr[0] = *reinterpret_cast<const unsigned*>(&Ws[nrow][ks * 16 + tig * 2]);
                bfr[1] = *reinterpret_cast<const unsigned*>(&Ws[nrow][ks * 16 + tig * 2 + 8]);
                mma16816(c[nt], a, bfr);
            }
        }
        __syncthreads();
    }

    const int lr0 = warp_m * 16 + g, lr1 = lr0 + 8;
    const int mrow0 = m0 + lr0, mrow1 = m0 + lr1;
    #pragma unroll
    for (int nt = 0; nt < 4; nt++) {
        int n = warp_n * 32 + nt * 8 + tig * 2;
        float b0 = bias[n], b1 = bias[n + 1];
        if (mrow0 < M) {
            float2 r2 = *reinterpret_cast<const float2*>(h + (size_t)mrow0 * 128 + n);
            c[nt][0] += b0 + r2.x;
            c[nt][1] += b1 + r2.y;
            *reinterpret_cast<float2*>(h + (size_t)mrow0 * 128 + n) =
                make_float2(c[nt][0], c[nt][1]);
        }
        if (mrow1 < M) {
            float2 r2 = *reinterpret_cast<const float2*>(h + (size_t)mrow1 * 128 + n);
            c[nt][2] += b0 + r2.x;
            c[nt][3] += b1 + r2.y;
            *reinterpret_cast<float2*>(h + (size_t)mrow1 * 128 + n) =
                make_float2(c[nt][2], c[nt][3]);
        }
    }
    if (DO_LN) {
        float s0 = 0.f, q0 = 0.f, s1 = 0.f, q1 = 0.f;
        #pragma unroll
        for (int nt = 0; nt < 4; nt++) {
            s0 += c[nt][0] + c[nt][1];
            q0 += c[nt][0] * c[nt][0] + c[nt][1] * c[nt][1];
            s1 += c[nt][2] + c[nt][3];
            q1 += c[nt][2] * c[nt][2] + c[nt][3] * c[nt][3];
        }
        #pragma unroll
        for (int o = 1; o < 4; o <<= 1) {
            s0 += __shfl_xor_sync(0xffffffffu, s0, o);
            q0 += __shfl_xor_sync(0xffffffffu, q0, o);
            s1 += __shfl_xor_sync(0xffffffffu, s1, o);
            q1 += __shfl_xor_sync(0xffffffffu, q1, o);
        }
        if (tig == 0) {
            psum[lr0][warp_n] = s0; psq[lr0][warp_n] = q0;
            psum[lr1][warp_n] = s1; psq[lr1][warp_n] = q1;
        }
        __syncthreads();
        float sum0 = psum[lr0][0] + psum[lr0][1] + psum[lr0][2] + psum[lr0][3];
        float sq0  = psq[lr0][0] + psq[lr0][1] + psq[lr0][2] + psq[lr0][3];
        float sum1 = psum[lr1][0] + psum[lr1][1] + psum[lr1][2] + psum[lr1][3];
        float sq1  = psq[lr1][0] + psq[lr1][1] + psq[lr1][2] + psq[lr1][3];
        float mean0 = sum0 * (1.f / 128.f);
        float rstd0 = rsqrtf(sq0 * (1.f / 128.f) - mean0 * mean0 + 1e-5f);
        float mean1 = sum1 * (1.f / 128.f);
        float rstd1 = rsqrtf(sq1 * (1.f / 128.f) - mean1 * mean1 + 1e-5f);
        #pragma unroll
        for (int nt = 0; nt < 4; nt++) {
            int n = warp_n * 32 + nt * 8 + tig * 2;
            float g0 = lns[n], g1 = lns[n + 1];
            float bb0 = lnb[n], bb1 = lnb[n + 1];
            if (mrow0 < M) {
                __half2 hv = __floats2half2_rn(
                    (c[nt][0] - mean0) * rstd0 * g0 + bb0,
                    (c[nt][1] - mean0) * rstd0 * g1 + bb1);
                *reinterpret_cast<unsigned*>(hn + (size_t)mrow0 * 128 + n)
                    = *reinterpret_cast<unsigned*>(&hv);
            }
            if (mrow1 < M) {
                __half2 hv = __floats2half2_rn(
                    (c[nt][2] - mean1) * rstd1 * g0 + bb0,
                    (c[nt][3] - mean1) * rstd1 * g1 + bb1);
                *reinterpret_cast<unsigned*>(hn + (size_t)mrow1 * 128 + n)
                    = *reinterpret_cast<unsigned*>(&hv);
            }
        }
    }
}

// ---------------- split-S flash attention (double-buffered K/V) ----------
#define BQ 128
#define BK 64
#define QPITCH 40
#define VPITCH 72

__global__ __launch_bounds__(256, 3) void attn_kernel(
    const __half* __restrict__ qkv, const __half* __restrict__ vT,
    float* __restrict__ po, float* __restrict__ pm, float* __restrict__ pl)
{
    __shared__ __half Qs[BQ][QPITCH];
    __shared__ __half Kt[2][BK][QPITCH];
    __shared__ __half Vt[2][DHEAD][VPITCH];
    const int tid = threadIdx.x;
    const int warp = tid >> 5;
    const int lane = tid & 31;
    const int g = lane >> 2;
    const int tig = lane & 3;
    const int b = blockIdx.z, h = blockIdx.y;
    const int tile = blockIdx.x / SPLITS;
    const int split = blockIdx.x % SPLITS;
    const int q0 = tile * BQ;
    const int qbase = warp * 16;
    const int kstart = split * KCHUNK;
    const int kend = min(kstart + KCHUNK, S_LEN);
    const int ntile = (kend - kstart + BK - 1) / BK;

    #pragma unroll
    for (int idx = tid; idx < BQ * 4; idx += 256) {
        int r = idx >> 2, quad = idx & 3;
        int q = q0 + r;
        uint4 v = make_uint4(0u, 0u, 0u, 0u);
        if (q < S_LEN)
            v = *reinterpret_cast<const uint4*>(
                qkv + ((size_t)(b * S_LEN + q)) * 384 + h * 32 + quad * 8);
        *reinterpret_cast<uint4*>(&Qs[r][quad * 8]) = v;
    }

    const __half* Kbase = qkv + (size_t)b * S_LEN * 384 + 128 + h * 32;
    const __half* Vbase = vT + (size_t)(b * N_HEADS + h) * DHEAD * VT_PITCH;
    const int kr = tid >> 2, kq = tid & 3;
    const int vr = tid >> 3, vq = tid & 7;

    uint4 kreg, vreg;
    {
        int kg = kstart + kr;
        kreg = (kg < S_LEN)
            ? *reinterpret_cast<const uint4*>(Kbase + (size_t)kg * 384 + kq * 8)
            : make_uint4(0u, 0u, 0u, 0u);
        vreg = *reinterpret_cast<const uint4*>(Vbase + (size_t)vr * VT_PITCH + kstart + vq * 8);
    }
    *reinterpret_cast<uint4*>(&Kt[0][kr][kq * 8]) = kreg;
    *reinterpret_cast<uint4*>(&Vt[0][vr][vq * 8]) = vreg;
    __syncthreads();

    unsigned A[2][4];
    #pragma unroll
    for (int ks = 0; ks < 2; ks++) {
        A[ks][0] = *reinterpret_cast<const unsigned*>(&Qs[qbase + g    ][ks * 16 + tig * 2]);
        A[ks][1] = *reinterpret_cast<const unsigned*>(&Qs[qbase + g + 8][ks * 16 + tig * 2]);
        A[ks][2] = *reinterpret_cast<const unsigned*>(&Qs[qbase + g    ][ks * 16 + tig * 2 + 8]);
        A[ks][3] = *reinterpret_cast<const unsigned*>(&Qs[qbase + g + 8][ks * 16 + tig * 2 + 8]);
    }

    float m0 = -1e30f, m1 = -1e30f, l0 = 0.f, l1 = 0.f;
    float o[4][4] = {};

    for (int t = 0; t < ntile; t++) {
        const int kb = kstart + t * BK;
        const int buf = t & 1;
        if (t + 1 < ntile) {
            int kb2 = kb + BK;
            int kg = kb2 + kr;
            kreg = (kg < S_LEN)
                ? *reinterpret_cast<const uint4*>(Kbase + (size_t)kg * 384 + kq * 8)
                : make_uint4(0u, 0u, 0u, 0u);
            vreg = *reinterpret_cast<const uint4*>(Vbase + (size_t)vr * VT_PITCH + kb2 + vq * 8);
        }

        float s[8][4];
        #pragma unroll
        for (int j = 0; j < 8; j++) {
            s[j][0] = s[j][1] = s[j][2] = s[j][3] = 0.f;
            #pragma unroll
            for (int ks = 0; ks < 2; ks++) {
                unsigned bfr[2];
                bfr[0] = *reinterpret_cast<const unsigned*>(&Kt[buf][j * 8 + g][ks * 16 + tig * 2]);
                bfr[1] = *reinterpret_cast<const unsigned*>(&Kt[buf][j * 8 + g][ks * 16 + tig * 2 + 8]);
                mma16816(s[j], A[ks], bfr);
            }
        }
        if (kb + BK > S_LEN) {
            #pragma unroll
            for (int j = 0; j < 8; j++) {
                int key = kb + j * 8 + tig * 2;
                if (key >= S_LEN)     { s[j][0] = -1e30f; s[j][2] = -1e30f; }
                if (key + 1 >= S_LEN) { s[j][1] = -1e30f; s[j][3] = -1e30f; }
            }
        }

        float t0 = -1e30f, t1 = -1e30f;
        #pragma unroll
        for (int j = 0; j < 8; j++) {
            t0 = fmaxf(t0, fmaxf(s[j][0], s[j][1]));
            t1 = fmaxf(t1, fmaxf(s[j][2], s[j][3]));
        }
        t0 = fmaxf(t0, __shfl_xor_sync(0xffffffffu, t0, 1));
        t0 = fmaxf(t0, __shfl_xor_sync(0xffffffffu, t0, 2));
        t1 = fmaxf(t1, __shfl_xor_sync(0xffffffffu, t1, 1));
        t1 = fmaxf(t1, __shfl_xor_sync(0xffffffffu, t1, 2));
        float mn0 = fmaxf(m0, t0), mn1 = fmaxf(m1, t1);
        float c0 = __expf(m0 - mn0), c1 = __expf(m1 - mn1);
        unsigned ph[8][2];
        float ps0 = 0.f, ps1 = 0.f;
        #pragma unroll
        for (int j = 0; j < 8; j++) {
            __half2 h2a = __floats2half2_rn(__expf(s[j][0] - mn0), __expf(s[j][1] - mn0));
            __half2 h2b = __floats2half2_rn(__expf(s[j][2] - mn1), __expf(s[j][3] - mn1));
            ph[j][0] = *reinterpret_cast<unsigned*>(&h2a);
            ph[j][1] = *reinterpret_cast<unsigned*>(&h2b);
            float2 fa = __half22float2(h2a);
            float2 fb = __half22float2(h2b);
            ps0 += fa.x + fa.y;
            ps1 += fb.x + fb.y;
        }
        ps0 += __shfl_xor_sync(0xffffffffu, ps0, 1);
        ps0 += __shfl_xor_sync(0xffffffffu, ps0, 2);
        ps1 += __shfl_xor_sync(0xffffffffu, ps1, 1);
        ps1 += __shfl_xor_sync(0xffffffffu, ps1, 2);
        l0 = l0 * c0 + ps0;
        l1 = l1 * c1 + ps1;
        m0 = mn0; m1 = mn1;
        #pragma unroll
        for (int nt = 0; nt < 4; nt++) {
            o[nt][0] *= c0; o[nt][1] *= c0;
            o[nt][2] *= c1; o[nt][3] *= c1;
        }

        #pragma unroll
        for (int kt = 0; kt < 4; kt++) {
            unsigned pa[4] = { ph[2 * kt][0], ph[2 * kt][1],
                               ph[2 * kt + 1][0], ph[2 * kt + 1][1] };
            #pragma unroll
            for (int nt = 0; nt < 4; nt++) {
                unsigned bfr[2];
                bfr[0] = *reinterpret_cast<const unsigned*>(&Vt[buf][nt * 8 + g][kt * 16 + tig * 2]);
                bfr[1] = *reinterpret_cast<const unsigned*>(&Vt[buf][nt * 8 + g][kt * 16 + tig * 2 + 8]);
                mma16816(o[nt], pa, bfr);
            }
        }
        if (t + 1 < ntile) {
            *reinterpret_cast<uint4*>(&Kt[buf ^ 1][kr][kq * 8]) = kreg;
            *reinterpret_cast<uint4*>(&Vt[buf ^ 1][vr][vq * 8]) = vreg;
        }
        __syncthreads();
    }

    const size_t pbase = (((size_t)split * BATCH + b) * N_HEADS + h) * S_LEN;
    int qa = q0 + qbase + g;
    int qb2 = qa + 8;
    if (qa < S_LEN) {
        #pragma unroll
        for (int nt = 0; nt < 4; nt++) {
            float2 v = make_float2(o[nt][0], o[nt][1]);
            *reinterpret_cast<float2*>(po + (pbase + qa) * DHEAD + nt * 8 + tig * 2) = v;
        }
        if (tig == 0) { pm[pbase + qa] = m0; pl[pbase + qa] = l0; }
    }
    if (qb2 < S_LEN) {
        #pragma unroll
        for (int nt = 0; nt < 4; nt++) {
            float2 v = make_float2(o[nt][2], o[nt][3]);
            *reinterpret_cast<float2*>(po + (pbase + qb2) * DHEAD + nt * 8 + tig * 2) = v;
        }
        if (tig == 0) { pm[pbase + qb2] = m1; pl[pbase + qb2] = l1; }
    }
}

// ---------------- merge split-S partials -> fp16 (float4 vectorized) -----
__global__ __launch_bounds__(128) void attn_merge_kernel(
    const float* __restrict__ po, const float* __restrict__ pm,
    const float* __restrict__ pl, __half* __restrict__ out)
{
    int idx = blockIdx.x * 128 + threadIdx.x;   // (row, d4-group)
    int rowid = idx >> 5;
    int t = idx & 31;
    if (rowid >= MROWS) return;
    int b = rowid / S_LEN, q = rowid % S_LEN;
    int hh = t >> 3;            // head
    int dd = (t & 7) * 4;       // dim within head (4-aligned)
    const size_t row = ((size_t)b * N_HEADS + hh) * S_LEN + q;
    const size_t stride = (size_t)BATCH * N_HEADS * S_LEN;
    float ms[SPLITS], ls[SPLITS];
    float M = -1e30f;
    #pragma unroll
    for (int s = 0; s < SPLITS; s++) {
        ms[s] = pm[row + s * stride];
        ls[s] = pl[row + s * stride];
        M = fmaxf(M, ms[s]);
    }
    float L = 0.f;
    float4 O = make_float4(0.f, 0.f, 0.f, 0.f);
    #pragma unroll
    for (int s = 0; s < SPLITS; s++) {
        float w = __expf(ms[s] - M);
        L += w * ls[s];
        float4 p = *reinterpret_cast<const float4*>(
            po + (row + s * stride) * DHEAD + dd);
        O.x += w * p.x; O.y += w * p.y; O.z += w * p.z; O.w += w * p.w;
    }
    float inv = 1.f / L;
    __half2 h2a = __floats2half2_rn(O.x * inv, O.y * inv);
    __half2 h2b = __floats2half2_rn(O.z * inv, O.w * inv);
    uint2 pk;
    pk.x = *reinterpret_cast<unsigned*>(&h2a);
    pk.y = *reinterpret_cast<unsigned*>(&h2b);
    *reinterpret_cast<uint2*>(out + (size_t)rowid * D_MODEL + t * 4) = pk;
}

// ---------------- head ----------------
__global__ __launch_bounds__(64) void head_kernel(
    const float* __restrict__ h, const float* __restrict__ ls,
    const float* __restrict__ lb, const float* __restrict__ hw,
    const float* __restrict__ hb, float* __restrict__ out)
{
    int bidx = threadIdx.x >> 5;
    if (bidx >= BATCH) return;
    int lane = threadIdx.x & 31;
    const float* xr = h + (size_t)bidx * S_LEN * D_MODEL;
    float4 v = *reinterpret_cast<const float4*>(xr + lane * 4);
    float sum = v.x + v.y + v.z + v.w;
    #pragma unroll
    for (int o = 16; o; o >>= 1) sum += __shfl_xor_sync(0xffffffffu, sum, o);
    float mean = sum * (1.f / 128.f);
    float dx = v.x - mean, dy = v.y - mean, dz = v.z - mean, dw = v.w - mean;
    float vs = dx * dx + dy * dy + dz * dz + dw * dw;
    #pragma unroll
    for (int o = 16; o; o >>= 1) vs += __shfl_xor_sync(0xffffffffu, vs, o);
    float rstd = rsqrtf(vs * (1.f / 128.f) + 1e-5f);
    float4 s4 = *reinterpret_cast<const float4*>(ls + lane * 4);
    float4 b4 = *reinterpret_cast<const float4*>(lb + lane * 4);
    float4 w4 = *reinterpret_cast<const float4*>(hw + lane * 4);
    float dot = (dx * rstd * s4.x + b4.x) * w4.x
              + (dy * rstd * s4.y + b4.y) * w4.y
              + (dz * rstd * s4.z + b4.z) * w4.z
              + (dw * rstd * s4.w + b4.w) * w4.w;
    #pragma unroll
    for (int o = 16; o; o >>= 1) dot += __shfl_xor_sync(0xffffffffu, dot, o);
    if (lane == 0) out[bidx] = dot + hb[0];
}

// ---------------- launch ----------------
extern "C" void kernel_launch(void* const* d_in, const int* in_sizes, int n_in,
                              void* d_out, int out_size)
{
    const float* x        = (const float*)d_in[0];
    const float* embed_w  = (const float*)d_in[1];
    const float* embed_b  = (const float*)d_in[2];
    const float* pos_emb  = (const float*)d_in[3];
    const float* cls      = (const float*)d_in[4];
    const float* in_w     = (const float*)d_in[5];
    const float* in_b     = (const float*)d_in[6];
    const float* out_w    = (const float*)d_in[7];
    const float* out_b    = (const float*)d_in[8];
    const float* ln1_s    = (const float*)d_in[9];
    const float* ln1_b    = (const float*)d_in[10];
    const float* ln2_s    = (const float*)d_in[11];
    const float* ln2_b    = (const float*)d_in[12];
    const float* ff1_w    = (const float*)d_in[13];
    const float* ff1_b    = (const float*)d_in[14];
    const float* ff2_w    = (const float*)d_in[15];
    const float* ff2_b    = (const float*)d_in[16];
    const float* hln_s    = (const float*)d_in[17];
    const float* hln_b    = (const float*)d_in[18];
    const float* head_w   = (const float*)d_in[19];
    const float* head_b   = (const float*)d_in[20];
    float* outp = (float*)d_out;

    float *h, *po, *pm, *pl;
    __half *hnh, *qkvh, *vt, *attnh, *ffh, *wh;
    cudaGetSymbolAddress((void**)&h,     g_h);
    cudaGetSymbolAddress((void**)&hnh,   g_hnh);
    cudaGetSymbolAddress((void**)&qkvh,  g_qkvh);
    cudaGetSymbolAddress((void**)&vt,    g_vt);
    cudaGetSymbolAddress((void**)&attnh, g_attnh);
    cudaGetSymbolAddress((void**)&ffh,   g_ffh);
    cudaGetSymbolAddress((void**)&po,    g_po);
    cudaGetSymbolAddress((void**)&pm,    g_pm);
    cudaGetSymbolAddress((void**)&pl,    g_pl);
    cudaGetSymbolAddress((void**)&wh,    g_wh);

    const int M = MROWS;
    const int MB128 = (M + 127) / 128;
    const int MB32  = (M + 31) / 32;
    const int QTILES = (S_LEN + BQ - 1) / BQ;

    // one fused weight-conversion launch
    convw_all_kernel<<<(CW_TOTAL + 255) / 256, 256>>>(in_w, out_w, ff1_w, ff2_w, wh);

    // embedding + fused LN1(layer 0)
    embed_ln_kernel<<<dim3(S_LEN, BATCH), 128>>>(
        x, embed_w, embed_b, pos_emb, cls, ln1_s, ln1_b, h, hnh);

    for (int i = 0; i < NL; i++) {
        hgemm_kernel<false, true, true><<<dim3(384 / 64, MB128), 256>>>(
            hnh, wh + WOFF_IN + (size_t)i * 384 * 128, in_b + (size_t)i * 384,
            qkvh, vt, M, 384, 128);
        attn_kernel<<<dim3(QTILES * SPLITS, N_HEADS, BATCH), 256>>>(qkvh, vt, po, pm, pl);
        attn_merge_kernel<<<(MROWS * 32 + 127) / 128, 128>>>(po, pm, pl, attnh);
        hgemm_ln_kernel<true><<<MB32, 256>>>(
            attnh, wh + WOFF_OUT + (size_t)i * 128 * 128, out_b + (size_t)i * 128,
            ln2_s + i * D_MODEL, ln2_b + i * D_MODEL, h, hnh, M, 128);
        hgemm_kernel<true, false, false><<<dim3(512 / 64, MB128), 256>>>(
            hnh, wh + WOFF_FF1 + (size_t)i * 512 * 128, ff1_b + (size_t)i * 512,
            ffh, nullptr, M, 512, 128);
        if (i + 1 < NL) {
            hgemm_ln_kernel<true><<<MB32, 256>>>(
                ffh, wh + WOFF_FF2 + (size_t)i * 128 * 512, ff2_b + (size_t)i * 128,
                ln1_s + (i + 1) * D_MODEL, ln1_b + (i + 1) * D_MODEL,
                h, hnh, M, 512);
        } else {
            hgemm_ln_kernel<false><<<MB32, 256>>>(
                ffh, wh + WOFF_FF2 + (size_t)i * 128 * 512, ff2_b + (size_t)i * 128,
                nullptr, nullptr, h, nullptr, M, 512);
        }
    }

    head_kernel<<<1, 64>>>(h, hln_s, hln_b, head_w, head_b, outp);
}

// round 10
// speedup vs baseline: 4.6505x; 1.0567x over previous
#include <cuda_runtime.h>
#include <cuda_fp16.h>
#include <math.h>

#define NL 3
#define D_MODEL 128
#define N_HEADS 4
#define DHEAD 32
#define DFF 512
#define DIN 64
#define BATCH 2
#define LSEQ 2048
#define S_LEN 2049
#define MROWS (BATCH * S_LEN)   // 4098
#define QK_SCALE 0.17677669529663687f

#define SPLITS 3
#define KCHUNK 704    // multiple of 64; 3*704 = 2112 >= 2049
#define VT_PITCH 2112
#define PSTRIDE ((size_t)BATCH * N_HEADS * S_LEN)

// ---------------- scratch (device globals; no allocation) ----------------
__device__ float  g_h[MROWS * D_MODEL];
__device__ __half g_hnh[MROWS * D_MODEL];
__device__ __half g_qkvh[MROWS * 3 * D_MODEL];
__device__ __half g_vt[BATCH * N_HEADS * DHEAD * VT_PITCH];
__device__ __half g_ffh[MROWS * DFF];
__device__ float  g_po[SPLITS * BATCH * N_HEADS * S_LEN * DHEAD];
__device__ float  g_pl[SPLITS * BATCH * N_HEADS * S_LEN];
// fp16 weights: in_w | out_w | ff1_w | ff2_w
#define WOFF_IN  0
#define WOFF_OUT (NL * 384 * 128)
#define WOFF_FF1 (WOFF_OUT + NL * 128 * 128)
#define WOFF_FF2 (WOFF_FF1 + NL * 512 * 128)
#define WTOTAL   (WOFF_FF2 + NL * 128 * 512)
__device__ __half g_wh[WTOTAL];

// segment sizes in float4 units
#define CW_N0 (NL * 384 * 128 / 4)
#define CW_N1 (NL * 128 * 128 / 4)
#define CW_N2 (NL * 512 * 128 / 4)
#define CW_N3 (NL * 128 * 512 / 4)
#define CW_TOTAL (CW_N0 + CW_N1 + CW_N2 + CW_N3)

// ---------------- mma helper ----------------
__device__ __forceinline__ void mma16816(
    float c[4], const unsigned a[4], const unsigned b[2])
{
    asm volatile(
        "mma.sync.aligned.m16n8k16.row.col.f32.f16.f16.f32 "
        "{%0,%1,%2,%3}, {%4,%5,%6,%7}, {%8,%9}, {%0,%1,%2,%3};\n"
        : "+f"(c[0]), "+f"(c[1]), "+f"(c[2]), "+f"(c[3])
        : "r"(a[0]), "r"(a[1]), "r"(a[2]), "r"(a[3]),
          "r"(b[0]), "r"(b[1]));
}

// ---------------- fused weight fp32 -> fp16 conversion (one launch) ------
__global__ __launch_bounds__(256) void convw_all_kernel(
    const float* __restrict__ s0, const float* __restrict__ s1,
    const float* __restrict__ s2, const float* __restrict__ s3,
    __half* __restrict__ dst)
{
    int i = blockIdx.x * 256 + threadIdx.x;
    if (i >= CW_TOTAL) return;
    const float* src;
    int off, local = i;
    if (local < CW_N0)                { src = s0; off = WOFF_IN; }
    else if ((local -= CW_N0) < CW_N1){ src = s1; off = WOFF_OUT; }
    else if ((local -= CW_N1) < CW_N2){ src = s2; off = WOFF_FF1; }
    else { local -= CW_N2;              src = s3; off = WOFF_FF2; }
    float4 v = *reinterpret_cast<const float4*>(src + (size_t)local * 4);
    __half2 a = __floats2half2_rn(v.x, v.y);
    __half2 b = __floats2half2_rn(v.z, v.w);
    uint2 pk;
    pk.x = *reinterpret_cast<unsigned*>(&a);
    pk.y = *reinterpret_cast<unsigned*>(&b);
    *reinterpret_cast<uint2*>(dst + (size_t)off + (size_t)local * 4) = pk;
}

// ---------------- embedding + fused LN1(layer0) ----------------
__global__ __launch_bounds__(128) void embed_ln_kernel(
    const float* __restrict__ x, const float* __restrict__ ew,
    const float* __restrict__ eb, const float* __restrict__ pos,
    const float* __restrict__ cls, const float* __restrict__ lns,
    const float* __restrict__ lnb, float* __restrict__ h,
    __half* __restrict__ hn)
{
    __shared__ float xs[DIN];
    __shared__ float red[8];
    int s = blockIdx.x, b = blockIdx.y;
    int d = threadIdx.x;
    if (s > 0 && d < DIN) xs[d] = x[((size_t)b * LSEQ + (s - 1)) * DIN + d];
    __syncthreads();
    float val;
    if (s == 0) {
        val = cls[d] + pos[d];
    } else {
        float acc = 0.f;
        const float* wr = ew + (size_t)d * DIN;
        #pragma unroll
        for (int j = 0; j < DIN; j++) acc = fmaf(xs[j], wr[j], acc);
        val = acc + eb[d] + pos[(size_t)s * D_MODEL + d];
    }
    size_t row = (size_t)b * S_LEN + s;
    h[row * D_MODEL + d] = val;
    int w = d >> 5, lane = d & 31;
    float sv = val, qv = val * val;
    #pragma unroll
    for (int o = 16; o; o >>= 1) {
        sv += __shfl_xor_sync(0xffffffffu, sv, o);
        qv += __shfl_xor_sync(0xffffffffu, qv, o);
    }
    if (lane == 0) { red[w] = sv; red[4 + w] = qv; }
    __syncthreads();
    float sum = red[0] + red[1] + red[2] + red[3];
    float sq  = red[4] + red[5] + red[6] + red[7];
    float mean = sum * (1.f / 128.f);
    float rstd = rsqrtf(sq * (1.f / 128.f) - mean * mean + 1e-5f);
    hn[row * D_MODEL + d] = __float2half_rn((val - mean) * rstd * lns[d] + lnb[d]);
}

// ---------------- tensor-core GEMM (128x64 tile, fp16 W, reg-prefetch) ----
#define GPITCH 40
template <bool RELU, bool QSCALE, bool VSTORE>
__global__ __launch_bounds__(256) void hgemm_kernel(
    const __half* __restrict__ A, const __half* __restrict__ W,
    const float* __restrict__ bias, __half* __restrict__ C,
    __half* __restrict__ vT, int M, int N, int K)
{
    __shared__ __half As[128][GPITCH];
    __shared__ __half Ws[64][GPITCH];
    const int tid = threadIdx.x;
    const int warp = tid >> 5;
    const int lane = tid & 31;
    const int g = lane >> 2;
    const int tig = lane & 3;
    const int warp_m = warp >> 1;
    const int warp_n = warp & 1;
    const int m0 = blockIdx.y * 128;
    const int n0 = blockIdx.x * 64;
    const int NK = K / 32;
    const int wr = tid >> 2, wq = tid & 3;

    float c[2][4][4] = {};

    uint4 aReg[2], wReg;
    #pragma unroll
    for (int it = 0; it < 2; it++) {
        int idx = tid + it * 256;
        int r = idx >> 2, quad = idx & 3;
        int m = m0 + r;
        aReg[it] = (m < M)
            ? *reinterpret_cast<const uint4*>(A + (size_t)m * K + quad * 8)
            : make_uint4(0u, 0u, 0u, 0u);
    }
    wReg = *reinterpret_cast<const uint4*>(W + (size_t)(n0 + wr) * K + wq * 8);

    for (int kt = 0; kt < NK; kt++) {
        #pragma unroll
        for (int it = 0; it < 2; it++) {
            int idx = tid + it * 256;
            int r = idx >> 2, quad = idx & 3;
            *reinterpret_cast<uint4*>(&As[r][quad * 8]) = aReg[it];
        }
        *reinterpret_cast<uint4*>(&Ws[wr][wq * 8]) = wReg;
        __syncthreads();
        if (kt + 1 < NK) {
            int k0 = (kt + 1) * 32;
            #pragma unroll
            for (int it = 0; it < 2; it++) {
                int idx = tid + it * 256;
                int r = idx >> 2, quad = idx & 3;
                int m = m0 + r;
                aReg[it] = (m < M)
                    ? *reinterpret_cast<const uint4*>(A + (size_t)m * K + k0 + quad * 8)
                    : make_uint4(0u, 0u, 0u, 0u);
            }
            wReg = *reinterpret_cast<const uint4*>(W + (size_t)(n0 + wr) * K + k0 + wq * 8);
        }
        #pragma unroll
        for (int ks = 0; ks < 2; ks++) {
            unsigned a[2][4];
            #pragma unroll
            for (int mt = 0; mt < 2; mt++) {
                int rbase = warp_m * 32 + mt * 16;
                a[mt][0] = *reinterpret_cast<const unsigned*>(&As[rbase + g    ][ks * 16 + tig * 2]);
                a[mt][1] = *reinterpret_cast<const unsigned*>(&As[rbase + g + 8][ks * 16 + tig * 2]);
                a[mt][2] = *reinterpret_cast<const unsigned*>(&As[rbase + g    ][ks * 16 + tig * 2 + 8]);
                a[mt][3] = *reinterpret_cast<const unsigned*>(&As[rbase + g + 8][ks * 16 + tig * 2 + 8]);
            }
            #pragma unroll
            for (int nt = 0; nt < 4; nt++) {
                unsigned bfr[2];
                int nrow = warp_n * 32 + nt * 8 + g;
                bfr[0] = *reinterpret_cast<const unsigned*>(&Ws[nrow][ks * 16 + tig * 2]);
                bfr[1] = *reinterpret_cast<const unsigned*>(&Ws[nrow][ks * 16 + tig * 2 + 8]);
                mma16816(c[0][nt], a[0], bfr);
                mma16816(c[1][nt], a[1], bfr);
            }
        }
        __syncthreads();
    }

    #pragma unroll
    for (int mt = 0; mt < 2; mt++) {
        #pragma unroll
        for (int half_row = 0; half_row < 2; half_row++) {
            int m = m0 + warp_m * 32 + mt * 16 + g + half_row * 8;
            if (m >= M) continue;
            int bb = m / S_LEN, ss = m % S_LEN;
            #pragma unroll
            for (int nt = 0; nt < 4; nt++) {
                int n = n0 + warp_n * 32 + nt * 8 + tig * 2;
                float v0 = c[mt][nt][half_row * 2 + 0] + bias[n];
                float v1 = c[mt][nt][half_row * 2 + 1] + bias[n + 1];
                if (RELU) { v0 = fmaxf(v0, 0.f); v1 = fmaxf(v1, 0.f); }
                if (VSTORE && n >= 256) {
                    int hh = (n - 256) >> 5, dd = (n - 256) & 31;
                    __half* vbase = vT + ((size_t)(bb * N_HEADS + hh) * DHEAD + dd) * VT_PITCH + ss;
                    vbase[0] = __float2half_rn(v0);
                    vbase[VT_PITCH] = __float2half_rn(v1);
                } else {
                    if (QSCALE && n < 128) { v0 *= QK_SCALE; v1 *= QK_SCALE; }
                    __half2 hv = __floats2half2_rn(v0, v1);
                    *reinterpret_cast<unsigned*>(
                        C + (size_t)m * N + n) = *reinterpret_cast<unsigned*>(&hv);
                }
            }
        }
    }
}

// ---------------- GEMM + residual + fused row-LN (N=128, fp16 W) ---------
// MERGE_A: A tile built in smem from split-S partials (po, pl), K=128.
template <bool DO_LN, bool MERGE_A>
__global__ __launch_bounds__(256) void hgemm_ln_kernel(
    const __half* __restrict__ A,
    const float* __restrict__ po, const float* __restrict__ pl,
    const __half* __restrict__ W, const float* __restrict__ bias,
    const float* __restrict__ lns, const float* __restrict__ lnb,
    float* __restrict__ h, __half* __restrict__ hn, int M, int K)
{
    constexpr int APITCH = MERGE_A ? 136 : GPITCH;
    __shared__ __half As[32][APITCH];
    __shared__ __half Ws[128][GPITCH];
    __shared__ float psum[32][4], psq[32][4];
    const int tid = threadIdx.x;
    const int warp = tid >> 5;
    const int lane = tid & 31;
    const int g = lane >> 2;
    const int tig = lane & 3;
    const int warp_m = warp >> 2;
    const int warp_n = warp & 3;
    const int m0 = blockIdx.x * 32;
    const int NK = K / 32;

    float c[4][4] = {};

    // ---- A staging ----
    const bool aAct = tid < 128;
    const int ar = tid >> 2, aq = tid & 3;
    uint4 aReg = make_uint4(0u, 0u, 0u, 0u);

    if (MERGE_A) {
        // build full 32x128 A tile from split partials: O = sum_s po_s / sum_s l_s
        int row = tid >> 3;               // 0..31
        int dseg = (tid & 7) * 16;        // 0..112, within one head
        int mrow = m0 + row;
        uint4 z = make_uint4(0u, 0u, 0u, 0u);
        if (mrow < M) {
            int bb = mrow / S_LEN, qq = mrow % S_LEN;
            int hh = dseg >> 5, dd = dseg & 31;
            size_t prow = ((size_t)bb * N_HEADS + hh) * S_LEN + qq;
            float linv = 1.f / (pl[prow] + pl[prow + PSTRIDE] + pl[prow + 2 * PSTRIDE]);
            float acc[16];
            #pragma unroll
            for (int t = 0; t < 4; t++) {
                float4 p0 = *reinterpret_cast<const float4*>(po + prow * DHEAD + dd + t * 4);
                float4 p1 = *reinterpret_cast<const float4*>(po + (prow + PSTRIDE) * DHEAD + dd + t * 4);
                float4 p2 = *reinterpret_cast<const float4*>(po + (prow + 2 * PSTRIDE) * DHEAD + dd + t * 4);
                acc[t * 4 + 0] = (p0.x + p1.x + p2.x) * linv;
                acc[t * 4 + 1] = (p0.y + p1.y + p2.y) * linv;
                acc[t * 4 + 2] = (p0.z + p1.z + p2.z) * linv;
                acc[t * 4 + 3] = (p0.w + p1.w + p2.w) * linv;
            }
            unsigned pk[8];
            #pragma unroll
            for (int t = 0; t < 8; t++) {
                __half2 hv = __floats2half2_rn(acc[t * 2], acc[t * 2 + 1]);
                pk[t] = *reinterpret_cast<unsigned*>(&hv);
            }
            *reinterpret_cast<uint4*>(&As[row][dseg]) = make_uint4(pk[0], pk[1], pk[2], pk[3]);
            *reinterpret_cast<uint4*>(&As[row][dseg + 8]) = make_uint4(pk[4], pk[5], pk[6], pk[7]);
        } else {
            *reinterpret_cast<uint4*>(&As[row][dseg]) = z;
            *reinterpret_cast<uint4*>(&As[row][dseg + 8]) = z;
        }
    } else {
        if (aAct) {
            int m = m0 + ar;
            if (m < M) aReg = *reinterpret_cast<const uint4*>(A + (size_t)m * K + aq * 8);
        }
    }

    uint4 wReg[2];
    #pragma unroll
    for (int it = 0; it < 2; it++) {
        int idx = tid + it * 256;
        int r = idx >> 2, q = idx & 3;
        wReg[it] = *reinterpret_cast<const uint4*>(W + (size_t)r * K + q * 8);
    }

    for (int kt = 0; kt < NK; kt++) {
        if (!MERGE_A && aAct) *reinterpret_cast<uint4*>(&As[ar][aq * 8]) = aReg;
        #pragma unroll
        for (int it = 0; it < 2; it++) {
            int idx = tid + it * 256;
            int r = idx >> 2, q = idx & 3;
            *reinterpret_cast<uint4*>(&Ws[r][q * 8]) = wReg[it];
        }
        __syncthreads();
        if (kt + 1 < NK) {
            int k0 = (kt + 1) * 32;
            if (!MERGE_A && aAct) {
                int m = m0 + ar;
                aReg = (m < M)
                    ? *reinterpret_cast<const uint4*>(A + (size_t)m * K + k0 + aq * 8)
                    : make_uint4(0u, 0u, 0u, 0u);
            }
            #pragma unroll
            for (int it = 0; it < 2; it++) {
                int idx = tid + it * 256;
                int r = idx >> 2, q = idx & 3;
                wReg[it] = *reinterpret_cast<const uint4*>(W + (size_t)r * K + k0 + q * 8);
            }
        }
        const int acol = MERGE_A ? kt * 32 : 0;
        #pragma unroll
        for (int ks = 0; ks < 2; ks++) {
            unsigned a[4];
            int rbase = warp_m * 16;
            a[0] = *reinterpret_cast<const unsigned*>(&As[rbase + g    ][acol + ks * 16 + tig * 2]);
            a[1] = *reinterpret_cast<const unsigned*>(&As[rbase + g + 8][acol + ks * 16 + tig * 2]);
            a[2] = *reinterpret_cast<const unsigned*>(&As[rbase + g    ][acol + ks * 16 + tig * 2 + 8]);
            a[3] = *reinterpret_cast<const unsigned*>(&As[rbase + g + 8][acol + ks * 16 + tig * 2 + 8]);
            #pragma unroll
            for (int nt = 0; nt < 4; nt++) {
                unsigned bfr[2];
                int nrow = warp_n * 32 + nt * 8 + g;
                bfr[0] = *reinterpret_cast<const unsigned*>(&Ws[nrow][ks * 16 + tig * 2]);
                bfr[1] = *reinterpret_cast<const unsigned*>(&Ws[nrow][ks * 16 + tig * 2 + 8]);
                mma16816(c[nt], a, bfr);
            }
        }
        __syncthreads();
    }

    const int lr0 = warp_m * 16 + g, lr1 = lr0 + 8;
    const int mrow0 = m0 + lr0, mrow1 = m0 + lr1;
    #pragma unroll
    for (int nt = 0; nt < 4; nt++) {
        int n = warp_n * 32 + nt * 8 + tig * 2;
        float b0 = bias[n], b1 = bias[n + 1];
        if (mrow0 < M) {
            float2 r2 = *reinterpret_cast<const float2*>(h + (size_t)mrow0 * 128 + n);
            c[nt][0] += b0 + r2.x;
            c[nt][1] += b1 + r2.y;
            *reinterpret_cast<float2*>(h + (size_t)mrow0 * 128 + n) =
                make_float2(c[nt][0], c[nt][1]);
        }
        if (mrow1 < M) {
            float2 r2 = *reinterpret_cast<const float2*>(h + (size_t)mrow1 * 128 + n);
            c[nt][2] += b0 + r2.x;
            c[nt][3] += b1 + r2.y;
            *reinterpret_cast<float2*>(h + (size_t)mrow1 * 128 + n) =
                make_float2(c[nt][2], c[nt][3]);
        }
    }
    if (DO_LN) {
        float s0 = 0.f, q0 = 0.f, s1 = 0.f, q1 = 0.f;
        #pragma unroll
        for (int nt = 0; nt < 4; nt++) {
            s0 += c[nt][0] + c[nt][1];
            q0 += c[nt][0] * c[nt][0] + c[nt][1] * c[nt][1];
            s1 += c[nt][2] + c[nt][3];
            q1 += c[nt][2] * c[nt][2] + c[nt][3] * c[nt][3];
        }
        #pragma unroll
        for (int o = 1; o < 4; o <<= 1) {
            s0 += __shfl_xor_sync(0xffffffffu, s0, o);
            q0 += __shfl_xor_sync(0xffffffffu, q0, o);
            s1 += __shfl_xor_sync(0xffffffffu, s1, o);
            q1 += __shfl_xor_sync(0xffffffffu, q1, o);
        }
        if (tig == 0) {
            psum[lr0][warp_n] = s0; psq[lr0][warp_n] = q0;
            psum[lr1][warp_n] = s1; psq[lr1][warp_n] = q1;
        }
        __syncthreads();
        float sum0 = psum[lr0][0] + psum[lr0][1] + psum[lr0][2] + psum[lr0][3];
        float sq0  = psq[lr0][0] + psq[lr0][1] + psq[lr0][2] + psq[lr0][3];
        float sum1 = psum[lr1][0] + psum[lr1][1] + psum[lr1][2] + psum[lr1][3];
        float sq1  = psq[lr1][0] + psq[lr1][1] + psq[lr1][2] + psq[lr1][3];
        float mean0 = sum0 * (1.f / 128.f);
        float rstd0 = rsqrtf(sq0 * (1.f / 128.f) - mean0 * mean0 + 1e-5f);
        float mean1 = sum1 * (1.f / 128.f);
        float rstd1 = rsqrtf(sq1 * (1.f / 128.f) - mean1 * mean1 + 1e-5f);
        #pragma unroll
        for (int nt = 0; nt < 4; nt++) {
            int n = warp_n * 32 + nt * 8 + tig * 2;
            float g0 = lns[n], g1 = lns[n + 1];
            float bb0 = lnb[n], bb1 = lnb[n + 1];
            if (mrow0 < M) {
                __half2 hv = __floats2half2_rn(
                    (c[nt][0] - mean0) * rstd0 * g0 + bb0,
                    (c[nt][1] - mean0) * rstd0 * g1 + bb1);
                *reinterpret_cast<unsigned*>(hn + (size_t)mrow0 * 128 + n)
                    = *reinterpret_cast<unsigned*>(&hv);
            }
            if (mrow1 < M) {
                __half2 hv = __floats2half2_rn(
                    (c[nt][2] - mean1) * rstd1 * g0 + bb0,
                    (c[nt][3] - mean1) * rstd1 * g1 + bb1);
                *reinterpret_cast<unsigned*>(hn + (size_t)mrow1 * 128 + n)
                    = *reinterpret_cast<unsigned*>(&hv);
            }
        }
    }
}

// ---------------- split-S flash attention (fixed max = 0) ----------------
#define BQ 128
#define BK 64
#define QPITCH 40
#define VPITCH 72

__global__ __launch_bounds__(256, 3) void attn_kernel(
    const __half* __restrict__ qkv, const __half* __restrict__ vT,
    float* __restrict__ po, float* __restrict__ pl)
{
    __shared__ __half Qs[BQ][QPITCH];
    __shared__ __half Kt[2][BK][QPITCH];
    __shared__ __half Vt[2][DHEAD][VPITCH];
    const int tid = threadIdx.x;
    const int warp = tid >> 5;
    const int lane = tid & 31;
    const int g = lane >> 2;
    const int tig = lane & 3;
    const int b = blockIdx.z, h = blockIdx.y;
    const int tile = blockIdx.x / SPLITS;
    const int split = blockIdx.x % SPLITS;
    const int q0 = tile * BQ;
    const int qbase = warp * 16;
    const int kstart = split * KCHUNK;
    const int kend = min(kstart + KCHUNK, S_LEN);
    const int ntile = (kend - kstart + BK - 1) / BK;

    #pragma unroll
    for (int idx = tid; idx < BQ * 4; idx += 256) {
        int r = idx >> 2, quad = idx & 3;
        int q = q0 + r;
        uint4 v = make_uint4(0u, 0u, 0u, 0u);
        if (q < S_LEN)
            v = *reinterpret_cast<const uint4*>(
                qkv + ((size_t)(b * S_LEN + q)) * 384 + h * 32 + quad * 8);
        *reinterpret_cast<uint4*>(&Qs[r][quad * 8]) = v;
    }

    const __half* Kbase = qkv + (size_t)b * S_LEN * 384 + 128 + h * 32;
    const __half* Vbase = vT + (size_t)(b * N_HEADS + h) * DHEAD * VT_PITCH;
    const int kr = tid >> 2, kq = tid & 3;
    const int vr = tid >> 3, vq = tid & 7;

    uint4 kreg, vreg;
    {
        int kg = kstart + kr;
        kreg = (kg < S_LEN)
            ? *reinterpret_cast<const uint4*>(Kbase + (size_t)kg * 384 + kq * 8)
            : make_uint4(0u, 0u, 0u, 0u);
        vreg = *reinterpret_cast<const uint4*>(Vbase + (size_t)vr * VT_PITCH + kstart + vq * 8);
    }
    *reinterpret_cast<uint4*>(&Kt[0][kr][kq * 8]) = kreg;
    *reinterpret_cast<uint4*>(&Vt[0][vr][vq * 8]) = vreg;
    __syncthreads();

    unsigned A[2][4];
    #pragma unroll
    for (int ks = 0; ks < 2; ks++) {
        A[ks][0] = *reinterpret_cast<const unsigned*>(&Qs[qbase + g    ][ks * 16 + tig * 2]);
        A[ks][1] = *reinterpret_cast<const unsigned*>(&Qs[qbase + g + 8][ks * 16 + tig * 2]);
        A[ks][2] = *reinterpret_cast<const unsigned*>(&Qs[qbase + g    ][ks * 16 + tig * 2 + 8]);
        A[ks][3] = *reinterpret_cast<const unsigned*>(&Qs[qbase + g + 8][ks * 16 + tig * 2 + 8]);
    }

    float l0 = 0.f, l1 = 0.f;     // per-lane partial sums (reduced at end)
    float o[4][4] = {};

    for (int t = 0; t < ntile; t++) {
        const int kb = kstart + t * BK;
        const int buf = t & 1;
        if (t + 1 < ntile) {
            int kb2 = kb + BK;
            int kg = kb2 + kr;
            kreg = (kg < S_LEN)
                ? *reinterpret_cast<const uint4*>(Kbase + (size_t)kg * 384 + kq * 8)
                : make_uint4(0u, 0u, 0u, 0u);
            vreg = *reinterpret_cast<const uint4*>(Vbase + (size_t)vr * VT_PITCH + kb2 + vq * 8);
        }

        float s[8][4];
        #pragma unroll
        for (int j = 0; j < 8; j++) {
            s[j][0] = s[j][1] = s[j][2] = s[j][3] = 0.f;
            #pragma unroll
            for (int ks = 0; ks < 2; ks++) {
                unsigned bfr[2];
                bfr[0] = *reinterpret_cast<const unsigned*>(&Kt[buf][j * 8 + g][ks * 16 + tig * 2]);
                bfr[1] = *reinterpret_cast<const unsigned*>(&Kt[buf][j * 8 + g][ks * 16 + tig * 2 + 8]);
                mma16816(s[j], A[ks], bfr);
            }
        }
        if (kb + BK > S_LEN) {
            #pragma unroll
            for (int j = 0; j < 8; j++) {
                int key = kb + j * 8 + tig * 2;
                if (key >= S_LEN)     { s[j][0] = -1e30f; s[j][2] = -1e30f; }
                if (key + 1 >= S_LEN) { s[j][1] = -1e30f; s[j][3] = -1e30f; }
            }
        }

        // fixed-max softmax: p = exp(s); accumulate per-lane l locally
        unsigned ph[8][2];
        #pragma unroll
        for (int j = 0; j < 8; j++) {
            __half2 h2a = __floats2half2_rn(__expf(s[j][0]), __expf(s[j][1]));
            __half2 h2b = __floats2half2_rn(__expf(s[j][2]), __expf(s[j][3]));
            ph[j][0] = *reinterpret_cast<unsigned*>(&h2a);
            ph[j][1] = *reinterpret_cast<unsigned*>(&h2b);
            float2 fa = __half22float2(h2a);
            float2 fb = __half22float2(h2b);
            l0 += fa.x + fa.y;
            l1 += fb.x + fb.y;
        }

        #pragma unroll
        for (int kt = 0; kt < 4; kt++) {
            unsigned pa[4] = { ph[2 * kt][0], ph[2 * kt][1],
                               ph[2 * kt + 1][0], ph[2 * kt + 1][1] };
            #pragma unroll
            for (int nt = 0; nt < 4; nt++) {
                unsigned bfr[2];
                bfr[0] = *reinterpret_cast<const unsigned*>(&Vt[buf][nt * 8 + g][kt * 16 + tig * 2]);
                bfr[1] = *reinterpret_cast<const unsigned*>(&Vt[buf][nt * 8 + g][kt * 16 + tig * 2 + 8]);
                mma16816(o[nt], pa, bfr);
            }
        }
        if (t + 1 < ntile) {
            *reinterpret_cast<uint4*>(&Kt[buf ^ 1][kr][kq * 8]) = kreg;
            *reinterpret_cast<uint4*>(&Vt[buf ^ 1][vr][vq * 8]) = vreg;
        }
        __syncthreads();
    }

    // one-time cross-lane l reduction (4 lanes per row)
    l0 += __shfl_xor_sync(0xffffffffu, l0, 1);
    l0 += __shfl_xor_sync(0xffffffffu, l0, 2);
    l1 += __shfl_xor_sync(0xffffffffu, l1, 1);
    l1 += __shfl_xor_sync(0xffffffffu, l1, 2);

    const size_t pbase = (((size_t)split * BATCH + b) * N_HEADS + h) * S_LEN;
    int qa = q0 + qbase + g;
    int qb2 = qa + 8;
    if (qa < S_LEN) {
        #pragma unroll
        for (int nt = 0; nt < 4; nt++) {
            float2 v = make_float2(o[nt][0], o[nt][1]);
            *reinterpret_cast<float2*>(po + (pbase + qa) * DHEAD + nt * 8 + tig * 2) = v;
        }
        if (tig == 0) pl[pbase + qa] = l0;
    }
    if (qb2 < S_LEN) {
        #pragma unroll
        for (int nt = 0; nt < 4; nt++) {
            float2 v = make_float2(o[nt][2], o[nt][3]);
            *reinterpret_cast<float2*>(po + (pbase + qb2) * DHEAD + nt * 8 + tig * 2) = v;
        }
        if (tig == 0) pl[pbase + qb2] = l1;
    }
}

// ---------------- head ----------------
__global__ __launch_bounds__(64) void head_kernel(
    const float* __restrict__ h, const float* __restrict__ ls,
    const float* __restrict__ lb, const float* __restrict__ hw,
    const float* __restrict__ hb, float* __restrict__ out)
{
    int bidx = threadIdx.x >> 5;
    if (bidx >= BATCH) return;
    int lane = threadIdx.x & 31;
    const float* xr = h + (size_t)bidx * S_LEN * D_MODEL;
    float4 v = *reinterpret_cast<const float4*>(xr + lane * 4);
    float sum = v.x + v.y + v.z + v.w;
    #pragma unroll
    for (int o = 16; o; o >>= 1) sum += __shfl_xor_sync(0xffffffffu, sum, o);
    float mean = sum * (1.f / 128.f);
    float dx = v.x - mean, dy = v.y - mean, dz = v.z - mean, dw = v.w - mean;
    float vs = dx * dx + dy * dy + dz * dz + dw * dw;
    #pragma unroll
    for (int o = 16; o; o >>= 1) vs += __shfl_xor_sync(0xffffffffu, vs, o);
    float rstd = rsqrtf(vs * (1.f / 128.f) + 1e-5f);
    float4 s4 = *reinterpret_cast<const float4*>(ls + lane * 4);
    float4 b4 = *reinterpret_cast<const float4*>(lb + lane * 4);
    float4 w4 = *reinterpret_cast<const float4*>(hw + lane * 4);
    float dot = (dx * rstd * s4.x + b4.x) * w4.x
              + (dy * rstd * s4.y + b4.y) * w4.y
              + (dz * rstd * s4.z + b4.z) * w4.z
              + (dw * rstd * s4.w + b4.w) * w4.w;
    #pragma unroll
    for (int o = 16; o; o >>= 1) dot += __shfl_xor_sync(0xffffffffu, dot, o);
    if (lane == 0) out[bidx] = dot + hb[0];
}

// ---------------- launch ----------------
extern "C" void kernel_launch(void* const* d_in, const int* in_sizes, int n_in,
                              void* d_out, int out_size)
{
    const float* x        = (const float*)d_in[0];
    const float* embed_w  = (const float*)d_in[1];
    const float* embed_b  = (const float*)d_in[2];
    const float* pos_emb  = (const float*)d_in[3];
    const float* cls      = (const float*)d_in[4];
    const float* in_w     = (const float*)d_in[5];
    const float* in_b     = (const float*)d_in[6];
    const float* out_w    = (const float*)d_in[7];
    const float* out_b    = (const float*)d_in[8];
    const float* ln1_s    = (const float*)d_in[9];
    const float* ln1_b    = (const float*)d_in[10];
    const float* ln2_s    = (const float*)d_in[11];
    const float* ln2_b    = (const float*)d_in[12];
    const float* ff1_w    = (const float*)d_in[13];
    const float* ff1_b    = (const float*)d_in[14];
    const float* ff2_w    = (const float*)d_in[15];
    const float* ff2_b    = (const float*)d_in[16];
    const float* hln_s    = (const float*)d_in[17];
    const float* hln_b    = (const float*)d_in[18];
    const float* head_w   = (const float*)d_in[19];
    const float* head_b   = (const float*)d_in[20];
    float* outp = (float*)d_out;

    float *h, *po, *pl;
    __half *hnh, *qkvh, *vt, *ffh, *wh;
    cudaGetSymbolAddress((void**)&h,     g_h);
    cudaGetSymbolAddress((void**)&hnh,   g_hnh);
    cudaGetSymbolAddress((void**)&qkvh,  g_qkvh);
    cudaGetSymbolAddress((void**)&vt,    g_vt);
    cudaGetSymbolAddress((void**)&ffh,   g_ffh);
    cudaGetSymbolAddress((void**)&po,    g_po);
    cudaGetSymbolAddress((void**)&pl,    g_pl);
    cudaGetSymbolAddress((void**)&wh,    g_wh);

    const int M = MROWS;
    const int MB128 = (M + 127) / 128;
    const int MB32  = (M + 31) / 32;
    const int QTILES = (S_LEN + BQ - 1) / BQ;

    convw_all_kernel<<<(CW_TOTAL + 255) / 256, 256>>>(in_w, out_w, ff1_w, ff2_w, wh);

    embed_ln_kernel<<<dim3(S_LEN, BATCH), 128>>>(
        x, embed_w, embed_b, pos_emb, cls, ln1_s, ln1_b, h, hnh);

    for (int i = 0; i < NL; i++) {
        hgemm_kernel<false, true, true><<<dim3(384 / 64, MB128), 256>>>(
            hnh, wh + WOFF_IN + (size_t)i * 384 * 128, in_b + (size_t)i * 384,
            qkvh, vt, M, 384, 128);
        attn_kernel<<<dim3(QTILES * SPLITS, N_HEADS, BATCH), 256>>>(qkvh, vt, po, pl);
        // out projection with fused split-merge A-stage + residual + LN2
        hgemm_ln_kernel<true, true><<<MB32, 256>>>(
            nullptr, po, pl,
            wh + WOFF_OUT + (size_t)i * 128 * 128, out_b + (size_t)i * 128,
            ln2_s + i * D_MODEL, ln2_b + i * D_MODEL, h, hnh, M, 128);
        hgemm_kernel<true, false, false><<<dim3(512 / 64, MB128), 256>>>(
            hnh, wh + WOFF_FF1 + (size_t)i * 512 * 128, ff1_b + (size_t)i * 512,
            ffh, nullptr, M, 512, 128);
        if (i + 1 < NL) {
            hgemm_ln_kernel<true, false><<<MB32, 256>>>(
                ffh, nullptr, nullptr,
                wh + WOFF_FF2 + (size_t)i * 128 * 512, ff2_b + (size_t)i * 128,
                ln1_s + (i + 1) * D_MODEL, ln1_b + (i + 1) * D_MODEL,
                h, hnh, M, 512);
        } else {
            hgemm_ln_kernel<false, false><<<MB32, 256>>>(
                ffh, nullptr, nullptr,
                wh + WOFF_FF2 + (size_t)i * 128 * 512, ff2_b + (size_t)i * 128,
                nullptr, nullptr, h, nullptr, M, 512);
        }
    }

    head_kernel<<<1, 64>>>(h, hln_s, hln_b, head_w, head_b, outp);
}

// round 11
// speedup vs baseline: 5.1625x; 1.1101x over previous
#include <cuda_runtime.h>
#include <cuda_fp16.h>
#include <math.h>

#define NL 3
#define D_MODEL 128
#define N_HEADS 4
#define DHEAD 32
#define DFF 512
#define DIN 64
#define BATCH 2
#define LSEQ 2048
#define S_LEN 2049
#define MROWS (BATCH * S_LEN)   // 4098
#define QK_SCALE 0.17677669529663687f

#define SPLITS 3
#define KCHUNK 704
#define VT_PITCH 2112
#define PSTRIDE ((size_t)BATCH * N_HEADS * S_LEN)

// ---------------- scratch (device globals; no allocation) ----------------
__device__ float  g_h[MROWS * D_MODEL];
__device__ __half g_hnh[MROWS * D_MODEL];
__device__ __half g_qkvh[MROWS * 3 * D_MODEL];
__device__ __half g_vt[BATCH * N_HEADS * DHEAD * VT_PITCH];
__device__ float  g_po[SPLITS * BATCH * N_HEADS * S_LEN * DHEAD];
__device__ float  g_pl[SPLITS * BATCH * N_HEADS * S_LEN];
#define WOFF_IN  0
#define WOFF_OUT (NL * 384 * 128)
#define WOFF_FF1 (WOFF_OUT + NL * 128 * 128)
#define WOFF_FF2 (WOFF_FF1 + NL * 512 * 128)
#define WTOTAL   (WOFF_FF2 + NL * 128 * 512)
__device__ __half g_wh[WTOTAL];

#define CW_N0 (NL * 384 * 128 / 4)
#define CW_N1 (NL * 128 * 128 / 4)
#define CW_N2 (NL * 512 * 128 / 4)
#define CW_N3 (NL * 128 * 512 / 4)
#define CW_TOTAL (CW_N0 + CW_N1 + CW_N2 + CW_N3)

// ---------------- mega kernel dynamic smem layout (bytes) ----------------
#define OFF_ATTN 0                    // __half [32][136]  = 8704
#define OFF_HN2  8704                 // __half [32][136]  = 8704
#define OFF_HRES 17408                // float  [32][128]  = 16384
#define OFF_F    33792                // __half [32][520]  = 33280
#define OFF_WS   67072                // __half staging    = 40960
#define OFF_PS   108032               // float  [32][4]    = 512
#define OFF_PQ   108544               // float  [32][4]    = 512
#define SMEM_MEGA 109056

// ---------------- mma helper ----------------
__device__ __forceinline__ void mma16816(
    float c[4], const unsigned a[4], const unsigned b[2])
{
    asm volatile(
        "mma.sync.aligned.m16n8k16.row.col.f32.f16.f16.f32 "
        "{%0,%1,%2,%3}, {%4,%5,%6,%7}, {%8,%9}, {%0,%1,%2,%3};\n"
        : "+f"(c[0]), "+f"(c[1]), "+f"(c[2]), "+f"(c[3])
        : "r"(a[0]), "r"(a[1]), "r"(a[2]), "r"(a[3]),
          "r"(b[0]), "r"(b[1]));
}

// ---------------- fused weight fp32 -> fp16 conversion ----------------
__global__ __launch_bounds__(256) void convw_all_kernel(
    const float* __restrict__ s0, const float* __restrict__ s1,
    const float* __restrict__ s2, const float* __restrict__ s3,
    __half* __restrict__ dst)
{
    int i = blockIdx.x * 256 + threadIdx.x;
    if (i >= CW_TOTAL) return;
    const float* src;
    int off, local = i;
    if (local < CW_N0)                { src = s0; off = WOFF_IN; }
    else if ((local -= CW_N0) < CW_N1){ src = s1; off = WOFF_OUT; }
    else if ((local -= CW_N1) < CW_N2){ src = s2; off = WOFF_FF1; }
    else { local -= CW_N2;              src = s3; off = WOFF_FF2; }
    float4 v = *reinterpret_cast<const float4*>(src + (size_t)local * 4);
    __half2 a = __floats2half2_rn(v.x, v.y);
    __half2 b = __floats2half2_rn(v.z, v.w);
    uint2 pk;
    pk.x = *reinterpret_cast<unsigned*>(&a);
    pk.y = *reinterpret_cast<unsigned*>(&b);
    *reinterpret_cast<uint2*>(dst + (size_t)off + (size_t)local * 4) = pk;
}

// ---------------- embedding + fused LN1(layer0) ----------------
__global__ __launch_bounds__(128) void embed_ln_kernel(
    const float* __restrict__ x, const float* __restrict__ ew,
    const float* __restrict__ eb, const float* __restrict__ pos,
    const float* __restrict__ cls, const float* __restrict__ lns,
    const float* __restrict__ lnb, float* __restrict__ h,
    __half* __restrict__ hn)
{
    __shared__ float xs[DIN];
    __shared__ float red[8];
    int s = blockIdx.x, b = blockIdx.y;
    int d = threadIdx.x;
    if (s > 0 && d < DIN) xs[d] = x[((size_t)b * LSEQ + (s - 1)) * DIN + d];
    __syncthreads();
    float val;
    if (s == 0) {
        val = cls[d] + pos[d];
    } else {
        float acc = 0.f;
        const float* wr = ew + (size_t)d * DIN;
        #pragma unroll
        for (int j = 0; j < DIN; j++) acc = fmaf(xs[j], wr[j], acc);
        val = acc + eb[d] + pos[(size_t)s * D_MODEL + d];
    }
    size_t row = (size_t)b * S_LEN + s;
    h[row * D_MODEL + d] = val;
    int w = d >> 5, lane = d & 31;
    float sv = val, qv = val * val;
    #pragma unroll
    for (int o = 16; o; o >>= 1) {
        sv += __shfl_xor_sync(0xffffffffu, sv, o);
        qv += __shfl_xor_sync(0xffffffffu, qv, o);
    }
    if (lane == 0) { red[w] = sv; red[4 + w] = qv; }
    __syncthreads();
    float sum = red[0] + red[1] + red[2] + red[3];
    float sq  = red[4] + red[5] + red[6] + red[7];
    float mean = sum * (1.f / 128.f);
    float rstd = rsqrtf(sq * (1.f / 128.f) - mean * mean + 1e-5f);
    hn[row * D_MODEL + d] = __float2half_rn((val - mean) * rstd * lns[d] + lnb[d]);
}

// ---------------- QKV tensor-core GEMM (128x64 tile) ----------------
#define GPITCH 40
__global__ __launch_bounds__(256) void qkv_gemm_kernel(
    const __half* __restrict__ A, const __half* __restrict__ W,
    const float* __restrict__ bias, __half* __restrict__ C,
    __half* __restrict__ vT, int M)
{
    const int N = 384, K = 128;
    __shared__ __half As[128][GPITCH];
    __shared__ __half Ws[64][GPITCH];
    const int tid = threadIdx.x;
    const int warp = tid >> 5;
    const int lane = tid & 31;
    const int g = lane >> 2;
    const int tig = lane & 3;
    const int warp_m = warp >> 1;
    const int warp_n = warp & 1;
    const int m0 = blockIdx.y * 128;
    const int n0 = blockIdx.x * 64;
    const int NK = K / 32;
    const int wr = tid >> 2, wq = tid & 3;

    float c[2][4][4] = {};

    uint4 aReg[2], wReg;
    #pragma unroll
    for (int it = 0; it < 2; it++) {
        int idx = tid + it * 256;
        int r = idx >> 2, quad = idx & 3;
        int m = m0 + r;
        aReg[it] = (m < M)
            ? *reinterpret_cast<const uint4*>(A + (size_t)m * K + quad * 8)
            : make_uint4(0u, 0u, 0u, 0u);
    }
    wReg = *reinterpret_cast<const uint4*>(W + (size_t)(n0 + wr) * K + wq * 8);

    for (int kt = 0; kt < NK; kt++) {
        #pragma unroll
        for (int it = 0; it < 2; it++) {
            int idx = tid + it * 256;
            int r = idx >> 2, quad = idx & 3;
            *reinterpret_cast<uint4*>(&As[r][quad * 8]) = aReg[it];
        }
        *reinterpret_cast<uint4*>(&Ws[wr][wq * 8]) = wReg;
        __syncthreads();
        if (kt + 1 < NK) {
            int k0 = (kt + 1) * 32;
            #pragma unroll
            for (int it = 0; it < 2; it++) {
                int idx = tid + it * 256;
                int r = idx >> 2, quad = idx & 3;
                int m = m0 + r;
                aReg[it] = (m < M)
                    ? *reinterpret_cast<const uint4*>(A + (size_t)m * K + k0 + quad * 8)
                    : make_uint4(0u, 0u, 0u, 0u);
            }
            wReg = *reinterpret_cast<const uint4*>(W + (size_t)(n0 + wr) * K + k0 + wq * 8);
        }
        #pragma unroll
        for (int ks = 0; ks < 2; ks++) {
            unsigned a[2][4];
            #pragma unroll
            for (int mt = 0; mt < 2; mt++) {
                int rbase = warp_m * 32 + mt * 16;
                a[mt][0] = *reinterpret_cast<const unsigned*>(&As[rbase + g    ][ks * 16 + tig * 2]);
                a[mt][1] = *reinterpret_cast<const unsigned*>(&As[rbase + g + 8][ks * 16 + tig * 2]);
                a[mt][2] = *reinterpret_cast<const unsigned*>(&As[rbase + g    ][ks * 16 + tig * 2 + 8]);
                a[mt][3] = *reinterpret_cast<const unsigned*>(&As[rbase + g + 8][ks * 16 + tig * 2 + 8]);
            }
            #pragma unroll
            for (int nt = 0; nt < 4; nt++) {
                unsigned bfr[2];
                int nrow = warp_n * 32 + nt * 8 + g;
                bfr[0] = *reinterpret_cast<const unsigned*>(&Ws[nrow][ks * 16 + tig * 2]);
                bfr[1] = *reinterpret_cast<const unsigned*>(&Ws[nrow][ks * 16 + tig * 2 + 8]);
                mma16816(c[0][nt], a[0], bfr);
                mma16816(c[1][nt], a[1], bfr);
            }
        }
        __syncthreads();
    }

    #pragma unroll
    for (int mt = 0; mt < 2; mt++) {
        #pragma unroll
        for (int half_row = 0; half_row < 2; half_row++) {
            int m = m0 + warp_m * 32 + mt * 16 + g + half_row * 8;
            if (m >= M) continue;
            int bb = m / S_LEN, ss = m % S_LEN;
            #pragma unroll
            for (int nt = 0; nt < 4; nt++) {
                int n = n0 + warp_n * 32 + nt * 8 + tig * 2;
                float v0 = c[mt][nt][half_row * 2 + 0] + bias[n];
                float v1 = c[mt][nt][half_row * 2 + 1] + bias[n + 1];
                if (n >= 256) {
                    int hh = (n - 256) >> 5, dd = (n - 256) & 31;
                    __half* vbase = vT + ((size_t)(bb * N_HEADS + hh) * DHEAD + dd) * VT_PITCH + ss;
                    vbase[0] = __float2half_rn(v0);
                    vbase[VT_PITCH] = __float2half_rn(v1);
                } else {
                    if (n < 128) { v0 *= QK_SCALE; v1 *= QK_SCALE; }
                    __half2 hv = __floats2half2_rn(v0, v1);
                    *reinterpret_cast<unsigned*>(
                        C + (size_t)m * N + n) = *reinterpret_cast<unsigned*>(&hv);
                }
            }
        }
    }
}

// ---------------- split-S flash attention (fixed max = 0) ----------------
#define BQ 128
#define BK 64
#define QPITCH 40
#define VPITCH 72

__global__ __launch_bounds__(256, 3) void attn_kernel(
    const __half* __restrict__ qkv, const __half* __restrict__ vT,
    float* __restrict__ po, float* __restrict__ pl)
{
    __shared__ __half Qs[BQ][QPITCH];
    __shared__ __half Kt[2][BK][QPITCH];
    __shared__ __half Vt[2][DHEAD][VPITCH];
    const int tid = threadIdx.x;
    const int warp = tid >> 5;
    const int lane = tid & 31;
    const int g = lane >> 2;
    const int tig = lane & 3;
    const int b = blockIdx.z, h = blockIdx.y;
    const int tile = blockIdx.x / SPLITS;
    const int split = blockIdx.x % SPLITS;
    const int q0 = tile * BQ;
    const int qbase = warp * 16;
    const int kstart = split * KCHUNK;
    const int kend = min(kstart + KCHUNK, S_LEN);
    const int ntile = (kend - kstart + BK - 1) / BK;

    #pragma unroll
    for (int idx = tid; idx < BQ * 4; idx += 256) {
        int r = idx >> 2, quad = idx & 3;
        int q = q0 + r;
        uint4 v = make_uint4(0u, 0u, 0u, 0u);
        if (q < S_LEN)
            v = *reinterpret_cast<const uint4*>(
                qkv + ((size_t)(b * S_LEN + q)) * 384 + h * 32 + quad * 8);
        *reinterpret_cast<uint4*>(&Qs[r][quad * 8]) = v;
    }

    const __half* Kbase = qkv + (size_t)b * S_LEN * 384 + 128 + h * 32;
    const __half* Vbase = vT + (size_t)(b * N_HEADS + h) * DHEAD * VT_PITCH;
    const int kr = tid >> 2, kq = tid & 3;
    const int vr = tid >> 3, vq = tid & 7;

    uint4 kreg, vreg;
    {
        int kg = kstart + kr;
        kreg = (kg < S_LEN)
            ? *reinterpret_cast<const uint4*>(Kbase + (size_t)kg * 384 + kq * 8)
            : make_uint4(0u, 0u, 0u, 0u);
        vreg = *reinterpret_cast<const uint4*>(Vbase + (size_t)vr * VT_PITCH + kstart + vq * 8);
    }
    *reinterpret_cast<uint4*>(&Kt[0][kr][kq * 8]) = kreg;
    *reinterpret_cast<uint4*>(&Vt[0][vr][vq * 8]) = vreg;
    __syncthreads();

    unsigned A[2][4];
    #pragma unroll
    for (int ks = 0; ks < 2; ks++) {
        A[ks][0] = *reinterpret_cast<const unsigned*>(&Qs[qbase + g    ][ks * 16 + tig * 2]);
        A[ks][1] = *reinterpret_cast<const unsigned*>(&Qs[qbase + g + 8][ks * 16 + tig * 2]);
        A[ks][2] = *reinterpret_cast<const unsigned*>(&Qs[qbase + g    ][ks * 16 + tig * 2 + 8]);
        A[ks][3] = *reinterpret_cast<const unsigned*>(&Qs[qbase + g + 8][ks * 16 + tig * 2 + 8]);
    }

    float l0 = 0.f, l1 = 0.f;
    float o[4][4] = {};

    for (int t = 0; t < ntile; t++) {
        const int kb = kstart + t * BK;
        const int buf = t & 1;
        if (t + 1 < ntile) {
            int kb2 = kb + BK;
            int kg = kb2 + kr;
            kreg = (kg < S_LEN)
                ? *reinterpret_cast<const uint4*>(Kbase + (size_t)kg * 384 + kq * 8)
                : make_uint4(0u, 0u, 0u, 0u);
            vreg = *reinterpret_cast<const uint4*>(Vbase + (size_t)vr * VT_PITCH + kb2 + vq * 8);
        }

        float s[8][4];
        #pragma unroll
        for (int j = 0; j < 8; j++) {
            s[j][0] = s[j][1] = s[j][2] = s[j][3] = 0.f;
            #pragma unroll
            for (int ks = 0; ks < 2; ks++) {
                unsigned bfr[2];
                bfr[0] = *reinterpret_cast<const unsigned*>(&Kt[buf][j * 8 + g][ks * 16 + tig * 2]);
                bfr[1] = *reinterpret_cast<const unsigned*>(&Kt[buf][j * 8 + g][ks * 16 + tig * 2 + 8]);
                mma16816(s[j], A[ks], bfr);
            }
        }
        if (kb + BK > S_LEN) {
            #pragma unroll
            for (int j = 0; j < 8; j++) {
                int key = kb + j * 8 + tig * 2;
                if (key >= S_LEN)     { s[j][0] = -1e30f; s[j][2] = -1e30f; }
                if (key + 1 >= S_LEN) { s[j][1] = -1e30f; s[j][3] = -1e30f; }
            }
        }

        unsigned ph[8][2];
        #pragma unroll
        for (int j = 0; j < 8; j++) {
            __half2 h2a = __floats2half2_rn(__expf(s[j][0]), __expf(s[j][1]));
            __half2 h2b = __floats2half2_rn(__expf(s[j][2]), __expf(s[j][3]));
            ph[j][0] = *reinterpret_cast<unsigned*>(&h2a);
            ph[j][1] = *reinterpret_cast<unsigned*>(&h2b);
            float2 fa = __half22float2(h2a);
            float2 fb = __half22float2(h2b);
            l0 += fa.x + fa.y;
            l1 += fb.x + fb.y;
        }

        #pragma unroll
        for (int kt = 0; kt < 4; kt++) {
            unsigned pa[4] = { ph[2 * kt][0], ph[2 * kt][1],
                               ph[2 * kt + 1][0], ph[2 * kt + 1][1] };
            #pragma unroll
            for (int nt = 0; nt < 4; nt++) {
                unsigned bfr[2];
                bfr[0] = *reinterpret_cast<const unsigned*>(&Vt[buf][nt * 8 + g][kt * 16 + tig * 2]);
                bfr[1] = *reinterpret_cast<const unsigned*>(&Vt[buf][nt * 8 + g][kt * 16 + tig * 2 + 8]);
                mma16816(o[nt], pa, bfr);
            }
        }
        if (t + 1 < ntile) {
            *reinterpret_cast<uint4*>(&Kt[buf ^ 1][kr][kq * 8]) = kreg;
            *reinterpret_cast<uint4*>(&Vt[buf ^ 1][vr][vq * 8]) = vreg;
        }
        __syncthreads();
    }

    l0 += __shfl_xor_sync(0xffffffffu, l0, 1);
    l0 += __shfl_xor_sync(0xffffffffu, l0, 2);
    l1 += __shfl_xor_sync(0xffffffffu, l1, 1);
    l1 += __shfl_xor_sync(0xffffffffu, l1, 2);

    const size_t pbase = (((size_t)split * BATCH + b) * N_HEADS + h) * S_LEN;
    int qa = q0 + qbase + g;
    int qb2 = qa + 8;
    if (qa < S_LEN) {
        #pragma unroll
        for (int nt = 0; nt < 4; nt++) {
            float2 v = make_float2(o[nt][0], o[nt][1]);
            *reinterpret_cast<float2*>(po + (pbase + qa) * DHEAD + nt * 8 + tig * 2) = v;
        }
        if (tig == 0) pl[pbase + qa] = l0;
    }
    if (qb2 < S_LEN) {
        #pragma unroll
        for (int nt = 0; nt < 4; nt++) {
            float2 v = make_float2(o[nt][2], o[nt][3]);
            *reinterpret_cast<float2*>(po + (pbase + qb2) * DHEAD + nt * 8 + tig * 2) = v;
        }
        if (tig == 0) pl[pbase + qb2] = l1;
    }
}

// ---------------- MEGA layer-tail kernel --------------------------------
// merge(po,pl) -> out-proj + resid -> LN2 -> FF1+ReLU -> FF2 + resid
// -> write h (+ optional LN1next -> hn).  32 rows per CTA, 256 threads.
template <bool LN_NEXT>
__global__ __launch_bounds__(256) void mega_tail_kernel(
    const float* __restrict__ po, const float* __restrict__ pl,
    const __half* __restrict__ Wout, const float* __restrict__ bout,
    const float* __restrict__ ln2s, const float* __restrict__ ln2b,
    const __half* __restrict__ W1, const float* __restrict__ b1,
    const __half* __restrict__ W2, const float* __restrict__ b2,
    const float* __restrict__ ln1s, const float* __restrict__ ln1b,
    float* __restrict__ h, __half* __restrict__ hn, int M)
{
    extern __shared__ char smem[];
    __half (*Attn)[136] = reinterpret_cast<__half(*)[136]>(smem + OFF_ATTN);
    __half (*HN2)[136]  = reinterpret_cast<__half(*)[136]>(smem + OFF_HN2);
    float (*Hres)[128]  = reinterpret_cast<float(*)[128]>(smem + OFF_HRES);
    __half (*F)[520]    = reinterpret_cast<__half(*)[520]>(smem + OFF_F);
    __half* Wsraw       = reinterpret_cast<__half*>(smem + OFF_WS);
    float (*psum)[4]    = reinterpret_cast<float(*)[4]>(smem + OFF_PS);
    float (*psq)[4]     = reinterpret_cast<float(*)[4]>(smem + OFF_PQ);

    const int tid = threadIdx.x;
    const int warp = tid >> 5;
    const int lane = tid & 31;
    const int g = lane >> 2;
    const int tig = lane & 3;
    const int warp_m = warp >> 2;   // 0..1
    const int warp_n = warp & 3;    // 0..3
    const int m0 = blockIdx.x * 32;

    // ---- stage 0: merge attention partials into Attn; load residual ----
    {
        int row = tid >> 3;               // 0..31
        int dseg = (tid & 7) * 16;        // 0..112
        int mrow = m0 + row;
        if (mrow < M) {
            int bb = mrow / S_LEN, qq = mrow % S_LEN;
            int hh = dseg >> 5, dd = dseg & 31;
            size_t prow = ((size_t)bb * N_HEADS + hh) * S_LEN + qq;
            float linv = 1.f / (pl[prow] + pl[prow + PSTRIDE] + pl[prow + 2 * PSTRIDE]);
            float acc[16];
            #pragma unroll
            for (int t = 0; t < 4; t++) {
                float4 p0 = *reinterpret_cast<const float4*>(po + prow * DHEAD + dd + t * 4);
                float4 p1 = *reinterpret_cast<const float4*>(po + (prow + PSTRIDE) * DHEAD + dd + t * 4);
                float4 p2 = *reinterpret_cast<const float4*>(po + (prow + 2 * PSTRIDE) * DHEAD + dd + t * 4);
                acc[t * 4 + 0] = (p0.x + p1.x + p2.x) * linv;
                acc[t * 4 + 1] = (p0.y + p1.y + p2.y) * linv;
                acc[t * 4 + 2] = (p0.z + p1.z + p2.z) * linv;
                acc[t * 4 + 3] = (p0.w + p1.w + p2.w) * linv;
            }
            unsigned pk[8];
            #pragma unroll
            for (int t = 0; t < 8; t++) {
                __half2 hv = __floats2half2_rn(acc[t * 2], acc[t * 2 + 1]);
                pk[t] = *reinterpret_cast<unsigned*>(&hv);
            }
            *reinterpret_cast<uint4*>(&Attn[row][dseg]) = make_uint4(pk[0], pk[1], pk[2], pk[3]);
            *reinterpret_cast<uint4*>(&Attn[row][dseg + 8]) = make_uint4(pk[4], pk[5], pk[6], pk[7]);
            // residual rows
            #pragma unroll
            for (int t = 0; t < 4; t++)
                *reinterpret_cast<float4*>(&Hres[row][dseg + t * 4]) =
                    *reinterpret_cast<const float4*>(h + (size_t)mrow * 128 + dseg + t * 4);
        } else {
            uint4 z = make_uint4(0u, 0u, 0u, 0u);
            *reinterpret_cast<uint4*>(&Attn[row][dseg]) = z;
            *reinterpret_cast<uint4*>(&Attn[row][dseg + 8]) = z;
            float4 fz = make_float4(0.f, 0.f, 0.f, 0.f);
            #pragma unroll
            for (int t = 0; t < 4; t++)
                *reinterpret_cast<float4*>(&Hres[row][dseg + t * 4]) = fz;
        }
    }
    // ---- stage Wout fully: [128][136] ----
    {
        __half (*WsA)[136] = reinterpret_cast<__half(*)[136]>(Wsraw);
        #pragma unroll
        for (int it = 0; it < 8; it++) {
            int idx = tid + it * 256;
            int r = idx >> 4, q = idx & 15;
            *reinterpret_cast<uint4*>(&WsA[r][q * 8]) =
                *reinterpret_cast<const uint4*>(Wout + (size_t)r * 128 + q * 8);
        }
    }
    __syncthreads();

    // ---- stage 1: out-proj GEMM (M=32, N=128, K=128, all in smem) ----
    float c1[4][4] = {};
    {
        __half (*WsA)[136] = reinterpret_cast<__half(*)[136]>(Wsraw);
        #pragma unroll
        for (int ks8 = 0; ks8 < 8; ks8++) {
            int kc = ks8 * 16;
            unsigned a[4];
            int rbase = warp_m * 16;
            a[0] = *reinterpret_cast<const unsigned*>(&Attn[rbase + g    ][kc + tig * 2]);
            a[1] = *reinterpret_cast<const unsigned*>(&Attn[rbase + g + 8][kc + tig * 2]);
            a[2] = *reinterpret_cast<const unsigned*>(&Attn[rbase + g    ][kc + tig * 2 + 8]);
            a[3] = *reinterpret_cast<const unsigned*>(&Attn[rbase + g + 8][kc + tig * 2 + 8]);
            #pragma unroll
            for (int nt = 0; nt < 4; nt++) {
                unsigned bfr[2];
                int nrow = warp_n * 32 + nt * 8 + g;
                bfr[0] = *reinterpret_cast<const unsigned*>(&WsA[nrow][kc + tig * 2]);
                bfr[1] = *reinterpret_cast<const unsigned*>(&WsA[nrow][kc + tig * 2 + 8]);
                mma16816(c1[nt], a, bfr);
            }
        }
    }
    const int lr0 = warp_m * 16 + g, lr1 = lr0 + 8;
    // bias + residual, update Hres (smem only; no global h write yet)
    #pragma unroll
    for (int nt = 0; nt < 4; nt++) {
        int n = warp_n * 32 + nt * 8 + tig * 2;
        float b0 = bout[n], b1v = bout[n + 1];
        c1[nt][0] += b0 + Hres[lr0][n];
        c1[nt][1] += b1v + Hres[lr0][n + 1];
        c1[nt][2] += b0 + Hres[lr1][n];
        c1[nt][3] += b1v + Hres[lr1][n + 1];
    }
    // LN2 -> HN2
    {
        float s0 = 0.f, q0 = 0.f, s1 = 0.f, q1 = 0.f;
        #pragma unroll
        for (int nt = 0; nt < 4; nt++) {
            s0 += c1[nt][0] + c1[nt][1];
            q0 += c1[nt][0] * c1[nt][0] + c1[nt][1] * c1[nt][1];
            s1 += c1[nt][2] + c1[nt][3];
            q1 += c1[nt][2] * c1[nt][2] + c1[nt][3] * c1[nt][3];
        }
        #pragma unroll
        for (int o = 1; o < 4; o <<= 1) {
            s0 += __shfl_xor_sync(0xffffffffu, s0, o);
            q0 += __shfl_xor_sync(0xffffffffu, q0, o);
            s1 += __shfl_xor_sync(0xffffffffu, s1, o);
            q1 += __shfl_xor_sync(0xffffffffu, q1, o);
        }
        if (tig == 0) {
            psum[lr0][warp_n] = s0; psq[lr0][warp_n] = q0;
            psum[lr1][warp_n] = s1; psq[lr1][warp_n] = q1;
        }
        __syncthreads();
        float sum0 = psum[lr0][0] + psum[lr0][1] + psum[lr0][2] + psum[lr0][3];
        float sq0  = psq[lr0][0] + psq[lr0][1] + psq[lr0][2] + psq[lr0][3];
        float sum1 = psum[lr1][0] + psum[lr1][1] + psum[lr1][2] + psum[lr1][3];
        float sq1  = psq[lr1][0] + psq[lr1][1] + psq[lr1][2] + psq[lr1][3];
        float mean0 = sum0 * (1.f / 128.f);
        float rstd0 = rsqrtf(sq0 * (1.f / 128.f) - mean0 * mean0 + 1e-5f);
        float mean1 = sum1 * (1.f / 128.f);
        float rstd1 = rsqrtf(sq1 * (1.f / 128.f) - mean1 * mean1 + 1e-5f);
        #pragma unroll
        for (int nt = 0; nt < 4; nt++) {
            int n = warp_n * 32 + nt * 8 + tig * 2;
            float g0 = ln2s[n], g1 = ln2s[n + 1];
            float bb0 = ln2b[n], bb1 = ln2b[n + 1];
            __half2 hv0 = __floats2half2_rn(
                (c1[nt][0] - mean0) * rstd0 * g0 + bb0,
                (c1[nt][1] - mean0) * rstd0 * g1 + bb1);
            __half2 hv1 = __floats2half2_rn(
                (c1[nt][2] - mean1) * rstd1 * g0 + bb0,
                (c1[nt][3] - mean1) * rstd1 * g1 + bb1);
            *reinterpret_cast<unsigned*>(&HN2[lr0][n]) = *reinterpret_cast<unsigned*>(&hv0);
            *reinterpret_cast<unsigned*>(&HN2[lr1][n]) = *reinterpret_cast<unsigned*>(&hv1);
            // persist residual for FF2
            Hres[lr0][n] = c1[nt][0]; Hres[lr0][n + 1] = c1[nt][1];
            Hres[lr1][n] = c1[nt][2]; Hres[lr1][n + 1] = c1[nt][3];
        }
    }

    // ---- stage 2: FF1 (M=32, N=512, K=128) ----
    float c2[2][8][4] = {};
    {
        __half (*WsB)[40] = reinterpret_cast<__half(*)[40]>(Wsraw);
        #pragma unroll
        for (int kt = 0; kt < 4; kt++) {
            __syncthreads();   // protect Ws (and HN2 on first iter)
            #pragma unroll
            for (int it = 0; it < 8; it++) {
                int idx = tid + it * 256;
                int r = idx >> 2, q = idx & 3;
                *reinterpret_cast<uint4*>(&WsB[r][q * 8]) =
                    *reinterpret_cast<const uint4*>(W1 + (size_t)r * 128 + kt * 32 + q * 8);
            }
            __syncthreads();
            #pragma unroll
            for (int ks = 0; ks < 2; ks++) {
                int kc = kt * 32 + ks * 16;
                unsigned a0[4], a1[4];
                a0[0] = *reinterpret_cast<const unsigned*>(&HN2[g     ][kc + tig * 2]);
                a0[1] = *reinterpret_cast<const unsigned*>(&HN2[g + 8 ][kc + tig * 2]);
                a0[2] = *reinterpret_cast<const unsigned*>(&HN2[g     ][kc + tig * 2 + 8]);
                a0[3] = *reinterpret_cast<const unsigned*>(&HN2[g + 8 ][kc + tig * 2 + 8]);
                a1[0] = *reinterpret_cast<const unsigned*>(&HN2[g + 16][kc + tig * 2]);
                a1[1] = *reinterpret_cast<const unsigned*>(&HN2[g + 24][kc + tig * 2]);
                a1[2] = *reinterpret_cast<const unsigned*>(&HN2[g + 16][kc + tig * 2 + 8]);
                a1[3] = *reinterpret_cast<const unsigned*>(&HN2[g + 24][kc + tig * 2 + 8]);
                #pragma unroll
                for (int nt = 0; nt < 8; nt++) {
                    unsigned bfr[2];
                    int nrow = warp * 64 + nt * 8 + g;
                    bfr[0] = *reinterpret_cast<const unsigned*>(&WsB[nrow][ks * 16 + tig * 2]);
                    bfr[1] = *reinterpret_cast<const unsigned*>(&WsB[nrow][ks * 16 + tig * 2 + 8]);
                    mma16816(c2[0][nt], a0, bfr);
                    mma16816(c2[1][nt], a1, bfr);
                }
            }
        }
    }
    // bias + ReLU -> F (fp16)
    #pragma unroll
    for (int mt = 0; mt < 2; mt++) {
        #pragma unroll
        for (int hr = 0; hr < 2; hr++) {
            int lr = mt * 16 + hr * 8 + g;
            #pragma unroll
            for (int nt = 0; nt < 8; nt++) {
                int n = warp * 64 + nt * 8 + tig * 2;
                float v0 = fmaxf(c2[mt][nt][hr * 2 + 0] + b1[n], 0.f);
                float v1 = fmaxf(c2[mt][nt][hr * 2 + 1] + b1[n + 1], 0.f);
                __half2 hv = __floats2half2_rn(v0, v1);
                *reinterpret_cast<unsigned*>(&F[lr][n]) = *reinterpret_cast<unsigned*>(&hv);
            }
        }
    }

    // ---- stage 3: FF2 (M=32, N=128, K=512) ----
    float c3[4][4] = {};
    {
        __half (*WsC)[72] = reinterpret_cast<__half(*)[72]>(Wsraw);
        #pragma unroll
        for (int kt = 0; kt < 8; kt++) {
            __syncthreads();   // protect Ws (and F on first iter)
            #pragma unroll
            for (int it = 0; it < 4; it++) {
                int idx = tid + it * 256;
                int r = idx >> 3, q = idx & 7;
                *reinterpret_cast<uint4*>(&WsC[r][q * 8]) =
                    *reinterpret_cast<const uint4*>(W2 + (size_t)r * 512 + kt * 64 + q * 8);
            }
            __syncthreads();
            #pragma unroll
            for (int ks = 0; ks < 4; ks++) {
                int kc = kt * 64 + ks * 16;
                unsigned a[4];
                int rbase = warp_m * 16;
                a[0] = *reinterpret_cast<const unsigned*>(&F[rbase + g    ][kc + tig * 2]);
                a[1] = *reinterpret_cast<const unsigned*>(&F[rbase + g + 8][kc + tig * 2]);
                a[2] = *reinterpret_cast<const unsigned*>(&F[rbase + g    ][kc + tig * 2 + 8]);
                a[3] = *reinterpret_cast<const unsigned*>(&F[rbase + g + 8][kc + tig * 2 + 8]);
                #pragma unroll
                for (int nt = 0; nt < 4; nt++) {
                    unsigned bfr[2];
                    int nrow = warp_n * 32 + nt * 8 + g;
                    bfr[0] = *reinterpret_cast<const unsigned*>(&WsC[nrow][ks * 16 + tig * 2]);
                    bfr[1] = *reinterpret_cast<const unsigned*>(&WsC[nrow][ks * 16 + tig * 2 + 8]);
                    mma16816(c3[nt], a, bfr);
                }
            }
        }
    }
    // epilogue: bias + residual -> h global (+ optional LN1next -> hn)
    const int mrow0 = m0 + lr0, mrow1 = m0 + lr1;
    #pragma unroll
    for (int nt = 0; nt < 4; nt++) {
        int n = warp_n * 32 + nt * 8 + tig * 2;
        float b0 = b2[n], b1v = b2[n + 1];
        c3[nt][0] += b0 + Hres[lr0][n];
        c3[nt][1] += b1v + Hres[lr0][n + 1];
        c3[nt][2] += b0 + Hres[lr1][n];
        c3[nt][3] += b1v + Hres[lr1][n + 1];
        if (mrow0 < M)
            *reinterpret_cast<float2*>(h + (size_t)mrow0 * 128 + n) =
                make_float2(c3[nt][0], c3[nt][1]);
        if (mrow1 < M)
            *reinterpret_cast<float2*>(h + (size_t)mrow1 * 128 + n) =
                make_float2(c3[nt][2], c3[nt][3]);
    }
    if (LN_NEXT) {
        float s0 = 0.f, q0 = 0.f, s1 = 0.f, q1 = 0.f;
        #pragma unroll
        for (int nt = 0; nt < 4; nt++) {
            s0 += c3[nt][0] + c3[nt][1];
            q0 += c3[nt][0] * c3[nt][0] + c3[nt][1] * c3[nt][1];
            s1 += c3[nt][2] + c3[nt][3];
            q1 += c3[nt][2] * c3[nt][2] + c3[nt][3] * c3[nt][3];
        }
        #pragma unroll
        for (int o = 1; o < 4; o <<= 1) {
            s0 += __shfl_xor_sync(0xffffffffu, s0, o);
            q0 += __shfl_xor_sync(0xffffffffu, q0, o);
            s1 += __shfl_xor_sync(0xffffffffu, s1, o);
            q1 += __shfl_xor_sync(0xffffffffu, q1, o);
        }
        __syncthreads();
        if (tig == 0) {
            psum[lr0][warp_n] = s0; psq[lr0][warp_n] = q0;
            psum[lr1][warp_n] = s1; psq[lr1][warp_n] = q1;
        }
        __syncthreads();
        float sum0 = psum[lr0][0] + psum[lr0][1] + psum[lr0][2] + psum[lr0][3];
        float sq0  = psq[lr0][0] + psq[lr0][1] + psq[lr0][2] + psq[lr0][3];
        float sum1 = psum[lr1][0] + psum[lr1][1] + psum[lr1][2] + psum[lr1][3];
        float sq1  = psq[lr1][0] + psq[lr1][1] + psq[lr1][2] + psq[lr1][3];
        float mean0 = sum0 * (1.f / 128.f);
        float rstd0 = rsqrtf(sq0 * (1.f / 128.f) - mean0 * mean0 + 1e-5f);
        float mean1 = sum1 * (1.f / 128.f);
        float rstd1 = rsqrtf(sq1 * (1.f / 128.f) - mean1 * mean1 + 1e-5f);
        #pragma unroll
        for (int nt = 0; nt < 4; nt++) {
            int n = warp_n * 32 + nt * 8 + tig * 2;
            float g0 = ln1s[n], g1 = ln1s[n + 1];
            float bb0 = ln1b[n], bb1 = ln1b[n + 1];
            if (mrow0 < M) {
                __half2 hv = __floats2half2_rn(
                    (c3[nt][0] - mean0) * rstd0 * g0 + bb0,
                    (c3[nt][1] - mean0) * rstd0 * g1 + bb1);
                *reinterpret_cast<unsigned*>(hn + (size_t)mrow0 * 128 + n)
                    = *reinterpret_cast<unsigned*>(&hv);
            }
            if (mrow1 < M) {
                __half2 hv = __floats2half2_rn(
                    (c3[nt][2] - mean1) * rstd1 * g0 + bb0,
                    (c3[nt][3] - mean1) * rstd1 * g1 + bb1);
                *reinterpret_cast<unsigned*>(hn + (size_t)mrow1 * 128 + n)
                    = *reinterpret_cast<unsigned*>(&hv);
            }
        }
    }
}

// ---------------- head ----------------
__global__ __launch_bounds__(64) void head_kernel(
    const float* __restrict__ h, const float* __restrict__ ls,
    const float* __restrict__ lb, const float* __restrict__ hw,
    const float* __restrict__ hb, float* __restrict__ out)
{
    int bidx = threadIdx.x >> 5;
    if (bidx >= BATCH) return;
    int lane = threadIdx.x & 31;
    const float* xr = h + (size_t)bidx * S_LEN * D_MODEL;
    float4 v = *reinterpret_cast<const float4*>(xr + lane * 4);
    float sum = v.x + v.y + v.z + v.w;
    #pragma unroll
    for (int o = 16; o; o >>= 1) sum += __shfl_xor_sync(0xffffffffu, sum, o);
    float mean = sum * (1.f / 128.f);
    float dx = v.x - mean, dy = v.y - mean, dz = v.z - mean, dw = v.w - mean;
    float vs = dx * dx + dy * dy + dz * dz + dw * dw;
    #pragma unroll
    for (int o = 16; o; o >>= 1) vs += __shfl_xor_sync(0xffffffffu, vs, o);
    float rstd = rsqrtf(vs * (1.f / 128.f) + 1e-5f);
    float4 s4 = *reinterpret_cast<const float4*>(ls + lane * 4);
    float4 b4 = *reinterpret_cast<const float4*>(lb + lane * 4);
    float4 w4 = *reinterpret_cast<const float4*>(hw + lane * 4);
    float dot = (dx * rstd * s4.x + b4.x) * w4.x
              + (dy * rstd * s4.y + b4.y) * w4.y
              + (dz * rstd * s4.z + b4.z) * w4.z
              + (dw * rstd * s4.w + b4.w) * w4.w;
    #pragma unroll
    for (int o = 16; o; o >>= 1) dot += __shfl_xor_sync(0xffffffffu, dot, o);
    if (lane == 0) out[bidx] = dot + hb[0];
}

// ---------------- launch ----------------
extern "C" void kernel_launch(void* const* d_in, const int* in_sizes, int n_in,
                              void* d_out, int out_size)
{
    const float* x        = (const float*)d_in[0];
    const float* embed_w  = (const float*)d_in[1];
    const float* embed_b  = (const float*)d_in[2];
    const float* pos_emb  = (const float*)d_in[3];
    const float* cls      = (const float*)d_in[4];
    const float* in_w     = (const float*)d_in[5];
    const float* in_b     = (const float*)d_in[6];
    const float* out_w    = (const float*)d_in[7];
    const float* out_b    = (const float*)d_in[8];
    const float* ln1_s    = (const float*)d_in[9];
    const float* ln1_b    = (const float*)d_in[10];
    const float* ln2_s    = (const float*)d_in[11];
    const float* ln2_b    = (const float*)d_in[12];
    const float* ff1_w    = (const float*)d_in[13];
    const float* ff1_b    = (const float*)d_in[14];
    const float* ff2_w    = (const float*)d_in[15];
    const float* ff2_b    = (const float*)d_in[16];
    const float* hln_s    = (const float*)d_in[17];
    const float* hln_b    = (const float*)d_in[18];
    const float* head_w   = (const float*)d_in[19];
    const float* head_b   = (const float*)d_in[20];
    float* outp = (float*)d_out;

    float *h, *po, *pl;
    __half *hnh, *qkvh, *vt, *wh;
    cudaGetSymbolAddress((void**)&h,     g_h);
    cudaGetSymbolAddress((void**)&hnh,   g_hnh);
    cudaGetSymbolAddress((void**)&qkvh,  g_qkvh);
    cudaGetSymbolAddress((void**)&vt,    g_vt);
    cudaGetSymbolAddress((void**)&po,    g_po);
    cudaGetSymbolAddress((void**)&pl,    g_pl);
    cudaGetSymbolAddress((void**)&wh,    g_wh);

    // allow >48KB dynamic smem for the mega kernels (host-side attr; capture-safe)
    cudaFuncSetAttribute(mega_tail_kernel<true>,
                         cudaFuncAttributeMaxDynamicSharedMemorySize, SMEM_MEGA);
    cudaFuncSetAttribute(mega_tail_kernel<false>,
                         cudaFuncAttributeMaxDynamicSharedMemorySize, SMEM_MEGA);

    const int M = MROWS;
    const int MB128 = (M + 127) / 128;
    const int MB32  = (M + 31) / 32;
    const int QTILES = (S_LEN + BQ - 1) / BQ;

    convw_all_kernel<<<(CW_TOTAL + 255) / 256, 256>>>(in_w, out_w, ff1_w, ff2_w, wh);

    embed_ln_kernel<<<dim3(S_LEN, BATCH), 128>>>(
        x, embed_w, embed_b, pos_emb, cls, ln1_s, ln1_b, h, hnh);

    for (int i = 0; i < NL; i++) {
        qkv_gemm_kernel<<<dim3(384 / 64, MB128), 256>>>(
            hnh, wh + WOFF_IN + (size_t)i * 384 * 128, in_b + (size_t)i * 384,
            qkvh, vt, M);
        attn_kernel<<<dim3(QTILES * SPLITS, N_HEADS, BATCH), 256>>>(qkvh, vt, po, pl);
        if (i + 1 < NL) {
            mega_tail_kernel<true><<<MB32, 256, SMEM_MEGA>>>(
                po, pl,
                wh + WOFF_OUT + (size_t)i * 128 * 128, out_b + (size_t)i * 128,
                ln2_s + i * D_MODEL, ln2_b + i * D_MODEL,
                wh + WOFF_FF1 + (size_t)i * 512 * 128, ff1_b + (size_t)i * 512,
                wh + WOFF_FF2 + (size_t)i * 128 * 512, ff2_b + (size_t)i * 128,
                ln1_s + (i + 1) * D_MODEL, ln1_b + (i + 1) * D_MODEL,
                h, hnh, M);
        } else {
            mega_tail_kernel<false><<<MB32, 256, SMEM_MEGA>>>(
                po, pl,
                wh + WOFF_OUT + (size_t)i * 128 * 128, out_b + (size_t)i * 128,
                ln2_s + i * D_MODEL, ln2_b + i * D_MODEL,
                wh + WOFF_FF1 + (size_t)i * 512 * 128, ff1_b + (size_t)i * 512,
                wh + WOFF_FF2 + (size_t)i * 128 * 512, ff2_b + (size_t)i * 128,
                nullptr, nullptr, h, nullptr, M);
        }
    }

    head_kernel<<<1, 64>>>(h, hln_s, hln_b, head_w, head_b, outp);
}

// round 12
// speedup vs baseline: 5.3041x; 1.0274x over previous
#include <cuda_runtime.h>
#include <cuda_fp16.h>
#include <math.h>

#define NL 3
#define D_MODEL 128
#define N_HEADS 4
#define DHEAD 32
#define DFF 512
#define DIN 64
#define BATCH 2
#define LSEQ 2048
#define S_LEN 2049
#define MROWS (BATCH * S_LEN)   // 4098
#define QK_SCALE 0.17677669529663687f

#define SPLITS 3
#define KCHUNK 704
#define VT_PITCH 2112
#define PSTRIDE ((size_t)BATCH * N_HEADS * S_LEN)

// ---------------- scratch (device globals; no allocation) ----------------
__device__ float  g_h[MROWS * D_MODEL];
__device__ __half g_hnh[MROWS * D_MODEL];
__device__ __half g_qkvh[MROWS * 3 * D_MODEL];
__device__ __half g_vt[BATCH * N_HEADS * DHEAD * VT_PITCH];
__device__ float  g_po[SPLITS * BATCH * N_HEADS * S_LEN * DHEAD];
__device__ float  g_pl[SPLITS * BATCH * N_HEADS * S_LEN];
#define WOFF_IN  0
#define WOFF_OUT (NL * 384 * 128)
#define WOFF_FF1 (WOFF_OUT + NL * 128 * 128)
#define WOFF_FF2 (WOFF_FF1 + NL * 512 * 128)
#define WTOTAL   (WOFF_FF2 + NL * 128 * 512)
__device__ __half g_wh[WTOTAL];

#define CW_N0 (NL * 384 * 128 / 4)
#define CW_N1 (NL * 128 * 128 / 4)
#define CW_N2 (NL * 512 * 128 / 4)
#define CW_N3 (NL * 128 * 512 / 4)
#define CW_TOTAL (CW_N0 + CW_N1 + CW_N2 + CW_N3)

// ---------------- mega kernel dynamic smem layout (bytes) ----------------
#define OFF_ATTN 0                    // __half [32][136]  = 8704
#define OFF_HN2  8704                 // __half [32][136]  = 8704
#define OFF_HRES 17408                // float  [32][128]  = 16384
#define OFF_F    33792                // __half [32][520]  = 33280
#define OFF_WS   67072                // __half staging    = 40960
#define OFF_PS   108032               // float  [32][4]    = 512
#define OFF_PQ   108544               // float  [32][4]    = 512
#define SMEM_MEGA 109056

// ---------------- mma helper ----------------
__device__ __forceinline__ void mma16816(
    float c[4], const unsigned a[4], const unsigned b[2])
{
    asm volatile(
        "mma.sync.aligned.m16n8k16.row.col.f32.f16.f16.f32 "
        "{%0,%1,%2,%3}, {%4,%5,%6,%7}, {%8,%9}, {%0,%1,%2,%3};\n"
        : "+f"(c[0]), "+f"(c[1]), "+f"(c[2]), "+f"(c[3])
        : "r"(a[0]), "r"(a[1]), "r"(a[2]), "r"(a[3]),
          "r"(b[0]), "r"(b[1]));
}

// ---------------- fused weight fp32 -> fp16 conversion ----------------
__global__ __launch_bounds__(256) void convw_all_kernel(
    const float* __restrict__ s0, const float* __restrict__ s1,
    const float* __restrict__ s2, const float* __restrict__ s3,
    __half* __restrict__ dst)
{
    int i = blockIdx.x * 256 + threadIdx.x;
    if (i >= CW_TOTAL) return;
    const float* src;
    int off, local = i;
    if (local < CW_N0)                { src = s0; off = WOFF_IN; }
    else if ((local -= CW_N0) < CW_N1){ src = s1; off = WOFF_OUT; }
    else if ((local -= CW_N1) < CW_N2){ src = s2; off = WOFF_FF1; }
    else { local -= CW_N2;              src = s3; off = WOFF_FF2; }
    float4 v = *reinterpret_cast<const float4*>(src + (size_t)local * 4);
    __half2 a = __floats2half2_rn(v.x, v.y);
    __half2 b = __floats2half2_rn(v.z, v.w);
    uint2 pk;
    pk.x = *reinterpret_cast<unsigned*>(&a);
    pk.y = *reinterpret_cast<unsigned*>(&b);
    *reinterpret_cast<uint2*>(dst + (size_t)off + (size_t)local * 4) = pk;
}

// ---------------- embedding + fused LN1(layer0) ----------------
__global__ __launch_bounds__(128) void embed_ln_kernel(
    const float* __restrict__ x, const float* __restrict__ ew,
    const float* __restrict__ eb, const float* __restrict__ pos,
    const float* __restrict__ cls, const float* __restrict__ lns,
    const float* __restrict__ lnb, float* __restrict__ h,
    __half* __restrict__ hn)
{
    __shared__ float xs[DIN];
    __shared__ float red[8];
    int s = blockIdx.x, b = blockIdx.y;
    int d = threadIdx.x;
    if (s > 0 && d < DIN) xs[d] = x[((size_t)b * LSEQ + (s - 1)) * DIN + d];
    __syncthreads();
    float val;
    if (s == 0) {
        val = cls[d] + pos[d];
    } else {
        float acc = 0.f;
        const float* wr = ew + (size_t)d * DIN;
        #pragma unroll
        for (int j = 0; j < DIN; j++) acc = fmaf(xs[j], wr[j], acc);
        val = acc + eb[d] + pos[(size_t)s * D_MODEL + d];
    }
    size_t row = (size_t)b * S_LEN + s;
    h[row * D_MODEL + d] = val;
    int w = d >> 5, lane = d & 31;
    float sv = val, qv = val * val;
    #pragma unroll
    for (int o = 16; o; o >>= 1) {
        sv += __shfl_xor_sync(0xffffffffu, sv, o);
        qv += __shfl_xor_sync(0xffffffffu, qv, o);
    }
    if (lane == 0) { red[w] = sv; red[4 + w] = qv; }
    __syncthreads();
    float sum = red[0] + red[1] + red[2] + red[3];
    float sq  = red[4] + red[5] + red[6] + red[7];
    float mean = sum * (1.f / 128.f);
    float rstd = rsqrtf(sq * (1.f / 128.f) - mean * mean + 1e-5f);
    hn[row * D_MODEL + d] = __float2half_rn((val - mean) * rstd * lns[d] + lnb[d]);
}

// ---------------- QKV tensor-core GEMM (layer 0 only) ----------------
#define GPITCH 40
__global__ __launch_bounds__(256) void qkv_gemm_kernel(
    const __half* __restrict__ A, const __half* __restrict__ W,
    const float* __restrict__ bias, __half* __restrict__ C,
    __half* __restrict__ vT, int M)
{
    const int N = 384, K = 128;
    __shared__ __half As[128][GPITCH];
    __shared__ __half Ws[64][GPITCH];
    const int tid = threadIdx.x;
    const int warp = tid >> 5;
    const int lane = tid & 31;
    const int g = lane >> 2;
    const int tig = lane & 3;
    const int warp_m = warp >> 1;
    const int warp_n = warp & 1;
    const int m0 = blockIdx.y * 128;
    const int n0 = blockIdx.x * 64;
    const int NK = K / 32;
    const int wr = tid >> 2, wq = tid & 3;

    float c[2][4][4] = {};

    uint4 aReg[2], wReg;
    #pragma unroll
    for (int it = 0; it < 2; it++) {
        int idx = tid + it * 256;
        int r = idx >> 2, quad = idx & 3;
        int m = m0 + r;
        aReg[it] = (m < M)
            ? *reinterpret_cast<const uint4*>(A + (size_t)m * K + quad * 8)
            : make_uint4(0u, 0u, 0u, 0u);
    }
    wReg = *reinterpret_cast<const uint4*>(W + (size_t)(n0 + wr) * K + wq * 8);

    for (int kt = 0; kt < NK; kt++) {
        #pragma unroll
        for (int it = 0; it < 2; it++) {
            int idx = tid + it * 256;
            int r = idx >> 2, quad = idx & 3;
            *reinterpret_cast<uint4*>(&As[r][quad * 8]) = aReg[it];
        }
        *reinterpret_cast<uint4*>(&Ws[wr][wq * 8]) = wReg;
        __syncthreads();
        if (kt + 1 < NK) {
            int k0 = (kt + 1) * 32;
            #pragma unroll
            for (int it = 0; it < 2; it++) {
                int idx = tid + it * 256;
                int r = idx >> 2, quad = idx & 3;
                int m = m0 + r;
                aReg[it] = (m < M)
                    ? *reinterpret_cast<const uint4*>(A + (size_t)m * K + k0 + quad * 8)
                    : make_uint4(0u, 0u, 0u, 0u);
            }
            wReg = *reinterpret_cast<const uint4*>(W + (size_t)(n0 + wr) * K + k0 + wq * 8);
        }
        #pragma unroll
        for (int ks = 0; ks < 2; ks++) {
            unsigned a[2][4];
            #pragma unroll
            for (int mt = 0; mt < 2; mt++) {
                int rbase = warp_m * 32 + mt * 16;
                a[mt][0] = *reinterpret_cast<const unsigned*>(&As[rbase + g    ][ks * 16 + tig * 2]);
                a[mt][1] = *reinterpret_cast<const unsigned*>(&As[rbase + g + 8][ks * 16 + tig * 2]);
                a[mt][2] = *reinterpret_cast<const unsigned*>(&As[rbase + g    ][ks * 16 + tig * 2 + 8]);
                a[mt][3] = *reinterpret_cast<const unsigned*>(&As[rbase + g + 8][ks * 16 + tig * 2 + 8]);
            }
            #pragma unroll
            for (int nt = 0; nt < 4; nt++) {
                unsigned bfr[2];
                int nrow = warp_n * 32 + nt * 8 + g;
                bfr[0] = *reinterpret_cast<const unsigned*>(&Ws[nrow][ks * 16 + tig * 2]);
                bfr[1] = *reinterpret_cast<const unsigned*>(&Ws[nrow][ks * 16 + tig * 2 + 8]);
                mma16816(c[0][nt], a[0], bfr);
                mma16816(c[1][nt], a[1], bfr);
            }
        }
        __syncthreads();
    }

    #pragma unroll
    for (int mt = 0; mt < 2; mt++) {
        #pragma unroll
        for (int half_row = 0; half_row < 2; half_row++) {
            int m = m0 + warp_m * 32 + mt * 16 + g + half_row * 8;
            if (m >= M) continue;
            int bb = m / S_LEN, ss = m % S_LEN;
            #pragma unroll
            for (int nt = 0; nt < 4; nt++) {
                int n = n0 + warp_n * 32 + nt * 8 + tig * 2;
                float v0 = c[mt][nt][half_row * 2 + 0] + bias[n];
                float v1 = c[mt][nt][half_row * 2 + 1] + bias[n + 1];
                if (n >= 256) {
                    int hh = (n - 256) >> 5, dd = (n - 256) & 31;
                    __half* vbase = vT + ((size_t)(bb * N_HEADS + hh) * DHEAD + dd) * VT_PITCH + ss;
                    vbase[0] = __float2half_rn(v0);
                    vbase[VT_PITCH] = __float2half_rn(v1);
                } else {
                    if (n < 128) { v0 *= QK_SCALE; v1 *= QK_SCALE; }
                    __half2 hv = __floats2half2_rn(v0, v1);
                    *reinterpret_cast<unsigned*>(
                        C + (size_t)m * N + n) = *reinterpret_cast<unsigned*>(&hv);
                }
            }
        }
    }
}

// ---------------- split-S flash attention (fixed max = 0) ----------------
#define BQ 128
#define BK 64
#define QPITCH 40
#define VPITCH 72

__global__ __launch_bounds__(256, 3) void attn_kernel(
    const __half* __restrict__ qkv, const __half* __restrict__ vT,
    float* __restrict__ po, float* __restrict__ pl)
{
    __shared__ __half Qs[BQ][QPITCH];
    __shared__ __half Kt[2][BK][QPITCH];
    __shared__ __half Vt[2][DHEAD][VPITCH];
    const int tid = threadIdx.x;
    const int warp = tid >> 5;
    const int lane = tid & 31;
    const int g = lane >> 2;
    const int tig = lane & 3;
    const int b = blockIdx.z, h = blockIdx.y;
    const int tile = blockIdx.x / SPLITS;
    const int split = blockIdx.x % SPLITS;
    const int q0 = tile * BQ;
    const int qbase = warp * 16;
    const int kstart = split * KCHUNK;
    const int kend = min(kstart + KCHUNK, S_LEN);
    const int ntile = (kend - kstart + BK - 1) / BK;

    #pragma unroll
    for (int idx = tid; idx < BQ * 4; idx += 256) {
        int r = idx >> 2, quad = idx & 3;
        int q = q0 + r;
        uint4 v = make_uint4(0u, 0u, 0u, 0u);
        if (q < S_LEN)
            v = *reinterpret_cast<const uint4*>(
                qkv + ((size_t)(b * S_LEN + q)) * 384 + h * 32 + quad * 8);
        *reinterpret_cast<uint4*>(&Qs[r][quad * 8]) = v;
    }

    const __half* Kbase = qkv + (size_t)b * S_LEN * 384 + 128 + h * 32;
    const __half* Vbase = vT + (size_t)(b * N_HEADS + h) * DHEAD * VT_PITCH;
    const int kr = tid >> 2, kq = tid & 3;
    const int vr = tid >> 3, vq = tid & 7;

    uint4 kreg, vreg;
    {
        int kg = kstart + kr;
        kreg = (kg < S_LEN)
            ? *reinterpret_cast<const uint4*>(Kbase + (size_t)kg * 384 + kq * 8)
            : make_uint4(0u, 0u, 0u, 0u);
        vreg = *reinterpret_cast<const uint4*>(Vbase + (size_t)vr * VT_PITCH + kstart + vq * 8);
    }
    *reinterpret_cast<uint4*>(&Kt[0][kr][kq * 8]) = kreg;
    *reinterpret_cast<uint4*>(&Vt[0][vr][vq * 8]) = vreg;
    __syncthreads();

    unsigned A[2][4];
    #pragma unroll
    for (int ks = 0; ks < 2; ks++) {
        A[ks][0] = *reinterpret_cast<const unsigned*>(&Qs[qbase + g    ][ks * 16 + tig * 2]);
        A[ks][1] = *reinterpret_cast<const unsigned*>(&Qs[qbase + g + 8][ks * 16 + tig * 2]);
        A[ks][2] = *reinterpret_cast<const unsigned*>(&Qs[qbase + g    ][ks * 16 + tig * 2 + 8]);
        A[ks][3] = *reinterpret_cast<const unsigned*>(&Qs[qbase + g + 8][ks * 16 + tig * 2 + 8]);
    }

    float l0 = 0.f, l1 = 0.f;
    float o[4][4] = {};

    for (int t = 0; t < ntile; t++) {
        const int kb = kstart + t * BK;
        const int buf = t & 1;
        if (t + 1 < ntile) {
            int kb2 = kb + BK;
            int kg = kb2 + kr;
            kreg = (kg < S_LEN)
                ? *reinterpret_cast<const uint4*>(Kbase + (size_t)kg * 384 + kq * 8)
                : make_uint4(0u, 0u, 0u, 0u);
            vreg = *reinterpret_cast<const uint4*>(Vbase + (size_t)vr * VT_PITCH + kb2 + vq * 8);
        }

        float s[8][4];
        #pragma unroll
        for (int j = 0; j < 8; j++) {
            s[j][0] = s[j][1] = s[j][2] = s[j][3] = 0.f;
            #pragma unroll
            for (int ks = 0; ks < 2; ks++) {
                unsigned bfr[2];
                bfr[0] = *reinterpret_cast<const unsigned*>(&Kt[buf][j * 8 + g][ks * 16 + tig * 2]);
                bfr[1] = *reinterpret_cast<const unsigned*>(&Kt[buf][j * 8 + g][ks * 16 + tig * 2 + 8]);
                mma16816(s[j], A[ks], bfr);
            }
        }
        if (kb + BK > S_LEN) {
            #pragma unroll
            for (int j = 0; j < 8; j++) {
                int key = kb + j * 8 + tig * 2;
                if (key >= S_LEN)     { s[j][0] = -1e30f; s[j][2] = -1e30f; }
                if (key + 1 >= S_LEN) { s[j][1] = -1e30f; s[j][3] = -1e30f; }
            }
        }

        unsigned ph[8][2];
        #pragma unroll
        for (int j = 0; j < 8; j++) {
            __half2 h2a = __floats2half2_rn(__expf(s[j][0]), __expf(s[j][1]));
            __half2 h2b = __floats2half2_rn(__expf(s[j][2]), __expf(s[j][3]));
            ph[j][0] = *reinterpret_cast<unsigned*>(&h2a);
            ph[j][1] = *reinterpret_cast<unsigned*>(&h2b);
            float2 fa = __half22float2(h2a);
            float2 fb = __half22float2(h2b);
            l0 += fa.x + fa.y;
            l1 += fb.x + fb.y;
        }

        #pragma unroll
        for (int kt = 0; kt < 4; kt++) {
            unsigned pa[4] = { ph[2 * kt][0], ph[2 * kt][1],
                               ph[2 * kt + 1][0], ph[2 * kt + 1][1] };
            #pragma unroll
            for (int nt = 0; nt < 4; nt++) {
                unsigned bfr[2];
                bfr[0] = *reinterpret_cast<const unsigned*>(&Vt[buf][nt * 8 + g][kt * 16 + tig * 2]);
                bfr[1] = *reinterpret_cast<const unsigned*>(&Vt[buf][nt * 8 + g][kt * 16 + tig * 2 + 8]);
                mma16816(o[nt], pa, bfr);
            }
        }
        if (t + 1 < ntile) {
            *reinterpret_cast<uint4*>(&Kt[buf ^ 1][kr][kq * 8]) = kreg;
            *reinterpret_cast<uint4*>(&Vt[buf ^ 1][vr][vq * 8]) = vreg;
        }
        __syncthreads();
    }

    l0 += __shfl_xor_sync(0xffffffffu, l0, 1);
    l0 += __shfl_xor_sync(0xffffffffu, l0, 2);
    l1 += __shfl_xor_sync(0xffffffffu, l1, 1);
    l1 += __shfl_xor_sync(0xffffffffu, l1, 2);

    const size_t pbase = (((size_t)split * BATCH + b) * N_HEADS + h) * S_LEN;
    int qa = q0 + qbase + g;
    int qb2 = qa + 8;
    if (qa < S_LEN) {
        #pragma unroll
        for (int nt = 0; nt < 4; nt++) {
            float2 v = make_float2(o[nt][0], o[nt][1]);
            *reinterpret_cast<float2*>(po + (pbase + qa) * DHEAD + nt * 8 + tig * 2) = v;
        }
        if (tig == 0) pl[pbase + qa] = l0;
    }
    if (qb2 < S_LEN) {
        #pragma unroll
        for (int nt = 0; nt < 4; nt++) {
            float2 v = make_float2(o[nt][2], o[nt][3]);
            *reinterpret_cast<float2*>(po + (pbase + qb2) * DHEAD + nt * 8 + tig * 2) = v;
        }
        if (tig == 0) pl[pbase + qb2] = l1;
    }
}

// ---------------- MEGA layer-tail kernel --------------------------------
// merge(po,pl) -> out-proj + resid -> LN2 -> FF1+ReLU -> FF2 + resid -> h
// QKV_NEXT: additionally LN1next (smem) -> QKV GEMM of next layer -> qkvh/vt.
template <bool QKV_NEXT>
__global__ __launch_bounds__(256) void mega_tail_kernel(
    const float* __restrict__ po, const float* __restrict__ pl,
    const __half* __restrict__ Wout, const float* __restrict__ bout,
    const float* __restrict__ ln2s, const float* __restrict__ ln2b,
    const __half* __restrict__ W1, const float* __restrict__ b1,
    const __half* __restrict__ W2, const float* __restrict__ b2,
    const float* __restrict__ ln1s, const float* __restrict__ ln1b,
    const __half* __restrict__ Win, const float* __restrict__ bin,
    float* __restrict__ h, __half* __restrict__ qkvh,
    __half* __restrict__ vT, int M)
{
    extern __shared__ char smem[];
    __half (*Attn)[136] = reinterpret_cast<__half(*)[136]>(smem + OFF_ATTN);
    __half (*HN2)[136]  = reinterpret_cast<__half(*)[136]>(smem + OFF_HN2);
    float (*Hres)[128]  = reinterpret_cast<float(*)[128]>(smem + OFF_HRES);
    __half (*F)[520]    = reinterpret_cast<__half(*)[520]>(smem + OFF_F);
    __half* Wsraw       = reinterpret_cast<__half*>(smem + OFF_WS);
    float (*psum)[4]    = reinterpret_cast<float(*)[4]>(smem + OFF_PS);
    float (*psq)[4]     = reinterpret_cast<float(*)[4]>(smem + OFF_PQ);

    const int tid = threadIdx.x;
    const int warp = tid >> 5;
    const int lane = tid & 31;
    const int g = lane >> 2;
    const int tig = lane & 3;
    const int warp_m = warp >> 2;   // 0..1
    const int warp_n = warp & 3;    // 0..3
    const int m0 = blockIdx.x * 32;

    // ---- stage 0: merge attention partials into Attn; load residual ----
    {
        int row = tid >> 3;
        int dseg = (tid & 7) * 16;
        int mrow = m0 + row;
        if (mrow < M) {
            int bb = mrow / S_LEN, qq = mrow % S_LEN;
            int hh = dseg >> 5, dd = dseg & 31;
            size_t prow = ((size_t)bb * N_HEADS + hh) * S_LEN + qq;
            float linv = 1.f / (pl[prow] + pl[prow + PSTRIDE] + pl[prow + 2 * PSTRIDE]);
            float acc[16];
            #pragma unroll
            for (int t = 0; t < 4; t++) {
                float4 p0 = *reinterpret_cast<const float4*>(po + prow * DHEAD + dd + t * 4);
                float4 p1 = *reinterpret_cast<const float4*>(po + (prow + PSTRIDE) * DHEAD + dd + t * 4);
                float4 p2 = *reinterpret_cast<const float4*>(po + (prow + 2 * PSTRIDE) * DHEAD + dd + t * 4);
                acc[t * 4 + 0] = (p0.x + p1.x + p2.x) * linv;
                acc[t * 4 + 1] = (p0.y + p1.y + p2.y) * linv;
                acc[t * 4 + 2] = (p0.z + p1.z + p2.z) * linv;
                acc[t * 4 + 3] = (p0.w + p1.w + p2.w) * linv;
            }
            unsigned pk[8];
            #pragma unroll
            for (int t = 0; t < 8; t++) {
                __half2 hv = __floats2half2_rn(acc[t * 2], acc[t * 2 + 1]);
                pk[t] = *reinterpret_cast<unsigned*>(&hv);
            }
            *reinterpret_cast<uint4*>(&Attn[row][dseg]) = make_uint4(pk[0], pk[1], pk[2], pk[3]);
            *reinterpret_cast<uint4*>(&Attn[row][dseg + 8]) = make_uint4(pk[4], pk[5], pk[6], pk[7]);
            #pragma unroll
            for (int t = 0; t < 4; t++)
                *reinterpret_cast<float4*>(&Hres[row][dseg + t * 4]) =
                    *reinterpret_cast<const float4*>(h + (size_t)mrow * 128 + dseg + t * 4);
        } else {
            uint4 z = make_uint4(0u, 0u, 0u, 0u);
            *reinterpret_cast<uint4*>(&Attn[row][dseg]) = z;
            *reinterpret_cast<uint4*>(&Attn[row][dseg + 8]) = z;
            float4 fz = make_float4(0.f, 0.f, 0.f, 0.f);
            #pragma unroll
            for (int t = 0; t < 4; t++)
                *reinterpret_cast<float4*>(&Hres[row][dseg + t * 4]) = fz;
        }
    }
    // ---- stage Wout fully: [128][136] ----
    {
        __half (*WsA)[136] = reinterpret_cast<__half(*)[136]>(Wsraw);
        #pragma unroll
        for (int it = 0; it < 8; it++) {
            int idx = tid + it * 256;
            int r = idx >> 4, q = idx & 15;
            *reinterpret_cast<uint4*>(&WsA[r][q * 8]) =
                *reinterpret_cast<const uint4*>(Wout + (size_t)r * 128 + q * 8);
        }
    }
    __syncthreads();

    // ---- stage 1: out-proj GEMM ----
    float c1[4][4] = {};
    {
        __half (*WsA)[136] = reinterpret_cast<__half(*)[136]>(Wsraw);
        #pragma unroll
        for (int ks8 = 0; ks8 < 8; ks8++) {
            int kc = ks8 * 16;
            unsigned a[4];
            int rbase = warp_m * 16;
            a[0] = *reinterpret_cast<const unsigned*>(&Attn[rbase + g    ][kc + tig * 2]);
            a[1] = *reinterpret_cast<const unsigned*>(&Attn[rbase + g + 8][kc + tig * 2]);
            a[2] = *reinterpret_cast<const unsigned*>(&Attn[rbase + g    ][kc + tig * 2 + 8]);
            a[3] = *reinterpret_cast<const unsigned*>(&Attn[rbase + g + 8][kc + tig * 2 + 8]);
            #pragma unroll
            for (int nt = 0; nt < 4; nt++) {
                unsigned bfr[2];
                int nrow = warp_n * 32 + nt * 8 + g;
                bfr[0] = *reinterpret_cast<const unsigned*>(&WsA[nrow][kc + tig * 2]);
                bfr[1] = *reinterpret_cast<const unsigned*>(&WsA[nrow][kc + tig * 2 + 8]);
                mma16816(c1[nt], a, bfr);
            }
        }
    }
    const int lr0 = warp_m * 16 + g, lr1 = lr0 + 8;
    #pragma unroll
    for (int nt = 0; nt < 4; nt++) {
        int n = warp_n * 32 + nt * 8 + tig * 2;
        float b0 = bout[n], b1v = bout[n + 1];
        c1[nt][0] += b0 + Hres[lr0][n];
        c1[nt][1] += b1v + Hres[lr0][n + 1];
        c1[nt][2] += b0 + Hres[lr1][n];
        c1[nt][3] += b1v + Hres[lr1][n + 1];
    }
    // LN2 -> HN2
    {
        float s0 = 0.f, q0 = 0.f, s1 = 0.f, q1 = 0.f;
        #pragma unroll
        for (int nt = 0; nt < 4; nt++) {
            s0 += c1[nt][0] + c1[nt][1];
            q0 += c1[nt][0] * c1[nt][0] + c1[nt][1] * c1[nt][1];
            s1 += c1[nt][2] + c1[nt][3];
            q1 += c1[nt][2] * c1[nt][2] + c1[nt][3] * c1[nt][3];
        }
        #pragma unroll
        for (int o = 1; o < 4; o <<= 1) {
            s0 += __shfl_xor_sync(0xffffffffu, s0, o);
            q0 += __shfl_xor_sync(0xffffffffu, q0, o);
            s1 += __shfl_xor_sync(0xffffffffu, s1, o);
            q1 += __shfl_xor_sync(0xffffffffu, q1, o);
        }
        if (tig == 0) {
            psum[lr0][warp_n] = s0; psq[lr0][warp_n] = q0;
            psum[lr1][warp_n] = s1; psq[lr1][warp_n] = q1;
        }
        __syncthreads();
        float sum0 = psum[lr0][0] + psum[lr0][1] + psum[lr0][2] + psum[lr0][3];
        float sq0  = psq[lr0][0] + psq[lr0][1] + psq[lr0][2] + psq[lr0][3];
        float sum1 = psum[lr1][0] + psum[lr1][1] + psum[lr1][2] + psum[lr1][3];
        float sq1  = psq[lr1][0] + psq[lr1][1] + psq[lr1][2] + psq[lr1][3];
        float mean0 = sum0 * (1.f / 128.f);
        float rstd0 = rsqrtf(sq0 * (1.f / 128.f) - mean0 * mean0 + 1e-5f);
        float mean1 = sum1 * (1.f / 128.f);
        float rstd1 = rsqrtf(sq1 * (1.f / 128.f) - mean1 * mean1 + 1e-5f);
        #pragma unroll
        for (int nt = 0; nt < 4; nt++) {
            int n = warp_n * 32 + nt * 8 + tig * 2;
            float g0 = ln2s[n], g1 = ln2s[n + 1];
            float bb0 = ln2b[n], bb1 = ln2b[n + 1];
            __half2 hv0 = __floats2half2_rn(
                (c1[nt][0] - mean0) * rstd0 * g0 + bb0,
                (c1[nt][1] - mean0) * rstd0 * g1 + bb1);
            __half2 hv1 = __floats2half2_rn(
                (c1[nt][2] - mean1) * rstd1 * g0 + bb0,
                (c1[nt][3] - mean1) * rstd1 * g1 + bb1);
            *reinterpret_cast<unsigned*>(&HN2[lr0][n]) = *reinterpret_cast<unsigned*>(&hv0);
            *reinterpret_cast<unsigned*>(&HN2[lr1][n]) = *reinterpret_cast<unsigned*>(&hv1);
            Hres[lr0][n] = c1[nt][0]; Hres[lr0][n + 1] = c1[nt][1];
            Hres[lr1][n] = c1[nt][2]; Hres[lr1][n + 1] = c1[nt][3];
        }
    }

    // ---- stage 2: FF1 (M=32, N=512, K=128) ----
    float c2[2][8][4] = {};
    {
        __half (*WsB)[40] = reinterpret_cast<__half(*)[40]>(Wsraw);
        #pragma unroll
        for (int kt = 0; kt < 4; kt++) {
            __syncthreads();
            #pragma unroll
            for (int it = 0; it < 8; it++) {
                int idx = tid + it * 256;
                int r = idx >> 2, q = idx & 3;
                *reinterpret_cast<uint4*>(&WsB[r][q * 8]) =
                    *reinterpret_cast<const uint4*>(W1 + (size_t)r * 128 + kt * 32 + q * 8);
            }
            __syncthreads();
            #pragma unroll
            for (int ks = 0; ks < 2; ks++) {
                int kc = kt * 32 + ks * 16;
                unsigned a0[4], a1[4];
                a0[0] = *reinterpret_cast<const unsigned*>(&HN2[g     ][kc + tig * 2]);
                a0[1] = *reinterpret_cast<const unsigned*>(&HN2[g + 8 ][kc + tig * 2]);
                a0[2] = *reinterpret_cast<const unsigned*>(&HN2[g     ][kc + tig * 2 + 8]);
                a0[3] = *reinterpret_cast<const unsigned*>(&HN2[g + 8 ][kc + tig * 2 + 8]);
                a1[0] = *reinterpret_cast<const unsigned*>(&HN2[g + 16][kc + tig * 2]);
                a1[1] = *reinterpret_cast<const unsigned*>(&HN2[g + 24][kc + tig * 2]);
                a1[2] = *reinterpret_cast<const unsigned*>(&HN2[g + 16][kc + tig * 2 + 8]);
                a1[3] = *reinterpret_cast<const unsigned*>(&HN2[g + 24][kc + tig * 2 + 8]);
                #pragma unroll
                for (int nt = 0; nt < 8; nt++) {
                    unsigned bfr[2];
                    int nrow = warp * 64 + nt * 8 + g;
                    bfr[0] = *reinterpret_cast<const unsigned*>(&WsB[nrow][ks * 16 + tig * 2]);
                    bfr[1] = *reinterpret_cast<const unsigned*>(&WsB[nrow][ks * 16 + tig * 2 + 8]);
                    mma16816(c2[0][nt], a0, bfr);
                    mma16816(c2[1][nt], a1, bfr);
                }
            }
        }
    }
    #pragma unroll
    for (int mt = 0; mt < 2; mt++) {
        #pragma unroll
        for (int hr = 0; hr < 2; hr++) {
            int lr = mt * 16 + hr * 8 + g;
            #pragma unroll
            for (int nt = 0; nt < 8; nt++) {
                int n = warp * 64 + nt * 8 + tig * 2;
                float v0 = fmaxf(c2[mt][nt][hr * 2 + 0] + b1[n], 0.f);
                float v1 = fmaxf(c2[mt][nt][hr * 2 + 1] + b1[n + 1], 0.f);
                __half2 hv = __floats2half2_rn(v0, v1);
                *reinterpret_cast<unsigned*>(&F[lr][n]) = *reinterpret_cast<unsigned*>(&hv);
            }
        }
    }

    // ---- stage 3: FF2 (M=32, N=128, K=512) ----
    float c3[4][4] = {};
    {
        __half (*WsC)[72] = reinterpret_cast<__half(*)[72]>(Wsraw);
        #pragma unroll
        for (int kt = 0; kt < 8; kt++) {
            __syncthreads();
            #pragma unroll
            for (int it = 0; it < 4; it++) {
                int idx = tid + it * 256;
                int r = idx >> 3, q = idx & 7;
                *reinterpret_cast<uint4*>(&WsC[r][q * 8]) =
                    *reinterpret_cast<const uint4*>(W2 + (size_t)r * 512 + kt * 64 + q * 8);
            }
            __syncthreads();
            #pragma unroll
            for (int ks = 0; ks < 4; ks++) {
                int kc = kt * 64 + ks * 16;
                unsigned a[4];
                int rbase = warp_m * 16;
                a[0] = *reinterpret_cast<const unsigned*>(&F[rbase + g    ][kc + tig * 2]);
                a[1] = *reinterpret_cast<const unsigned*>(&F[rbase + g + 8][kc + tig * 2]);
                a[2] = *reinterpret_cast<const unsigned*>(&F[rbase + g    ][kc + tig * 2 + 8]);
                a[3] = *reinterpret_cast<const unsigned*>(&F[rbase + g + 8][kc + tig * 2 + 8]);
                #pragma unroll
                for (int nt = 0; nt < 4; nt++) {
                    unsigned bfr[2];
                    int nrow = warp_n * 32 + nt * 8 + g;
                    bfr[0] = *reinterpret_cast<const unsigned*>(&WsC[nrow][ks * 16 + tig * 2]);
                    bfr[1] = *reinterpret_cast<const unsigned*>(&WsC[nrow][ks * 16 + tig * 2 + 8]);
                    mma16816(c3[nt], a, bfr);
                }
            }
        }
    }
    // epilogue: bias + residual -> h global
    const int mrow0 = m0 + lr0, mrow1 = m0 + lr1;
    #pragma unroll
    for (int nt = 0; nt < 4; nt++) {
        int n = warp_n * 32 + nt * 8 + tig * 2;
        float b0 = b2[n], b1v = b2[n + 1];
        c3[nt][0] += b0 + Hres[lr0][n];
        c3[nt][1] += b1v + Hres[lr0][n + 1];
        c3[nt][2] += b0 + Hres[lr1][n];
        c3[nt][3] += b1v + Hres[lr1][n + 1];
        if (mrow0 < M)
            *reinterpret_cast<float2*>(h + (size_t)mrow0 * 128 + n) =
                make_float2(c3[nt][0], c3[nt][1]);
        if (mrow1 < M)
            *reinterpret_cast<float2*>(h + (size_t)mrow1 * 128 + n) =
                make_float2(c3[nt][2], c3[nt][3]);
    }

    if (QKV_NEXT) {
        // ---- LN1next -> HN2 (smem) ----
        float s0 = 0.f, q0 = 0.f, s1 = 0.f, q1 = 0.f;
        #pragma unroll
        for (int nt = 0; nt < 4; nt++) {
            s0 += c3[nt][0] + c3[nt][1];
            q0 += c3[nt][0] * c3[nt][0] + c3[nt][1] * c3[nt][1];
            s1 += c3[nt][2] + c3[nt][3];
            q1 += c3[nt][2] * c3[nt][2] + c3[nt][3] * c3[nt][3];
        }
        #pragma unroll
        for (int o = 1; o < 4; o <<= 1) {
            s0 += __shfl_xor_sync(0xffffffffu, s0, o);
            q0 += __shfl_xor_sync(0xffffffffu, q0, o);
            s1 += __shfl_xor_sync(0xffffffffu, s1, o);
            q1 += __shfl_xor_sync(0xffffffffu, q1, o);
        }
        __syncthreads();
        if (tig == 0) {
            psum[lr0][warp_n] = s0; psq[lr0][warp_n] = q0;
            psum[lr1][warp_n] = s1; psq[lr1][warp_n] = q1;
        }
        __syncthreads();
        float sum0 = psum[lr0][0] + psum[lr0][1] + psum[lr0][2] + psum[lr0][3];
        float sq0  = psq[lr0][0] + psq[lr0][1] + psq[lr0][2] + psq[lr0][3];
        float sum1 = psum[lr1][0] + psum[lr1][1] + psum[lr1][2] + psum[lr1][3];
        float sq1  = psq[lr1][0] + psq[lr1][1] + psq[lr1][2] + psq[lr1][3];
        float mean0 = sum0 * (1.f / 128.f);
        float rstd0 = rsqrtf(sq0 * (1.f / 128.f) - mean0 * mean0 + 1e-5f);
        float mean1 = sum1 * (1.f / 128.f);
        float rstd1 = rsqrtf(sq1 * (1.f / 128.f) - mean1 * mean1 + 1e-5f);
        #pragma unroll
        for (int nt = 0; nt < 4; nt++) {
            int n = warp_n * 32 + nt * 8 + tig * 2;
            float g0 = ln1s[n], g1 = ln1s[n + 1];
            float bb0 = ln1b[n], bb1 = ln1b[n + 1];
            __half2 hv0 = __floats2half2_rn(
                (c3[nt][0] - mean0) * rstd0 * g0 + bb0,
                (c3[nt][1] - mean0) * rstd0 * g1 + bb1);
            __half2 hv1 = __floats2half2_rn(
                (c3[nt][2] - mean1) * rstd1 * g0 + bb0,
                (c3[nt][3] - mean1) * rstd1 * g1 + bb1);
            *reinterpret_cast<unsigned*>(&HN2[lr0][n]) = *reinterpret_cast<unsigned*>(&hv0);
            *reinterpret_cast<unsigned*>(&HN2[lr1][n]) = *reinterpret_cast<unsigned*>(&hv1);
        }

        // ---- stage 4: QKV GEMM of next layer (M=32, N=384, K=128) ----
        __half (*WsA)[136] = reinterpret_cast<__half(*)[136]>(Wsraw);
        for (int chunk = 0; chunk < 3; chunk++) {
            __syncthreads();   // protect WsA from prior reads / HN2 writes
            #pragma unroll
            for (int it = 0; it < 8; it++) {
                int idx = tid + it * 256;
                int r = idx >> 4, q = idx & 15;
                *reinterpret_cast<uint4*>(&WsA[r][q * 8]) =
                    *reinterpret_cast<const uint4*>(
                        Win + (size_t)(chunk * 128 + r) * 128 + q * 8);
            }
            __syncthreads();
            float c4[4][4] = {};
            #pragma unroll
            for (int ks8 = 0; ks8 < 8; ks8++) {
                int kc = ks8 * 16;
                unsigned a[4];
                int rbase = warp_m * 16;
                a[0] = *reinterpret_cast<const unsigned*>(&HN2[rbase + g    ][kc + tig * 2]);
                a[1] = *reinterpret_cast<const unsigned*>(&HN2[rbase + g + 8][kc + tig * 2]);
                a[2] = *reinterpret_cast<const unsigned*>(&HN2[rbase + g    ][kc + tig * 2 + 8]);
                a[3] = *reinterpret_cast<const unsigned*>(&HN2[rbase + g + 8][kc + tig * 2 + 8]);
                #pragma unroll
                for (int nt = 0; nt < 4; nt++) {
                    unsigned bfr[2];
                    int nrow = warp_n * 32 + nt * 8 + g;
                    bfr[0] = *reinterpret_cast<const unsigned*>(&WsA[nrow][kc + tig * 2]);
                    bfr[1] = *reinterpret_cast<const unsigned*>(&WsA[nrow][kc + tig * 2 + 8]);
                    mma16816(c4[nt], a, bfr);
                }
            }
            // epilogue for this chunk
            #pragma unroll
            for (int nt = 0; nt < 4; nt++) {
                int nl = warp_n * 32 + nt * 8 + tig * 2;
                int n = chunk * 128 + nl;
                float b0 = bin[n], b1v = bin[n + 1];
                float v00 = c4[nt][0] + b0, v01 = c4[nt][1] + b1v;
                float v10 = c4[nt][2] + b0, v11 = c4[nt][3] + b1v;
                if (chunk < 2) {
                    if (chunk == 0) { v00 *= QK_SCALE; v01 *= QK_SCALE;
                                      v10 *= QK_SCALE; v11 *= QK_SCALE; }
                    if (mrow0 < M) {
                        __half2 hv = __floats2half2_rn(v00, v01);
                        *reinterpret_cast<unsigned*>(qkvh + (size_t)mrow0 * 384 + n)
                            = *reinterpret_cast<unsigned*>(&hv);
                    }
                    if (mrow1 < M) {
                        __half2 hv = __floats2half2_rn(v10, v11);
                        *reinterpret_cast<unsigned*>(qkvh + (size_t)mrow1 * 384 + n)
                            = *reinterpret_cast<unsigned*>(&hv);
                    }
                } else {
                    int hh = nl >> 5, dd = nl & 31;
                    if (mrow0 < M) {
                        int bb = mrow0 / S_LEN, ss = mrow0 % S_LEN;
                        __half* vb = vT + ((size_t)(bb * N_HEADS + hh) * DHEAD + dd) * VT_PITCH + ss;
                        vb[0] = __float2half_rn(v00);
                        vb[VT_PITCH] = __float2half_rn(v01);
                    }
                    if (mrow1 < M) {
                        int bb = mrow1 / S_LEN, ss = mrow1 % S_LEN;
                        __half* vb = vT + ((size_t)(bb * N_HEADS + hh) * DHEAD + dd) * VT_PITCH + ss;
                        vb[0] = __float2half_rn(v10);
                        vb[VT_PITCH] = __float2half_rn(v11);
                    }
                }
            }
        }
    }
}

// ---------------- head ----------------
__global__ __launch_bounds__(64) void head_kernel(
    const float* __restrict__ h, const float* __restrict__ ls,
    const float* __restrict__ lb, const float* __restrict__ hw,
    const float* __restrict__ hb, float* __restrict__ out)
{
    int bidx = threadIdx.x >> 5;
    if (bidx >= BATCH) return;
    int lane = threadIdx.x & 31;
    const float* xr = h + (size_t)bidx * S_LEN * D_MODEL;
    float4 v = *reinterpret_cast<const float4*>(xr + lane * 4);
    float sum = v.x + v.y + v.z + v.w;
    #pragma unroll
    for (int o = 16; o; o >>= 1) sum += __shfl_xor_sync(0xffffffffu, sum, o);
    float mean = sum * (1.f / 128.f);
    float dx = v.x - mean, dy = v.y - mean, dz = v.z - mean, dw = v.w - mean;
    float vs = dx * dx + dy * dy + dz * dz + dw * dw;
    #pragma unroll
    for (int o = 16; o; o >>= 1) vs += __shfl_xor_sync(0xffffffffu, vs, o);
    float rstd = rsqrtf(vs * (1.f / 128.f) + 1e-5f);
    float4 s4 = *reinterpret_cast<const float4*>(ls + lane * 4);
    float4 b4 = *reinterpret_cast<const float4*>(lb + lane * 4);
    float4 w4 = *reinterpret_cast<const float4*>(hw + lane * 4);
    float dot = (dx * rstd * s4.x + b4.x) * w4.x
              + (dy * rstd * s4.y + b4.y) * w4.y
              + (dz * rstd * s4.z + b4.z) * w4.z
              + (dw * rstd * s4.w + b4.w) * w4.w;
    #pragma unroll
    for (int o = 16; o; o >>= 1) dot += __shfl_xor_sync(0xffffffffu, dot, o);
    if (lane == 0) out[bidx] = dot + hb[0];
}

// ---------------- launch ----------------
extern "C" void kernel_launch(void* const* d_in, const int* in_sizes, int n_in,
                              void* d_out, int out_size)
{
    const float* x        = (const float*)d_in[0];
    const float* embed_w  = (const float*)d_in[1];
    const float* embed_b  = (const float*)d_in[2];
    const float* pos_emb  = (const float*)d_in[3];
    const float* cls      = (const float*)d_in[4];
    const float* in_w     = (const float*)d_in[5];
    const float* in_b     = (const float*)d_in[6];
    const float* out_w    = (const float*)d_in[7];
    const float* out_b    = (const float*)d_in[8];
    const float* ln1_s    = (const float*)d_in[9];
    const float* ln1_b    = (const float*)d_in[10];
    const float* ln2_s    = (const float*)d_in[11];
    const float* ln2_b    = (const float*)d_in[12];
    const float* ff1_w    = (const float*)d_in[13];
    const float* ff1_b    = (const float*)d_in[14];
    const float* ff2_w    = (const float*)d_in[15];
    const float* ff2_b    = (const float*)d_in[16];
    const float* hln_s    = (const float*)d_in[17];
    const float* hln_b    = (const float*)d_in[18];
    const float* head_w   = (const float*)d_in[19];
    const float* head_b   = (const float*)d_in[20];
    float* outp = (float*)d_out;

    float *h, *po, *pl;
    __half *hnh, *qkvh, *vt, *wh;
    cudaGetSymbolAddress((void**)&h,     g_h);
    cudaGetSymbolAddress((void**)&hnh,   g_hnh);
    cudaGetSymbolAddress((void**)&qkvh,  g_qkvh);
    cudaGetSymbolAddress((void**)&vt,    g_vt);
    cudaGetSymbolAddress((void**)&po,    g_po);
    cudaGetSymbolAddress((void**)&pl,    g_pl);
    cudaGetSymbolAddress((void**)&wh,    g_wh);

    cudaFuncSetAttribute(mega_tail_kernel<true>,
                         cudaFuncAttributeMaxDynamicSharedMemorySize, SMEM_MEGA);
    cudaFuncSetAttribute(mega_tail_kernel<false>,
                         cudaFuncAttributeMaxDynamicSharedMemorySize, SMEM_MEGA);

    const int M = MROWS;
    const int MB128 = (M + 127) / 128;
    const int MB32  = (M + 31) / 32;
    const int QTILES = (S_LEN + BQ - 1) / BQ;

    convw_all_kernel<<<(CW_TOTAL + 255) / 256, 256>>>(in_w, out_w, ff1_w, ff2_w, wh);

    embed_ln_kernel<<<dim3(S_LEN, BATCH), 128>>>(
        x, embed_w, embed_b, pos_emb, cls, ln1_s, ln1_b, h, hnh);

    // layer 0 QKV (from embed's hn)
    qkv_gemm_kernel<<<dim3(384 / 64, MB128), 256>>>(
        hnh, wh + WOFF_IN, in_b, qkvh, vt, M);

    for (int i = 0; i < NL; i++) {
        attn_kernel<<<dim3(QTILES * SPLITS, N_HEADS, BATCH), 256>>>(qkvh, vt, po, pl);
        if (i + 1 < NL) {
            mega_tail_kernel<true><<<MB32, 256, SMEM_MEGA>>>(
                po, pl,
                wh + WOFF_OUT + (size_t)i * 128 * 128, out_b + (size_t)i * 128,
                ln2_s + i * D_MODEL, ln2_b + i * D_MODEL,
                wh + WOFF_FF1 + (size_t)i * 512 * 128, ff1_b + (size_t)i * 512,
                wh + WOFF_FF2 + (size_t)i * 128 * 512, ff2_b + (size_t)i * 128,
                ln1_s + (i + 1) * D_MODEL, ln1_b + (i + 1) * D_MODEL,
                wh + WOFF_IN + (size_t)(i + 1) * 384 * 128, in_b + (size_t)(i + 1) * 384,
                h, qkvh, vt, M);
        } else {
            mega_tail_kernel<false><<<MB32, 256, SMEM_MEGA>>>(
                po, pl,
                wh + WOFF_OUT + (size_t)i * 128 * 128, out_b + (size_t)i * 128,
                ln2_s + i * D_MODEL, ln2_b + i * D_MODEL,
                wh + WOFF_FF1 + (size_t)i * 512 * 128, ff1_b + (size_t)i * 512,
                wh + WOFF_FF2 + (size_t)i * 128 * 512, ff2_b + (size_t)i * 128,
                nullptr, nullptr, nullptr, nullptr,
                h, nullptr, nullptr, M);
        }
    }

    head_kernel<<<1, 64>>>(h, hln_s, hln_b, head_w, head_b, outp);
}

// round 13
// speedup vs baseline: 5.3671x; 1.0119x over previous
#include <cuda_runtime.h>
#include <cuda_fp16.h>
#include <math.h>

#define NL 3
#define D_MODEL 128
#define N_HEADS 4
#define DHEAD 32
#define DFF 512
#define DIN 64
#define BATCH 2
#define LSEQ 2048
#define S_LEN 2049
#define MROWS (BATCH * S_LEN)   // 4098
#define QK_SCALE 0.17677669529663687f

#define SPLITS 3
#define KCHUNK 704
#define VT_PITCH 2112
#define PSTRIDE ((size_t)BATCH * N_HEADS * S_LEN)

// ---------------- scratch (device globals; no allocation) ----------------
__device__ float  g_h[MROWS * D_MODEL];
__device__ __half g_hnh[MROWS * D_MODEL];
__device__ __half g_qkvh[MROWS * 3 * D_MODEL];
__device__ __half g_vt[BATCH * N_HEADS * DHEAD * VT_PITCH];
__device__ float  g_po[SPLITS * BATCH * N_HEADS * S_LEN * DHEAD];
__device__ float  g_pl[SPLITS * BATCH * N_HEADS * S_LEN];
#define WOFF_IN  0
#define WOFF_OUT (NL * 384 * 128)
#define WOFF_FF1 (WOFF_OUT + NL * 128 * 128)
#define WOFF_FF2 (WOFF_FF1 + NL * 512 * 128)
#define WTOTAL   (WOFF_FF2 + NL * 128 * 512)
__device__ __half g_wh[WTOTAL];

#define CW_N0 (NL * 384 * 128 / 4)
#define CW_N1 (NL * 128 * 128 / 4)
#define CW_N2 (NL * 512 * 128 / 4)
#define CW_N3 (NL * 128 * 512 / 4)
#define CW_TOTAL (CW_N0 + CW_N1 + CW_N2 + CW_N3)

// ---------------- mega kernel dynamic smem layout (bytes) ----------------
#define OFF_ATTN 0                    // __half [32][136]  = 8704
#define OFF_HN2  8704                 // __half [32][136]  = 8704
#define OFF_HRES 17408                // float  [32][128]  = 16384
#define OFF_F    33792                // __half [32][520]  = 33280
#define OFF_WS   67072                // __half staging    = 40960
#define OFF_PS   108032               // float  [32][4]    = 512
#define OFF_PQ   108544               // float  [32][4]    = 512
#define SMEM_MEGA 109056

// ---------------- mma helper ----------------
__device__ __forceinline__ void mma16816(
    float c[4], const unsigned a[4], const unsigned b[2])
{
    asm volatile(
        "mma.sync.aligned.m16n8k16.row.col.f32.f16.f16.f32 "
        "{%0,%1,%2,%3}, {%4,%5,%6,%7}, {%8,%9}, {%0,%1,%2,%3};\n"
        : "+f"(c[0]), "+f"(c[1]), "+f"(c[2]), "+f"(c[3])
        : "r"(a[0]), "r"(a[1]), "r"(a[2]), "r"(a[3]),
          "r"(b[0]), "r"(b[1]));
}

// ---------------- fused weight fp32 -> fp16 conversion ----------------
__global__ __launch_bounds__(256) void convw_all_kernel(
    const float* __restrict__ s0, const float* __restrict__ s1,
    const float* __restrict__ s2, const float* __restrict__ s3,
    __half* __restrict__ dst)
{
    int i = blockIdx.x * 256 + threadIdx.x;
    if (i >= CW_TOTAL) return;
    const float* src;
    int off, local = i;
    if (local < CW_N0)                { src = s0; off = WOFF_IN; }
    else if ((local -= CW_N0) < CW_N1){ src = s1; off = WOFF_OUT; }
    else if ((local -= CW_N1) < CW_N2){ src = s2; off = WOFF_FF1; }
    else { local -= CW_N2;              src = s3; off = WOFF_FF2; }
    float4 v = *reinterpret_cast<const float4*>(src + (size_t)local * 4);
    __half2 a = __floats2half2_rn(v.x, v.y);
    __half2 b = __floats2half2_rn(v.z, v.w);
    uint2 pk;
    pk.x = *reinterpret_cast<unsigned*>(&a);
    pk.y = *reinterpret_cast<unsigned*>(&b);
    *reinterpret_cast<uint2*>(dst + (size_t)off + (size_t)local * 4) = pk;
}

// ---------------- embedding + fused LN1(layer0) ----------------
__global__ __launch_bounds__(128) void embed_ln_kernel(
    const float* __restrict__ x, const float* __restrict__ ew,
    const float* __restrict__ eb, const float* __restrict__ pos,
    const float* __restrict__ cls, const float* __restrict__ lns,
    const float* __restrict__ lnb, float* __restrict__ h,
    __half* __restrict__ hn)
{
    __shared__ float xs[DIN];
    __shared__ float red[8];
    int s = blockIdx.x, b = blockIdx.y;
    int d = threadIdx.x;
    if (s > 0 && d < DIN) xs[d] = x[((size_t)b * LSEQ + (s - 1)) * DIN + d];
    __syncthreads();
    float val;
    if (s == 0) {
        val = cls[d] + pos[d];
    } else {
        float acc = 0.f;
        const float* wr = ew + (size_t)d * DIN;
        #pragma unroll
        for (int j = 0; j < DIN; j++) acc = fmaf(xs[j], wr[j], acc);
        val = acc + eb[d] + pos[(size_t)s * D_MODEL + d];
    }
    size_t row = (size_t)b * S_LEN + s;
    h[row * D_MODEL + d] = val;
    int w = d >> 5, lane = d & 31;
    float sv = val, qv = val * val;
    #pragma unroll
    for (int o = 16; o; o >>= 1) {
        sv += __shfl_xor_sync(0xffffffffu, sv, o);
        qv += __shfl_xor_sync(0xffffffffu, qv, o);
    }
    if (lane == 0) { red[w] = sv; red[4 + w] = qv; }
    __syncthreads();
    float sum = red[0] + red[1] + red[2] + red[3];
    float sq  = red[4] + red[5] + red[6] + red[7];
    float mean = sum * (1.f / 128.f);
    float rstd = rsqrtf(sq * (1.f / 128.f) - mean * mean + 1e-5f);
    hn[row * D_MODEL + d] = __float2half_rn((val - mean) * rstd * lns[d] + lnb[d]);
}

// ---------------- QKV tensor-core GEMM (layer 0 only) ----------------
#define GPITCH 40
__global__ __launch_bounds__(256) void qkv_gemm_kernel(
    const __half* __restrict__ A, const __half* __restrict__ W,
    const float* __restrict__ bias, __half* __restrict__ C,
    __half* __restrict__ vT, int M)
{
    const int N = 384, K = 128;
    __shared__ __half As[128][GPITCH];
    __shared__ __half Ws[64][GPITCH];
    const int tid = threadIdx.x;
    const int warp = tid >> 5;
    const int lane = tid & 31;
    const int g = lane >> 2;
    const int tig = lane & 3;
    const int warp_m = warp >> 1;
    const int warp_n = warp & 1;
    const int m0 = blockIdx.y * 128;
    const int n0 = blockIdx.x * 64;
    const int NK = K / 32;
    const int wr = tid >> 2, wq = tid & 3;

    float c[2][4][4] = {};

    uint4 aReg[2], wReg;
    #pragma unroll
    for (int it = 0; it < 2; it++) {
        int idx = tid + it * 256;
        int r = idx >> 2, quad = idx & 3;
        int m = m0 + r;
        aReg[it] = (m < M)
            ? *reinterpret_cast<const uint4*>(A + (size_t)m * K + quad * 8)
            : make_uint4(0u, 0u, 0u, 0u);
    }
    wReg = *reinterpret_cast<const uint4*>(W + (size_t)(n0 + wr) * K + wq * 8);

    for (int kt = 0; kt < NK; kt++) {
        #pragma unroll
        for (int it = 0; it < 2; it++) {
            int idx = tid + it * 256;
            int r = idx >> 2, quad = idx & 3;
            *reinterpret_cast<uint4*>(&As[r][quad * 8]) = aReg[it];
        }
        *reinterpret_cast<uint4*>(&Ws[wr][wq * 8]) = wReg;
        __syncthreads();
        if (kt + 1 < NK) {
            int k0 = (kt + 1) * 32;
            #pragma unroll
            for (int it = 0; it < 2; it++) {
                int idx = tid + it * 256;
                int r = idx >> 2, quad = idx & 3;
                int m = m0 + r;
                aReg[it] = (m < M)
                    ? *reinterpret_cast<const uint4*>(A + (size_t)m * K + k0 + quad * 8)
                    : make_uint4(0u, 0u, 0u, 0u);
            }
            wReg = *reinterpret_cast<const uint4*>(W + (size_t)(n0 + wr) * K + k0 + wq * 8);
        }
        #pragma unroll
        for (int ks = 0; ks < 2; ks++) {
            unsigned a[2][4];
            #pragma unroll
            for (int mt = 0; mt < 2; mt++) {
                int rbase = warp_m * 32 + mt * 16;
                a[mt][0] = *reinterpret_cast<const unsigned*>(&As[rbase + g    ][ks * 16 + tig * 2]);
                a[mt][1] = *reinterpret_cast<const unsigned*>(&As[rbase + g + 8][ks * 16 + tig * 2]);
                a[mt][2] = *reinterpret_cast<const unsigned*>(&As[rbase + g    ][ks * 16 + tig * 2 + 8]);
                a[mt][3] = *reinterpret_cast<const unsigned*>(&As[rbase + g + 8][ks * 16 + tig * 2 + 8]);
            }
            #pragma unroll
            for (int nt = 0; nt < 4; nt++) {
                unsigned bfr[2];
                int nrow = warp_n * 32 + nt * 8 + g;
                bfr[0] = *reinterpret_cast<const unsigned*>(&Ws[nrow][ks * 16 + tig * 2]);
                bfr[1] = *reinterpret_cast<const unsigned*>(&Ws[nrow][ks * 16 + tig * 2 + 8]);
                mma16816(c[0][nt], a[0], bfr);
                mma16816(c[1][nt], a[1], bfr);
            }
        }
        __syncthreads();
    }

    #pragma unroll
    for (int mt = 0; mt < 2; mt++) {
        #pragma unroll
        for (int half_row = 0; half_row < 2; half_row++) {
            int m = m0 + warp_m * 32 + mt * 16 + g + half_row * 8;
            if (m >= M) continue;
            int bb = m / S_LEN, ss = m % S_LEN;
            #pragma unroll
            for (int nt = 0; nt < 4; nt++) {
                int n = n0 + warp_n * 32 + nt * 8 + tig * 2;
                float v0 = c[mt][nt][half_row * 2 + 0] + bias[n];
                float v1 = c[mt][nt][half_row * 2 + 1] + bias[n + 1];
                if (n >= 256) {
                    int hh = (n - 256) >> 5, dd = (n - 256) & 31;
                    __half* vbase = vT + ((size_t)(bb * N_HEADS + hh) * DHEAD + dd) * VT_PITCH + ss;
                    vbase[0] = __float2half_rn(v0);
                    vbase[VT_PITCH] = __float2half_rn(v1);
                } else {
                    if (n < 128) { v0 *= QK_SCALE; v1 *= QK_SCALE; }
                    __half2 hv = __floats2half2_rn(v0, v1);
                    *reinterpret_cast<unsigned*>(
                        C + (size_t)m * N + n) = *reinterpret_cast<unsigned*>(&hv);
                }
            }
        }
    }
}

// ---------------- split-S flash attention (fixed max = 0) ----------------
#define BQ 128
#define BK 64
#define QPITCH 40
#define VPITCH 72

__global__ __launch_bounds__(256, 3) void attn_kernel(
    const __half* __restrict__ qkv, const __half* __restrict__ vT,
    float* __restrict__ po, float* __restrict__ pl)
{
    __shared__ __half Qs[BQ][QPITCH];
    __shared__ __half Kt[2][BK][QPITCH];
    __shared__ __half Vt[2][DHEAD][VPITCH];
    const int tid = threadIdx.x;
    const int warp = tid >> 5;
    const int lane = tid & 31;
    const int g = lane >> 2;
    const int tig = lane & 3;
    const int b = blockIdx.z, h = blockIdx.y;
    const int tile = blockIdx.x / SPLITS;
    const int split = blockIdx.x % SPLITS;
    const int q0 = tile * BQ;
    const int qbase = warp * 16;
    const int kstart = split * KCHUNK;
    const int kend = min(kstart + KCHUNK, S_LEN);
    const int ntile = (kend - kstart + BK - 1) / BK;

    #pragma unroll
    for (int idx = tid; idx < BQ * 4; idx += 256) {
        int r = idx >> 2, quad = idx & 3;
        int q = q0 + r;
        uint4 v = make_uint4(0u, 0u, 0u, 0u);
        if (q < S_LEN)
            v = *reinterpret_cast<const uint4*>(
                qkv + ((size_t)(b * S_LEN + q)) * 384 + h * 32 + quad * 8);
        *reinterpret_cast<uint4*>(&Qs[r][quad * 8]) = v;
    }

    const __half* Kbase = qkv + (size_t)b * S_LEN * 384 + 128 + h * 32;
    const __half* Vbase = vT + (size_t)(b * N_HEADS + h) * DHEAD * VT_PITCH;
    const int kr = tid >> 2, kq = tid & 3;
    const int vr = tid >> 3, vq = tid & 7;

    uint4 kreg, vreg;
    {
        int kg = kstart + kr;
        kreg = (kg < S_LEN)
            ? *reinterpret_cast<const uint4*>(Kbase + (size_t)kg * 384 + kq * 8)
            : make_uint4(0u, 0u, 0u, 0u);
        vreg = *reinterpret_cast<const uint4*>(Vbase + (size_t)vr * VT_PITCH + kstart + vq * 8);
    }
    *reinterpret_cast<uint4*>(&Kt[0][kr][kq * 8]) = kreg;
    *reinterpret_cast<uint4*>(&Vt[0][vr][vq * 8]) = vreg;
    __syncthreads();

    unsigned A[2][4];
    #pragma unroll
    for (int ks = 0; ks < 2; ks++) {
        A[ks][0] = *reinterpret_cast<const unsigned*>(&Qs[qbase + g    ][ks * 16 + tig * 2]);
        A[ks][1] = *reinterpret_cast<const unsigned*>(&Qs[qbase + g + 8][ks * 16 + tig * 2]);
        A[ks][2] = *reinterpret_cast<const unsigned*>(&Qs[qbase + g    ][ks * 16 + tig * 2 + 8]);
        A[ks][3] = *reinterpret_cast<const unsigned*>(&Qs[qbase + g + 8][ks * 16 + tig * 2 + 8]);
    }

    float l0 = 0.f, l1 = 0.f;
    float o[4][4] = {};

    for (int t = 0; t < ntile; t++) {
        const int kb = kstart + t * BK;
        const int buf = t & 1;
        if (t + 1 < ntile) {
            int kb2 = kb + BK;
            int kg = kb2 + kr;
            kreg = (kg < S_LEN)
                ? *reinterpret_cast<const uint4*>(Kbase + (size_t)kg * 384 + kq * 8)
                : make_uint4(0u, 0u, 0u, 0u);
            vreg = *reinterpret_cast<const uint4*>(Vbase + (size_t)vr * VT_PITCH + kb2 + vq * 8);
        }

        float s[8][4];
        #pragma unroll
        for (int j = 0; j < 8; j++) {
            s[j][0] = s[j][1] = s[j][2] = s[j][3] = 0.f;
            #pragma unroll
            for (int ks = 0; ks < 2; ks++) {
                unsigned bfr[2];
                bfr[0] = *reinterpret_cast<const unsigned*>(&Kt[buf][j * 8 + g][ks * 16 + tig * 2]);
                bfr[1] = *reinterpret_cast<const unsigned*>(&Kt[buf][j * 8 + g][ks * 16 + tig * 2 + 8]);
                mma16816(s[j], A[ks], bfr);
            }
        }
        if (kb + BK > S_LEN) {
            #pragma unroll
            for (int j = 0; j < 8; j++) {
                int key = kb + j * 8 + tig * 2;
                if (key >= S_LEN)     { s[j][0] = -1e30f; s[j][2] = -1e30f; }
                if (key + 1 >= S_LEN) { s[j][1] = -1e30f; s[j][3] = -1e30f; }
            }
        }

        unsigned ph[8][2];
        #pragma unroll
        for (int j = 0; j < 8; j++) {
            __half2 h2a = __floats2half2_rn(__expf(s[j][0]), __expf(s[j][1]));
            __half2 h2b = __floats2half2_rn(__expf(s[j][2]), __expf(s[j][3]));
            ph[j][0] = *reinterpret_cast<unsigned*>(&h2a);
            ph[j][1] = *reinterpret_cast<unsigned*>(&h2b);
            float2 fa = __half22float2(h2a);
            float2 fb = __half22float2(h2b);
            l0 += fa.x + fa.y;
            l1 += fb.x + fb.y;
        }

        #pragma unroll
        for (int kt = 0; kt < 4; kt++) {
            unsigned pa[4] = { ph[2 * kt][0], ph[2 * kt][1],
                               ph[2 * kt + 1][0], ph[2 * kt + 1][1] };
            #pragma unroll
            for (int nt = 0; nt < 4; nt++) {
                unsigned bfr[2];
                bfr[0] = *reinterpret_cast<const unsigned*>(&Vt[buf][nt * 8 + g][kt * 16 + tig * 2]);
                bfr[1] = *reinterpret_cast<const unsigned*>(&Vt[buf][nt * 8 + g][kt * 16 + tig * 2 + 8]);
                mma16816(o[nt], pa, bfr);
            }
        }
        if (t + 1 < ntile) {
            *reinterpret_cast<uint4*>(&Kt[buf ^ 1][kr][kq * 8]) = kreg;
            *reinterpret_cast<uint4*>(&Vt[buf ^ 1][vr][vq * 8]) = vreg;
        }
        __syncthreads();
    }

    l0 += __shfl_xor_sync(0xffffffffu, l0, 1);
    l0 += __shfl_xor_sync(0xffffffffu, l0, 2);
    l1 += __shfl_xor_sync(0xffffffffu, l1, 1);
    l1 += __shfl_xor_sync(0xffffffffu, l1, 2);

    const size_t pbase = (((size_t)split * BATCH + b) * N_HEADS + h) * S_LEN;
    int qa = q0 + qbase + g;
    int qb2 = qa + 8;
    if (qa < S_LEN) {
        #pragma unroll
        for (int nt = 0; nt < 4; nt++) {
            float2 v = make_float2(o[nt][0], o[nt][1]);
            *reinterpret_cast<float2*>(po + (pbase + qa) * DHEAD + nt * 8 + tig * 2) = v;
        }
        if (tig == 0) pl[pbase + qa] = l0;
    }
    if (qb2 < S_LEN) {
        #pragma unroll
        for (int nt = 0; nt < 4; nt++) {
            float2 v = make_float2(o[nt][2], o[nt][3]);
            *reinterpret_cast<float2*>(po + (pbase + qb2) * DHEAD + nt * 8 + tig * 2) = v;
        }
        if (tig == 0) pl[pbase + qb2] = l1;
    }
}

// ---------------- MEGA layer-tail kernel (reg-prefetched weights) --------
// merge(po,pl) -> out-proj + resid -> LN2 -> FF1+ReLU -> FF2 + resid -> h
// QKV_NEXT: additionally LN1next (smem) -> QKV GEMM of next layer -> qkvh/vt.
template <bool QKV_NEXT>
__global__ __launch_bounds__(256) void mega_tail_kernel(
    const float* __restrict__ po, const float* __restrict__ pl,
    const __half* __restrict__ Wout, const float* __restrict__ bout,
    const float* __restrict__ ln2s, const float* __restrict__ ln2b,
    const __half* __restrict__ W1, const float* __restrict__ b1,
    const __half* __restrict__ W2, const float* __restrict__ b2,
    const float* __restrict__ ln1s, const float* __restrict__ ln1b,
    const __half* __restrict__ Win, const float* __restrict__ bin,
    float* __restrict__ h, __half* __restrict__ qkvh,
    __half* __restrict__ vT, int M)
{
    extern __shared__ char smem[];
    __half (*Attn)[136] = reinterpret_cast<__half(*)[136]>(smem + OFF_ATTN);
    __half (*HN2)[136]  = reinterpret_cast<__half(*)[136]>(smem + OFF_HN2);
    float (*Hres)[128]  = reinterpret_cast<float(*)[128]>(smem + OFF_HRES);
    __half (*F)[520]    = reinterpret_cast<__half(*)[520]>(smem + OFF_F);
    __half* Wsraw       = reinterpret_cast<__half*>(smem + OFF_WS);
    float (*psum)[4]    = reinterpret_cast<float(*)[4]>(smem + OFF_PS);
    float (*psq)[4]     = reinterpret_cast<float(*)[4]>(smem + OFF_PQ);

    const int tid = threadIdx.x;
    const int warp = tid >> 5;
    const int lane = tid & 31;
    const int g = lane >> 2;
    const int tig = lane & 3;
    const int warp_m = warp >> 2;   // 0..1
    const int warp_n = warp & 3;    // 0..3
    const int m0 = blockIdx.x * 32;

    // ---- stage Wout fully (issued first; overlaps merge loads) ----
    {
        __half (*WsA)[136] = reinterpret_cast<__half(*)[136]>(Wsraw);
        #pragma unroll
        for (int it = 0; it < 8; it++) {
            int idx = tid + it * 256;
            int r = idx >> 4, q = idx & 15;
            *reinterpret_cast<uint4*>(&WsA[r][q * 8]) =
                *reinterpret_cast<const uint4*>(Wout + (size_t)r * 128 + q * 8);
        }
    }

    // ---- stage 0: merge attention partials into Attn; load residual ----
    {
        int row = tid >> 3;
        int dseg = (tid & 7) * 16;
        int mrow = m0 + row;
        if (mrow < M) {
            int bb = mrow / S_LEN, qq = mrow % S_LEN;
            int hh = dseg >> 5, dd = dseg & 31;
            size_t prow = ((size_t)bb * N_HEADS + hh) * S_LEN + qq;
            float linv = 1.f / (pl[prow] + pl[prow + PSTRIDE] + pl[prow + 2 * PSTRIDE]);
            float acc[16];
            #pragma unroll
            for (int t = 0; t < 4; t++) {
                float4 p0 = *reinterpret_cast<const float4*>(po + prow * DHEAD + dd + t * 4);
                float4 p1 = *reinterpret_cast<const float4*>(po + (prow + PSTRIDE) * DHEAD + dd + t * 4);
                float4 p2 = *reinterpret_cast<const float4*>(po + (prow + 2 * PSTRIDE) * DHEAD + dd + t * 4);
                acc[t * 4 + 0] = (p0.x + p1.x + p2.x) * linv;
                acc[t * 4 + 1] = (p0.y + p1.y + p2.y) * linv;
                acc[t * 4 + 2] = (p0.z + p1.z + p2.z) * linv;
                acc[t * 4 + 3] = (p0.w + p1.w + p2.w) * linv;
            }
            unsigned pk[8];
            #pragma unroll
            for (int t = 0; t < 8; t++) {
                __half2 hv = __floats2half2_rn(acc[t * 2], acc[t * 2 + 1]);
                pk[t] = *reinterpret_cast<unsigned*>(&hv);
            }
            *reinterpret_cast<uint4*>(&Attn[row][dseg]) = make_uint4(pk[0], pk[1], pk[2], pk[3]);
            *reinterpret_cast<uint4*>(&Attn[row][dseg + 8]) = make_uint4(pk[4], pk[5], pk[6], pk[7]);
            #pragma unroll
            for (int t = 0; t < 4; t++)
                *reinterpret_cast<float4*>(&Hres[row][dseg + t * 4]) =
                    *reinterpret_cast<const float4*>(h + (size_t)mrow * 128 + dseg + t * 4);
        } else {
            uint4 z = make_uint4(0u, 0u, 0u, 0u);
            *reinterpret_cast<uint4*>(&Attn[row][dseg]) = z;
            *reinterpret_cast<uint4*>(&Attn[row][dseg + 8]) = z;
            float4 fz = make_float4(0.f, 0.f, 0.f, 0.f);
            #pragma unroll
            for (int t = 0; t < 4; t++)
                *reinterpret_cast<float4*>(&Hres[row][dseg + t * 4]) = fz;
        }
    }
    __syncthreads();

    // ---- stage 1: out-proj GEMM ----
    float c1[4][4] = {};
    {
        __half (*WsA)[136] = reinterpret_cast<__half(*)[136]>(Wsraw);
        #pragma unroll
        for (int ks8 = 0; ks8 < 8; ks8++) {
            int kc = ks8 * 16;
            unsigned a[4];
            int rbase = warp_m * 16;
            a[0] = *reinterpret_cast<const unsigned*>(&Attn[rbase + g    ][kc + tig * 2]);
            a[1] = *reinterpret_cast<const unsigned*>(&Attn[rbase + g + 8][kc + tig * 2]);
            a[2] = *reinterpret_cast<const unsigned*>(&Attn[rbase + g    ][kc + tig * 2 + 8]);
            a[3] = *reinterpret_cast<const unsigned*>(&Attn[rbase + g + 8][kc + tig * 2 + 8]);
            #pragma unroll
            for (int nt = 0; nt < 4; nt++) {
                unsigned bfr[2];
                int nrow = warp_n * 32 + nt * 8 + g;
                bfr[0] = *reinterpret_cast<const unsigned*>(&WsA[nrow][kc + tig * 2]);
                bfr[1] = *reinterpret_cast<const unsigned*>(&WsA[nrow][kc + tig * 2 + 8]);
                mma16816(c1[nt], a, bfr);
            }
        }
    }

    // prefetch FF1 chunk 0 (independent of LN2 below; overlaps it)
    uint4 w1Reg[8];
    #pragma unroll
    for (int it = 0; it < 8; it++) {
        int idx = tid + it * 256;
        int r = idx >> 2, q = idx & 3;
        w1Reg[it] = *reinterpret_cast<const uint4*>(W1 + (size_t)r * 128 + q * 8);
    }

    const int lr0 = warp_m * 16 + g, lr1 = lr0 + 8;
    #pragma unroll
    for (int nt = 0; nt < 4; nt++) {
        int n = warp_n * 32 + nt * 8 + tig * 2;
        float b0 = bout[n], b1v = bout[n + 1];
        c1[nt][0] += b0 + Hres[lr0][n];
        c1[nt][1] += b1v + Hres[lr0][n + 1];
        c1[nt][2] += b0 + Hres[lr1][n];
        c1[nt][3] += b1v + Hres[lr1][n + 1];
    }
    // LN2 -> HN2
    {
        float s0 = 0.f, q0 = 0.f, s1 = 0.f, q1 = 0.f;
        #pragma unroll
        for (int nt = 0; nt < 4; nt++) {
            s0 += c1[nt][0] + c1[nt][1];
            q0 += c1[nt][0] * c1[nt][0] + c1[nt][1] * c1[nt][1];
            s1 += c1[nt][2] + c1[nt][3];
            q1 += c1[nt][2] * c1[nt][2] + c1[nt][3] * c1[nt][3];
        }
        #pragma unroll
        for (int o = 1; o < 4; o <<= 1) {
            s0 += __shfl_xor_sync(0xffffffffu, s0, o);
            q0 += __shfl_xor_sync(0xffffffffu, q0, o);
            s1 += __shfl_xor_sync(0xffffffffu, s1, o);
            q1 += __shfl_xor_sync(0xffffffffu, q1, o);
        }
        if (tig == 0) {
            psum[lr0][warp_n] = s0; psq[lr0][warp_n] = q0;
            psum[lr1][warp_n] = s1; psq[lr1][warp_n] = q1;
        }
        __syncthreads();
        float sum0 = psum[lr0][0] + psum[lr0][1] + psum[lr0][2] + psum[lr0][3];
        float sq0  = psq[lr0][0] + psq[lr0][1] + psq[lr0][2] + psq[lr0][3];
        float sum1 = psum[lr1][0] + psum[lr1][1] + psum[lr1][2] + psum[lr1][3];
        float sq1  = psq[lr1][0] + psq[lr1][1] + psq[lr1][2] + psq[lr1][3];
        float mean0 = sum0 * (1.f / 128.f);
        float rstd0 = rsqrtf(sq0 * (1.f / 128.f) - mean0 * mean0 + 1e-5f);
        float mean1 = sum1 * (1.f / 128.f);
        float rstd1 = rsqrtf(sq1 * (1.f / 128.f) - mean1 * mean1 + 1e-5f);
        #pragma unroll
        for (int nt = 0; nt < 4; nt++) {
            int n = warp_n * 32 + nt * 8 + tig * 2;
            float g0 = ln2s[n], g1 = ln2s[n + 1];
            float bb0 = ln2b[n], bb1 = ln2b[n + 1];
            __half2 hv0 = __floats2half2_rn(
                (c1[nt][0] - mean0) * rstd0 * g0 + bb0,
                (c1[nt][1] - mean0) * rstd0 * g1 + bb1);
            __half2 hv1 = __floats2half2_rn(
                (c1[nt][2] - mean1) * rstd1 * g0 + bb0,
                (c1[nt][3] - mean1) * rstd1 * g1 + bb1);
            *reinterpret_cast<unsigned*>(&HN2[lr0][n]) = *reinterpret_cast<unsigned*>(&hv0);
            *reinterpret_cast<unsigned*>(&HN2[lr1][n]) = *reinterpret_cast<unsigned*>(&hv1);
            Hres[lr0][n] = c1[nt][0]; Hres[lr0][n + 1] = c1[nt][1];
            Hres[lr1][n] = c1[nt][2]; Hres[lr1][n + 1] = c1[nt][3];
        }
    }

    // ---- stage 2: FF1 (M=32, N=512, K=128), reg-prefetched chunks ----
    float c2[2][8][4] = {};
    {
        __half (*WsB)[40] = reinterpret_cast<__half(*)[40]>(Wsraw);
        #pragma unroll
        for (int kt = 0; kt < 4; kt++) {
            __syncthreads();   // protect Ws readers (and HN2 writes on kt=0)
            #pragma unroll
            for (int it = 0; it < 8; it++) {
                int idx = tid + it * 256;
                int r = idx >> 2, q = idx & 3;
                *reinterpret_cast<uint4*>(&WsB[r][q * 8]) = w1Reg[it];
            }
            __syncthreads();
            if (kt + 1 < 4) {
                int k0 = (kt + 1) * 32;
                #pragma unroll
                for (int it = 0; it < 8; it++) {
                    int idx = tid + it * 256;
                    int r = idx >> 2, q = idx & 3;
                    w1Reg[it] = *reinterpret_cast<const uint4*>(
                        W1 + (size_t)r * 128 + k0 + q * 8);
                }
            }
            #pragma unroll
            for (int ks = 0; ks < 2; ks++) {
                int kc = kt * 32 + ks * 16;
                unsigned a0[4], a1[4];
                a0[0] = *reinterpret_cast<const unsigned*>(&HN2[g     ][kc + tig * 2]);
                a0[1] = *reinterpret_cast<const unsigned*>(&HN2[g + 8 ][kc + tig * 2]);
                a0[2] = *reinterpret_cast<const unsigned*>(&HN2[g     ][kc + tig * 2 + 8]);
                a0[3] = *reinterpret_cast<const unsigned*>(&HN2[g + 8 ][kc + tig * 2 + 8]);
                a1[0] = *reinterpret_cast<const unsigned*>(&HN2[g + 16][kc + tig * 2]);
                a1[1] = *reinterpret_cast<const unsigned*>(&HN2[g + 24][kc + tig * 2]);
                a1[2] = *reinterpret_cast<const unsigned*>(&HN2[g + 16][kc + tig * 2 + 8]);
                a1[3] = *reinterpret_cast<const unsigned*>(&HN2[g + 24][kc + tig * 2 + 8]);
                #pragma unroll
                for (int nt = 0; nt < 8; nt++) {
                    unsigned bfr[2];
                    int nrow = warp * 64 + nt * 8 + g;
                    bfr[0] = *reinterpret_cast<const unsigned*>(&WsB[nrow][ks * 16 + tig * 2]);
                    bfr[1] = *reinterpret_cast<const unsigned*>(&WsB[nrow][ks * 16 + tig * 2 + 8]);
                    mma16816(c2[0][nt], a0, bfr);
                    mma16816(c2[1][nt], a1, bfr);
                }
            }
        }
    }

    // prefetch FF2 chunk 0 (overlaps ReLU epilogue)
    uint4 w2Reg[4];
    #pragma unroll
    for (int it = 0; it < 4; it++) {
        int idx = tid + it * 256;
        int r = idx >> 3, q = idx & 7;
        w2Reg[it] = *reinterpret_cast<const uint4*>(W2 + (size_t)r * 512 + q * 8);
    }

    // bias + ReLU -> F (fp16)
    #pragma unroll
    for (int mt = 0; mt < 2; mt++) {
        #pragma unroll
        for (int hr = 0; hr < 2; hr++) {
            int lr = mt * 16 + hr * 8 + g;
            #pragma unroll
            for (int nt = 0; nt < 8; nt++) {
                int n = warp * 64 + nt * 8 + tig * 2;
                float v0 = fmaxf(c2[mt][nt][hr * 2 + 0] + b1[n], 0.f);
                float v1 = fmaxf(c2[mt][nt][hr * 2 + 1] + b1[n + 1], 0.f);
                __half2 hv = __floats2half2_rn(v0, v1);
                *reinterpret_cast<unsigned*>(&F[lr][n]) = *reinterpret_cast<unsigned*>(&hv);
            }
        }
    }

    // ---- stage 3: FF2 (M=32, N=128, K=512), reg-prefetched chunks ----
    float c3[4][4] = {};
    {
        __half (*WsC)[72] = reinterpret_cast<__half(*)[72]>(Wsraw);
        #pragma unroll
        for (int kt = 0; kt < 8; kt++) {
            __syncthreads();   // protect Ws readers (and F writes on kt=0)
            #pragma unroll
            for (int it = 0; it < 4; it++) {
                int idx = tid + it * 256;
                int r = idx >> 3, q = idx & 7;
                *reinterpret_cast<uint4*>(&WsC[r][q * 8]) = w2Reg[it];
            }
            __syncthreads();
            if (kt + 1 < 8) {
                int k0 = (kt + 1) * 64;
                #pragma unroll
                for (int it = 0; it < 4; it++) {
                    int idx = tid + it * 256;
                    int r = idx >> 3, q = idx & 7;
                    w2Reg[it] = *reinterpret_cast<const uint4*>(
                        W2 + (size_t)r * 512 + k0 + q * 8);
                }
            }
            #pragma unroll
            for (int ks = 0; ks < 4; ks++) {
                int kc = kt * 64 + ks * 16;
                unsigned a[4];
                int rbase = warp_m * 16;
                a[0] = *reinterpret_cast<const unsigned*>(&F[rbase + g    ][kc + tig * 2]);
                a[1] = *reinterpret_cast<const unsigned*>(&F[rbase + g + 8][kc + tig * 2]);
                a[2] = *reinterpret_cast<const unsigned*>(&F[rbase + g    ][kc + tig * 2 + 8]);
                a[3] = *reinterpret_cast<const unsigned*>(&F[rbase + g + 8][kc + tig * 2 + 8]);
                #pragma unroll
                for (int nt = 0; nt < 4; nt++) {
                    unsigned bfr[2];
                    int nrow = warp_n * 32 + nt * 8 + g;
                    bfr[0] = *reinterpret_cast<const unsigned*>(&WsC[nrow][ks * 16 + tig * 2]);
                    bfr[1] = *reinterpret_cast<const unsigned*>(&WsC[nrow][ks * 16 + tig * 2 + 8]);
                    mma16816(c3[nt], a, bfr);
                }
            }
        }
    }

    // prefetch QKV chunk 0 (overlaps FF2 epilogue + LN1next)
    uint4 w4Reg[8];
    if (QKV_NEXT) {
        #pragma unroll
        for (int it = 0; it < 8; it++) {
            int idx = tid + it * 256;
            int r = idx >> 4, q = idx & 15;
            w4Reg[it] = *reinterpret_cast<const uint4*>(Win + (size_t)r * 128 + q * 8);
        }
    }

    // epilogue: bias + residual -> h global
    const int mrow0 = m0 + lr0, mrow1 = m0 + lr1;
    #pragma unroll
    for (int nt = 0; nt < 4; nt++) {
        int n = warp_n * 32 + nt * 8 + tig * 2;
        float b0 = b2[n], b1v = b2[n + 1];
        c3[nt][0] += b0 + Hres[lr0][n];
        c3[nt][1] += b1v + Hres[lr0][n + 1];
        c3[nt][2] += b0 + Hres[lr1][n];
        c3[nt][3] += b1v + Hres[lr1][n + 1];
        if (mrow0 < M)
            *reinterpret_cast<float2*>(h + (size_t)mrow0 * 128 + n) =
                make_float2(c3[nt][0], c3[nt][1]);
        if (mrow1 < M)
            *reinterpret_cast<float2*>(h + (size_t)mrow1 * 128 + n) =
                make_float2(c3[nt][2], c3[nt][3]);
    }

    if (QKV_NEXT) {
        // ---- LN1next -> HN2 (smem) ----
        float s0 = 0.f, q0 = 0.f, s1 = 0.f, q1 = 0.f;
        #pragma unroll
        for (int nt = 0; nt < 4; nt++) {
            s0 += c3[nt][0] + c3[nt][1];
            q0 += c3[nt][0] * c3[nt][0] + c3[nt][1] * c3[nt][1];
            s1 += c3[nt][2] + c3[nt][3];
            q1 += c3[nt][2] * c3[nt][2] + c3[nt][3] * c3[nt][3];
        }
        #pragma unroll
        for (int o = 1; o < 4; o <<= 1) {
            s0 += __shfl_xor_sync(0xffffffffu, s0, o);
            q0 += __shfl_xor_sync(0xffffffffu, q0, o);
            s1 += __shfl_xor_sync(0xffffffffu, s1, o);
            q1 += __shfl_xor_sync(0xffffffffu, q1, o);
        }
        __syncthreads();
        if (tig == 0) {
            psum[lr0][warp_n] = s0; psq[lr0][warp_n] = q0;
            psum[lr1][warp_n] = s1; psq[lr1][warp_n] = q1;
        }
        __syncthreads();
        float sum0 = psum[lr0][0] + psum[lr0][1] + psum[lr0][2] + psum[lr0][3];
        float sq0  = psq[lr0][0] + psq[lr0][1] + psq[lr0][2] + psq[lr0][3];
        float sum1 = psum[lr1][0] + psum[lr1][1] + psum[lr1][2] + psum[lr1][3];
        float sq1  = psq[lr1][0] + psq[lr1][1] + psq[lr1][2] + psq[lr1][3];
        float mean0 = sum0 * (1.f / 128.f);
        float rstd0 = rsqrtf(sq0 * (1.f / 128.f) - mean0 * mean0 + 1e-5f);
        float mean1 = sum1 * (1.f / 128.f);
        float rstd1 = rsqrtf(sq1 * (1.f / 128.f) - mean1 * mean1 + 1e-5f);
        #pragma unroll
        for (int nt = 0; nt < 4; nt++) {
            int n = warp_n * 32 + nt * 8 + tig * 2;
            float g0 = ln1s[n], g1 = ln1s[n + 1];
            float bb0 = ln1b[n], bb1 = ln1b[n + 1];
            __half2 hv0 = __floats2half2_rn(
                (c3[nt][0] - mean0) * rstd0 * g0 + bb0,
                (c3[nt][1] - mean0) * rstd0 * g1 + bb1);
            __half2 hv1 = __floats2half2_rn(
                (c3[nt][2] - mean1) * rstd1 * g0 + bb0,
                (c3[nt][3] - mean1) * rstd1 * g1 + bb1);
            *reinterpret_cast<unsigned*>(&HN2[lr0][n]) = *reinterpret_cast<unsigned*>(&hv0);
            *reinterpret_cast<unsigned*>(&HN2[lr1][n]) = *reinterpret_cast<unsigned*>(&hv1);
        }

        // ---- stage 4: QKV GEMM of next layer (3 chunks, reg-prefetched) ----
        __half (*WsA)[136] = reinterpret_cast<__half(*)[136]>(Wsraw);
        for (int chunk = 0; chunk < 3; chunk++) {
            __syncthreads();   // protect WsA readers / HN2 writes
            #pragma unroll
            for (int it = 0; it < 8; it++) {
                int idx = tid + it * 256;
                int r = idx >> 4, q = idx & 15;
                *reinterpret_cast<uint4*>(&WsA[r][q * 8]) = w4Reg[it];
            }
            __syncthreads();
            if (chunk + 1 < 3) {
                #pragma unroll
                for (int it = 0; it < 8; it++) {
                    int idx = tid + it * 256;
                    int r = idx >> 4, q = idx & 15;
                    w4Reg[it] = *reinterpret_cast<const uint4*>(
                        Win + (size_t)((chunk + 1) * 128 + r) * 128 + q * 8);
                }
            }
            float c4[4][4] = {};
            #pragma unroll
            for (int ks8 = 0; ks8 < 8; ks8++) {
                int kc = ks8 * 16;
                unsigned a[4];
                int rbase = warp_m * 16;
                a[0] = *reinterpret_cast<const unsigned*>(&HN2[rbase + g    ][kc + tig * 2]);
                a[1] = *reinterpret_cast<const unsigned*>(&HN2[rbase + g + 8][kc + tig * 2]);
                a[2] = *reinterpret_cast<const unsigned*>(&HN2[rbase + g    ][kc + tig * 2 + 8]);
                a[3] = *reinterpret_cast<const unsigned*>(&HN2[rbase + g + 8][kc + tig * 2 + 8]);
                #pragma unroll
                for (int nt = 0; nt < 4; nt++) {
                    unsigned bfr[2];
                    int nrow = warp_n * 32 + nt * 8 + g;
                    bfr[0] = *reinterpret_cast<const unsigned*>(&WsA[nrow][kc + tig * 2]);
                    bfr[1] = *reinterpret_cast<const unsigned*>(&WsA[nrow][kc + tig * 2 + 8]);
                    mma16816(c4[nt], a, bfr);
                }
            }
            #pragma unroll
            for (int nt = 0; nt < 4; nt++) {
                int nl = warp_n * 32 + nt * 8 + tig * 2;
                int n = chunk * 128 + nl;
                float b0 = bin[n], b1v = bin[n + 1];
                float v00 = c4[nt][0] + b0, v01 = c4[nt][1] + b1v;
                float v10 = c4[nt][2] + b0, v11 = c4[nt][3] + b1v;
                if (chunk < 2) {
                    if (chunk == 0) { v00 *= QK_SCALE; v01 *= QK_SCALE;
                                      v10 *= QK_SCALE; v11 *= QK_SCALE; }
                    if (mrow0 < M) {
                        __half2 hv = __floats2half2_rn(v00, v01);
                        *reinterpret_cast<unsigned*>(qkvh + (size_t)mrow0 * 384 + n)
                            = *reinterpret_cast<unsigned*>(&hv);
                    }
                    if (mrow1 < M) {
                        __half2 hv = __floats2half2_rn(v10, v11);
                        *reinterpret_cast<unsigned*>(qkvh + (size_t)mrow1 * 384 + n)
                            = *reinterpret_cast<unsigned*>(&hv);
                    }
                } else {
                    int hh = nl >> 5, dd = nl & 31;
                    if (mrow0 < M) {
                        int bb = mrow0 / S_LEN, ss = mrow0 % S_LEN;
                        __half* vb = vT + ((size_t)(bb * N_HEADS + hh) * DHEAD + dd) * VT_PITCH + ss;
                        vb[0] = __float2half_rn(v00);
                        vb[VT_PITCH] = __float2half_rn(v01);
                    }
                    if (mrow1 < M) {
                        int bb = mrow1 / S_LEN, ss = mrow1 % S_LEN;
                        __half* vb = vT + ((size_t)(bb * N_HEADS + hh) * DHEAD + dd) * VT_PITCH + ss;
                        vb[0] = __float2half_rn(v10);
                        vb[VT_PITCH] = __float2half_rn(v11);
                    }
                }
            }
        }
    }
}

// ---------------- head ----------------
__global__ __launch_bounds__(64) void head_kernel(
    const float* __restrict__ h, const float* __restrict__ ls,
    const float* __restrict__ lb, const float* __restrict__ hw,
    const float* __restrict__ hb, float* __restrict__ out)
{
    int bidx = threadIdx.x >> 5;
    if (bidx >= BATCH) return;
    int lane = threadIdx.x & 31;
    const float* xr = h + (size_t)bidx * S_LEN * D_MODEL;
    float4 v = *reinterpret_cast<const float4*>(xr + lane * 4);
    float sum = v.x + v.y + v.z + v.w;
    #pragma unroll
    for (int o = 16; o; o >>= 1) sum += __shfl_xor_sync(0xffffffffu, sum, o);
    float mean = sum * (1.f / 128.f);
    float dx = v.x - mean, dy = v.y - mean, dz = v.z - mean, dw = v.w - mean;
    float vs = dx * dx + dy * dy + dz * dz + dw * dw;
    #pragma unroll
    for (int o = 16; o; o >>= 1) vs += __shfl_xor_sync(0xffffffffu, vs, o);
    float rstd = rsqrtf(vs * (1.f / 128.f) + 1e-5f);
    float4 s4 = *reinterpret_cast<const float4*>(ls + lane * 4);
    float4 b4 = *reinterpret_cast<const float4*>(lb + lane * 4);
    float4 w4 = *reinterpret_cast<const float4*>(hw + lane * 4);
    float dot = (dx * rstd * s4.x + b4.x) * w4.x
              + (dy * rstd * s4.y + b4.y) * w4.y
              + (dz * rstd * s4.z + b4.z) * w4.z
              + (dw * rstd * s4.w + b4.w) * w4.w;
    #pragma unroll
    for (int o = 16; o; o >>= 1) dot += __shfl_xor_sync(0xffffffffu, dot, o);
    if (lane == 0) out[bidx] = dot + hb[0];
}

// ---------------- launch ----------------
extern "C" void kernel_launch(void* const* d_in, const int* in_sizes, int n_in,
                              void* d_out, int out_size)
{
    const float* x        = (const float*)d_in[0];
    const float* embed_w  = (const float*)d_in[1];
    const float* embed_b  = (const float*)d_in[2];
    const float* pos_emb  = (const float*)d_in[3];
    const float* cls      = (const float*)d_in[4];
    const float* in_w     = (const float*)d_in[5];
    const float* in_b     = (const float*)d_in[6];
    const float* out_w    = (const float*)d_in[7];
    const float* out_b    = (const float*)d_in[8];
    const float* ln1_s    = (const float*)d_in[9];
    const float* ln1_b    = (const float*)d_in[10];
    const float* ln2_s    = (const float*)d_in[11];
    const float* ln2_b    = (const float*)d_in[12];
    const float* ff1_w    = (const float*)d_in[13];
    const float* ff1_b    = (const float*)d_in[14];
    const float* ff2_w    = (const float*)d_in[15];
    const float* ff2_b    = (const float*)d_in[16];
    const float* hln_s    = (const float*)d_in[17];
    const float* hln_b    = (const float*)d_in[18];
    const float* head_w   = (const float*)d_in[19];
    const float* head_b   = (const float*)d_in[20];
    float* outp = (float*)d_out;

    float *h, *po, *pl;
    __half *hnh, *qkvh, *vt, *wh;
    cudaGetSymbolAddress((void**)&h,     g_h);
    cudaGetSymbolAddress((void**)&hnh,   g_hnh);
    cudaGetSymbolAddress((void**)&qkvh,  g_qkvh);
    cudaGetSymbolAddress((void**)&vt,    g_vt);
    cudaGetSymbolAddress((void**)&po,    g_po);
    cudaGetSymbolAddress((void**)&pl,    g_pl);
    cudaGetSymbolAddress((void**)&wh,    g_wh);

    cudaFuncSetAttribute(mega_tail_kernel<true>,
                         cudaFuncAttributeMaxDynamicSharedMemorySize, SMEM_MEGA);
    cudaFuncSetAttribute(mega_tail_kernel<false>,
                         cudaFuncAttributeMaxDynamicSharedMemorySize, SMEM_MEGA);

    const int M = MROWS;
    const int MB128 = (M + 127) / 128;
    const int MB32  = (M + 31) / 32;
    const int QTILES = (S_LEN + BQ - 1) / BQ;

    convw_all_kernel<<<(CW_TOTAL + 255) / 256, 256>>>(in_w, out_w, ff1_w, ff2_w, wh);

    embed_ln_kernel<<<dim3(S_LEN, BATCH), 128>>>(
        x, embed_w, embed_b, pos_emb, cls, ln1_s, ln1_b, h, hnh);

    // layer 0 QKV (from embed's hn)
    qkv_gemm_kernel<<<dim3(384 / 64, MB128), 256>>>(
        hnh, wh + WOFF_IN, in_b, qkvh, vt, M);

    for (int i = 0; i < NL; i++) {
        attn_kernel<<<dim3(QTILES * SPLITS, N_HEADS, BATCH), 256>>>(qkvh, vt, po, pl);
        if (i + 1 < NL) {
            mega_tail_kernel<true><<<MB32, 256, SMEM_MEGA>>>(
                po, pl,
                wh + WOFF_OUT + (size_t)i * 128 * 128, out_b + (size_t)i * 128,
                ln2_s + i * D_MODEL, ln2_b + i * D_MODEL,
                wh + WOFF_FF1 + (size_t)i * 512 * 128, ff1_b + (size_t)i * 512,
                wh + WOFF_FF2 + (size_t)i * 128 * 512, ff2_b + (size_t)i * 128,
                ln1_s + (i + 1) * D_MODEL, ln1_b + (i + 1) * D_MODEL,
                wh + WOFF_IN + (size_t)(i + 1) * 384 * 128, in_b + (size_t)(i + 1) * 384,
                h, qkvh, vt, M);
        } else {
            mega_tail_kernel<false><<<MB32, 256, SMEM_MEGA>>>(
                po, pl,
                wh + WOFF_OUT + (size_t)i * 128 * 128, out_b + (size_t)i * 128,
                ln2_s + i * D_MODEL, ln2_b + i * D_MODEL,
                wh + WOFF_FF1 + (size_t)i * 512 * 128, ff1_b + (size_t)i * 512,
                wh + WOFF_FF2 + (size_t)i * 128 * 512, ff2_b + (size_t)i * 128,
                nullptr, nullptr, nullptr, nullptr,
                h, nullptr, nullptr, M);
        }
    }

    head_kernel<<<1, 64>>>(h, hln_s, hln_b, head_w, head_b, outp);
}